// round 1
// baseline (speedup 1.0000x reference)
#include <cuda_runtime.h>
#include <math.h>

// ---------------- problem constants ----------------
#define EXP    4
#define BATCH  8
#define NQ_    144
#define NLAYERS 2
#define NHEADS 16
#define HDIM   64
#define HID    1024
#define OUTD   4096
#define TDIM   256
#define LV_    576
#define LP_    192
#define MAXSQ  64
#define MAXKV  320
#define GN     (HID + 2*TDIM)   // 1536

// ---------------- scratch (static device globals; no allocation) ----------------
__device__ float g_x   [EXP*BATCH*MAXSQ*HID];
__device__ float g_xln [EXP*BATCH*MAXSQ*HID];
__device__ float g_att [EXP*BATCH*MAXSQ*HID];
__device__ float g_q   [EXP*BATCH*MAXSQ*HID];
__device__ float g_kvn [EXP*BATCH*MAXKV*HID];
__device__ float g_kv  [EXP*BATCH*MAXKV*2048];   // K in cols [0,1024), V in [1024,2048)
__device__ float g_ffn [EXP*BATCH*MAXSQ*4096];
__device__ float g_y   [EXP*BATCH*NQ_*HID];
__device__ float g_gates[BATCH*EXP];
__device__ float g_gi  [BATCH*HID];

// ---------------- reductions ----------------
__device__ __forceinline__ void blockReduce2(float& a, float& b, float* sh) {
    __syncthreads();
    int lane = threadIdx.x & 31, wid = threadIdx.x >> 5;
    #pragma unroll
    for (int o = 16; o; o >>= 1) { a += __shfl_xor_sync(~0u, a, o); b += __shfl_xor_sync(~0u, b, o); }
    if (lane == 0) { sh[wid] = a; sh[wid + 32] = b; }
    __syncthreads();
    int nw = blockDim.x >> 5;
    if (wid == 0) {
        a = (lane < nw) ? sh[lane] : 0.f;
        b = (lane < nw) ? sh[lane + 32] : 0.f;
        #pragma unroll
        for (int o = 16; o; o >>= 1) { a += __shfl_xor_sync(~0u, a, o); b += __shfl_xor_sync(~0u, b, o); }
        if (lane == 0) { sh[0] = a; sh[32] = b; }
    }
    __syncthreads();
    a = sh[0]; b = sh[32];
}

__device__ __forceinline__ float blockReduce1(float a, float* sh) {
    __syncthreads();
    int lane = threadIdx.x & 31, wid = threadIdx.x >> 5;
    #pragma unroll
    for (int o = 16; o; o >>= 1) a += __shfl_xor_sync(~0u, a, o);
    if (lane == 0) sh[wid] = a;
    __syncthreads();
    int nw = blockDim.x >> 5;
    if (wid == 0) {
        a = (lane < nw) ? sh[lane] : 0.f;
        #pragma unroll
        for (int o = 16; o; o >>= 1) a += __shfl_xor_sync(~0u, a, o);
        if (lane == 0) sh[0] = a;
    }
    __syncthreads();
    return sh[0];
}

// ---------------- gate: mean over image tokens ----------------
__global__ void k_gate_mean(const float* __restrict__ img, float* __restrict__ gi) {
    int b = blockIdx.x;
    for (int h = threadIdx.x; h < HID; h += blockDim.x) {
        float s = 0.f;
        for (int l = 0; l < LV_; l++) s += img[((long)b*LV_ + l)*HID + h];
        gi[b*HID + h] = s * (1.f/LV_);
    }
}

// ---------------- gate: LN + logits + softmax + top2 ----------------
__global__ void k_gate(const float* __restrict__ gi, const float* __restrict__ temb,
                       const float* __restrict__ eemb, const int* __restrict__ tids,
                       const int* __restrict__ eids, const float* __restrict__ glw,
                       const float* __restrict__ glb, const float* __restrict__ gwt,
                       const float* __restrict__ gbias, float* __restrict__ gates) {
    int b = blockIdx.x, tid = threadIdx.x;
    __shared__ float sh[64];
    __shared__ float logits[EXP];
    int ti = tids[b], ei = eids[b];
    float s = 0.f, ss = 0.f;
    for (int i = tid; i < GN; i += 256) {
        float v = (i < HID) ? gi[b*HID + i]
                : (i < HID + TDIM) ? temb[ti*TDIM + i - HID]
                : eemb[ei*TDIM + i - HID - TDIM];
        s += v; ss += v*v;
    }
    blockReduce2(s, ss, sh);
    float m  = s * (1.f/GN);
    float rs = rsqrtf(ss * (1.f/GN) - m*m + 1e-5f);
    for (int e = 0; e < EXP; e++) {
        float d = 0.f;
        for (int i = tid; i < GN; i += 256) {
            float v = (i < HID) ? gi[b*HID + i]
                    : (i < HID + TDIM) ? temb[ti*TDIM + i - HID]
                    : eemb[ei*TDIM + i - HID - TDIM];
            d += ((v - m)*rs*glw[i] + glb[i]) * gwt[(long)e*GN + i];
        }
        d = blockReduce1(d, sh);
        if (tid == 0) logits[e] = d + gbias[e];
    }
    __syncthreads();
    if (tid == 0) {
        float w[EXP]; float mx = -1e30f;
        for (int e = 0; e < EXP; e++) { float l = fminf(fmaxf(logits[e], -15.f), 15.f); w[e] = l; mx = fmaxf(mx, l); }
        float sum = 0.f;
        for (int e = 0; e < EXP; e++) { w[e] = expf(w[e] - mx); sum += w[e]; }
        for (int e = 0; e < EXP; e++) w[e] /= sum;
        int i0 = 0;
        for (int e = 1; e < EXP; e++) if (w[e] > w[i0]) i0 = e;
        int i1 = -1;
        for (int e = 0; e < EXP; e++) { if (e == i0) continue; if (i1 < 0 || w[e] > w[i1]) i1 = e; }
        float t = w[i0] + w[i1] + 1e-9f;
        for (int e = 0; e < EXP; e++) gates[b*EXP + e] = 0.f;
        gates[b*EXP + i0] = w[i0] / t;
        gates[b*EXP + i1] = w[i1] / t;
    }
}

// ---------------- init x = query tile (broadcast over b) ----------------
__global__ void k_initx(const float* __restrict__ query, int qo, float* __restrict__ gx,
                        const float* __restrict__ gates) {
    int r = blockIdx.x, b = blockIdx.y, e = blockIdx.z;
    if (gates[b*EXP + e] == 0.f) return;
    const float* srow = query + ((long)e*NQ_ + qo + r)*HID;
    float* d = gx + ((long)(e*BATCH + b)*MAXSQ + r)*HID;
    for (int i = threadIdx.x; i < HID; i += blockDim.x) d[i] = srow[i];
}

// ---------------- LayerNorm (generic rows) ----------------
__global__ void k_ln(const float* __restrict__ src, long srcBS,
                     const float* __restrict__ w, const float* __restrict__ bvec, long pES,
                     float* __restrict__ dst, long dstBS, const float* __restrict__ gates) {
    int r = blockIdx.x, b = blockIdx.y, e = blockIdx.z;
    if (gates[b*EXP + e] == 0.f) return;
    const float* row = src + (long)(e*BATCH + b)*srcBS + (long)r*HID;
    float* drow = dst + (long)(e*BATCH + b)*dstBS + (long)r*HID;
    __shared__ float sh[64];
    float v[4]; float s = 0.f, ss = 0.f;
    #pragma unroll
    for (int t = 0; t < 4; t++) { v[t] = row[threadIdx.x + t*256]; s += v[t]; ss += v[t]*v[t]; }
    blockReduce2(s, ss, sh);
    float m  = s * (1.f/HID);
    float rs = rsqrtf(ss * (1.f/HID) - m*m + 1e-5f);
    const float* we = w + (long)e*pES;
    const float* be = bvec + (long)e*pES;
    #pragma unroll
    for (int t = 0; t < 4; t++) {
        int i = threadIdx.x + t*256;
        drow[i] = (v[t] - m)*rs*we[i] + be[i];
    }
}

// ---------------- LayerNorm with kv0 gather (query tile ++ z chunk) ----------------
__global__ void k_ln_kv(int sq, int qo, int io, const float* __restrict__ query,
                        const float* __restrict__ img, const float* __restrict__ pp,
                        const float* __restrict__ w, const float* __restrict__ bvec, long pES,
                        float* __restrict__ dst, const float* __restrict__ gates) {
    int r = blockIdx.x, b = blockIdx.y, e = blockIdx.z;
    if (gates[b*EXP + e] == 0.f) return;
    const float* row;
    if (r < sq) row = query + ((long)e*NQ_ + qo + r)*HID;
    else {
        int zi = io + r - sq;
        if (zi < LV_) row = img + ((long)b*LV_ + zi)*HID;
        else          row = pp  + ((long)b*LP_ + zi - LV_)*HID;
    }
    float* drow = dst + ((long)(e*BATCH + b)*MAXKV + r)*HID;
    __shared__ float sh[64];
    float v[4]; float s = 0.f, ss = 0.f;
    #pragma unroll
    for (int t = 0; t < 4; t++) { v[t] = row[threadIdx.x + t*256]; s += v[t]; ss += v[t]*v[t]; }
    blockReduce2(s, ss, sh);
    float m  = s * (1.f/HID);
    float rs = rsqrtf(ss * (1.f/HID) - m*m + 1e-5f);
    const float* we = w + (long)e*pES;
    const float* be = bvec + (long)e*pES;
    #pragma unroll
    for (int t = 0; t < 4; t++) {
        int i = threadIdx.x + t*256;
        drow[i] = (v[t] - m)*rs*we[i] + be[i];
    }
}

// ---------------- generic NT GEMM:  C = A(M,K) @ W(N,K)^T, fused epilogues ----------------
// epi 0: C = acc + bias
// epi 1: C = gelu_exact(acc + bias)
// epi 2: C = C + ls * (acc + bias)     (residual in-place)
__global__ __launch_bounds__(256) void k_gemm(
    int M, int N, int K,
    const float* __restrict__ Abase, long aBS,
    const float* __restrict__ Wbase, long wES,
    const float* __restrict__ biasB, long bES,
    float* __restrict__ Cbase, long cBS,
    const float* __restrict__ lsB, long lsES,
    int epi, const float* __restrict__ gates) {
    int e = blockIdx.z / BATCH, b = blockIdx.z % BATCH;
    if (gates[b*EXP + e] == 0.f) return;
    const float* A = Abase + (long)blockIdx.z * aBS;
    const float* W = Wbase + (long)e * wES;
    float* C = Cbase + (long)blockIdx.z * cBS;
    int m0 = blockIdx.y * 64, n0 = blockIdx.x * 64;

    __shared__ __align__(16) float As[16][64];
    __shared__ __align__(16) float Ws[16][64];
    int tid = threadIdx.x;
    int lr = tid >> 2, lk = (tid & 3) << 2;
    int tr = (tid >> 4) << 2, tc = (tid & 15) << 2;
    float acc[4][4] = {};

    for (int k0 = 0; k0 < K; k0 += 16) {
        int ar = m0 + lr;
        float4 av = (ar < M) ? *(const float4*)(A + (long)ar*K + k0 + lk)
                             : make_float4(0.f, 0.f, 0.f, 0.f);
        As[lk+0][lr] = av.x; As[lk+1][lr] = av.y; As[lk+2][lr] = av.z; As[lk+3][lr] = av.w;
        float4 wv = *(const float4*)(W + (long)(n0 + lr)*K + k0 + lk);
        Ws[lk+0][lr] = wv.x; Ws[lk+1][lr] = wv.y; Ws[lk+2][lr] = wv.z; Ws[lk+3][lr] = wv.w;
        __syncthreads();
        #pragma unroll
        for (int k = 0; k < 16; k++) {
            float4 a4 = *(const float4*)&As[k][tr];
            float4 w4 = *(const float4*)&Ws[k][tc];
            float ra[4] = {a4.x, a4.y, a4.z, a4.w};
            float rw[4] = {w4.x, w4.y, w4.z, w4.w};
            #pragma unroll
            for (int i = 0; i < 4; i++)
                #pragma unroll
                for (int j = 0; j < 4; j++) acc[i][j] += ra[i]*rw[j];
        }
        __syncthreads();
    }
    const float* bias = biasB + (long)e*bES;
    #pragma unroll
    for (int i = 0; i < 4; i++) {
        int row = m0 + tr + i;
        if (row >= M) continue;
        #pragma unroll
        for (int j = 0; j < 4; j++) {
            int col = n0 + tc + j;
            float v = acc[i][j] + bias[col];
            long idx = (long)row*N + col;
            if (epi == 1) {
                C[idx] = 0.5f * v * (1.f + erff(v * 0.70710678118654752f));
            } else if (epi == 2) {
                const float* ls = lsB + (long)e*lsES;
                C[idx] = C[idx] + ls[col]*v;
            } else {
                C[idx] = v;
            }
        }
    }
}

// ---------------- attention: one warp per (head, query row) ----------------
__global__ void k_attn(int sq, int kvlen,
                       const float* __restrict__ q, const float* __restrict__ kv,
                       float* __restrict__ att, const float* __restrict__ gates) {
    int e = blockIdx.z, b = blockIdx.y;
    if (gates[b*EXP + e] == 0.f) return;
    int warp = threadIdx.x >> 5, lane = threadIdx.x & 31;
    int w = blockIdx.x * 4 + warp;
    if (w >= NHEADS * sq) return;
    int h = w / sq, qi = w % sq;
    __shared__ float sc[4][MAXKV];

    long xoff  = (long)(e*BATCH + b) * MAXSQ * HID;
    long kvoff = (long)(e*BATCH + b) * MAXKV * 2048;
    const float* qr = q + xoff + (long)qi*HID + h*HDIM;
    float q0 = qr[lane], q1 = qr[lane + 32];
    const float* kbase = kv + kvoff + h*HDIM;
    float mx = -1e30f;
    for (int j = 0; j < kvlen; j++) {
        const float* kr = kbase + (long)j*2048;
        float p = q0*kr[lane] + q1*kr[lane + 32];
        #pragma unroll
        for (int o = 16; o; o >>= 1) p += __shfl_xor_sync(~0u, p, o);
        p *= 0.125f;                      // 1/sqrt(64)
        if (lane == 0) sc[warp][j] = p;
        mx = fmaxf(mx, p);
    }
    __syncwarp();
    float se = 0.f;
    for (int j = lane; j < kvlen; j += 32) {
        float ex = __expf(sc[warp][j] - mx);
        sc[warp][j] = ex;
        se += ex;
    }
    #pragma unroll
    for (int o = 16; o; o >>= 1) se += __shfl_xor_sync(~0u, se, o);
    __syncwarp();
    float inv = 1.f / se;
    const float* vbase = kv + kvoff + 1024 + h*HDIM;
    float a0 = 0.f, a1 = 0.f;
    for (int j = 0; j < kvlen; j++) {
        float p = sc[warp][j];
        const float* vr = vbase + (long)j*2048;
        a0 += p*vr[lane]; a1 += p*vr[lane + 32];
    }
    float* orow = att + xoff + (long)qi*HID + h*HDIM;
    orow[lane]      = a0 * inv;
    orow[lane + 32] = a1 * inv;
}

// ---------------- copy stage result into y ----------------
__global__ void k_copy_y(const float* __restrict__ gx, int qo, float* __restrict__ y,
                         const float* __restrict__ gates) {
    int r = blockIdx.x, b = blockIdx.y, e = blockIdx.z;
    if (gates[b*EXP + e] == 0.f) return;
    const float* srow = gx + ((long)(e*BATCH + b)*MAXSQ + r)*HID;
    float* d = y + ((long)(e*BATCH + b)*NQ_ + qo + r)*HID;
    for (int i = threadIdx.x; i < HID; i += blockDim.x) d[i] = srow[i];
}

// ---------------- fused output projection + gate-combine over active experts ----------------
__global__ __launch_bounds__(256) void k_gemm_out(
    const float* __restrict__ y, const float* __restrict__ Wo, const float* __restrict__ bo,
    float* __restrict__ outp, const float* __restrict__ gates) {
    int b = blockIdx.z;
    int m0 = blockIdx.y * 64, n0 = blockIdx.x * 64;
    __shared__ __align__(16) float As[16][64];
    __shared__ __align__(16) float Ws[16][64];
    int tid = threadIdx.x;
    int lr = tid >> 2, lk = (tid & 3) << 2;
    int tr = (tid >> 4) << 2, tc = (tid & 15) << 2;
    float tot[4][4] = {};
    float bsum[4] = {0.f, 0.f, 0.f, 0.f};

    for (int e = 0; e < EXP; e++) {
        float g = gates[b*EXP + e];
        if (g == 0.f) continue;                       // uniform per block (b fixed)
        const float* A = y  + (long)(e*BATCH + b)*NQ_*HID;
        const float* W = Wo + (long)e*OUTD*HID;
        float acc[4][4] = {};
        for (int k0 = 0; k0 < HID; k0 += 16) {
            int ar = m0 + lr;
            float4 av = (ar < NQ_) ? *(const float4*)(A + (long)ar*HID + k0 + lk)
                                   : make_float4(0.f, 0.f, 0.f, 0.f);
            As[lk+0][lr] = av.x; As[lk+1][lr] = av.y; As[lk+2][lr] = av.z; As[lk+3][lr] = av.w;
            float4 wv = *(const float4*)(W + (long)(n0 + lr)*HID + k0 + lk);
            Ws[lk+0][lr] = wv.x; Ws[lk+1][lr] = wv.y; Ws[lk+2][lr] = wv.z; Ws[lk+3][lr] = wv.w;
            __syncthreads();
            #pragma unroll
            for (int k = 0; k < 16; k++) {
                float4 a4 = *(const float4*)&As[k][tr];
                float4 w4 = *(const float4*)&Ws[k][tc];
                float ra[4] = {a4.x, a4.y, a4.z, a4.w};
                float rw[4] = {w4.x, w4.y, w4.z, w4.w};
                #pragma unroll
                for (int i = 0; i < 4; i++)
                    #pragma unroll
                    for (int j = 0; j < 4; j++) acc[i][j] += ra[i]*rw[j];
            }
            __syncthreads();
        }
        #pragma unroll
        for (int i = 0; i < 4; i++)
            #pragma unroll
            for (int j = 0; j < 4; j++) tot[i][j] += g*acc[i][j];
        #pragma unroll
        for (int j = 0; j < 4; j++) bsum[j] += g*bo[(long)e*OUTD + n0 + tc + j];
    }
    #pragma unroll
    for (int i = 0; i < 4; i++) {
        int row = m0 + tr + i;
        if (row >= NQ_) continue;
        #pragma unroll
        for (int j = 0; j < 4; j++)
            outp[((long)b*NQ_ + row)*OUTD + n0 + tc + j] = tot[i][j] + bsum[j];
    }
}

// ---------------- RMS norm + final scaling (in place on d_out) ----------------
__global__ void k_rms(float* __restrict__ out, const float* __restrict__ fw,
                      const float* __restrict__ gain) {
    int q = blockIdx.x, b = blockIdx.y;
    float* row = out + ((long)b*NQ_ + q)*OUTD;
    __shared__ float sh[64];
    float v[16]; float ss = 0.f;
    #pragma unroll
    for (int t = 0; t < 16; t++) { v[t] = row[threadIdx.x + t*256]; ss += v[t]*v[t]; }
    ss = blockReduce1(ss, sh);
    float sc = rsqrtf(ss * (1.f/OUTD) + 1e-6f);
    #pragma unroll
    for (int t = 0; t < 16; t++) {
        int o = threadIdx.x + t*256;
        row[o] = v[t]*sc*fw[o]*gain[o];
    }
}

// ---------------- host orchestration ----------------
extern "C" void kernel_launch(void* const* d_in, const int* in_sizes, int n_in,
                              void* d_out, int out_size) {
    const float* image     = (const float*)d_in[0];
    const float* pp        = (const float*)d_in[1];
    const int*   tids      = (const int*)  d_in[2];
    const int*   eids      = (const int*)  d_in[3];
    const float* query     = (const float*)d_in[4];
    const float* ln1_w     = (const float*)d_in[5];
    const float* ln1_b     = (const float*)d_in[6];
    const float* ln1kv_w   = (const float*)d_in[7];
    const float* ln1kv_b   = (const float*)d_in[8];
    const float* attn_in_w = (const float*)d_in[9];
    const float* attn_in_b = (const float*)d_in[10];
    const float* attn_out_w= (const float*)d_in[11];
    const float* attn_out_b= (const float*)d_in[12];
    const float* ls1       = (const float*)d_in[13];
    const float* ls2       = (const float*)d_in[14];
    const float* ln2_w     = (const float*)d_in[15];
    const float* ln2_b     = (const float*)d_in[16];
    const float* fc_w      = (const float*)d_in[17];
    const float* fc_b      = (const float*)d_in[18];
    const float* proj_w    = (const float*)d_in[19];
    const float* proj_b    = (const float*)d_in[20];
    const float* outp_w    = (const float*)d_in[21];
    const float* outp_b    = (const float*)d_in[22];
    const float* temb      = (const float*)d_in[23];
    const float* eemb      = (const float*)d_in[24];
    const float* glw       = (const float*)d_in[25];
    const float* glb       = (const float*)d_in[26];
    const float* gwt       = (const float*)d_in[27];
    const float* gbias     = (const float*)d_in[28];
    const float* gain      = (const float*)d_in[29];
    const float* fw        = (const float*)d_in[30];
    float* out = (float*)d_out;

    float *px, *pxln, *patt, *pq, *pkvn, *pkv, *pffn, *py, *pg, *pgi;
    cudaGetSymbolAddress((void**)&px,   g_x);
    cudaGetSymbolAddress((void**)&pxln, g_xln);
    cudaGetSymbolAddress((void**)&patt, g_att);
    cudaGetSymbolAddress((void**)&pq,   g_q);
    cudaGetSymbolAddress((void**)&pkvn, g_kvn);
    cudaGetSymbolAddress((void**)&pkv,  g_kv);
    cudaGetSymbolAddress((void**)&pffn, g_ffn);
    cudaGetSymbolAddress((void**)&py,   g_y);
    cudaGetSymbolAddress((void**)&pg,   g_gates);
    cudaGetSymbolAddress((void**)&pgi,  g_gi);

    k_gate_mean<<<BATCH, 256>>>(image, pgi);
    k_gate<<<BATCH, 256>>>(pgi, temb, eemb, tids, eids, glw, glb, gwt, gbias, pg);

    const int sqs[3] = {64, 48, 32};
    const int qos[3] = {0, 64, 112};
    const int ios[3] = {0, 256, 512};

    for (int s = 0; s < 3; s++) {
        int sq = sqs[s], qo = qos[s], io = ios[s];
        int kvlen = sq + 256;
        k_initx<<<dim3(sq, BATCH, EXP), 256>>>(query, qo, px, pg);
        for (int l = 0; l < NLAYERS; l++) {
            // LN of kv0 (fixed source) and of current x
            k_ln_kv<<<dim3(kvlen, BATCH, EXP), 256>>>(sq, qo, io, query, image, pp,
                ln1kv_w + (long)l*HID, ln1kv_b + (long)l*HID, (long)NLAYERS*HID, pkvn, pg);
            k_ln<<<dim3(sq, BATCH, EXP), 256>>>(px, (long)MAXSQ*HID,
                ln1_w + (long)l*HID, ln1_b + (long)l*HID, (long)NLAYERS*HID,
                pxln, (long)MAXSQ*HID, pg);
            // Q projection
            k_gemm<<<dim3(16, (sq + 63)/64, EXP*BATCH), 256>>>(sq, HID, HID,
                pxln, (long)MAXSQ*HID,
                attn_in_w + (long)l*3*HID*HID, (long)NLAYERS*3*HID*HID,
                attn_in_b + (long)l*3*HID,     (long)NLAYERS*3*HID,
                pq, (long)MAXSQ*HID, (const float*)0, 0, 0, pg);
            // K,V projection (fused N=2048)
            k_gemm<<<dim3(32, (kvlen + 63)/64, EXP*BATCH), 256>>>(kvlen, 2048, HID,
                pkvn, (long)MAXKV*HID,
                attn_in_w + (long)l*3*HID*HID + (long)HID*HID, (long)NLAYERS*3*HID*HID,
                attn_in_b + (long)l*3*HID + HID,               (long)NLAYERS*3*HID,
                pkv, (long)MAXKV*2048, (const float*)0, 0, 0, pg);
            // attention
            k_attn<<<dim3((NHEADS*sq + 3)/4, BATCH, EXP), 128>>>(sq, kvlen, pq, pkv, patt, pg);
            // output projection + residual (x += ls1 * (...))
            k_gemm<<<dim3(16, (sq + 63)/64, EXP*BATCH), 256>>>(sq, HID, HID,
                patt, (long)MAXSQ*HID,
                attn_out_w + (long)l*HID*HID, (long)NLAYERS*HID*HID,
                attn_out_b + (long)l*HID,     (long)NLAYERS*HID,
                px, (long)MAXSQ*HID,
                ls1 + (long)l*HID, (long)NLAYERS*HID, 2, pg);
            // MLP
            k_ln<<<dim3(sq, BATCH, EXP), 256>>>(px, (long)MAXSQ*HID,
                ln2_w + (long)l*HID, ln2_b + (long)l*HID, (long)NLAYERS*HID,
                pxln, (long)MAXSQ*HID, pg);
            k_gemm<<<dim3(64, (sq + 63)/64, EXP*BATCH), 256>>>(sq, 4096, HID,
                pxln, (long)MAXSQ*HID,
                fc_w + (long)l*4*HID*HID, (long)NLAYERS*4*HID*HID,
                fc_b + (long)l*4*HID,     (long)NLAYERS*4*HID,
                pffn, (long)MAXSQ*4096, (const float*)0, 0, 1, pg);
            k_gemm<<<dim3(16, (sq + 63)/64, EXP*BATCH), 256>>>(sq, HID, 4096,
                pffn, (long)MAXSQ*4096,
                proj_w + (long)l*HID*4*HID, (long)NLAYERS*HID*4*HID,
                proj_b + (long)l*HID,       (long)NLAYERS*HID,
                px, (long)MAXSQ*HID,
                ls2 + (long)l*HID, (long)NLAYERS*HID, 2, pg);
        }
        k_copy_y<<<dim3(sq, BATCH, EXP), 256>>>(px, qo, py, pg);
    }

    // final projection fused with gate combine, then RMS + scaling
    k_gemm_out<<<dim3(OUTD/64, (NQ_ + 63)/64, BATCH), 256>>>(py, outp_w, outp_b, out, pg);
    k_rms<<<dim3(NQ_, BATCH), 256>>>(out, fw, gain);
}

// round 3
// speedup vs baseline: 1.5224x; 1.5224x over previous
#include <cuda_runtime.h>
#include <cuda_bf16.h>
#include <math.h>
#include <stdint.h>

// ---------------- problem constants ----------------
#define EXP    4
#define BATCH  8
#define NQ_    144
#define NLAYERS 2
#define NHEADS 16
#define HDIM   64
#define HID    1024
#define OUTD   4096
#define TDIM   256
#define LV_    576
#define LP_    192
#define MAXSQ  64
#define MAXKV  320
#define GN     (HID + 2*TDIM)   // 1536

// ---------------- scratch (static device globals; no allocation) ----------------
__device__ float g_x   [EXP*BATCH*MAXSQ*HID];
__device__ float g_xln [EXP*BATCH*MAXSQ*HID];
__device__ float g_att [EXP*BATCH*MAXSQ*HID];
__device__ float g_q   [EXP*BATCH*MAXSQ*HID];
__device__ float g_kvn [EXP*BATCH*MAXKV*HID];
__device__ float g_kv  [EXP*BATCH*MAXKV*2048];   // K in cols [0,1024), V in [1024,2048)
__device__ float g_ffn [EXP*BATCH*MAXSQ*4096];
__device__ float g_y   [EXP*BATCH*NQ_*HID];
__device__ float g_gates[BATCH*EXP];
__device__ float g_gi  [BATCH*HID];

// ================= HMMA helpers (baseline PTX, no 'a' features) =================
__device__ __forceinline__ void mma16816(float* c, const uint32_t* a, const uint32_t* b) {
    asm volatile("mma.sync.aligned.m16n8k16.row.col.f32.bf16.bf16.f32 "
        "{%0,%1,%2,%3}, {%4,%5,%6,%7}, {%8,%9}, {%0,%1,%2,%3};"
        : "+f"(c[0]), "+f"(c[1]), "+f"(c[2]), "+f"(c[3])
        : "r"(a[0]), "r"(a[1]), "r"(a[2]), "r"(a[3]), "r"(b[0]), "r"(b[1]));
}

__device__ __forceinline__ uint32_t pack2(__nv_bfloat16 a, __nv_bfloat16 b) {
    return (uint32_t)__bfloat16_as_ushort(a) | ((uint32_t)__bfloat16_as_ushort(b) << 16);
}
// split float4 into bf16-hi pairs and bf16-lo (residual) pairs
__device__ __forceinline__ void split4(float4 v, uint2& h, uint2& l) {
    __nv_bfloat16 h0 = __float2bfloat16(v.x), h1 = __float2bfloat16(v.y);
    __nv_bfloat16 h2 = __float2bfloat16(v.z), h3 = __float2bfloat16(v.w);
    __nv_bfloat16 l0 = __float2bfloat16(v.x - __bfloat162float(h0));
    __nv_bfloat16 l1 = __float2bfloat16(v.y - __bfloat162float(h1));
    __nv_bfloat16 l2 = __float2bfloat16(v.z - __bfloat162float(h2));
    __nv_bfloat16 l3 = __float2bfloat16(v.w - __bfloat162float(h3));
    h = make_uint2(pack2(h0, h1), pack2(h2, h3));
    l = make_uint2(pack2(l0, l1), pack2(l2, l3));
}

#define PITCH 17   // u32 (bf16x2 pair) pitch per row: 16 pairs + 1 pad

// ================= tensor-core GEMM: C = A(rows,K) @ W(N,K)^T =================
// Rows contiguous across 32 (e,b) slots, RP rows per slot.
// epi 0: C = acc+bias.  epi 1: C = gelu(acc+bias).  epi 2: C += ls*(acc+bias)
__global__ __launch_bounds__(256, 1) void k_tgemm(
    int N, int K, int RP, int validM,
    const float* __restrict__ A,
    const float* __restrict__ Wb, long wES,
    const float* __restrict__ biasB, long bES,
    float* __restrict__ C,
    const float* __restrict__ lsB, long lsES,
    int epi, const float* __restrict__ gates)
{
    int m0 = blockIdx.y * 128;
    int n0 = blockIdx.x * 128;
    int p0 = m0 / RP, p1 = (m0 + 127) / RP;
    bool any = false;
    for (int p = p0; p <= p1; ++p)
        if (gates[(p & 7) * EXP + (p >> 3)] != 0.f) any = true;
    if (!any) return;
    int eBlk = p0 >> 3;

    __shared__ uint32_t AsH[128][PITCH], AsL[128][PITCH];
    __shared__ uint32_t BsH[128][PITCH], BsL[128][PITCH];

    int tid = threadIdx.x;
    int warp = tid >> 5, lane = tid & 31;
    int wm = warp & 3, wn = warp >> 2;
    int g8 = lane >> 2, tg = lane & 3;

    const float* W = Wb + (long)eBlk * wES;
    float acc[2][8][4] = {};

    int nch = K >> 5;
    for (int c = 0; c < nch; ++c) {
        int k0 = c << 5;
        #pragma unroll
        for (int i = 0; i < 4; ++i) {
            int idx = tid + i * 256;
            int row = idx >> 3, c4 = idx & 7;
            uint2 h, l;
            float4 va = *(const float4*)(A + (long)(m0 + row) * K + k0 + (c4 << 2));
            split4(va, h, l);
            AsH[row][c4*2] = h.x; AsH[row][c4*2+1] = h.y;
            AsL[row][c4*2] = l.x; AsL[row][c4*2+1] = l.y;
            float4 vb = *(const float4*)(W + (long)(n0 + row) * K + k0 + (c4 << 2));
            split4(vb, h, l);
            BsH[row][c4*2] = h.x; BsH[row][c4*2+1] = h.y;
            BsL[row][c4*2] = l.x; BsL[row][c4*2+1] = l.y;
        }
        __syncthreads();
        #pragma unroll
        for (int kh = 0; kh < 2; ++kh) {
            int kb = kh * 8;
            uint32_t ah[2][4], al[2][4];
            #pragma unroll
            for (int mt = 0; mt < 2; ++mt) {
                int r = wm * 32 + mt * 16 + g8;
                ah[mt][0] = AsH[r][kb+tg];     ah[mt][1] = AsH[r+8][kb+tg];
                ah[mt][2] = AsH[r][kb+tg+4];   ah[mt][3] = AsH[r+8][kb+tg+4];
                al[mt][0] = AsL[r][kb+tg];     al[mt][1] = AsL[r+8][kb+tg];
                al[mt][2] = AsL[r][kb+tg+4];   al[mt][3] = AsL[r+8][kb+tg+4];
            }
            #pragma unroll
            for (int nt = 0; nt < 8; ++nt) {
                int n = wn * 64 + nt * 8 + g8;
                uint32_t bh[2] = { BsH[n][kb+tg], BsH[n][kb+tg+4] };
                uint32_t bl[2] = { BsL[n][kb+tg], BsL[n][kb+tg+4] };
                #pragma unroll
                for (int mt = 0; mt < 2; ++mt) {
                    mma16816(acc[mt][nt], ah[mt], bh);
                    mma16816(acc[mt][nt], ah[mt], bl);
                    mma16816(acc[mt][nt], al[mt], bh);
                }
            }
        }
        __syncthreads();
    }

    // epilogue
    const float* bias = biasB + (long)eBlk * bES;
    const float* ls = lsB ? (lsB + (long)eBlk * lsES) : (const float*)0;
    #pragma unroll
    for (int mt = 0; mt < 2; ++mt) {
        int r0 = m0 + wm * 32 + mt * 16 + g8;
        int r1 = r0 + 8;
        int p0r = r0 / RP, q0r = r0 % RP;
        int p1r = r1 / RP, q1r = r1 % RP;
        bool ok0 = (q0r < validM) && (gates[(p0r & 7) * EXP + (p0r >> 3)] != 0.f);
        bool ok1 = (q1r < validM) && (gates[(p1r & 7) * EXP + (p1r >> 3)] != 0.f);
        #pragma unroll
        for (int nt = 0; nt < 8; ++nt) {
            int col = n0 + wn * 64 + nt * 8 + tg * 2;
            float* cc = acc[mt][nt];
            #pragma unroll
            for (int q = 0; q < 4; ++q) {
                int row = (q < 2) ? r0 : r1;
                bool ok = (q < 2) ? ok0 : ok1;
                if (!ok) continue;
                int cl = col + (q & 1);
                float v = cc[q] + bias[cl];
                long idx = (long)row * N + cl;
                if (epi == 1)      C[idx] = 0.5f * v * (1.f + erff(v * 0.70710678118654752f));
                else if (epi == 2) C[idx] = C[idx] + ls[cl] * v;
                else               C[idx] = v;
            }
        }
    }
}

// ================= final projection: out[b] = sum_e g_e (y_e @ Wo_e^T + bo_e) =================
__global__ __launch_bounds__(256, 1) void k_tgemm_out(
    const float* __restrict__ y, const float* __restrict__ Wo, const float* __restrict__ bo,
    float* __restrict__ outp, const float* __restrict__ gates)
{
    int m0 = blockIdx.y * 128, n0 = blockIdx.x * 128, b = blockIdx.z;

    __shared__ uint32_t AsH[128][PITCH], AsL[128][PITCH];
    __shared__ uint32_t BsH[128][PITCH], BsL[128][PITCH];

    int tid = threadIdx.x;
    int warp = tid >> 5, lane = tid & 31;
    int wm = warp & 3, wn = warp >> 2;
    int g8 = lane >> 2, tg = lane & 3;

    float acc[2][8][4] = {};

    for (int e = 0; e < EXP; ++e) {
        float g = gates[b * EXP + e];
        if (g == 0.f) continue;
        const float* Ae = y  + (long)(e * BATCH + b) * NQ_ * HID;
        const float* W  = Wo + (long)e * OUTD * HID;
        for (int c = 0; c < 32; ++c) {
            int k0 = c << 5;
            #pragma unroll
            for (int i = 0; i < 4; ++i) {
                int idx = tid + i * 256;
                int row = idx >> 3, c4 = idx & 7;
                uint2 h, l;
                float4 va = make_float4(0.f, 0.f, 0.f, 0.f);
                if (m0 + row < NQ_) {
                    va = *(const float4*)(Ae + (long)(m0 + row) * HID + k0 + (c4 << 2));
                    va.x *= g; va.y *= g; va.z *= g; va.w *= g;
                }
                split4(va, h, l);
                AsH[row][c4*2] = h.x; AsH[row][c4*2+1] = h.y;
                AsL[row][c4*2] = l.x; AsL[row][c4*2+1] = l.y;
                float4 vb = *(const float4*)(W + (long)(n0 + row) * HID + k0 + (c4 << 2));
                split4(vb, h, l);
                BsH[row][c4*2] = h.x; BsH[row][c4*2+1] = h.y;
                BsL[row][c4*2] = l.x; BsL[row][c4*2+1] = l.y;
            }
            __syncthreads();
            #pragma unroll
            for (int kh = 0; kh < 2; ++kh) {
                int kb = kh * 8;
                uint32_t ah[2][4], al[2][4];
                #pragma unroll
                for (int mt = 0; mt < 2; ++mt) {
                    int r = wm * 32 + mt * 16 + g8;
                    ah[mt][0] = AsH[r][kb+tg];     ah[mt][1] = AsH[r+8][kb+tg];
                    ah[mt][2] = AsH[r][kb+tg+4];   ah[mt][3] = AsH[r+8][kb+tg+4];
                    al[mt][0] = AsL[r][kb+tg];     al[mt][1] = AsL[r+8][kb+tg];
                    al[mt][2] = AsL[r][kb+tg+4];   al[mt][3] = AsL[r+8][kb+tg+4];
                }
                #pragma unroll
                for (int nt = 0; nt < 8; ++nt) {
                    int n = wn * 64 + nt * 8 + g8;
                    uint32_t bh[2] = { BsH[n][kb+tg], BsH[n][kb+tg+4] };
                    uint32_t bl[2] = { BsL[n][kb+tg], BsL[n][kb+tg+4] };
                    #pragma unroll
                    for (int mt = 0; mt < 2; ++mt) {
                        mma16816(acc[mt][nt], ah[mt], bh);
                        mma16816(acc[mt][nt], ah[mt], bl);
                        mma16816(acc[mt][nt], al[mt], bh);
                    }
                }
            }
            __syncthreads();
        }
    }

    #pragma unroll
    for (int mt = 0; mt < 2; ++mt) {
        int r0 = m0 + wm * 32 + mt * 16 + g8;
        int r1 = r0 + 8;
        #pragma unroll
        for (int nt = 0; nt < 8; ++nt) {
            int col = n0 + wn * 64 + nt * 8 + tg * 2;
            float* cc = acc[mt][nt];
            #pragma unroll
            for (int q = 0; q < 4; ++q) {
                int row = (q < 2) ? r0 : r1;
                if (row >= NQ_) continue;
                int cl = col + (q & 1);
                float bs = 0.f;
                #pragma unroll
                for (int e = 0; e < EXP; ++e)
                    bs += gates[b * EXP + e] * bo[(long)e * OUTD + cl];
                outp[((long)b * NQ_ + row) * OUTD + cl] = cc[q] + bs;
            }
        }
    }
}

// ---------------- reductions ----------------
__device__ __forceinline__ void blockReduce2(float& a, float& b, float* sh) {
    __syncthreads();
    int lane = threadIdx.x & 31, wid = threadIdx.x >> 5;
    #pragma unroll
    for (int o = 16; o; o >>= 1) { a += __shfl_xor_sync(~0u, a, o); b += __shfl_xor_sync(~0u, b, o); }
    if (lane == 0) { sh[wid] = a; sh[wid + 32] = b; }
    __syncthreads();
    int nw = blockDim.x >> 5;
    if (wid == 0) {
        a = (lane < nw) ? sh[lane] : 0.f;
        b = (lane < nw) ? sh[lane + 32] : 0.f;
        #pragma unroll
        for (int o = 16; o; o >>= 1) { a += __shfl_xor_sync(~0u, a, o); b += __shfl_xor_sync(~0u, b, o); }
        if (lane == 0) { sh[0] = a; sh[32] = b; }
    }
    __syncthreads();
    a = sh[0]; b = sh[32];
}

__device__ __forceinline__ float blockReduce1(float a, float* sh) {
    __syncthreads();
    int lane = threadIdx.x & 31, wid = threadIdx.x >> 5;
    #pragma unroll
    for (int o = 16; o; o >>= 1) a += __shfl_xor_sync(~0u, a, o);
    if (lane == 0) sh[wid] = a;
    __syncthreads();
    int nw = blockDim.x >> 5;
    if (wid == 0) {
        a = (lane < nw) ? sh[lane] : 0.f;
        #pragma unroll
        for (int o = 16; o; o >>= 1) a += __shfl_xor_sync(~0u, a, o);
        if (lane == 0) sh[0] = a;
    }
    __syncthreads();
    return sh[0];
}

// ---------------- gate: mean over image tokens ----------------
__global__ void k_gate_mean(const float* __restrict__ img, float* __restrict__ gi) {
    int b = blockIdx.x;
    for (int h = threadIdx.x; h < HID; h += blockDim.x) {
        float s = 0.f;
        for (int l = 0; l < LV_; l++) s += img[((long)b*LV_ + l)*HID + h];
        gi[b*HID + h] = s * (1.f/LV_);
    }
}

// ---------------- gate: LN + logits + softmax + top2 ----------------
__global__ void k_gate(const float* __restrict__ gi, const float* __restrict__ temb,
                       const float* __restrict__ eemb, const int* __restrict__ tids,
                       const int* __restrict__ eids, const float* __restrict__ glw,
                       const float* __restrict__ glb, const float* __restrict__ gwt,
                       const float* __restrict__ gbias, float* __restrict__ gates) {
    int b = blockIdx.x, tid = threadIdx.x;
    __shared__ float sh[64];
    __shared__ float logits[EXP];
    int ti = tids[b], ei = eids[b];
    float s = 0.f, ss = 0.f;
    for (int i = tid; i < GN; i += 256) {
        float v = (i < HID) ? gi[b*HID + i]
                : (i < HID + TDIM) ? temb[ti*TDIM + i - HID]
                : eemb[ei*TDIM + i - HID - TDIM];
        s += v; ss += v*v;
    }
    blockReduce2(s, ss, sh);
    float m  = s * (1.f/GN);
    float rs = rsqrtf(ss * (1.f/GN) - m*m + 1e-5f);
    for (int e = 0; e < EXP; e++) {
        float d = 0.f;
        for (int i = tid; i < GN; i += 256) {
            float v = (i < HID) ? gi[b*HID + i]
                    : (i < HID + TDIM) ? temb[ti*TDIM + i - HID]
                    : eemb[ei*TDIM + i - HID - TDIM];
            d += ((v - m)*rs*glw[i] + glb[i]) * gwt[(long)e*GN + i];
        }
        d = blockReduce1(d, sh);
        if (tid == 0) logits[e] = d + gbias[e];
    }
    __syncthreads();
    if (tid == 0) {
        float w[EXP]; float mx = -1e30f;
        for (int e = 0; e < EXP; e++) { float l = fminf(fmaxf(logits[e], -15.f), 15.f); w[e] = l; mx = fmaxf(mx, l); }
        float sum = 0.f;
        for (int e = 0; e < EXP; e++) { w[e] = expf(w[e] - mx); sum += w[e]; }
        for (int e = 0; e < EXP; e++) w[e] /= sum;
        int i0 = 0;
        for (int e = 1; e < EXP; e++) if (w[e] > w[i0]) i0 = e;
        int i1 = -1;
        for (int e = 0; e < EXP; e++) { if (e == i0) continue; if (i1 < 0 || w[e] > w[i1]) i1 = e; }
        float t = w[i0] + w[i1] + 1e-9f;
        for (int e = 0; e < EXP; e++) gates[b*EXP + e] = 0.f;
        gates[b*EXP + i0] = w[i0] / t;
        gates[b*EXP + i1] = w[i1] / t;
    }
}

// ---------------- init x = query tile ----------------
__global__ void k_initx(const float* __restrict__ query, int qo, float* __restrict__ gx,
                        const float* __restrict__ gates) {
    int r = blockIdx.x, b = blockIdx.y, e = blockIdx.z;
    if (gates[b*EXP + e] == 0.f) return;
    const float* srow = query + ((long)e*NQ_ + qo + r)*HID;
    float* d = gx + ((long)(e*BATCH + b)*MAXSQ + r)*HID;
    for (int i = threadIdx.x; i < HID; i += blockDim.x) d[i] = srow[i];
}

// ---------------- LayerNorm ----------------
__global__ void k_ln(const float* __restrict__ src, long srcBS,
                     const float* __restrict__ w, const float* __restrict__ bvec, long pES,
                     float* __restrict__ dst, long dstBS, const float* __restrict__ gates) {
    int r = blockIdx.x, b = blockIdx.y, e = blockIdx.z;
    if (gates[b*EXP + e] == 0.f) return;
    const float* row = src + (long)(e*BATCH + b)*srcBS + (long)r*HID;
    float* drow = dst + (long)(e*BATCH + b)*dstBS + (long)r*HID;
    __shared__ float sh[64];
    float v[4]; float s = 0.f, ss = 0.f;
    #pragma unroll
    for (int t = 0; t < 4; t++) { v[t] = row[threadIdx.x + t*256]; s += v[t]; ss += v[t]*v[t]; }
    blockReduce2(s, ss, sh);
    float m  = s * (1.f/HID);
    float rs = rsqrtf(ss * (1.f/HID) - m*m + 1e-5f);
    const float* we = w + (long)e*pES;
    const float* be = bvec + (long)e*pES;
    #pragma unroll
    for (int t = 0; t < 4; t++) {
        int i = threadIdx.x + t*256;
        drow[i] = (v[t] - m)*rs*we[i] + be[i];
    }
}

// ---------------- LayerNorm with kv0 gather ----------------
__global__ void k_ln_kv(int sq, int qo, int io, const float* __restrict__ query,
                        const float* __restrict__ img, const float* __restrict__ pp,
                        const float* __restrict__ w, const float* __restrict__ bvec, long pES,
                        float* __restrict__ dst, const float* __restrict__ gates) {
    int r = blockIdx.x, b = blockIdx.y, e = blockIdx.z;
    if (gates[b*EXP + e] == 0.f) return;
    const float* row;
    if (r < sq) row = query + ((long)e*NQ_ + qo + r)*HID;
    else {
        int zi = io + r - sq;
        if (zi < LV_) row = img + ((long)b*LV_ + zi)*HID;
        else          row = pp  + ((long)b*LP_ + zi - LV_)*HID;
    }
    float* drow = dst + ((long)(e*BATCH + b)*MAXKV + r)*HID;
    __shared__ float sh[64];
    float v[4]; float s = 0.f, ss = 0.f;
    #pragma unroll
    for (int t = 0; t < 4; t++) { v[t] = row[threadIdx.x + t*256]; s += v[t]; ss += v[t]*v[t]; }
    blockReduce2(s, ss, sh);
    float m  = s * (1.f/HID);
    float rs = rsqrtf(ss * (1.f/HID) - m*m + 1e-5f);
    const float* we = w + (long)e*pES;
    const float* be = bvec + (long)e*pES;
    #pragma unroll
    for (int t = 0; t < 4; t++) {
        int i = threadIdx.x + t*256;
        drow[i] = (v[t] - m)*rs*we[i] + be[i];
    }
}

// ---------------- attention: one warp per (head, query row) ----------------
__global__ void k_attn(int sq, int kvlen,
                       const float* __restrict__ q, const float* __restrict__ kv,
                       float* __restrict__ att, const float* __restrict__ gates) {
    int e = blockIdx.z, b = blockIdx.y;
    if (gates[b*EXP + e] == 0.f) return;
    int warp = threadIdx.x >> 5, lane = threadIdx.x & 31;
    int w = blockIdx.x * 4 + warp;
    if (w >= NHEADS * sq) return;
    int h = w / sq, qi = w % sq;
    __shared__ float sc[4][MAXKV];

    long xoff  = (long)(e*BATCH + b) * MAXSQ * HID;
    long kvoff = (long)(e*BATCH + b) * MAXKV * 2048;
    const float* qr = q + xoff + (long)qi*HID + h*HDIM;
    float q0 = qr[lane], q1 = qr[lane + 32];
    const float* kbase = kv + kvoff + h*HDIM;
    float mx = -1e30f;
    for (int j = 0; j < kvlen; j++) {
        const float* kr = kbase + (long)j*2048;
        float p = q0*kr[lane] + q1*kr[lane + 32];
        #pragma unroll
        for (int o = 16; o; o >>= 1) p += __shfl_xor_sync(~0u, p, o);
        p *= 0.125f;
        if (lane == 0) sc[warp][j] = p;
        mx = fmaxf(mx, p);
    }
    __syncwarp();
    float se = 0.f;
    for (int j = lane; j < kvlen; j += 32) {
        float ex = __expf(sc[warp][j] - mx);
        sc[warp][j] = ex;
        se += ex;
    }
    #pragma unroll
    for (int o = 16; o; o >>= 1) se += __shfl_xor_sync(~0u, se, o);
    __syncwarp();
    float inv = 1.f / se;
    const float* vbase = kv + kvoff + 1024 + h*HDIM;
    float a0 = 0.f, a1 = 0.f;
    for (int j = 0; j < kvlen; j++) {
        float p = sc[warp][j];
        const float* vr = vbase + (long)j*2048;
        a0 += p*vr[lane]; a1 += p*vr[lane + 32];
    }
    float* orow = att + xoff + (long)qi*HID + h*HDIM;
    orow[lane]      = a0 * inv;
    orow[lane + 32] = a1 * inv;
}

// ---------------- copy stage result into y ----------------
__global__ void k_copy_y(const float* __restrict__ gx, int qo, float* __restrict__ y,
                         const float* __restrict__ gates) {
    int r = blockIdx.x, b = blockIdx.y, e = blockIdx.z;
    if (gates[b*EXP + e] == 0.f) return;
    const float* srow = gx + ((long)(e*BATCH + b)*MAXSQ + r)*HID;
    float* d = y + ((long)(e*BATCH + b)*NQ_ + qo + r)*HID;
    for (int i = threadIdx.x; i < HID; i += blockDim.x) d[i] = srow[i];
}

// ---------------- RMS norm + final scaling (in place on d_out) ----------------
__global__ void k_rms(float* __restrict__ out, const float* __restrict__ fw,
                      const float* __restrict__ gain) {
    int q = blockIdx.x, b = blockIdx.y;
    float* row = out + ((long)b*NQ_ + q)*OUTD;
    __shared__ float sh[64];
    float v[16]; float ss = 0.f;
    #pragma unroll
    for (int t = 0; t < 16; t++) { v[t] = row[threadIdx.x + t*256]; ss += v[t]*v[t]; }
    ss = blockReduce1(ss, sh);
    float sc = rsqrtf(ss * (1.f/OUTD) + 1e-6f);
    #pragma unroll
    for (int t = 0; t < 16; t++) {
        int o = threadIdx.x + t*256;
        row[o] = v[t]*sc*fw[o]*gain[o];
    }
}

// ---------------- host orchestration ----------------
extern "C" void kernel_launch(void* const* d_in, const int* in_sizes, int n_in,
                              void* d_out, int out_size) {
    const float* image     = (const float*)d_in[0];
    const float* pp        = (const float*)d_in[1];
    const int*   tids      = (const int*)  d_in[2];
    const int*   eids      = (const int*)  d_in[3];
    const float* query     = (const float*)d_in[4];
    const float* ln1_w     = (const float*)d_in[5];
    const float* ln1_b     = (const float*)d_in[6];
    const float* ln1kv_w   = (const float*)d_in[7];
    const float* ln1kv_b   = (const float*)d_in[8];
    const float* attn_in_w = (const float*)d_in[9];
    const float* attn_in_b = (const float*)d_in[10];
    const float* attn_out_w= (const float*)d_in[11];
    const float* attn_out_b= (const float*)d_in[12];
    const float* ls1       = (const float*)d_in[13];
    const float* ls2       = (const float*)d_in[14];
    const float* ln2_w     = (const float*)d_in[15];
    const float* ln2_b     = (const float*)d_in[16];
    const float* fc_w      = (const float*)d_in[17];
    const float* fc_b      = (const float*)d_in[18];
    const float* proj_w    = (const float*)d_in[19];
    const float* proj_b    = (const float*)d_in[20];
    const float* outp_w    = (const float*)d_in[21];
    const float* outp_b    = (const float*)d_in[22];
    const float* temb      = (const float*)d_in[23];
    const float* eemb      = (const float*)d_in[24];
    const float* glw       = (const float*)d_in[25];
    const float* glb       = (const float*)d_in[26];
    const float* gwt       = (const float*)d_in[27];
    const float* gbias     = (const float*)d_in[28];
    const float* gain      = (const float*)d_in[29];
    const float* fw        = (const float*)d_in[30];
    float* out = (float*)d_out;

    float *px, *pxln, *patt, *pq, *pkvn, *pkv, *pffn, *py, *pg, *pgi;
    cudaGetSymbolAddress((void**)&px,   g_x);
    cudaGetSymbolAddress((void**)&pxln, g_xln);
    cudaGetSymbolAddress((void**)&patt, g_att);
    cudaGetSymbolAddress((void**)&pq,   g_q);
    cudaGetSymbolAddress((void**)&pkvn, g_kvn);
    cudaGetSymbolAddress((void**)&pkv,  g_kv);
    cudaGetSymbolAddress((void**)&pffn, g_ffn);
    cudaGetSymbolAddress((void**)&py,   g_y);
    cudaGetSymbolAddress((void**)&pg,   g_gates);
    cudaGetSymbolAddress((void**)&pgi,  g_gi);

    k_gate_mean<<<BATCH, 256>>>(image, pgi);
    k_gate<<<BATCH, 256>>>(pgi, temb, eemb, tids, eids, glw, glb, gwt, gbias, pg);

    const int sqs[3] = {64, 48, 32};
    const int qos[3] = {0, 64, 112};
    const int ios[3] = {0, 256, 512};
    const long HH = (long)HID*HID;

    for (int s = 0; s < 3; s++) {
        int sq = sqs[s], qo = qos[s], io = ios[s];
        int kvlen = sq + 256;
        k_initx<<<dim3(sq, BATCH, EXP), 256>>>(query, qo, px, pg);
        for (int l = 0; l < NLAYERS; l++) {
            k_ln_kv<<<dim3(kvlen, BATCH, EXP), 256>>>(sq, qo, io, query, image, pp,
                ln1kv_w + (long)l*HID, ln1kv_b + (long)l*HID, (long)NLAYERS*HID, pkvn, pg);
            k_ln<<<dim3(sq, BATCH, EXP), 256>>>(px, (long)MAXSQ*HID,
                ln1_w + (long)l*HID, ln1_b + (long)l*HID, (long)NLAYERS*HID,
                pxln, (long)MAXSQ*HID, pg);
            // Q projection (tensor)
            k_tgemm<<<dim3(8, 16), 256>>>(HID, HID, MAXSQ, sq,
                pxln, attn_in_w + (long)l*3*HH, (long)NLAYERS*3*HH,
                attn_in_b + (long)l*3*HID, (long)NLAYERS*3*HID,
                pq, (const float*)0, 0, 0, pg);
            // fused K,V projection (tensor, N=2048)
            k_tgemm<<<dim3(16, 80), 256>>>(2048, HID, MAXKV, kvlen,
                pkvn, attn_in_w + (long)l*3*HH + HH, (long)NLAYERS*3*HH,
                attn_in_b + (long)l*3*HID + HID, (long)NLAYERS*3*HID,
                pkv, (const float*)0, 0, 0, pg);
            // attention
            k_attn<<<dim3((NHEADS*sq + 3)/4, BATCH, EXP), 128>>>(sq, kvlen, pq, pkv, patt, pg);
            // attention out projection + residual
            k_tgemm<<<dim3(8, 16), 256>>>(HID, HID, MAXSQ, sq,
                patt, attn_out_w + (long)l*HH, (long)NLAYERS*HH,
                attn_out_b + (long)l*HID, (long)NLAYERS*HID,
                px, ls1 + (long)l*HID, (long)NLAYERS*HID, 2, pg);
            // MLP
            k_ln<<<dim3(sq, BATCH, EXP), 256>>>(px, (long)MAXSQ*HID,
                ln2_w + (long)l*HID, ln2_b + (long)l*HID, (long)NLAYERS*HID,
                pxln, (long)MAXSQ*HID, pg);
            k_tgemm<<<dim3(32, 16), 256>>>(4*HID, HID, MAXSQ, sq,
                pxln, fc_w + (long)l*4*HH, (long)NLAYERS*4*HH,
                fc_b + (long)l*4*HID, (long)NLAYERS*4*HID,
                pffn, (const float*)0, 0, 1, pg);
            k_tgemm<<<dim3(8, 16), 256>>>(HID, 4*HID, MAXSQ, sq,
                pffn, proj_w + (long)l*4*HH, (long)NLAYERS*4*HH,
                proj_b + (long)l*HID, (long)NLAYERS*HID,
                px, ls2 + (long)l*HID, (long)NLAYERS*HID, 2, pg);
        }
        k_copy_y<<<dim3(sq, BATCH, EXP), 256>>>(px, qo, py, pg);
    }

    k_tgemm_out<<<dim3(OUTD/128, 2, BATCH), 256>>>(py, outp_w, outp_b, out, pg);
    k_rms<<<dim3(NQ_, BATCH), 256>>>(out, fw, gain);
}

// round 4
// speedup vs baseline: 1.8741x; 1.2310x over previous
#include <cuda_runtime.h>
#include <cuda_bf16.h>
#include <math.h>
#include <stdint.h>

typedef unsigned short u16;

// ---------------- problem constants ----------------
#define EXP    4
#define BATCH  8
#define NQ_    144
#define NLAYERS 2
#define NHEADS 16
#define HDIM   64
#define HID    1024
#define OUTD   4096
#define TDIM   256
#define LV_    576
#define LP_    192
#define MAXSQ  64
#define MAXKV  320
#define GN     (HID + 2*TDIM)   // 1536

// ---------------- fp32 scratch ----------------
__device__ float g_x   [EXP*BATCH*MAXSQ*HID];
__device__ float g_q   [EXP*BATCH*MAXSQ*HID];
__device__ float g_kv  [EXP*BATCH*MAXKV*2048];   // K in [0,1024), V in [1024,2048)
__device__ float g_gates[BATCH*EXP];
__device__ float g_gi  [BATCH*HID];

// ---------------- bf16 hi/lo activation scratch ----------------
__device__ u16 g_xln_h[EXP*BATCH*MAXSQ*HID],  g_xln_l[EXP*BATCH*MAXSQ*HID];
__device__ u16 g_kvn_h[EXP*BATCH*MAXKV*HID],  g_kvn_l[EXP*BATCH*MAXKV*HID];
__device__ u16 g_att_h[EXP*BATCH*MAXSQ*HID],  g_att_l[EXP*BATCH*MAXSQ*HID];
__device__ u16 g_ffn_h[EXP*BATCH*MAXSQ*4096], g_ffn_l[EXP*BATCH*MAXSQ*4096];
__device__ u16 g_y_h  [EXP*BATCH*NQ_*HID],    g_y_l  [EXP*BATCH*NQ_*HID];

// ---------------- bf16 hi/lo weight scratch ----------------
#define AIW_N (EXP*NLAYERS*3*HID*HID)   // 25165824
#define AOW_N (EXP*NLAYERS*HID*HID)     // 8388608
#define FCW_N (EXP*NLAYERS*4*HID*HID)   // 33554432
#define PJW_N (EXP*NLAYERS*HID*4*HID)   // 33554432
#define OPW_N (EXP*OUTD*HID)            // 16777216
__device__ u16 g_aiw_h[AIW_N], g_aiw_l[AIW_N];
__device__ u16 g_aow_h[AOW_N], g_aow_l[AOW_N];
__device__ u16 g_fcw_h[FCW_N], g_fcw_l[FCW_N];
__device__ u16 g_pjw_h[PJW_N], g_pjw_l[PJW_N];
__device__ u16 g_opw_h[OPW_N], g_opw_l[OPW_N];

// ================= helpers =================
__device__ __forceinline__ void mma16816(float* c, const uint32_t* a, const uint32_t* b) {
    asm volatile("mma.sync.aligned.m16n8k16.row.col.f32.bf16.bf16.f32 "
        "{%0,%1,%2,%3}, {%4,%5,%6,%7}, {%8,%9}, {%0,%1,%2,%3};"
        : "+f"(c[0]), "+f"(c[1]), "+f"(c[2]), "+f"(c[3])
        : "r"(a[0]), "r"(a[1]), "r"(a[2]), "r"(a[3]), "r"(b[0]), "r"(b[1]));
}
__device__ __forceinline__ uint32_t pack2(__nv_bfloat16 a, __nv_bfloat16 b) {
    return (uint32_t)__bfloat16_as_ushort(a) | ((uint32_t)__bfloat16_as_ushort(b) << 16);
}
__device__ __forceinline__ void split4(float4 v, uint2& h, uint2& l) {
    __nv_bfloat16 h0 = __float2bfloat16(v.x), h1 = __float2bfloat16(v.y);
    __nv_bfloat16 h2 = __float2bfloat16(v.z), h3 = __float2bfloat16(v.w);
    __nv_bfloat16 l0 = __float2bfloat16(v.x - __bfloat162float(h0));
    __nv_bfloat16 l1 = __float2bfloat16(v.y - __bfloat162float(h1));
    __nv_bfloat16 l2 = __float2bfloat16(v.z - __bfloat162float(h2));
    __nv_bfloat16 l3 = __float2bfloat16(v.w - __bfloat162float(h3));
    h = make_uint2(pack2(h0, h1), pack2(h2, h3));
    l = make_uint2(pack2(l0, l1), pack2(l2, l3));
}
__device__ __forceinline__ void split1(float v, u16& h, u16& l) {
    __nv_bfloat16 hh = __float2bfloat16(v);
    h = __bfloat16_as_ushort(hh);
    l = __bfloat16_as_ushort(__float2bfloat16(v - __bfloat162float(hh)));
}

// ---------------- weight pre-split ----------------
__global__ void k_split4(const float4* __restrict__ src, uint2* __restrict__ h,
                         uint2* __restrict__ l, int n4) {
    int stride = gridDim.x * blockDim.x;
    for (int i = blockIdx.x * blockDim.x + threadIdx.x; i < n4; i += stride) {
        uint2 hh, ll;
        split4(src[i], hh, ll);
        h[i] = hh; l[i] = ll;
    }
}

#define PITCH 17   // u32 pitch per smem row (16 data + 1 pad)

// ================= tensor GEMM: C = A(rows,K) @ W(N,K)^T, bf16 hi/lo inputs =================
// epi 0: C=acc+bias (fp32). epi 1: split(gelu(acc+bias)) -> Chi/Clo. epi 2: C += ls*(acc+bias)
__global__ __launch_bounds__(256, 1) void k_tgemm(
    int N, int K, int RP, int validM,
    const u16* __restrict__ Ah, const u16* __restrict__ Al,
    const u16* __restrict__ Wh, const u16* __restrict__ Wl, long wES,
    const float* __restrict__ biasB, long bES,
    float* __restrict__ C, u16* __restrict__ Chi, u16* __restrict__ Clo,
    const float* __restrict__ lsB, long lsES,
    int epi, const float* __restrict__ gates)
{
    int m0 = blockIdx.y * 128;
    int n0 = blockIdx.x * 128;
    int p0 = m0 / RP, p1 = (m0 + 127) / RP;
    bool any = false;
    for (int p = p0; p <= p1; ++p)
        if (gates[(p & 7) * EXP + (p >> 3)] != 0.f) any = true;
    if (!any) return;
    int eBlk = p0 >> 3;

    __shared__ uint32_t AsH[128][PITCH], AsL[128][PITCH];
    __shared__ uint32_t BsH[128][PITCH], BsL[128][PITCH];

    int tid = threadIdx.x;
    int warp = tid >> 5, lane = tid & 31;
    int wm = warp & 3, wn = warp >> 2;
    int g8 = lane >> 2, tg = lane & 3;

    const u16* WhE = Wh + (long)eBlk * wES;
    const u16* WlE = Wl + (long)eBlk * wES;

    // prefetch pointers: 2 uint4 (16 ushort) per thread per array
    const u16 *pAh[2], *pAl[2], *pBh[2], *pBl[2];
    int rows_[2], q4_[2];
    #pragma unroll
    for (int j = 0; j < 2; ++j) {
        int lin = j * 256 + tid;
        int row = lin >> 2, q = lin & 3;
        rows_[j] = row; q4_[j] = q * 4;
        pAh[j] = Ah  + (long)(m0 + row) * K + q * 8;
        pAl[j] = Al  + (long)(m0 + row) * K + q * 8;
        pBh[j] = WhE + (long)(n0 + row) * K + q * 8;
        pBl[j] = WlE + (long)(n0 + row) * K + q * 8;
    }

    float acc[2][8][4] = {};
    uint4 rAh[2], rAl[2], rBh[2], rBl[2];
    int nch = K >> 5;

    #pragma unroll
    for (int j = 0; j < 2; ++j) {
        rAh[j] = *(const uint4*)(pAh[j]); rAl[j] = *(const uint4*)(pAl[j]);
        rBh[j] = *(const uint4*)(pBh[j]); rBl[j] = *(const uint4*)(pBl[j]);
    }

    for (int c = 0; c < nch; ++c) {
        #pragma unroll
        for (int j = 0; j < 2; ++j) {
            int r = rows_[j], o = q4_[j];
            AsH[r][o] = rAh[j].x; AsH[r][o+1] = rAh[j].y; AsH[r][o+2] = rAh[j].z; AsH[r][o+3] = rAh[j].w;
            AsL[r][o] = rAl[j].x; AsL[r][o+1] = rAl[j].y; AsL[r][o+2] = rAl[j].z; AsL[r][o+3] = rAl[j].w;
            BsH[r][o] = rBh[j].x; BsH[r][o+1] = rBh[j].y; BsH[r][o+2] = rBh[j].z; BsH[r][o+3] = rBh[j].w;
            BsL[r][o] = rBl[j].x; BsL[r][o+1] = rBl[j].y; BsL[r][o+2] = rBl[j].z; BsL[r][o+3] = rBl[j].w;
        }
        __syncthreads();
        if (c + 1 < nch) {
            long off = (long)(c + 1) * 32;
            #pragma unroll
            for (int j = 0; j < 2; ++j) {
                rAh[j] = *(const uint4*)(pAh[j] + off); rAl[j] = *(const uint4*)(pAl[j] + off);
                rBh[j] = *(const uint4*)(pBh[j] + off); rBl[j] = *(const uint4*)(pBl[j] + off);
            }
        }
        #pragma unroll
        for (int kh = 0; kh < 2; ++kh) {
            int kb = kh * 8;
            uint32_t ah[2][4], al[2][4];
            #pragma unroll
            for (int mt = 0; mt < 2; ++mt) {
                int r = wm * 32 + mt * 16 + g8;
                ah[mt][0] = AsH[r][kb+tg];     ah[mt][1] = AsH[r+8][kb+tg];
                ah[mt][2] = AsH[r][kb+tg+4];   ah[mt][3] = AsH[r+8][kb+tg+4];
                al[mt][0] = AsL[r][kb+tg];     al[mt][1] = AsL[r+8][kb+tg];
                al[mt][2] = AsL[r][kb+tg+4];   al[mt][3] = AsL[r+8][kb+tg+4];
            }
            #pragma unroll
            for (int nt = 0; nt < 8; ++nt) {
                int n = wn * 64 + nt * 8 + g8;
                uint32_t bh[2] = { BsH[n][kb+tg], BsH[n][kb+tg+4] };
                uint32_t bl[2] = { BsL[n][kb+tg], BsL[n][kb+tg+4] };
                #pragma unroll
                for (int mt = 0; mt < 2; ++mt) {
                    mma16816(acc[mt][nt], ah[mt], bh);
                    mma16816(acc[mt][nt], ah[mt], bl);
                    mma16816(acc[mt][nt], al[mt], bh);
                }
            }
        }
        __syncthreads();
    }

    const float* bias = biasB + (long)eBlk * bES;
    const float* ls = lsB ? (lsB + (long)eBlk * lsES) : (const float*)0;
    #pragma unroll
    for (int mt = 0; mt < 2; ++mt) {
        int r0 = m0 + wm * 32 + mt * 16 + g8;
        int r1 = r0 + 8;
        int p0r = r0 / RP, q0r = r0 % RP;
        int p1r = r1 / RP, q1r = r1 % RP;
        bool ok0 = (q0r < validM) && (gates[(p0r & 7) * EXP + (p0r >> 3)] != 0.f);
        bool ok1 = (q1r < validM) && (gates[(p1r & 7) * EXP + (p1r >> 3)] != 0.f);
        #pragma unroll
        for (int nt = 0; nt < 8; ++nt) {
            int col = n0 + wn * 64 + nt * 8 + tg * 2;
            float* cc = acc[mt][nt];
            #pragma unroll
            for (int q = 0; q < 4; ++q) {
                int row = (q < 2) ? r0 : r1;
                bool ok = (q < 2) ? ok0 : ok1;
                if (!ok) continue;
                int cl = col + (q & 1);
                float v = cc[q] + bias[cl];
                long idx = (long)row * N + cl;
                if (epi == 1) {
                    float gv = 0.5f * v * (1.f + erff(v * 0.70710678118654752f));
                    split1(gv, Chi[idx], Clo[idx]);
                } else if (epi == 2) {
                    C[idx] = C[idx] + ls[cl] * v;
                } else {
                    C[idx] = v;
                }
            }
        }
    }
}

// ================= out projection: out[b] = sum_e (g y_e) @ Wo_e^T + sum_e g bo_e =================
// y hi/lo are pre-scaled by gate, so the MMA accumulator sums experts directly.
__global__ __launch_bounds__(256, 1) void k_tgemm_out(
    const u16* __restrict__ Yh, const u16* __restrict__ Yl,
    const u16* __restrict__ Wh, const u16* __restrict__ Wl,
    const float* __restrict__ bo,
    float* __restrict__ outp, const float* __restrict__ gates)
{
    int m0 = blockIdx.y * 128, n0 = blockIdx.x * 128, b = blockIdx.z;

    __shared__ uint32_t AsH[128][PITCH], AsL[128][PITCH];
    __shared__ uint32_t BsH[128][PITCH], BsL[128][PITCH];

    int tid = threadIdx.x;
    int warp = tid >> 5, lane = tid & 31;
    int wm = warp & 3, wn = warp >> 2;
    int g8 = lane >> 2, tg = lane & 3;

    float acc[2][8][4] = {};
    int rows_[2], q4_[2];
    #pragma unroll
    for (int j = 0; j < 2; ++j) {
        int lin = j * 256 + tid;
        rows_[j] = lin >> 2; q4_[j] = (lin & 3) * 4;
    }

    for (int e = 0; e < EXP; ++e) {
        float g = gates[b * EXP + e];
        if (g == 0.f) continue;
        const u16* AhE = Yh + (long)(e * BATCH + b) * NQ_ * HID;
        const u16* AlE = Yl + (long)(e * BATCH + b) * NQ_ * HID;
        const u16* WhE = Wh + (long)e * OUTD * HID;
        const u16* WlE = Wl + (long)e * OUTD * HID;

        uint4 rAh[2], rAl[2], rBh[2], rBl[2];
        const uint4 z4 = make_uint4(0u, 0u, 0u, 0u);
        #pragma unroll
        for (int j = 0; j < 2; ++j) {
            int row = rows_[j], q = q4_[j] >> 2;
            bool okr = (m0 + row) < NQ_;
            rAh[j] = okr ? *(const uint4*)(AhE + (long)(m0 + row) * HID + q * 8) : z4;
            rAl[j] = okr ? *(const uint4*)(AlE + (long)(m0 + row) * HID + q * 8) : z4;
            rBh[j] = *(const uint4*)(WhE + (long)(n0 + row) * HID + q * 8);
            rBl[j] = *(const uint4*)(WlE + (long)(n0 + row) * HID + q * 8);
        }

        for (int c = 0; c < 32; ++c) {
            #pragma unroll
            for (int j = 0; j < 2; ++j) {
                int r = rows_[j], o = q4_[j];
                AsH[r][o] = rAh[j].x; AsH[r][o+1] = rAh[j].y; AsH[r][o+2] = rAh[j].z; AsH[r][o+3] = rAh[j].w;
                AsL[r][o] = rAl[j].x; AsL[r][o+1] = rAl[j].y; AsL[r][o+2] = rAl[j].z; AsL[r][o+3] = rAl[j].w;
                BsH[r][o] = rBh[j].x; BsH[r][o+1] = rBh[j].y; BsH[r][o+2] = rBh[j].z; BsH[r][o+3] = rBh[j].w;
                BsL[r][o] = rBl[j].x; BsL[r][o+1] = rBl[j].y; BsL[r][o+2] = rBl[j].z; BsL[r][o+3] = rBl[j].w;
            }
            __syncthreads();
            if (c + 1 < 32) {
                long off = (long)(c + 1) * 32;
                #pragma unroll
                for (int j = 0; j < 2; ++j) {
                    int row = rows_[j], q = q4_[j] >> 2;
                    bool okr = (m0 + row) < NQ_;
                    rAh[j] = okr ? *(const uint4*)(AhE + (long)(m0 + row) * HID + q * 8 + off) : z4;
                    rAl[j] = okr ? *(const uint4*)(AlE + (long)(m0 + row) * HID + q * 8 + off) : z4;
                    rBh[j] = *(const uint4*)(WhE + (long)(n0 + row) * HID + q * 8 + off);
                    rBl[j] = *(const uint4*)(WlE + (long)(n0 + row) * HID + q * 8 + off);
                }
            }
            #pragma unroll
            for (int kh = 0; kh < 2; ++kh) {
                int kb = kh * 8;
                uint32_t ah[2][4], al[2][4];
                #pragma unroll
                for (int mt = 0; mt < 2; ++mt) {
                    int r = wm * 32 + mt * 16 + g8;
                    ah[mt][0] = AsH[r][kb+tg];     ah[mt][1] = AsH[r+8][kb+tg];
                    ah[mt][2] = AsH[r][kb+tg+4];   ah[mt][3] = AsH[r+8][kb+tg+4];
                    al[mt][0] = AsL[r][kb+tg];     al[mt][1] = AsL[r+8][kb+tg];
                    al[mt][2] = AsL[r][kb+tg+4];   al[mt][3] = AsL[r+8][kb+tg+4];
                }
                #pragma unroll
                for (int nt = 0; nt < 8; ++nt) {
                    int n = wn * 64 + nt * 8 + g8;
                    uint32_t bh[2] = { BsH[n][kb+tg], BsH[n][kb+tg+4] };
                    uint32_t bl[2] = { BsL[n][kb+tg], BsL[n][kb+tg+4] };
                    #pragma unroll
                    for (int mt = 0; mt < 2; ++mt) {
                        mma16816(acc[mt][nt], ah[mt], bh);
                        mma16816(acc[mt][nt], ah[mt], bl);
                        mma16816(acc[mt][nt], al[mt], bh);
                    }
                }
            }
            __syncthreads();
        }
    }

    #pragma unroll
    for (int mt = 0; mt < 2; ++mt) {
        int r0 = m0 + wm * 32 + mt * 16 + g8;
        int r1 = r0 + 8;
        #pragma unroll
        for (int nt = 0; nt < 8; ++nt) {
            int col = n0 + wn * 64 + nt * 8 + tg * 2;
            float* cc = acc[mt][nt];
            #pragma unroll
            for (int q = 0; q < 4; ++q) {
                int row = (q < 2) ? r0 : r1;
                if (row >= NQ_) continue;
                int cl = col + (q & 1);
                float bs = 0.f;
                #pragma unroll
                for (int e = 0; e < EXP; ++e)
                    bs += gates[b * EXP + e] * bo[(long)e * OUTD + cl];
                outp[((long)b * NQ_ + row) * OUTD + cl] = cc[q] + bs;
            }
        }
    }
}

// ---------------- reductions ----------------
__device__ __forceinline__ void blockReduce2(float& a, float& b, float* sh) {
    __syncthreads();
    int lane = threadIdx.x & 31, wid = threadIdx.x >> 5;
    #pragma unroll
    for (int o = 16; o; o >>= 1) { a += __shfl_xor_sync(~0u, a, o); b += __shfl_xor_sync(~0u, b, o); }
    if (lane == 0) { sh[wid] = a; sh[wid + 32] = b; }
    __syncthreads();
    int nw = blockDim.x >> 5;
    if (wid == 0) {
        a = (lane < nw) ? sh[lane] : 0.f;
        b = (lane < nw) ? sh[lane + 32] : 0.f;
        #pragma unroll
        for (int o = 16; o; o >>= 1) { a += __shfl_xor_sync(~0u, a, o); b += __shfl_xor_sync(~0u, b, o); }
        if (lane == 0) { sh[0] = a; sh[32] = b; }
    }
    __syncthreads();
    a = sh[0]; b = sh[32];
}
__device__ __forceinline__ float blockReduce1(float a, float* sh) {
    __syncthreads();
    int lane = threadIdx.x & 31, wid = threadIdx.x >> 5;
    #pragma unroll
    for (int o = 16; o; o >>= 1) a += __shfl_xor_sync(~0u, a, o);
    if (lane == 0) sh[wid] = a;
    __syncthreads();
    int nw = blockDim.x >> 5;
    if (wid == 0) {
        a = (lane < nw) ? sh[lane] : 0.f;
        #pragma unroll
        for (int o = 16; o; o >>= 1) a += __shfl_xor_sync(~0u, a, o);
        if (lane == 0) sh[0] = a;
    }
    __syncthreads();
    return sh[0];
}

// ---------------- gate kernels ----------------
__global__ void k_gate_mean(const float* __restrict__ img, float* __restrict__ gi) {
    int b = blockIdx.x;
    for (int h = threadIdx.x; h < HID; h += blockDim.x) {
        float s = 0.f;
        for (int l = 0; l < LV_; l++) s += img[((long)b*LV_ + l)*HID + h];
        gi[b*HID + h] = s * (1.f/LV_);
    }
}
__global__ void k_gate(const float* __restrict__ gi, const float* __restrict__ temb,
                       const float* __restrict__ eemb, const int* __restrict__ tids,
                       const int* __restrict__ eids, const float* __restrict__ glw,
                       const float* __restrict__ glb, const float* __restrict__ gwt,
                       const float* __restrict__ gbias, float* __restrict__ gates) {
    int b = blockIdx.x, tid = threadIdx.x;
    __shared__ float sh[64];
    __shared__ float logits[EXP];
    int ti = tids[b], ei = eids[b];
    float s = 0.f, ss = 0.f;
    for (int i = tid; i < GN; i += 256) {
        float v = (i < HID) ? gi[b*HID + i]
                : (i < HID + TDIM) ? temb[ti*TDIM + i - HID]
                : eemb[ei*TDIM + i - HID - TDIM];
        s += v; ss += v*v;
    }
    blockReduce2(s, ss, sh);
    float m  = s * (1.f/GN);
    float rs = rsqrtf(ss * (1.f/GN) - m*m + 1e-5f);
    for (int e = 0; e < EXP; e++) {
        float d = 0.f;
        for (int i = tid; i < GN; i += 256) {
            float v = (i < HID) ? gi[b*HID + i]
                    : (i < HID + TDIM) ? temb[ti*TDIM + i - HID]
                    : eemb[ei*TDIM + i - HID - TDIM];
            d += ((v - m)*rs*glw[i] + glb[i]) * gwt[(long)e*GN + i];
        }
        d = blockReduce1(d, sh);
        if (tid == 0) logits[e] = d + gbias[e];
    }
    __syncthreads();
    if (tid == 0) {
        float w[EXP]; float mx = -1e30f;
        for (int e = 0; e < EXP; e++) { float l = fminf(fmaxf(logits[e], -15.f), 15.f); w[e] = l; mx = fmaxf(mx, l); }
        float sum = 0.f;
        for (int e = 0; e < EXP; e++) { w[e] = expf(w[e] - mx); sum += w[e]; }
        for (int e = 0; e < EXP; e++) w[e] /= sum;
        int i0 = 0;
        for (int e = 1; e < EXP; e++) if (w[e] > w[i0]) i0 = e;
        int i1 = -1;
        for (int e = 0; e < EXP; e++) { if (e == i0) continue; if (i1 < 0 || w[e] > w[i1]) i1 = e; }
        float t = w[i0] + w[i1] + 1e-9f;
        for (int e = 0; e < EXP; e++) gates[b*EXP + e] = 0.f;
        gates[b*EXP + i0] = w[i0] / t;
        gates[b*EXP + i1] = w[i1] / t;
    }
}

// ---------------- init x = query tile ----------------
__global__ void k_initx(const float* __restrict__ query, int qo, float* __restrict__ gx,
                        const float* __restrict__ gates) {
    int r = blockIdx.x, b = blockIdx.y, e = blockIdx.z;
    if (gates[b*EXP + e] == 0.f) return;
    const float* srow = query + ((long)e*NQ_ + qo + r)*HID;
    float* d = gx + ((long)(e*BATCH + b)*MAXSQ + r)*HID;
    for (int i = threadIdx.x; i < HID; i += blockDim.x) d[i] = srow[i];
}

// ---------------- LayerNorm -> bf16 hi/lo ----------------
__global__ void k_ln(const float* __restrict__ src, long srcBS,
                     const float* __restrict__ w, const float* __restrict__ bvec, long pES,
                     u16* __restrict__ dh, u16* __restrict__ dl, long dstBS,
                     const float* __restrict__ gates) {
    int r = blockIdx.x, b = blockIdx.y, e = blockIdx.z;
    if (gates[b*EXP + e] == 0.f) return;
    const float* row = src + (long)(e*BATCH + b)*srcBS + (long)r*HID;
    long doff = (long)(e*BATCH + b)*dstBS + (long)r*HID;
    __shared__ float sh[64];
    float v[4]; float s = 0.f, ss = 0.f;
    #pragma unroll
    for (int t = 0; t < 4; t++) { v[t] = row[threadIdx.x + t*256]; s += v[t]; ss += v[t]*v[t]; }
    blockReduce2(s, ss, sh);
    float m  = s * (1.f/HID);
    float rs = rsqrtf(ss * (1.f/HID) - m*m + 1e-5f);
    const float* we = w + (long)e*pES;
    const float* be = bvec + (long)e*pES;
    #pragma unroll
    for (int t = 0; t < 4; t++) {
        int i = threadIdx.x + t*256;
        float rv = (v[t] - m)*rs*we[i] + be[i];
        split1(rv, dh[doff + i], dl[doff + i]);
    }
}

// ---------------- LayerNorm with kv0 gather -> bf16 hi/lo ----------------
__global__ void k_ln_kv(int sq, int qo, int io, const float* __restrict__ query,
                        const float* __restrict__ img, const float* __restrict__ pp,
                        const float* __restrict__ w, const float* __restrict__ bvec, long pES,
                        u16* __restrict__ dh, u16* __restrict__ dl,
                        const float* __restrict__ gates) {
    int r = blockIdx.x, b = blockIdx.y, e = blockIdx.z;
    if (gates[b*EXP + e] == 0.f) return;
    const float* row;
    if (r < sq) row = query + ((long)e*NQ_ + qo + r)*HID;
    else {
        int zi = io + r - sq;
        if (zi < LV_) row = img + ((long)b*LV_ + zi)*HID;
        else          row = pp  + ((long)b*LP_ + zi - LV_)*HID;
    }
    long doff = ((long)(e*BATCH + b)*MAXKV + r)*HID;
    __shared__ float sh[64];
    float v[4]; float s = 0.f, ss = 0.f;
    #pragma unroll
    for (int t = 0; t < 4; t++) { v[t] = row[threadIdx.x + t*256]; s += v[t]; ss += v[t]*v[t]; }
    blockReduce2(s, ss, sh);
    float m  = s * (1.f/HID);
    float rs = rsqrtf(ss * (1.f/HID) - m*m + 1e-5f);
    const float* we = w + (long)e*pES;
    const float* be = bvec + (long)e*pES;
    #pragma unroll
    for (int t = 0; t < 4; t++) {
        int i = threadIdx.x + t*256;
        float rv = (v[t] - m)*rs*we[i] + be[i];
        split1(rv, dh[doff + i], dl[doff + i]);
    }
}

// ---------------- attention -> bf16 hi/lo output ----------------
__global__ void k_attn(int sq, int kvlen,
                       const float* __restrict__ q, const float* __restrict__ kv,
                       u16* __restrict__ ath, u16* __restrict__ atl,
                       const float* __restrict__ gates) {
    int e = blockIdx.z, b = blockIdx.y;
    if (gates[b*EXP + e] == 0.f) return;
    int warp = threadIdx.x >> 5, lane = threadIdx.x & 31;
    int w = blockIdx.x * 4 + warp;
    if (w >= NHEADS * sq) return;
    int h = w / sq, qi = w % sq;
    __shared__ float sc[4][MAXKV];

    long xoff  = (long)(e*BATCH + b) * MAXSQ * HID;
    long kvoff = (long)(e*BATCH + b) * MAXKV * 2048;
    const float* qr = q + xoff + (long)qi*HID + h*HDIM;
    float q0 = qr[lane], q1 = qr[lane + 32];
    const float* kbase = kv + kvoff + h*HDIM;
    float mx = -1e30f;
    for (int j = 0; j < kvlen; j++) {
        const float* kr = kbase + (long)j*2048;
        float p = q0*kr[lane] + q1*kr[lane + 32];
        #pragma unroll
        for (int o = 16; o; o >>= 1) p += __shfl_xor_sync(~0u, p, o);
        p *= 0.125f;
        if (lane == 0) sc[warp][j] = p;
        mx = fmaxf(mx, p);
    }
    __syncwarp();
    float se = 0.f;
    for (int j = lane; j < kvlen; j += 32) {
        float ex = __expf(sc[warp][j] - mx);
        sc[warp][j] = ex;
        se += ex;
    }
    #pragma unroll
    for (int o = 16; o; o >>= 1) se += __shfl_xor_sync(~0u, se, o);
    __syncwarp();
    float inv = 1.f / se;
    const float* vbase = kv + kvoff + 1024 + h*HDIM;
    float a0 = 0.f, a1 = 0.f;
    for (int j = 0; j < kvlen; j++) {
        float p = sc[warp][j];
        const float* vr = vbase + (long)j*2048;
        a0 += p*vr[lane]; a1 += p*vr[lane + 32];
    }
    long ooff = xoff + (long)qi*HID + h*HDIM;
    split1(a0 * inv, ath[ooff + lane],      atl[ooff + lane]);
    split1(a1 * inv, ath[ooff + lane + 32], atl[ooff + lane + 32]);
}

// ---------------- copy stage result into y (pre-scaled by gate) -> bf16 hi/lo ----------------
__global__ void k_copy_y(const float* __restrict__ gx, int qo,
                         u16* __restrict__ yh, u16* __restrict__ yl,
                         const float* __restrict__ gates) {
    int r = blockIdx.x, b = blockIdx.y, e = blockIdx.z;
    float g = gates[b*EXP + e];
    if (g == 0.f) return;
    const float* srow = gx + ((long)(e*BATCH + b)*MAXSQ + r)*HID;
    long doff = ((long)(e*BATCH + b)*NQ_ + qo + r)*HID;
    for (int i = threadIdx.x; i < HID; i += blockDim.x)
        split1(g * srow[i], yh[doff + i], yl[doff + i]);
}

// ---------------- RMS norm + final scaling ----------------
__global__ void k_rms(float* __restrict__ out, const float* __restrict__ fw,
                      const float* __restrict__ gain) {
    int q = blockIdx.x, b = blockIdx.y;
    float* row = out + ((long)b*NQ_ + q)*OUTD;
    __shared__ float sh[64];
    float v[16]; float ss = 0.f;
    #pragma unroll
    for (int t = 0; t < 16; t++) { v[t] = row[threadIdx.x + t*256]; ss += v[t]*v[t]; }
    ss = blockReduce1(ss, sh);
    float sc = rsqrtf(ss * (1.f/OUTD) + 1e-6f);
    #pragma unroll
    for (int t = 0; t < 16; t++) {
        int o = threadIdx.x + t*256;
        row[o] = v[t]*sc*fw[o]*gain[o];
    }
}

// ---------------- host orchestration ----------------
extern "C" void kernel_launch(void* const* d_in, const int* in_sizes, int n_in,
                              void* d_out, int out_size) {
    const float* image     = (const float*)d_in[0];
    const float* pp        = (const float*)d_in[1];
    const int*   tids      = (const int*)  d_in[2];
    const int*   eids      = (const int*)  d_in[3];
    const float* query     = (const float*)d_in[4];
    const float* ln1_w     = (const float*)d_in[5];
    const float* ln1_b     = (const float*)d_in[6];
    const float* ln1kv_w   = (const float*)d_in[7];
    const float* ln1kv_b   = (const float*)d_in[8];
    const float* attn_in_w = (const float*)d_in[9];
    const float* attn_in_b = (const float*)d_in[10];
    const float* attn_out_w= (const float*)d_in[11];
    const float* attn_out_b= (const float*)d_in[12];
    const float* ls1       = (const float*)d_in[13];
    const float* ls2       = (const float*)d_in[14];
    const float* ln2_w     = (const float*)d_in[15];
    const float* ln2_b     = (const float*)d_in[16];
    const float* fc_w      = (const float*)d_in[17];
    const float* fc_b      = (const float*)d_in[18];
    const float* proj_w    = (const float*)d_in[19];
    const float* proj_b    = (const float*)d_in[20];
    const float* outp_w    = (const float*)d_in[21];
    const float* outp_b    = (const float*)d_in[22];
    const float* temb      = (const float*)d_in[23];
    const float* eemb      = (const float*)d_in[24];
    const float* glw       = (const float*)d_in[25];
    const float* glb       = (const float*)d_in[26];
    const float* gwt       = (const float*)d_in[27];
    const float* gbias     = (const float*)d_in[28];
    const float* gain      = (const float*)d_in[29];
    const float* fw        = (const float*)d_in[30];
    float* out = (float*)d_out;

    float *px, *pq, *pkv, *pg, *pgi;
    cudaGetSymbolAddress((void**)&px,  g_x);
    cudaGetSymbolAddress((void**)&pq,  g_q);
    cudaGetSymbolAddress((void**)&pkv, g_kv);
    cudaGetSymbolAddress((void**)&pg,  g_gates);
    cudaGetSymbolAddress((void**)&pgi, g_gi);

    u16 *xh, *xl, *kh, *kl, *ah, *al, *fh, *fl, *yh, *yl;
    cudaGetSymbolAddress((void**)&xh, g_xln_h); cudaGetSymbolAddress((void**)&xl, g_xln_l);
    cudaGetSymbolAddress((void**)&kh, g_kvn_h); cudaGetSymbolAddress((void**)&kl, g_kvn_l);
    cudaGetSymbolAddress((void**)&ah, g_att_h); cudaGetSymbolAddress((void**)&al, g_att_l);
    cudaGetSymbolAddress((void**)&fh, g_ffn_h); cudaGetSymbolAddress((void**)&fl, g_ffn_l);
    cudaGetSymbolAddress((void**)&yh, g_y_h);   cudaGetSymbolAddress((void**)&yl, g_y_l);

    u16 *aiwh, *aiwl, *aowh, *aowl, *fcwh, *fcwl, *pjwh, *pjwl, *opwh, *opwl;
    cudaGetSymbolAddress((void**)&aiwh, g_aiw_h); cudaGetSymbolAddress((void**)&aiwl, g_aiw_l);
    cudaGetSymbolAddress((void**)&aowh, g_aow_h); cudaGetSymbolAddress((void**)&aowl, g_aow_l);
    cudaGetSymbolAddress((void**)&fcwh, g_fcw_h); cudaGetSymbolAddress((void**)&fcwl, g_fcw_l);
    cudaGetSymbolAddress((void**)&pjwh, g_pjw_h); cudaGetSymbolAddress((void**)&pjwl, g_pjw_l);
    cudaGetSymbolAddress((void**)&opwh, g_opw_h); cudaGetSymbolAddress((void**)&opwl, g_opw_l);

    // weight pre-split (once per launch)
    k_split4<<<4096, 256>>>((const float4*)attn_in_w,  (uint2*)aiwh, (uint2*)aiwl, AIW_N/4);
    k_split4<<<4096, 256>>>((const float4*)attn_out_w, (uint2*)aowh, (uint2*)aowl, AOW_N/4);
    k_split4<<<4096, 256>>>((const float4*)fc_w,       (uint2*)fcwh, (uint2*)fcwl, FCW_N/4);
    k_split4<<<4096, 256>>>((const float4*)proj_w,     (uint2*)pjwh, (uint2*)pjwl, PJW_N/4);
    k_split4<<<4096, 256>>>((const float4*)outp_w,     (uint2*)opwh, (uint2*)opwl, OPW_N/4);

    k_gate_mean<<<BATCH, 256>>>(image, pgi);
    k_gate<<<BATCH, 256>>>(pgi, temb, eemb, tids, eids, glw, glb, gwt, gbias, pg);

    const int sqs[3] = {64, 48, 32};
    const int qos[3] = {0, 64, 112};
    const int ios[3] = {0, 256, 512};
    const long HH = (long)HID*HID;

    for (int s = 0; s < 3; s++) {
        int sq = sqs[s], qo = qos[s], io = ios[s];
        int kvlen = sq + 256;
        k_initx<<<dim3(sq, BATCH, EXP), 256>>>(query, qo, px, pg);
        for (int l = 0; l < NLAYERS; l++) {
            k_ln_kv<<<dim3(kvlen, BATCH, EXP), 256>>>(sq, qo, io, query, image, pp,
                ln1kv_w + (long)l*HID, ln1kv_b + (long)l*HID, (long)NLAYERS*HID, kh, kl, pg);
            k_ln<<<dim3(sq, BATCH, EXP), 256>>>(px, (long)MAXSQ*HID,
                ln1_w + (long)l*HID, ln1_b + (long)l*HID, (long)NLAYERS*HID,
                xh, xl, (long)MAXSQ*HID, pg);
            // Q projection
            k_tgemm<<<dim3(8, 16), 256>>>(HID, HID, MAXSQ, sq,
                xh, xl, aiwh + (long)l*3*HH, aiwl + (long)l*3*HH, (long)NLAYERS*3*HH,
                attn_in_b + (long)l*3*HID, (long)NLAYERS*3*HID,
                pq, (u16*)0, (u16*)0, (const float*)0, 0, 0, pg);
            // fused K,V projection (N=2048)
            k_tgemm<<<dim3(16, 80), 256>>>(2048, HID, MAXKV, kvlen,
                kh, kl, aiwh + (long)l*3*HH + HH, aiwl + (long)l*3*HH + HH, (long)NLAYERS*3*HH,
                attn_in_b + (long)l*3*HID + HID, (long)NLAYERS*3*HID,
                pkv, (u16*)0, (u16*)0, (const float*)0, 0, 0, pg);
            // attention
            k_attn<<<dim3((NHEADS*sq + 3)/4, BATCH, EXP), 128>>>(sq, kvlen, pq, pkv, ah, al, pg);
            // attn-out projection + residual
            k_tgemm<<<dim3(8, 16), 256>>>(HID, HID, MAXSQ, sq,
                ah, al, aowh + (long)l*HH, aowl + (long)l*HH, (long)NLAYERS*HH,
                attn_out_b + (long)l*HID, (long)NLAYERS*HID,
                px, (u16*)0, (u16*)0, ls1 + (long)l*HID, (long)NLAYERS*HID, 2, pg);
            // MLP
            k_ln<<<dim3(sq, BATCH, EXP), 256>>>(px, (long)MAXSQ*HID,
                ln2_w + (long)l*HID, ln2_b + (long)l*HID, (long)NLAYERS*HID,
                xh, xl, (long)MAXSQ*HID, pg);
            k_tgemm<<<dim3(32, 16), 256>>>(4*HID, HID, MAXSQ, sq,
                xh, xl, fcwh + (long)l*4*HH, fcwl + (long)l*4*HH, (long)NLAYERS*4*HH,
                fc_b + (long)l*4*HID, (long)NLAYERS*4*HID,
                (float*)0, fh, fl, (const float*)0, 0, 1, pg);
            k_tgemm<<<dim3(8, 16), 256>>>(HID, 4*HID, MAXSQ, sq,
                fh, fl, pjwh + (long)l*4*HH, pjwl + (long)l*4*HH, (long)NLAYERS*4*HH,
                proj_b + (long)l*HID, (long)NLAYERS*HID,
                px, (u16*)0, (u16*)0, ls2 + (long)l*HID, (long)NLAYERS*HID, 2, pg);
        }
        k_copy_y<<<dim3(sq, BATCH, EXP), 256>>>(px, qo, yh, yl, pg);
    }

    k_tgemm_out<<<dim3(OUTD/128, 2, BATCH), 256>>>(yh, yl, opwh, opwl, outp_b, out, pg);
    k_rms<<<dim3(NQ_, BATCH), 256>>>(out, fw, gain);
}

// round 5
// speedup vs baseline: 2.0491x; 1.0934x over previous
#include <cuda_runtime.h>
#include <cuda_bf16.h>
#include <math.h>
#include <stdint.h>

typedef unsigned short u16;

// ---------------- problem constants ----------------
#define EXP    4
#define BATCH  8
#define NQ_    144
#define NLAYERS 2
#define NHEADS 16
#define HDIM   64
#define HID    1024
#define OUTD   4096
#define TDIM   256
#define LV_    576
#define LP_    192
#define MAXSQ  64
#define MAXKV  320
#define NSLOT  16
#define GN     (HID + 2*TDIM)   // 1536

// ---------------- fp32 scratch ----------------
__device__ float g_x   [2048*HID];          // compact rows (<=1536 used)
__device__ float g_q   [2048*HID];
__device__ float g_kv  [8192*2048];         // compact kv rows (<=5632), K|V
__device__ float g_gates[BATCH*EXP];
__device__ float g_gi  [BATCH*HID];

// slot metadata
__device__ int   g_cnt[EXP], g_soff[EXP];
__device__ int   g_se[NSLOT], g_sb[NSLOT];
__device__ float g_sg[NSLOT];

// ---------------- bf16 hi/lo activation scratch ----------------
__device__ u16 g_xln_h[2048*HID],  g_xln_l[2048*HID];
__device__ u16 g_kvn_h[8192*HID],  g_kvn_l[8192*HID];
__device__ u16 g_att_h[2048*HID],  g_att_l[2048*HID];
__device__ u16 g_ffn_h[2048*4096], g_ffn_l[2048*4096];
__device__ u16 g_y_h  [EXP*BATCH*NQ_*HID], g_y_l[EXP*BATCH*NQ_*HID];

// ---------------- bf16 hi/lo weight scratch ----------------
#define AIW_N (EXP*NLAYERS*3*HID*HID)
#define AOW_N (EXP*NLAYERS*HID*HID)
#define FCW_N (EXP*NLAYERS*4*HID*HID)
#define PJW_N (EXP*NLAYERS*HID*4*HID)
#define OPW_N (EXP*OUTD*HID)
__device__ u16 g_aiw_h[AIW_N], g_aiw_l[AIW_N];
__device__ u16 g_aow_h[AOW_N], g_aow_l[AOW_N];
__device__ u16 g_fcw_h[FCW_N], g_fcw_l[FCW_N];
__device__ u16 g_pjw_h[PJW_N], g_pjw_l[PJW_N];
__device__ u16 g_opw_h[OPW_N], g_opw_l[OPW_N];

// ================= helpers =================
__device__ __forceinline__ void mma16816(float* c, const uint32_t* a, const uint32_t* b) {
    asm volatile("mma.sync.aligned.m16n8k16.row.col.f32.bf16.bf16.f32 "
        "{%0,%1,%2,%3}, {%4,%5,%6,%7}, {%8,%9}, {%0,%1,%2,%3};"
        : "+f"(c[0]), "+f"(c[1]), "+f"(c[2]), "+f"(c[3])
        : "r"(a[0]), "r"(a[1]), "r"(a[2]), "r"(a[3]), "r"(b[0]), "r"(b[1]));
}
__device__ __forceinline__ uint32_t pack2(__nv_bfloat16 a, __nv_bfloat16 b) {
    return (uint32_t)__bfloat16_as_ushort(a) | ((uint32_t)__bfloat16_as_ushort(b) << 16);
}
__device__ __forceinline__ void split4(float4 v, uint2& h, uint2& l) {
    __nv_bfloat16 h0 = __float2bfloat16(v.x), h1 = __float2bfloat16(v.y);
    __nv_bfloat16 h2 = __float2bfloat16(v.z), h3 = __float2bfloat16(v.w);
    __nv_bfloat16 l0 = __float2bfloat16(v.x - __bfloat162float(h0));
    __nv_bfloat16 l1 = __float2bfloat16(v.y - __bfloat162float(h1));
    __nv_bfloat16 l2 = __float2bfloat16(v.z - __bfloat162float(h2));
    __nv_bfloat16 l3 = __float2bfloat16(v.w - __bfloat162float(h3));
    h = make_uint2(pack2(h0, h1), pack2(h2, h3));
    l = make_uint2(pack2(l0, l1), pack2(l2, l3));
}
__device__ __forceinline__ void split1(float v, u16& h, u16& l) {
    __nv_bfloat16 hh = __float2bfloat16(v);
    h = __bfloat16_as_ushort(hh);
    l = __bfloat16_as_ushort(__float2bfloat16(v - __bfloat162float(hh)));
}
// compact row base for slot s (expert e), R rows per slot, expert segs 128-aligned
__device__ __forceinline__ int slot_rowbase(const int* cnt, const int* soff, int s, int e, int R) {
    int base = 0;
    #pragma unroll
    for (int i = 0; i < EXP; ++i)
        if (i < e) base += ((cnt[i]*R + 127) & ~127);
    return base + (s - soff[e])*R;
}

// ---------------- weight pre-split ----------------
__global__ void k_split4(const float4* __restrict__ src, uint2* __restrict__ h,
                         uint2* __restrict__ l, int n4) {
    int stride = gridDim.x * blockDim.x;
    for (int i = blockIdx.x * blockDim.x + threadIdx.x; i < n4; i += stride) {
        uint2 hh, ll;
        split4(src[i], hh, ll);
        h[i] = hh; l[i] = ll;
    }
}

#define PITCH 17

// ================= tensor GEMM (compact rows): C = A @ W_e^T =================
// epi 0: C=acc+bias. epi 1: split(gelu(acc+bias))->Chi/Clo. epi 2: C += ls*(acc+bias)
__global__ __launch_bounds__(256, 1) void k_tgemm(
    int N, int K, int R,
    const u16* __restrict__ Ah, const u16* __restrict__ Al,
    const u16* __restrict__ Wh, const u16* __restrict__ Wl, long wES,
    const float* __restrict__ biasB, long bES,
    float* __restrict__ C, u16* __restrict__ Chi, u16* __restrict__ Clo,
    const float* __restrict__ lsB, long lsES,
    int epi, const int* __restrict__ cnt)
{
    int m0 = blockIdx.y * 128;
    int n0 = blockIdx.x * 128;
    // resolve expert segment
    int base = 0, e = -1;
    #pragma unroll
    for (int i = 0; i < EXP; ++i) {
        int seg = ((cnt[i]*R + 127) & ~127);
        if (e < 0) {
            if (m0 < base + seg) e = i;
            else base += seg;
        }
    }
    if (e < 0) return;
    int vrows = cnt[e]*R;

    __shared__ uint32_t AsH[128][PITCH], AsL[128][PITCH];
    __shared__ uint32_t BsH[128][PITCH], BsL[128][PITCH];

    int tid = threadIdx.x;
    int warp = tid >> 5, lane = tid & 31;
    int wm = warp & 3, wn = warp >> 2;
    int g8 = lane >> 2, tg = lane & 3;

    const u16* WhE = Wh + (long)e * wES;
    const u16* WlE = Wl + (long)e * wES;

    const u16 *pAh[2], *pAl[2], *pBh[2], *pBl[2];
    int rows_[2], q4_[2];
    #pragma unroll
    for (int j = 0; j < 2; ++j) {
        int lin = j * 256 + tid;
        int row = lin >> 2, q = lin & 3;
        rows_[j] = row; q4_[j] = q * 4;
        pAh[j] = Ah  + (long)(m0 + row) * K + q * 8;
        pAl[j] = Al  + (long)(m0 + row) * K + q * 8;
        pBh[j] = WhE + (long)(n0 + row) * K + q * 8;
        pBl[j] = WlE + (long)(n0 + row) * K + q * 8;
    }

    float acc[2][8][4] = {};
    uint4 rAh[2], rAl[2], rBh[2], rBl[2];
    int nch = K >> 5;

    #pragma unroll
    for (int j = 0; j < 2; ++j) {
        rAh[j] = *(const uint4*)(pAh[j]); rAl[j] = *(const uint4*)(pAl[j]);
        rBh[j] = *(const uint4*)(pBh[j]); rBl[j] = *(const uint4*)(pBl[j]);
    }

    for (int c = 0; c < nch; ++c) {
        #pragma unroll
        for (int j = 0; j < 2; ++j) {
            int r = rows_[j], o = q4_[j];
            AsH[r][o] = rAh[j].x; AsH[r][o+1] = rAh[j].y; AsH[r][o+2] = rAh[j].z; AsH[r][o+3] = rAh[j].w;
            AsL[r][o] = rAl[j].x; AsL[r][o+1] = rAl[j].y; AsL[r][o+2] = rAl[j].z; AsL[r][o+3] = rAl[j].w;
            BsH[r][o] = rBh[j].x; BsH[r][o+1] = rBh[j].y; BsH[r][o+2] = rBh[j].z; BsH[r][o+3] = rBh[j].w;
            BsL[r][o] = rBl[j].x; BsL[r][o+1] = rBl[j].y; BsL[r][o+2] = rBl[j].z; BsL[r][o+3] = rBl[j].w;
        }
        __syncthreads();
        if (c + 1 < nch) {
            long off = (long)(c + 1) * 32;
            #pragma unroll
            for (int j = 0; j < 2; ++j) {
                rAh[j] = *(const uint4*)(pAh[j] + off); rAl[j] = *(const uint4*)(pAl[j] + off);
                rBh[j] = *(const uint4*)(pBh[j] + off); rBl[j] = *(const uint4*)(pBl[j] + off);
            }
        }
        #pragma unroll
        for (int kh = 0; kh < 2; ++kh) {
            int kb = kh * 8;
            uint32_t ah[2][4], al[2][4];
            #pragma unroll
            for (int mt = 0; mt < 2; ++mt) {
                int r = wm * 32 + mt * 16 + g8;
                ah[mt][0] = AsH[r][kb+tg];     ah[mt][1] = AsH[r+8][kb+tg];
                ah[mt][2] = AsH[r][kb+tg+4];   ah[mt][3] = AsH[r+8][kb+tg+4];
                al[mt][0] = AsL[r][kb+tg];     al[mt][1] = AsL[r+8][kb+tg];
                al[mt][2] = AsL[r][kb+tg+4];   al[mt][3] = AsL[r+8][kb+tg+4];
            }
            #pragma unroll
            for (int nt = 0; nt < 8; ++nt) {
                int n = wn * 64 + nt * 8 + g8;
                uint32_t bh[2] = { BsH[n][kb+tg], BsH[n][kb+tg+4] };
                uint32_t bl[2] = { BsL[n][kb+tg], BsL[n][kb+tg+4] };
                #pragma unroll
                for (int mt = 0; mt < 2; ++mt) {
                    mma16816(acc[mt][nt], ah[mt], bh);
                    mma16816(acc[mt][nt], ah[mt], bl);
                    mma16816(acc[mt][nt], al[mt], bh);
                }
            }
        }
        __syncthreads();
    }

    const float* bias = biasB + (long)e * bES;
    const float* ls = lsB ? (lsB + (long)e * lsES) : (const float*)0;
    #pragma unroll
    for (int mt = 0; mt < 2; ++mt) {
        int r0 = m0 + wm * 32 + mt * 16 + g8;
        int r1 = r0 + 8;
        bool ok0 = (r0 - base) < vrows;
        bool ok1 = (r1 - base) < vrows;
        #pragma unroll
        for (int nt = 0; nt < 8; ++nt) {
            int col = n0 + wn * 64 + nt * 8 + tg * 2;
            float* cc = acc[mt][nt];
            #pragma unroll
            for (int q = 0; q < 4; ++q) {
                int row = (q < 2) ? r0 : r1;
                bool ok = (q < 2) ? ok0 : ok1;
                if (!ok) continue;
                int cl = col + (q & 1);
                float v = cc[q] + bias[cl];
                long idx = (long)row * N + cl;
                if (epi == 1) {
                    float gv = 0.5f * v * (1.f + erff(v * 0.70710678118654752f));
                    split1(gv, Chi[idx], Clo[idx]);
                } else if (epi == 2) {
                    C[idx] = C[idx] + ls[cl] * v;
                } else {
                    C[idx] = v;
                }
            }
        }
    }
}

// ================= out projection (y in (e,b) layout, pre-scaled by gate) =================
__global__ __launch_bounds__(256, 1) void k_tgemm_out(
    const u16* __restrict__ Yh, const u16* __restrict__ Yl,
    const u16* __restrict__ Wh, const u16* __restrict__ Wl,
    const float* __restrict__ bo,
    float* __restrict__ outp, const float* __restrict__ gates)
{
    int m0 = blockIdx.y * 128, n0 = blockIdx.x * 128, b = blockIdx.z;

    __shared__ uint32_t AsH[128][PITCH], AsL[128][PITCH];
    __shared__ uint32_t BsH[128][PITCH], BsL[128][PITCH];

    int tid = threadIdx.x;
    int warp = tid >> 5, lane = tid & 31;
    int wm = warp & 3, wn = warp >> 2;
    int g8 = lane >> 2, tg = lane & 3;

    float acc[2][8][4] = {};
    int rows_[2], q4_[2];
    #pragma unroll
    for (int j = 0; j < 2; ++j) {
        int lin = j * 256 + tid;
        rows_[j] = lin >> 2; q4_[j] = (lin & 3) * 4;
    }

    for (int e = 0; e < EXP; ++e) {
        float g = gates[b * EXP + e];
        if (g == 0.f) continue;
        const u16* AhE = Yh + (long)(e * BATCH + b) * NQ_ * HID;
        const u16* AlE = Yl + (long)(e * BATCH + b) * NQ_ * HID;
        const u16* WhE = Wh + (long)e * OUTD * HID;
        const u16* WlE = Wl + (long)e * OUTD * HID;

        uint4 rAh[2], rAl[2], rBh[2], rBl[2];
        const uint4 z4 = make_uint4(0u, 0u, 0u, 0u);
        #pragma unroll
        for (int j = 0; j < 2; ++j) {
            int row = rows_[j], q = q4_[j] >> 2;
            bool okr = (m0 + row) < NQ_;
            rAh[j] = okr ? *(const uint4*)(AhE + (long)(m0 + row) * HID + q * 8) : z4;
            rAl[j] = okr ? *(const uint4*)(AlE + (long)(m0 + row) * HID + q * 8) : z4;
            rBh[j] = *(const uint4*)(WhE + (long)(n0 + row) * HID + q * 8);
            rBl[j] = *(const uint4*)(WlE + (long)(n0 + row) * HID + q * 8);
        }

        for (int c = 0; c < 32; ++c) {
            #pragma unroll
            for (int j = 0; j < 2; ++j) {
                int r = rows_[j], o = q4_[j];
                AsH[r][o] = rAh[j].x; AsH[r][o+1] = rAh[j].y; AsH[r][o+2] = rAh[j].z; AsH[r][o+3] = rAh[j].w;
                AsL[r][o] = rAl[j].x; AsL[r][o+1] = rAl[j].y; AsL[r][o+2] = rAl[j].z; AsL[r][o+3] = rAl[j].w;
                BsH[r][o] = rBh[j].x; BsH[r][o+1] = rBh[j].y; BsH[r][o+2] = rBh[j].z; BsH[r][o+3] = rBh[j].w;
                BsL[r][o] = rBl[j].x; BsL[r][o+1] = rBl[j].y; BsL[r][o+2] = rBl[j].z; BsL[r][o+3] = rBl[j].w;
            }
            __syncthreads();
            if (c + 1 < 32) {
                long off = (long)(c + 1) * 32;
                #pragma unroll
                for (int j = 0; j < 2; ++j) {
                    int row = rows_[j], q = q4_[j] >> 2;
                    bool okr = (m0 + row) < NQ_;
                    rAh[j] = okr ? *(const uint4*)(AhE + (long)(m0 + row) * HID + q * 8 + off) : z4;
                    rAl[j] = okr ? *(const uint4*)(AlE + (long)(m0 + row) * HID + q * 8 + off) : z4;
                    rBh[j] = *(const uint4*)(WhE + (long)(n0 + row) * HID + q * 8 + off);
                    rBl[j] = *(const uint4*)(WlE + (long)(n0 + row) * HID + q * 8 + off);
                }
            }
            #pragma unroll
            for (int kh = 0; kh < 2; ++kh) {
                int kb = kh * 8;
                uint32_t ah[2][4], al[2][4];
                #pragma unroll
                for (int mt = 0; mt < 2; ++mt) {
                    int r = wm * 32 + mt * 16 + g8;
                    ah[mt][0] = AsH[r][kb+tg];     ah[mt][1] = AsH[r+8][kb+tg];
                    ah[mt][2] = AsH[r][kb+tg+4];   ah[mt][3] = AsH[r+8][kb+tg+4];
                    al[mt][0] = AsL[r][kb+tg];     al[mt][1] = AsL[r+8][kb+tg];
                    al[mt][2] = AsL[r][kb+tg+4];   al[mt][3] = AsL[r+8][kb+tg+4];
                }
                #pragma unroll
                for (int nt = 0; nt < 8; ++nt) {
                    int n = wn * 64 + nt * 8 + g8;
                    uint32_t bh[2] = { BsH[n][kb+tg], BsH[n][kb+tg+4] };
                    uint32_t bl[2] = { BsL[n][kb+tg], BsL[n][kb+tg+4] };
                    #pragma unroll
                    for (int mt = 0; mt < 2; ++mt) {
                        mma16816(acc[mt][nt], ah[mt], bh);
                        mma16816(acc[mt][nt], ah[mt], bl);
                        mma16816(acc[mt][nt], al[mt], bh);
                    }
                }
            }
            __syncthreads();
        }
    }

    #pragma unroll
    for (int mt = 0; mt < 2; ++mt) {
        int r0 = m0 + wm * 32 + mt * 16 + g8;
        int r1 = r0 + 8;
        #pragma unroll
        for (int nt = 0; nt < 8; ++nt) {
            int col = n0 + wn * 64 + nt * 8 + tg * 2;
            float* cc = acc[mt][nt];
            #pragma unroll
            for (int q = 0; q < 4; ++q) {
                int row = (q < 2) ? r0 : r1;
                if (row >= NQ_) continue;
                int cl = col + (q & 1);
                float bs = 0.f;
                #pragma unroll
                for (int e = 0; e < EXP; ++e)
                    bs += gates[b * EXP + e] * bo[(long)e * OUTD + cl];
                outp[((long)b * NQ_ + row) * OUTD + cl] = cc[q] + bs;
            }
        }
    }
}

// ---------------- reductions ----------------
__device__ __forceinline__ void blockReduce2(float& a, float& b, float* sh) {
    __syncthreads();
    int lane = threadIdx.x & 31, wid = threadIdx.x >> 5;
    #pragma unroll
    for (int o = 16; o; o >>= 1) { a += __shfl_xor_sync(~0u, a, o); b += __shfl_xor_sync(~0u, b, o); }
    if (lane == 0) { sh[wid] = a; sh[wid + 32] = b; }
    __syncthreads();
    int nw = blockDim.x >> 5;
    if (wid == 0) {
        a = (lane < nw) ? sh[lane] : 0.f;
        b = (lane < nw) ? sh[lane + 32] : 0.f;
        #pragma unroll
        for (int o = 16; o; o >>= 1) { a += __shfl_xor_sync(~0u, a, o); b += __shfl_xor_sync(~0u, b, o); }
        if (lane == 0) { sh[0] = a; sh[32] = b; }
    }
    __syncthreads();
    a = sh[0]; b = sh[32];
}
__device__ __forceinline__ float blockReduce1(float a, float* sh) {
    __syncthreads();
    int lane = threadIdx.x & 31, wid = threadIdx.x >> 5;
    #pragma unroll
    for (int o = 16; o; o >>= 1) a += __shfl_xor_sync(~0u, a, o);
    if (lane == 0) sh[wid] = a;
    __syncthreads();
    int nw = blockDim.x >> 5;
    if (wid == 0) {
        a = (lane < nw) ? sh[lane] : 0.f;
        #pragma unroll
        for (int o = 16; o; o >>= 1) a += __shfl_xor_sync(~0u, a, o);
        if (lane == 0) sh[0] = a;
    }
    __syncthreads();
    return sh[0];
}

// ---------------- gate kernels ----------------
__global__ void k_gate_mean(const float* __restrict__ img, float* __restrict__ gi) {
    int b = blockIdx.x;
    for (int h = threadIdx.x; h < HID; h += blockDim.x) {
        float s = 0.f;
        for (int l = 0; l < LV_; l++) s += img[((long)b*LV_ + l)*HID + h];
        gi[b*HID + h] = s * (1.f/LV_);
    }
}
__global__ void k_gate(const float* __restrict__ gi, const float* __restrict__ temb,
                       const float* __restrict__ eemb, const int* __restrict__ tids,
                       const int* __restrict__ eids, const float* __restrict__ glw,
                       const float* __restrict__ glb, const float* __restrict__ gwt,
                       const float* __restrict__ gbias, float* __restrict__ gates) {
    int b = blockIdx.x, tid = threadIdx.x;
    __shared__ float sh[64];
    __shared__ float logits[EXP];
    int ti = tids[b], ei = eids[b];
    float s = 0.f, ss = 0.f;
    for (int i = tid; i < GN; i += 256) {
        float v = (i < HID) ? gi[b*HID + i]
                : (i < HID + TDIM) ? temb[ti*TDIM + i - HID]
                : eemb[ei*TDIM + i - HID - TDIM];
        s += v; ss += v*v;
    }
    blockReduce2(s, ss, sh);
    float m  = s * (1.f/GN);
    float rs = rsqrtf(ss * (1.f/GN) - m*m + 1e-5f);
    for (int e = 0; e < EXP; e++) {
        float d = 0.f;
        for (int i = tid; i < GN; i += 256) {
            float v = (i < HID) ? gi[b*HID + i]
                    : (i < HID + TDIM) ? temb[ti*TDIM + i - HID]
                    : eemb[ei*TDIM + i - HID - TDIM];
            d += ((v - m)*rs*glw[i] + glb[i]) * gwt[(long)e*GN + i];
        }
        d = blockReduce1(d, sh);
        if (tid == 0) logits[e] = d + gbias[e];
    }
    __syncthreads();
    if (tid == 0) {
        float w[EXP]; float mx = -1e30f;
        for (int e = 0; e < EXP; e++) { float l = fminf(fmaxf(logits[e], -15.f), 15.f); w[e] = l; mx = fmaxf(mx, l); }
        float sum = 0.f;
        for (int e = 0; e < EXP; e++) { w[e] = expf(w[e] - mx); sum += w[e]; }
        for (int e = 0; e < EXP; e++) w[e] /= sum;
        int i0 = 0;
        for (int e = 1; e < EXP; e++) if (w[e] > w[i0]) i0 = e;
        int i1 = -1;
        for (int e = 0; e < EXP; e++) { if (e == i0) continue; if (i1 < 0 || w[e] > w[i1]) i1 = e; }
        float t = w[i0] + w[i1] + 1e-9f;
        for (int e = 0; e < EXP; e++) gates[b*EXP + e] = 0.f;
        gates[b*EXP + i0] = w[i0] / t;
        gates[b*EXP + i1] = w[i1] / t;
    }
}
// build compact slot tables (expert-major)
__global__ void k_slots(const float* __restrict__ gates, int* cnt, int* soff,
                        int* se, int* sb, float* sg) {
    if (threadIdx.x == 0) {
        int s = 0;
        for (int e = 0; e < EXP; e++) {
            soff[e] = s;
            int c = 0;
            for (int b = 0; b < BATCH; b++) {
                float g = gates[b*EXP + e];
                if (g != 0.f) { se[s] = e; sb[s] = b; sg[s] = g; s++; c++; }
            }
            cnt[e] = c;
        }
    }
}

// ---------------- init x = query tile (compact) ----------------
__global__ void k_initx(int R, const float* __restrict__ query, int qo,
                        float* __restrict__ gx, const int* __restrict__ cnt,
                        const int* __restrict__ soff, const int* __restrict__ se) {
    int r = blockIdx.x, s = blockIdx.y;
    int e = se[s];
    const float* srow = query + ((long)e*NQ_ + qo + r)*HID;
    float* d = gx + (long)(slot_rowbase(cnt, soff, s, e, R) + r)*HID;
    for (int i = threadIdx.x; i < HID; i += blockDim.x) d[i] = srow[i];
}

// ---------------- LayerNorm (compact rows) -> bf16 hi/lo ----------------
__global__ void k_ln(int R, const float* __restrict__ src,
                     const float* __restrict__ w, const float* __restrict__ bvec, long pES,
                     u16* __restrict__ dh, u16* __restrict__ dl,
                     const int* __restrict__ cnt, const int* __restrict__ soff,
                     const int* __restrict__ se) {
    int r = blockIdx.x, s = blockIdx.y;
    int e = se[s];
    long row = (long)(slot_rowbase(cnt, soff, s, e, R) + r)*HID;
    __shared__ float sh[64];
    float v[4]; float sm = 0.f, ss = 0.f;
    #pragma unroll
    for (int t = 0; t < 4; t++) { v[t] = src[row + threadIdx.x + t*256]; sm += v[t]; ss += v[t]*v[t]; }
    blockReduce2(sm, ss, sh);
    float m  = sm * (1.f/HID);
    float rs = rsqrtf(ss * (1.f/HID) - m*m + 1e-5f);
    const float* we = w + (long)e*pES;
    const float* be = bvec + (long)e*pES;
    #pragma unroll
    for (int t = 0; t < 4; t++) {
        int i = threadIdx.x + t*256;
        float rv = (v[t] - m)*rs*we[i] + be[i];
        split1(rv, dh[row + i], dl[row + i]);
    }
}

// ---------------- LayerNorm with kv0 gather (compact) -> bf16 hi/lo ----------------
__global__ void k_ln_kv(int sq, int kvR, int qo, int io,
                        const float* __restrict__ query, const float* __restrict__ img,
                        const float* __restrict__ pp,
                        const float* __restrict__ w, const float* __restrict__ bvec, long pES,
                        u16* __restrict__ dh, u16* __restrict__ dl,
                        const int* __restrict__ cnt, const int* __restrict__ soff,
                        const int* __restrict__ se, const int* __restrict__ sb) {
    int r = blockIdx.x, s = blockIdx.y;
    int e = se[s], b = sb[s];
    const float* row;
    if (r < sq) row = query + ((long)e*NQ_ + qo + r)*HID;
    else {
        int zi = io + r - sq;
        if (zi < LV_) row = img + ((long)b*LV_ + zi)*HID;
        else          row = pp  + ((long)b*LP_ + zi - LV_)*HID;
    }
    long doff = (long)(slot_rowbase(cnt, soff, s, e, kvR) + r)*HID;
    __shared__ float sh[64];
    float v[4]; float sm = 0.f, ss = 0.f;
    #pragma unroll
    for (int t = 0; t < 4; t++) { v[t] = row[threadIdx.x + t*256]; sm += v[t]; ss += v[t]*v[t]; }
    blockReduce2(sm, ss, sh);
    float m  = sm * (1.f/HID);
    float rs = rsqrtf(ss * (1.f/HID) - m*m + 1e-5f);
    const float* we = w + (long)e*pES;
    const float* be = bvec + (long)e*pES;
    #pragma unroll
    for (int t = 0; t < 4; t++) {
        int i = threadIdx.x + t*256;
        float rv = (v[t] - m)*rs*we[i] + be[i];
        split1(rv, dh[doff + i], dl[doff + i]);
    }
}

// ---------------- attention (compact) -> bf16 hi/lo ----------------
__global__ void k_attn(int sq, int kvlen,
                       const float* __restrict__ q, const float* __restrict__ kv,
                       u16* __restrict__ ath, u16* __restrict__ atl,
                       const int* __restrict__ cnt, const int* __restrict__ soff,
                       const int* __restrict__ se) {
    int s = blockIdx.y;
    int e = se[s];
    int warp = threadIdx.x >> 5, lane = threadIdx.x & 31;
    int w = blockIdx.x * 4 + warp;
    if (w >= NHEADS * sq) return;
    int h = w / sq, qi = w % sq;
    __shared__ float sc[4][MAXKV];

    long qrow  = slot_rowbase(cnt, soff, s, e, sq) + qi;
    long kvrow = slot_rowbase(cnt, soff, s, e, kvlen);
    const float* qr = q + qrow*HID + h*HDIM;
    float q0 = qr[lane], q1 = qr[lane + 32];
    const float* kbase = kv + kvrow*2048 + h*HDIM;
    float mx = -1e30f;
    for (int j = 0; j < kvlen; j++) {
        const float* kr = kbase + (long)j*2048;
        float p = q0*kr[lane] + q1*kr[lane + 32];
        #pragma unroll
        for (int o = 16; o; o >>= 1) p += __shfl_xor_sync(~0u, p, o);
        p *= 0.125f;
        if (lane == 0) sc[warp][j] = p;
        mx = fmaxf(mx, p);
    }
    __syncwarp();
    float se_ = 0.f;
    for (int j = lane; j < kvlen; j += 32) {
        float ex = __expf(sc[warp][j] - mx);
        sc[warp][j] = ex;
        se_ += ex;
    }
    #pragma unroll
    for (int o = 16; o; o >>= 1) se_ += __shfl_xor_sync(~0u, se_, o);
    __syncwarp();
    float inv = 1.f / se_;
    const float* vbase = kv + kvrow*2048 + 1024 + h*HDIM;
    float a0 = 0.f, a1 = 0.f;
    for (int j = 0; j < kvlen; j++) {
        float p = sc[warp][j];
        const float* vr = vbase + (long)j*2048;
        a0 += p*vr[lane]; a1 += p*vr[lane + 32];
    }
    long ooff = qrow*HID + h*HDIM;
    split1(a0 * inv, ath[ooff + lane],      atl[ooff + lane]);
    split1(a1 * inv, ath[ooff + lane + 32], atl[ooff + lane + 32]);
}

// ---------------- copy stage result into y (pre-scaled by gate) ----------------
__global__ void k_copy_y(int R, const float* __restrict__ gx, int qo,
                         u16* __restrict__ yh, u16* __restrict__ yl,
                         const int* __restrict__ cnt, const int* __restrict__ soff,
                         const int* __restrict__ se, const int* __restrict__ sb,
                         const float* __restrict__ sg) {
    int r = blockIdx.x, s = blockIdx.y;
    int e = se[s], b = sb[s];
    float g = sg[s];
    const float* srow = gx + (long)(slot_rowbase(cnt, soff, s, e, R) + r)*HID;
    long doff = ((long)(e*BATCH + b)*NQ_ + qo + r)*HID;
    for (int i = threadIdx.x; i < HID; i += blockDim.x)
        split1(g * srow[i], yh[doff + i], yl[doff + i]);
}

// ---------------- RMS norm + final scaling ----------------
__global__ void k_rms(float* __restrict__ out, const float* __restrict__ fw,
                      const float* __restrict__ gain) {
    int q = blockIdx.x, b = blockIdx.y;
    float* row = out + ((long)b*NQ_ + q)*OUTD;
    __shared__ float sh[64];
    float v[16]; float ss = 0.f;
    #pragma unroll
    for (int t = 0; t < 16; t++) { v[t] = row[threadIdx.x + t*256]; ss += v[t]*v[t]; }
    ss = blockReduce1(ss, sh);
    float sc = rsqrtf(ss * (1.f/OUTD) + 1e-6f);
    #pragma unroll
    for (int t = 0; t < 16; t++) {
        int o = threadIdx.x + t*256;
        row[o] = v[t]*sc*fw[o]*gain[o];
    }
}

// ---------------- host orchestration ----------------
extern "C" void kernel_launch(void* const* d_in, const int* in_sizes, int n_in,
                              void* d_out, int out_size) {
    const float* image     = (const float*)d_in[0];
    const float* pp        = (const float*)d_in[1];
    const int*   tids      = (const int*)  d_in[2];
    const int*   eids      = (const int*)  d_in[3];
    const float* query     = (const float*)d_in[4];
    const float* ln1_w     = (const float*)d_in[5];
    const float* ln1_b     = (const float*)d_in[6];
    const float* ln1kv_w   = (const float*)d_in[7];
    const float* ln1kv_b   = (const float*)d_in[8];
    const float* attn_in_w = (const float*)d_in[9];
    const float* attn_in_b = (const float*)d_in[10];
    const float* attn_out_w= (const float*)d_in[11];
    const float* attn_out_b= (const float*)d_in[12];
    const float* ls1       = (const float*)d_in[13];
    const float* ls2       = (const float*)d_in[14];
    const float* ln2_w     = (const float*)d_in[15];
    const float* ln2_b     = (const float*)d_in[16];
    const float* fc_w      = (const float*)d_in[17];
    const float* fc_b      = (const float*)d_in[18];
    const float* proj_w    = (const float*)d_in[19];
    const float* proj_b    = (const float*)d_in[20];
    const float* outp_w    = (const float*)d_in[21];
    const float* outp_b    = (const float*)d_in[22];
    const float* temb      = (const float*)d_in[23];
    const float* eemb      = (const float*)d_in[24];
    const float* glw       = (const float*)d_in[25];
    const float* glb       = (const float*)d_in[26];
    const float* gwt       = (const float*)d_in[27];
    const float* gbias     = (const float*)d_in[28];
    const float* gain      = (const float*)d_in[29];
    const float* fw        = (const float*)d_in[30];
    float* out = (float*)d_out;

    float *px, *pq, *pkv, *pg, *pgi, *psg;
    int *pcnt, *psoff, *pse, *psb;
    cudaGetSymbolAddress((void**)&px,   g_x);
    cudaGetSymbolAddress((void**)&pq,   g_q);
    cudaGetSymbolAddress((void**)&pkv,  g_kv);
    cudaGetSymbolAddress((void**)&pg,   g_gates);
    cudaGetSymbolAddress((void**)&pgi,  g_gi);
    cudaGetSymbolAddress((void**)&pcnt, g_cnt);
    cudaGetSymbolAddress((void**)&psoff,g_soff);
    cudaGetSymbolAddress((void**)&pse,  g_se);
    cudaGetSymbolAddress((void**)&psb,  g_sb);
    cudaGetSymbolAddress((void**)&psg,  g_sg);

    u16 *xh, *xl, *kh, *kl, *ah, *al, *fh, *fl, *yh, *yl;
    cudaGetSymbolAddress((void**)&xh, g_xln_h); cudaGetSymbolAddress((void**)&xl, g_xln_l);
    cudaGetSymbolAddress((void**)&kh, g_kvn_h); cudaGetSymbolAddress((void**)&kl, g_kvn_l);
    cudaGetSymbolAddress((void**)&ah, g_att_h); cudaGetSymbolAddress((void**)&al, g_att_l);
    cudaGetSymbolAddress((void**)&fh, g_ffn_h); cudaGetSymbolAddress((void**)&fl, g_ffn_l);
    cudaGetSymbolAddress((void**)&yh, g_y_h);   cudaGetSymbolAddress((void**)&yl, g_y_l);

    u16 *aiwh, *aiwl, *aowh, *aowl, *fcwh, *fcwl, *pjwh, *pjwl, *opwh, *opwl;
    cudaGetSymbolAddress((void**)&aiwh, g_aiw_h); cudaGetSymbolAddress((void**)&aiwl, g_aiw_l);
    cudaGetSymbolAddress((void**)&aowh, g_aow_h); cudaGetSymbolAddress((void**)&aowl, g_aow_l);
    cudaGetSymbolAddress((void**)&fcwh, g_fcw_h); cudaGetSymbolAddress((void**)&fcwl, g_fcw_l);
    cudaGetSymbolAddress((void**)&pjwh, g_pjw_h); cudaGetSymbolAddress((void**)&pjwl, g_pjw_l);
    cudaGetSymbolAddress((void**)&opwh, g_opw_h); cudaGetSymbolAddress((void**)&opwl, g_opw_l);

    k_split4<<<4096, 256>>>((const float4*)attn_in_w,  (uint2*)aiwh, (uint2*)aiwl, AIW_N/4);
    k_split4<<<4096, 256>>>((const float4*)attn_out_w, (uint2*)aowh, (uint2*)aowl, AOW_N/4);
    k_split4<<<4096, 256>>>((const float4*)fc_w,       (uint2*)fcwh, (uint2*)fcwl, FCW_N/4);
    k_split4<<<4096, 256>>>((const float4*)proj_w,     (uint2*)pjwh, (uint2*)pjwl, PJW_N/4);
    k_split4<<<4096, 256>>>((const float4*)outp_w,     (uint2*)opwh, (uint2*)opwl, OPW_N/4);

    k_gate_mean<<<BATCH, 256>>>(image, pgi);
    k_gate<<<BATCH, 256>>>(pgi, temb, eemb, tids, eids, glw, glb, gwt, gbias, pg);
    k_slots<<<1, 32>>>(pg, pcnt, psoff, pse, psb, psg);

    const int sqs[3] = {64, 48, 32};
    const int qos[3] = {0, 64, 112};
    const int ios[3] = {0, 256, 512};
    // upper-bound M-block counts: ceil(16*R/128) + 4 pad blocks
    const int xb[3]  = {12, 10, 8};
    const int kvb[3] = {44, 42, 40};
    const long HH = (long)HID*HID;

    for (int s = 0; s < 3; s++) {
        int sq = sqs[s], qo = qos[s], io = ios[s];
        int kvlen = sq + 256;
        k_initx<<<dim3(sq, NSLOT), 256>>>(sq, query, qo, px, pcnt, psoff, pse);
        for (int l = 0; l < NLAYERS; l++) {
            k_ln_kv<<<dim3(kvlen, NSLOT), 256>>>(sq, kvlen, qo, io, query, image, pp,
                ln1kv_w + (long)l*HID, ln1kv_b + (long)l*HID, (long)NLAYERS*HID,
                kh, kl, pcnt, psoff, pse, psb);
            k_ln<<<dim3(sq, NSLOT), 256>>>(sq, px,
                ln1_w + (long)l*HID, ln1_b + (long)l*HID, (long)NLAYERS*HID,
                xh, xl, pcnt, psoff, pse);
            // Q projection
            k_tgemm<<<dim3(8, xb[s]), 256>>>(HID, HID, sq,
                xh, xl, aiwh + (long)l*3*HH, aiwl + (long)l*3*HH, (long)NLAYERS*3*HH,
                attn_in_b + (long)l*3*HID, (long)NLAYERS*3*HID,
                pq, (u16*)0, (u16*)0, (const float*)0, 0, 0, pcnt);
            // fused K,V projection
            k_tgemm<<<dim3(16, kvb[s]), 256>>>(2048, HID, kvlen,
                kh, kl, aiwh + (long)l*3*HH + HH, aiwl + (long)l*3*HH + HH, (long)NLAYERS*3*HH,
                attn_in_b + (long)l*3*HID + HID, (long)NLAYERS*3*HID,
                pkv, (u16*)0, (u16*)0, (const float*)0, 0, 0, pcnt);
            // attention
            k_attn<<<dim3((NHEADS*sq + 3)/4, NSLOT), 128>>>(sq, kvlen, pq, pkv,
                ah, al, pcnt, psoff, pse);
            // attn-out projection + residual
            k_tgemm<<<dim3(8, xb[s]), 256>>>(HID, HID, sq,
                ah, al, aowh + (long)l*HH, aowl + (long)l*HH, (long)NLAYERS*HH,
                attn_out_b + (long)l*HID, (long)NLAYERS*HID,
                px, (u16*)0, (u16*)0, ls1 + (long)l*HID, (long)NLAYERS*HID, 2, pcnt);
            // MLP
            k_ln<<<dim3(sq, NSLOT), 256>>>(sq, px,
                ln2_w + (long)l*HID, ln2_b + (long)l*HID, (long)NLAYERS*HID,
                xh, xl, pcnt, psoff, pse);
            k_tgemm<<<dim3(32, xb[s]), 256>>>(4*HID, HID, sq,
                xh, xl, fcwh + (long)l*4*HH, fcwl + (long)l*4*HH, (long)NLAYERS*4*HH,
                fc_b + (long)l*4*HID, (long)NLAYERS*4*HID,
                (float*)0, fh, fl, (const float*)0, 0, 1, pcnt);
            k_tgemm<<<dim3(8, xb[s]), 256>>>(HID, 4*HID, sq,
                fh, fl, pjwh + (long)l*4*HH, pjwl + (long)l*4*HH, (long)NLAYERS*4*HH,
                proj_b + (long)l*HID, (long)NLAYERS*HID,
                px, (u16*)0, (u16*)0, ls2 + (long)l*HID, (long)NLAYERS*HID, 2, pcnt);
        }
        k_copy_y<<<dim3(sq, NSLOT), 256>>>(sq, px, qo, yh, yl, pcnt, psoff, pse, psb, psg);
    }

    k_tgemm_out<<<dim3(OUTD/128, 2, BATCH), 256>>>(yh, yl, opwh, opwl, outp_b, out, pg);
    k_rms<<<dim3(NQ_, BATCH), 256>>>(out, fw, gain);
}

// round 7
// speedup vs baseline: 2.6039x; 1.2707x over previous
#include <cuda_runtime.h>
#include <cuda_bf16.h>
#include <math.h>
#include <stdint.h>

typedef unsigned short u16;

// ---------------- problem constants ----------------
#define EXP    4
#define BATCH  8
#define NQ_    144
#define NLAYERS 2
#define NHEADS 16
#define HDIM   64
#define HID    1024
#define OUTD   4096
#define TDIM   256
#define LV_    576
#define LP_    192
#define NSLOT  16
#define GN     (HID + 2*TDIM)   // 1536
#define KVR    912              // 320+304+288 kv rows per slot
#define XROWS  3072             // >= 16*144 + 4*127
#define KVROWS 16384            // >= 16*912 + 4*127

// ---------------- fp32 scratch ----------------
__device__ float g_x   [XROWS*HID];
__device__ float g_q   [XROWS*HID];
__device__ float g_kv  [KVROWS*2048];       // K | V
__device__ float g_o   [XROWS*OUTD];
__device__ float g_gates[BATCH*EXP];
__device__ float g_gi  [BATCH*HID];

// slot metadata
__device__ int   g_cnt[EXP], g_soff[EXP];
__device__ int   g_se[NSLOT], g_sb[NSLOT];
__device__ float g_sg[NSLOT];
__device__ int   g_xseg[EXP+1], g_kvseg[EXP+1];
__device__ int   g_xvalid[EXP], g_kvvalid[EXP];
__device__ int   g_sxb[NSLOT], g_skvb[NSLOT];
__device__ int   g_b2s[BATCH*2];

// ---------------- bf16 hi/lo activation scratch ----------------
__device__ u16 g_xln_h[XROWS*HID],  g_xln_l[XROWS*HID];
__device__ u16 g_kvn_h[KVROWS*HID], g_kvn_l[KVROWS*HID];
__device__ u16 g_att_h[XROWS*HID],  g_att_l[XROWS*HID];
__device__ u16 g_ffn_h[XROWS*4096], g_ffn_l[XROWS*4096];

// ---------------- bf16 hi/lo weight scratch ----------------
#define AIW_N (EXP*NLAYERS*3*HID*HID)
#define AOW_N (EXP*NLAYERS*HID*HID)
#define FCW_N (EXP*NLAYERS*4*HID*HID)
#define PJW_N (EXP*NLAYERS*HID*4*HID)
#define OPW_N (EXP*OUTD*HID)
__device__ u16 g_aiw_h[AIW_N], g_aiw_l[AIW_N];
__device__ u16 g_aow_h[AOW_N], g_aow_l[AOW_N];
__device__ u16 g_fcw_h[FCW_N], g_fcw_l[FCW_N];
__device__ u16 g_pjw_h[PJW_N], g_pjw_l[PJW_N];
__device__ u16 g_opw_h[OPW_N], g_opw_l[OPW_N];

// ================= helpers =================
__device__ __forceinline__ void mma16816(float* c, const uint32_t* a, const uint32_t* b) {
    asm volatile("mma.sync.aligned.m16n8k16.row.col.f32.bf16.bf16.f32 "
        "{%0,%1,%2,%3}, {%4,%5,%6,%7}, {%8,%9}, {%0,%1,%2,%3};"
        : "+f"(c[0]), "+f"(c[1]), "+f"(c[2]), "+f"(c[3])
        : "r"(a[0]), "r"(a[1]), "r"(a[2]), "r"(a[3]), "r"(b[0]), "r"(b[1]));
}
__device__ __forceinline__ uint32_t pack2(__nv_bfloat16 a, __nv_bfloat16 b) {
    return (uint32_t)__bfloat16_as_ushort(a) | ((uint32_t)__bfloat16_as_ushort(b) << 16);
}
__device__ __forceinline__ void split4(float4 v, uint2& h, uint2& l) {
    __nv_bfloat16 h0 = __float2bfloat16(v.x), h1 = __float2bfloat16(v.y);
    __nv_bfloat16 h2 = __float2bfloat16(v.z), h3 = __float2bfloat16(v.w);
    __nv_bfloat16 l0 = __float2bfloat16(v.x - __bfloat162float(h0));
    __nv_bfloat16 l1 = __float2bfloat16(v.y - __bfloat162float(h1));
    __nv_bfloat16 l2 = __float2bfloat16(v.z - __bfloat162float(h2));
    __nv_bfloat16 l3 = __float2bfloat16(v.w - __bfloat162float(h3));
    h = make_uint2(pack2(h0, h1), pack2(h2, h3));
    l = make_uint2(pack2(l0, l1), pack2(l2, l3));
}
__device__ __forceinline__ void split1(float v, u16& h, u16& l) {
    __nv_bfloat16 hh = __float2bfloat16(v);
    h = __bfloat16_as_ushort(hh);
    l = __bfloat16_as_ushort(__float2bfloat16(v - __bfloat162float(hh)));
}

// ---------------- weight pre-split ----------------
__global__ void k_split4(const float4* __restrict__ src, uint2* __restrict__ h,
                         uint2* __restrict__ l, int n4) {
    int stride = gridDim.x * blockDim.x;
    for (int i = blockIdx.x * blockDim.x + threadIdx.x; i < n4; i += stride) {
        uint2 hh, ll;
        split4(src[i], hh, ll);
        h[i] = hh; l[i] = ll;
    }
}

#define PITCH 17

// ================= tensor GEMM (compact rows): C = A @ W_e^T =================
// epi 0: C=acc+bias. epi 1: split(gelu(acc+bias))->Chi/Clo. epi 2: C += ls*(acc+bias). epi 3: C=acc.
__global__ __launch_bounds__(256, 1) void k_tgemm(
    int N, int K,
    const u16* __restrict__ Ah, const u16* __restrict__ Al,
    const u16* __restrict__ Wh, const u16* __restrict__ Wl, long wES,
    const float* __restrict__ biasB, long bES,
    float* __restrict__ C, u16* __restrict__ Chi, u16* __restrict__ Clo,
    const float* __restrict__ lsB, long lsES,
    int epi, const int* __restrict__ segbase, const int* __restrict__ valid)
{
    int m0 = blockIdx.y * 128;
    int n0 = blockIdx.x * 128;
    int e = -1, base = 0;
    #pragma unroll
    for (int i = 0; i < EXP; ++i)
        if (e < 0 && m0 >= segbase[i] && m0 < segbase[i+1]) { e = i; base = segbase[i]; }
    if (e < 0) return;
    int vrows = valid[e];

    __shared__ uint32_t AsH[128][PITCH], AsL[128][PITCH];
    __shared__ uint32_t BsH[128][PITCH], BsL[128][PITCH];

    int tid = threadIdx.x;
    int warp = tid >> 5, lane = tid & 31;
    int wm = warp & 3, wn = warp >> 2;
    int g8 = lane >> 2, tg = lane & 3;

    const u16* WhE = Wh + (long)e * wES;
    const u16* WlE = Wl + (long)e * wES;

    const u16 *pAh[2], *pAl[2], *pBh[2], *pBl[2];
    int rows_[2], q4_[2];
    #pragma unroll
    for (int j = 0; j < 2; ++j) {
        int lin = j * 256 + tid;
        int row = lin >> 2, q = lin & 3;
        rows_[j] = row; q4_[j] = q * 4;
        pAh[j] = Ah  + (long)(m0 + row) * K + q * 8;
        pAl[j] = Al  + (long)(m0 + row) * K + q * 8;
        pBh[j] = WhE + (long)(n0 + row) * K + q * 8;
        pBl[j] = WlE + (long)(n0 + row) * K + q * 8;
    }

    float acc[2][8][4] = {};
    uint4 rAh[2], rAl[2], rBh[2], rBl[2];
    int nch = K >> 5;

    #pragma unroll
    for (int j = 0; j < 2; ++j) {
        rAh[j] = *(const uint4*)(pAh[j]); rAl[j] = *(const uint4*)(pAl[j]);
        rBh[j] = *(const uint4*)(pBh[j]); rBl[j] = *(const uint4*)(pBl[j]);
    }

    for (int c = 0; c < nch; ++c) {
        #pragma unroll
        for (int j = 0; j < 2; ++j) {
            int r = rows_[j], o = q4_[j];
            AsH[r][o] = rAh[j].x; AsH[r][o+1] = rAh[j].y; AsH[r][o+2] = rAh[j].z; AsH[r][o+3] = rAh[j].w;
            AsL[r][o] = rAl[j].x; AsL[r][o+1] = rAl[j].y; AsL[r][o+2] = rAl[j].z; AsL[r][o+3] = rAl[j].w;
            BsH[r][o] = rBh[j].x; BsH[r][o+1] = rBh[j].y; BsH[r][o+2] = rBh[j].z; BsH[r][o+3] = rBh[j].w;
            BsL[r][o] = rBl[j].x; BsL[r][o+1] = rBl[j].y; BsL[r][o+2] = rBl[j].z; BsL[r][o+3] = rBl[j].w;
        }
        __syncthreads();
        if (c + 1 < nch) {
            long off = (long)(c + 1) * 32;
            #pragma unroll
            for (int j = 0; j < 2; ++j) {
                rAh[j] = *(const uint4*)(pAh[j] + off); rAl[j] = *(const uint4*)(pAl[j] + off);
                rBh[j] = *(const uint4*)(pBh[j] + off); rBl[j] = *(const uint4*)(pBl[j] + off);
            }
        }
        #pragma unroll
        for (int kh = 0; kh < 2; ++kh) {
            int kb = kh * 8;
            uint32_t ah[2][4], al[2][4];
            #pragma unroll
            for (int mt = 0; mt < 2; ++mt) {
                int r = wm * 32 + mt * 16 + g8;
                ah[mt][0] = AsH[r][kb+tg];     ah[mt][1] = AsH[r+8][kb+tg];
                ah[mt][2] = AsH[r][kb+tg+4];   ah[mt][3] = AsH[r+8][kb+tg+4];
                al[mt][0] = AsL[r][kb+tg];     al[mt][1] = AsL[r+8][kb+tg];
                al[mt][2] = AsL[r][kb+tg+4];   al[mt][3] = AsL[r+8][kb+tg+4];
            }
            #pragma unroll
            for (int nt = 0; nt < 8; ++nt) {
                int n = wn * 64 + nt * 8 + g8;
                uint32_t bh[2] = { BsH[n][kb+tg], BsH[n][kb+tg+4] };
                uint32_t bl[2] = { BsL[n][kb+tg], BsL[n][kb+tg+4] };
                #pragma unroll
                for (int mt = 0; mt < 2; ++mt) {
                    mma16816(acc[mt][nt], ah[mt], bh);
                    mma16816(acc[mt][nt], ah[mt], bl);
                    mma16816(acc[mt][nt], al[mt], bh);
                }
            }
        }
        __syncthreads();
    }

    const float* bias = biasB ? (biasB + (long)e * bES) : (const float*)0;
    const float* ls = lsB ? (lsB + (long)e * lsES) : (const float*)0;
    #pragma unroll
    for (int mt = 0; mt < 2; ++mt) {
        int r0 = m0 + wm * 32 + mt * 16 + g8;
        int r1 = r0 + 8;
        bool ok0 = (r0 - base) < vrows;
        bool ok1 = (r1 - base) < vrows;
        #pragma unroll
        for (int nt = 0; nt < 8; ++nt) {
            int col = n0 + wn * 64 + nt * 8 + tg * 2;
            float* cc = acc[mt][nt];
            #pragma unroll
            for (int q = 0; q < 4; ++q) {
                int row = (q < 2) ? r0 : r1;
                bool ok = (q < 2) ? ok0 : ok1;
                if (!ok) continue;
                int cl = col + (q & 1);
                long idx = (long)row * N + cl;
                if (epi == 3) { C[idx] = cc[q]; continue; }
                float v = cc[q] + bias[cl];
                if (epi == 1) {
                    float gv = 0.5f * v * (1.f + erff(v * 0.70710678118654752f));
                    split1(gv, Chi[idx], Clo[idx]);
                } else if (epi == 2) {
                    C[idx] = C[idx] + ls[cl] * v;
                } else {
                    C[idx] = v;
                }
            }
        }
    }
}

// ---------------- reductions ----------------
__device__ __forceinline__ void blockReduce2(float& a, float& b, float* sh) {
    __syncthreads();
    int lane = threadIdx.x & 31, wid = threadIdx.x >> 5;
    #pragma unroll
    for (int o = 16; o; o >>= 1) { a += __shfl_xor_sync(~0u, a, o); b += __shfl_xor_sync(~0u, b, o); }
    if (lane == 0) { sh[wid] = a; sh[wid + 32] = b; }
    __syncthreads();
    int nw = blockDim.x >> 5;
    if (wid == 0) {
        a = (lane < nw) ? sh[lane] : 0.f;
        b = (lane < nw) ? sh[lane + 32] : 0.f;
        #pragma unroll
        for (int o = 16; o; o >>= 1) { a += __shfl_xor_sync(~0u, a, o); b += __shfl_xor_sync(~0u, b, o); }
        if (lane == 0) { sh[0] = a; sh[32] = b; }
    }
    __syncthreads();
    a = sh[0]; b = sh[32];
}
__device__ __forceinline__ float blockReduce1(float a, float* sh) {
    __syncthreads();
    int lane = threadIdx.x & 31, wid = threadIdx.x >> 5;
    #pragma unroll
    for (int o = 16; o; o >>= 1) a += __shfl_xor_sync(~0u, a, o);
    if (lane == 0) sh[wid] = a;
    __syncthreads();
    int nw = blockDim.x >> 5;
    if (wid == 0) {
        a = (lane < nw) ? sh[lane] : 0.f;
        #pragma unroll
        for (int o = 16; o; o >>= 1) a += __shfl_xor_sync(~0u, a, o);
        if (lane == 0) sh[0] = a;
    }
    __syncthreads();
    return sh[0];
}

// ---------------- gate kernels ----------------
__global__ void k_gate_mean(const float* __restrict__ img, float* __restrict__ gi) {
    int b = blockIdx.x;
    for (int h = threadIdx.x; h < HID; h += blockDim.x) {
        float s = 0.f;
        for (int l = 0; l < LV_; l++) s += img[((long)b*LV_ + l)*HID + h];
        gi[b*HID + h] = s * (1.f/LV_);
    }
}
__global__ void k_gate(const float* __restrict__ gi, const float* __restrict__ temb,
                       const float* __restrict__ eemb, const int* __restrict__ tids,
                       const int* __restrict__ eids, const float* __restrict__ glw,
                       const float* __restrict__ glb, const float* __restrict__ gwt,
                       const float* __restrict__ gbias, float* __restrict__ gates) {
    int b = blockIdx.x, tid = threadIdx.x;
    __shared__ float sh[64];
    __shared__ float logits[EXP];
    int ti = tids[b], ei = eids[b];
    float s = 0.f, ss = 0.f;
    for (int i = tid; i < GN; i += 256) {
        float v = (i < HID) ? gi[b*HID + i]
                : (i < HID + TDIM) ? temb[ti*TDIM + i - HID]
                : eemb[ei*TDIM + i - HID - TDIM];
        s += v; ss += v*v;
    }
    blockReduce2(s, ss, sh);
    float m  = s * (1.f/GN);
    float rs = rsqrtf(ss * (1.f/GN) - m*m + 1e-5f);
    for (int e = 0; e < EXP; e++) {
        float d = 0.f;
        for (int i = tid; i < GN; i += 256) {
            float v = (i < HID) ? gi[b*HID + i]
                    : (i < HID + TDIM) ? temb[ti*TDIM + i - HID]
                    : eemb[ei*TDIM + i - HID - TDIM];
            d += ((v - m)*rs*glw[i] + glb[i]) * gwt[(long)e*GN + i];
        }
        d = blockReduce1(d, sh);
        if (tid == 0) logits[e] = d + gbias[e];
    }
    __syncthreads();
    if (tid == 0) {
        float w[EXP]; float mx = -1e30f;
        for (int e = 0; e < EXP; e++) { float l = fminf(fmaxf(logits[e], -15.f), 15.f); w[e] = l; mx = fmaxf(mx, l); }
        float sum = 0.f;
        for (int e = 0; e < EXP; e++) { w[e] = expf(w[e] - mx); sum += w[e]; }
        for (int e = 0; e < EXP; e++) w[e] /= sum;
        int i0 = 0;
        for (int e = 1; e < EXP; e++) if (w[e] > w[i0]) i0 = e;
        int i1 = -1;
        for (int e = 0; e < EXP; e++) { if (e == i0) continue; if (i1 < 0 || w[e] > w[i1]) i1 = e; }
        float t = w[i0] + w[i1] + 1e-9f;
        for (int e = 0; e < EXP; e++) gates[b*EXP + e] = 0.f;
        gates[b*EXP + i0] = w[i0] / t;
        gates[b*EXP + i1] = w[i1] / t;
    }
}
// build compact slot tables (expert-major), segment bases, per-batch slot map
__global__ void k_slots(const float* __restrict__ gates, int* cnt, int* soff,
                        int* se, int* sb, float* sg,
                        int* xseg, int* kvseg, int* xvalid, int* kvvalid,
                        int* sxb, int* skvb, int* b2s) {
    if (threadIdx.x == 0) {
        int s = 0;
        for (int e = 0; e < EXP; e++) {
            soff[e] = s;
            int c = 0;
            for (int b = 0; b < BATCH; b++) {
                float g = gates[b*EXP + e];
                if (g != 0.f) { se[s] = e; sb[s] = b; sg[s] = g; s++; c++; }
            }
            cnt[e] = c;
        }
        xseg[0] = 0; kvseg[0] = 0;
        for (int e = 0; e < EXP; e++) {
            xvalid[e]  = cnt[e]*NQ_;
            kvvalid[e] = cnt[e]*KVR;
            xseg[e+1]  = xseg[e]  + ((cnt[e]*NQ_ + 127) & ~127);
            kvseg[e+1] = kvseg[e] + ((cnt[e]*KVR + 127) & ~127);
        }
        for (int i = 0; i < NSLOT; i++) {
            int e = se[i];
            sxb[i]  = xseg[e]  + (i - soff[e])*NQ_;
            skvb[i] = kvseg[e] + (i - soff[e])*KVR;
        }
        int fill[BATCH];
        for (int b = 0; b < BATCH; b++) fill[b] = 0;
        for (int i = 0; i < NSLOT; i++) {
            int b = sb[i];
            b2s[b*2 + fill[b]] = i;
            fill[b]++;
        }
    }
}

// ---------------- init x = full query block per slot ----------------
__global__ void k_initx(const float* __restrict__ query, float* __restrict__ gx,
                        const int* __restrict__ se, const int* __restrict__ sxb) {
    int r = blockIdx.x, s = blockIdx.y;
    int e = se[s];
    const float* srow = query + ((long)e*NQ_ + r)*HID;
    float* d = gx + (long)(sxb[s] + r)*HID;
    for (int i = threadIdx.x; i < HID; i += blockDim.x) d[i] = srow[i];
}

// ---------------- LayerNorm (x rows) -> bf16 hi/lo ----------------
__global__ void k_ln(const float* __restrict__ src,
                     const float* __restrict__ w, const float* __restrict__ bvec, long pES,
                     u16* __restrict__ dh, u16* __restrict__ dl,
                     const int* __restrict__ se, const int* __restrict__ sxb) {
    int r = blockIdx.x, s = blockIdx.y;
    int e = se[s];
    long row = (long)(sxb[s] + r)*HID;
    __shared__ float sh[64];
    float v[4]; float sm = 0.f, ss = 0.f;
    #pragma unroll
    for (int t = 0; t < 4; t++) { v[t] = src[row + threadIdx.x + t*256]; sm += v[t]; ss += v[t]*v[t]; }
    blockReduce2(sm, ss, sh);
    float m  = sm * (1.f/HID);
    float rs = rsqrtf(ss * (1.f/HID) - m*m + 1e-5f);
    const float* we = w + (long)e*pES;
    const float* be = bvec + (long)e*pES;
    #pragma unroll
    for (int t = 0; t < 4; t++) {
        int i = threadIdx.x + t*256;
        float rv = (v[t] - m)*rs*we[i] + be[i];
        split1(rv, dh[row + i], dl[row + i]);
    }
}

// ---------------- LayerNorm with kv0 gather (all stages) -> bf16 hi/lo ----------------
__global__ void k_ln_kv(const float* __restrict__ query, const float* __restrict__ img,
                        const float* __restrict__ pp,
                        const float* __restrict__ w, const float* __restrict__ bvec, long pES,
                        u16* __restrict__ dh, u16* __restrict__ dl,
                        const int* __restrict__ se, const int* __restrict__ sb,
                        const int* __restrict__ skvb) {
    int r = blockIdx.x, s = blockIdx.y;
    int e = se[s], b = sb[s];
    // stage resolve: kv offsets 0/320/624, sq 64/48/32, qo 0/64/112, io 0/256/512
    int rl, sq, qo, io;
    if (r < 320)      { rl = r;       sq = 64; qo = 0;   io = 0;   }
    else if (r < 624) { rl = r - 320; sq = 48; qo = 64;  io = 256; }
    else              { rl = r - 624; sq = 32; qo = 112; io = 512; }
    const float* row;
    if (rl < sq) row = query + ((long)e*NQ_ + qo + rl)*HID;
    else {
        int zi = io + rl - sq;
        if (zi < LV_) row = img + ((long)b*LV_ + zi)*HID;
        else          row = pp  + ((long)b*LP_ + zi - LV_)*HID;
    }
    long doff = (long)(skvb[s] + r)*HID;
    __shared__ float sh[64];
    float v[4]; float sm = 0.f, ss = 0.f;
    #pragma unroll
    for (int t = 0; t < 4; t++) { v[t] = row[threadIdx.x + t*256]; sm += v[t]; ss += v[t]*v[t]; }
    blockReduce2(sm, ss, sh);
    float m  = sm * (1.f/HID);
    float rs = rsqrtf(ss * (1.f/HID) - m*m + 1e-5f);
    const float* we = w + (long)e*pES;
    const float* be = bvec + (long)e*pES;
    #pragma unroll
    for (int t = 0; t < 4; t++) {
        int i = threadIdx.x + t*256;
        float rv = (v[t] - m)*rs*we[i] + be[i];
        split1(rv, dh[doff + i], dl[doff + i]);
    }
}

// ---------------- attention (all stages) -> bf16 hi/lo ----------------
__global__ void k_attn(const float* __restrict__ q, const float* __restrict__ kv,
                       u16* __restrict__ ath, u16* __restrict__ atl,
                       const int* __restrict__ sxb, const int* __restrict__ skvb) {
    int s = blockIdx.y, st = blockIdx.z;
    int sq    = (st == 0) ? 64 : (st == 1 ? 48 : 32);
    int qo    = (st == 0) ? 0  : (st == 1 ? 64 : 112);
    int kvo   = (st == 0) ? 0  : (st == 1 ? 320 : 624);
    int kvlen = sq + 256;
    int warp = threadIdx.x >> 5, lane = threadIdx.x & 31;
    int w = blockIdx.x * 4 + warp;
    if (w >= NHEADS * sq) return;
    int h = w / sq, qi = w % sq;
    __shared__ float sc[4][320];

    long qrow  = (long)sxb[s] + qo + qi;
    long kvrow = (long)skvb[s] + kvo;
    const float* qr = q + qrow*HID + h*HDIM;
    float q0 = qr[lane], q1 = qr[lane + 32];
    const float* kbase = kv + kvrow*2048 + h*HDIM;
    float mx = -1e30f;
    for (int j = 0; j < kvlen; j++) {
        const float* kr = kbase + (long)j*2048;
        float p = q0*kr[lane] + q1*kr[lane + 32];
        #pragma unroll
        for (int o = 16; o; o >>= 1) p += __shfl_xor_sync(~0u, p, o);
        p *= 0.125f;
        if (lane == 0) sc[warp][j] = p;
        mx = fmaxf(mx, p);
    }
    __syncwarp();
    float se_ = 0.f;
    for (int j = lane; j < kvlen; j += 32) {
        float ex = __expf(sc[warp][j] - mx);
        sc[warp][j] = ex;
        se_ += ex;
    }
    #pragma unroll
    for (int o = 16; o; o >>= 1) se_ += __shfl_xor_sync(~0u, se_, o);
    __syncwarp();
    float inv = 1.f / se_;
    const float* vbase = kv + kvrow*2048 + 1024 + h*HDIM;
    float a0 = 0.f, a1 = 0.f;
    for (int j = 0; j < kvlen; j++) {
        float p = sc[warp][j];
        const float* vr = vbase + (long)j*2048;
        a0 += p*vr[lane]; a1 += p*vr[lane + 32];
    }
    long ooff = qrow*HID + h*HDIM;
    split1(a0 * inv, ath[ooff + lane],      atl[ooff + lane]);
    split1(a1 * inv, ath[ooff + lane + 32], atl[ooff + lane + 32]);
}

// ---------------- gate-scaled split of final x -> bf16 hi/lo ----------------
__global__ void k_gsplit(const float* __restrict__ gx,
                         u16* __restrict__ dh, u16* __restrict__ dl,
                         const int* __restrict__ sxb, const float* __restrict__ sg) {
    int r = blockIdx.x, s = blockIdx.y;
    float g = sg[s];
    long row = (long)(sxb[s] + r)*HID;
    for (int i = threadIdx.x; i < HID; i += blockDim.x)
        split1(g * gx[row + i], dh[row + i], dl[row + i]);
}

// ---------------- combine 2 slots per batch + gated bias + RMS + final scaling ----------------
__global__ void k_rms_combine(const float* __restrict__ O, const float* __restrict__ bo,
                              float* __restrict__ out, const float* __restrict__ fw,
                              const float* __restrict__ gain,
                              const int* __restrict__ b2s, const int* __restrict__ se,
                              const float* __restrict__ sg, const int* __restrict__ sxb) {
    int qrow = blockIdx.x, b = blockIdx.y;
    int s0 = b2s[b*2], s1 = b2s[b*2 + 1];
    int e0 = se[s0], e1 = se[s1];
    float g0 = sg[s0], g1 = sg[s1];
    long r0 = (long)(sxb[s0] + qrow)*OUTD;
    long r1 = (long)(sxb[s1] + qrow)*OUTD;
    const float* bo0 = bo + (long)e0*OUTD;
    const float* bo1 = bo + (long)e1*OUTD;
    float* orow = out + ((long)b*NQ_ + qrow)*OUTD;
    __shared__ float sh[64];
    float v[16]; float ss = 0.f;
    #pragma unroll
    for (int t = 0; t < 16; t++) {
        int o = threadIdx.x + t*256;
        float val = O[r0 + o] + O[r1 + o] + g0*bo0[o] + g1*bo1[o];
        v[t] = val; ss += val*val;
    }
    ss = blockReduce1(ss, sh);
    float sc = rsqrtf(ss * (1.f/OUTD) + 1e-6f);
    #pragma unroll
    for (int t = 0; t < 16; t++) {
        int o = threadIdx.x + t*256;
        orow[o] = v[t]*sc*fw[o]*gain[o];
    }
}

// ---------------- host orchestration ----------------
extern "C" void kernel_launch(void* const* d_in, const int* in_sizes, int n_in,
                              void* d_out, int out_size) {
    const float* image     = (const float*)d_in[0];
    const float* pp        = (const float*)d_in[1];
    const int*   tids      = (const int*)  d_in[2];
    const int*   eids      = (const int*)  d_in[3];
    const float* query     = (const float*)d_in[4];
    const float* ln1_w     = (const float*)d_in[5];
    const float* ln1_b     = (const float*)d_in[6];
    const float* ln1kv_w   = (const float*)d_in[7];
    const float* ln1kv_b   = (const float*)d_in[8];
    const float* attn_in_w = (const float*)d_in[9];
    const float* attn_in_b = (const float*)d_in[10];
    const float* attn_out_w= (const float*)d_in[11];
    const float* attn_out_b= (const float*)d_in[12];
    const float* ls1       = (const float*)d_in[13];
    const float* ls2       = (const float*)d_in[14];
    const float* ln2_w     = (const float*)d_in[15];
    const float* ln2_b     = (const float*)d_in[16];
    const float* fc_w      = (const float*)d_in[17];
    const float* fc_b      = (const float*)d_in[18];
    const float* proj_w    = (const float*)d_in[19];
    const float* proj_b    = (const float*)d_in[20];
    const float* outp_w    = (const float*)d_in[21];
    const float* outp_b    = (const float*)d_in[22];
    const float* temb      = (const float*)d_in[23];
    const float* eemb      = (const float*)d_in[24];
    const float* glw       = (const float*)d_in[25];
    const float* glb       = (const float*)d_in[26];
    const float* gwt       = (const float*)d_in[27];
    const float* gbias     = (const float*)d_in[28];
    const float* gain      = (const float*)d_in[29];
    const float* fw        = (const float*)d_in[30];
    float* out = (float*)d_out;

    float *px, *pq, *pkv, *po, *pg, *pgi, *psg;
    int *pcnt, *psoff, *pse, *psb, *pxseg, *pkvseg, *pxval, *pkvval, *psxb, *pskvb, *pb2s;
    cudaGetSymbolAddress((void**)&px,    g_x);
    cudaGetSymbolAddress((void**)&pq,    g_q);
    cudaGetSymbolAddress((void**)&pkv,   g_kv);
    cudaGetSymbolAddress((void**)&po,    g_o);
    cudaGetSymbolAddress((void**)&pg,    g_gates);
    cudaGetSymbolAddress((void**)&pgi,   g_gi);
    cudaGetSymbolAddress((void**)&pcnt,  g_cnt);
    cudaGetSymbolAddress((void**)&psoff, g_soff);
    cudaGetSymbolAddress((void**)&pse,   g_se);
    cudaGetSymbolAddress((void**)&psb,   g_sb);
    cudaGetSymbolAddress((void**)&psg,   g_sg);
    cudaGetSymbolAddress((void**)&pxseg, g_xseg);
    cudaGetSymbolAddress((void**)&pkvseg,g_kvseg);
    cudaGetSymbolAddress((void**)&pxval, g_xvalid);
    cudaGetSymbolAddress((void**)&pkvval,g_kvvalid);
    cudaGetSymbolAddress((void**)&psxb,  g_sxb);
    cudaGetSymbolAddress((void**)&pskvb, g_skvb);
    cudaGetSymbolAddress((void**)&pb2s,  g_b2s);

    u16 *xh, *xl, *kh, *kl, *ah, *al, *fh, *fl;
    cudaGetSymbolAddress((void**)&xh, g_xln_h); cudaGetSymbolAddress((void**)&xl, g_xln_l);
    cudaGetSymbolAddress((void**)&kh, g_kvn_h); cudaGetSymbolAddress((void**)&kl, g_kvn_l);
    cudaGetSymbolAddress((void**)&ah, g_att_h); cudaGetSymbolAddress((void**)&al, g_att_l);
    cudaGetSymbolAddress((void**)&fh, g_ffn_h); cudaGetSymbolAddress((void**)&fl, g_ffn_l);

    u16 *aiwh, *aiwl, *aowh, *aowl, *fcwh, *fcwl, *pjwh, *pjwl, *opwh, *opwl;
    cudaGetSymbolAddress((void**)&aiwh, g_aiw_h); cudaGetSymbolAddress((void**)&aiwl, g_aiw_l);
    cudaGetSymbolAddress((void**)&aowh, g_aow_h); cudaGetSymbolAddress((void**)&aowl, g_aow_l);
    cudaGetSymbolAddress((void**)&fcwh, g_fcw_h); cudaGetSymbolAddress((void**)&fcwl, g_fcw_l);
    cudaGetSymbolAddress((void**)&pjwh, g_pjw_h); cudaGetSymbolAddress((void**)&pjwl, g_pjw_l);
    cudaGetSymbolAddress((void**)&opwh, g_opw_h); cudaGetSymbolAddress((void**)&opwl, g_opw_l);

    k_split4<<<4096, 256>>>((const float4*)attn_in_w,  (uint2*)aiwh, (uint2*)aiwl, AIW_N/4);
    k_split4<<<4096, 256>>>((const float4*)attn_out_w, (uint2*)aowh, (uint2*)aowl, AOW_N/4);
    k_split4<<<4096, 256>>>((const float4*)fc_w,       (uint2*)fcwh, (uint2*)fcwl, FCW_N/4);
    k_split4<<<4096, 256>>>((const float4*)proj_w,     (uint2*)pjwh, (uint2*)pjwl, PJW_N/4);
    k_split4<<<4096, 256>>>((const float4*)outp_w,     (uint2*)opwh, (uint2*)opwl, OPW_N/4);

    k_gate_mean<<<BATCH, 256>>>(image, pgi);
    k_gate<<<BATCH, 256>>>(pgi, temb, eemb, tids, eids, glw, glb, gwt, gbias, pg);
    k_slots<<<1, 32>>>(pg, pcnt, psoff, pse, psb, psg,
                       pxseg, pkvseg, pxval, pkvval, psxb, pskvb, pb2s);

    k_initx<<<dim3(NQ_, NSLOT), 256>>>(query, px, pse, psxb);

    const long HH = (long)HID*HID;
    const int XMB = 22;    // ceil((16*144 + 4*127)/128)
    const int KVMB = 118;  // ceil((16*912 + 4*127)/128)

    for (int l = 0; l < NLAYERS; l++) {
        k_ln_kv<<<dim3(KVR, NSLOT), 256>>>(query, image, pp,
            ln1kv_w + (long)l*HID, ln1kv_b + (long)l*HID, (long)NLAYERS*HID,
            kh, kl, pse, psb, pskvb);
        k_ln<<<dim3(NQ_, NSLOT), 256>>>(px,
            ln1_w + (long)l*HID, ln1_b + (long)l*HID, (long)NLAYERS*HID,
            xh, xl, pse, psxb);
        // Q projection (all stages)
        k_tgemm<<<dim3(8, XMB), 256>>>(HID, HID,
            xh, xl, aiwh + (long)l*3*HH, aiwl + (long)l*3*HH, (long)NLAYERS*3*HH,
            attn_in_b + (long)l*3*HID, (long)NLAYERS*3*HID,
            pq, (u16*)0, (u16*)0, (const float*)0, 0, 0, pxseg, pxval);
        // fused K,V projection (all stages)
        k_tgemm<<<dim3(16, KVMB), 256>>>(2048, HID,
            kh, kl, aiwh + (long)l*3*HH + HH, aiwl + (long)l*3*HH + HH, (long)NLAYERS*3*HH,
            attn_in_b + (long)l*3*HID + HID, (long)NLAYERS*3*HID,
            pkv, (u16*)0, (u16*)0, (const float*)0, 0, 0, pkvseg, pkvval);
        // attention (all stages)
        k_attn<<<dim3(256, NSLOT, 3), 128>>>(pq, pkv, ah, al, psxb, pskvb);
        // attn-out projection + residual
        k_tgemm<<<dim3(8, XMB), 256>>>(HID, HID,
            ah, al, aowh + (long)l*HH, aowl + (long)l*HH, (long)NLAYERS*HH,
            attn_out_b + (long)l*HID, (long)NLAYERS*HID,
            px, (u16*)0, (u16*)0, ls1 + (long)l*HID, (long)NLAYERS*HID, 2, pxseg, pxval);
        // MLP
        k_ln<<<dim3(NQ_, NSLOT), 256>>>(px,
            ln2_w + (long)l*HID, ln2_b + (long)l*HID, (long)NLAYERS*HID,
            xh, xl, pse, psxb);
        k_tgemm<<<dim3(32, XMB), 256>>>(4*HID, HID,
            xh, xl, fcwh + (long)l*4*HH, fcwl + (long)l*4*HH, (long)NLAYERS*4*HH,
            fc_b + (long)l*4*HID, (long)NLAYERS*4*HID,
            (float*)0, fh, fl, (const float*)0, 0, 1, pxseg, pxval);
        k_tgemm<<<dim3(8, XMB), 256>>>(HID, 4*HID,
            fh, fl, pjwh + (long)l*4*HH, pjwl + (long)l*4*HH, (long)NLAYERS*4*HH,
            proj_b + (long)l*HID, (long)NLAYERS*HID,
            px, (u16*)0, (u16*)0, ls2 + (long)l*HID, (long)NLAYERS*HID, 2, pxseg, pxval);
    }

    // final projection: gate-scaled x -> per-slot O, then combine + RMS
    k_gsplit<<<dim3(NQ_, NSLOT), 256>>>(px, xh, xl, psxb, psg);
    k_tgemm<<<dim3(OUTD/128, XMB), 256>>>(OUTD, HID,
        xh, xl, opwh, opwl, (long)OUTD*HID,
        (const float*)0, 0,
        po, (u16*)0, (u16*)0, (const float*)0, 0, 3, pxseg, pxval);
    k_rms_combine<<<dim3(NQ_, BATCH), 256>>>(po, outp_b, out, fw, gain, pb2s, pse, psg, psxb);
}

// round 8
// speedup vs baseline: 3.2232x; 1.2379x over previous
#include <cuda_runtime.h>
#include <cuda_bf16.h>
#include <math.h>
#include <stdint.h>

typedef unsigned short u16;

// ---------------- problem constants ----------------
#define EXP    4
#define BATCH  8
#define NQ_    144
#define NLAYERS 2
#define NHEADS 16
#define HDIM   64
#define HID    1024
#define OUTD   4096
#define TDIM   256
#define LV_    576
#define LP_    192
#define NSLOT  16
#define GN     (HID + 2*TDIM)   // 1536
#define KVR    912              // 320+304+288 kv rows per slot
#define XROWS  3072
#define KVROWS 16384

// ---------------- fp32 scratch ----------------
__device__ float g_x   [XROWS*HID];
__device__ float g_q   [XROWS*HID];
__device__ float g_kv  [KVROWS*2048];       // K | V
__device__ float g_o   [XROWS*OUTD];
__device__ float g_gates[BATCH*EXP];
__device__ float g_gi  [BATCH*HID];

// slot metadata
__device__ int   g_cnt[EXP], g_soff[EXP];
__device__ int   g_se[NSLOT], g_sb[NSLOT];
__device__ float g_sg[NSLOT];
__device__ int   g_xseg[EXP+1], g_kvseg[EXP+1];
__device__ int   g_xvalid[EXP], g_kvvalid[EXP];
__device__ int   g_sxb[NSLOT], g_skvb[NSLOT];
__device__ int   g_b2s[BATCH*2];

// ---------------- bf16 hi/lo activation scratch ----------------
__device__ u16 g_xln_h[XROWS*HID],  g_xln_l[XROWS*HID];
__device__ u16 g_kvn_h[KVROWS*HID], g_kvn_l[KVROWS*HID];
__device__ u16 g_att_h[XROWS*HID],  g_att_l[XROWS*HID];
__device__ u16 g_ffn_h[XROWS*4096], g_ffn_l[XROWS*4096];

// ---------------- bf16 hi/lo weight scratch ----------------
#define AIW_N (EXP*NLAYERS*3*HID*HID)
#define AOW_N (EXP*NLAYERS*HID*HID)
#define FCW_N (EXP*NLAYERS*4*HID*HID)
#define PJW_N (EXP*NLAYERS*HID*4*HID)
#define OPW_N (EXP*OUTD*HID)
__device__ u16 g_aiw_h[AIW_N], g_aiw_l[AIW_N];
__device__ u16 g_aow_h[AOW_N], g_aow_l[AOW_N];
__device__ u16 g_fcw_h[FCW_N], g_fcw_l[FCW_N];
__device__ u16 g_pjw_h[PJW_N], g_pjw_l[PJW_N];
__device__ u16 g_opw_h[OPW_N], g_opw_l[OPW_N];

// ================= helpers =================
__device__ __forceinline__ void mma16816(float* c, const uint32_t* a, const uint32_t* b) {
    asm volatile("mma.sync.aligned.m16n8k16.row.col.f32.bf16.bf16.f32 "
        "{%0,%1,%2,%3}, {%4,%5,%6,%7}, {%8,%9}, {%0,%1,%2,%3};"
        : "+f"(c[0]), "+f"(c[1]), "+f"(c[2]), "+f"(c[3])
        : "r"(a[0]), "r"(a[1]), "r"(a[2]), "r"(a[3]), "r"(b[0]), "r"(b[1]));
}
__device__ __forceinline__ uint32_t pack2(__nv_bfloat16 a, __nv_bfloat16 b) {
    return (uint32_t)__bfloat16_as_ushort(a) | ((uint32_t)__bfloat16_as_ushort(b) << 16);
}
__device__ __forceinline__ void split4(float4 v, uint2& h, uint2& l) {
    __nv_bfloat16 h0 = __float2bfloat16(v.x), h1 = __float2bfloat16(v.y);
    __nv_bfloat16 h2 = __float2bfloat16(v.z), h3 = __float2bfloat16(v.w);
    __nv_bfloat16 l0 = __float2bfloat16(v.x - __bfloat162float(h0));
    __nv_bfloat16 l1 = __float2bfloat16(v.y - __bfloat162float(h1));
    __nv_bfloat16 l2 = __float2bfloat16(v.z - __bfloat162float(h2));
    __nv_bfloat16 l3 = __float2bfloat16(v.w - __bfloat162float(h3));
    h = make_uint2(pack2(h0, h1), pack2(h2, h3));
    l = make_uint2(pack2(l0, l1), pack2(l2, l3));
}
__device__ __forceinline__ void split1(float v, u16& h, u16& l) {
    __nv_bfloat16 hh = __float2bfloat16(v);
    h = __bfloat16_as_ushort(hh);
    l = __bfloat16_as_ushort(__float2bfloat16(v - __bfloat162float(hh)));
}
__device__ __forceinline__ uint32_t smem_u32(const void* p) {
    uint32_t a;
    asm("{ .reg .u64 t; cvta.to.shared.u64 t, %1; cvt.u32.u64 %0, t; }" : "=r"(a) : "l"(p));
    return a;
}
#define CP16(dst, src) asm volatile("cp.async.cg.shared.global [%0], [%1], 16;" :: "r"(dst), "l"(src) : "memory")
#define CPCOMMIT() asm volatile("cp.async.commit_group;" ::: "memory")
#define CPWAIT0()  asm volatile("cp.async.wait_group 0;" ::: "memory")

// ---------------- merged weight pre-split (single launch) ----------------
__global__ void k_split_all(const float4* __restrict__ s0, uint2* __restrict__ h0, uint2* __restrict__ l0,
                            const float4* __restrict__ s1, uint2* __restrict__ h1, uint2* __restrict__ l1,
                            const float4* __restrict__ s2, uint2* __restrict__ h2, uint2* __restrict__ l2,
                            const float4* __restrict__ s3, uint2* __restrict__ h3, uint2* __restrict__ l3,
                            const float4* __restrict__ s4, uint2* __restrict__ h4, uint2* __restrict__ l4) {
    const long n0 = AIW_N/4, n1 = AOW_N/4, n2 = FCW_N/4, n3 = PJW_N/4, n4 = OPW_N/4;
    const long total = n0 + n1 + n2 + n3 + n4;
    long stride = (long)gridDim.x * blockDim.x;
    for (long i = (long)blockIdx.x * blockDim.x + threadIdx.x; i < total; i += stride) {
        const float4* s; uint2 *h, *l; long k = i;
        if (k < n0)              { s = s0; h = h0; l = l0; }
        else if ((k -= n0) < n1) { s = s1; h = h1; l = l1; }
        else if ((k -= n1) < n2) { s = s2; h = h2; l = l2; }
        else if ((k -= n2) < n3) { s = s3; h = h3; l = l3; }
        else                     { k -= n3; s = s4; h = h4; l = l4; }
        uint2 hh, ll;
        split4(s[k], hh, ll);
        h[k] = hh; l[k] = ll;
    }
}

#define PITCH 20                       // u32 per row: 16 data + 4 pad (16B-aligned rows)
#define ARR_U32 (128*PITCH)            // 2560 u32 per array
#define BUF_U32 (4*ARR_U32)            // 10240 u32 per stage
#define TG_DSMEM (2*BUF_U32*4)         // 81920 bytes

// ================= tensor GEMM (compact rows): C = A @ W_e^T =================
// cp.async 2-stage pipeline, one barrier per 32-K chunk.
// epi 0: C=acc+bias. epi 1: split(gelu(acc+bias))->Chi/Clo. epi 2: C += ls*(acc+bias). epi 3: C=acc.
__global__ __launch_bounds__(256, 2) void k_tgemm(
    int N, int K,
    const u16* __restrict__ Ah, const u16* __restrict__ Al,
    const u16* __restrict__ Wh, const u16* __restrict__ Wl, long wES,
    const float* __restrict__ biasB, long bES,
    float* __restrict__ C, u16* __restrict__ Chi, u16* __restrict__ Clo,
    const float* __restrict__ lsB, long lsES,
    int epi, const int* __restrict__ segbase, const int* __restrict__ valid)
{
    int m0 = blockIdx.y * 128;
    int n0 = blockIdx.x * 128;
    int e = -1, base = 0;
    #pragma unroll
    for (int i = 0; i < EXP; ++i)
        if (e < 0 && m0 >= segbase[i] && m0 < segbase[i+1]) { e = i; base = segbase[i]; }
    if (e < 0) return;
    int vrows = valid[e];

    extern __shared__ uint32_t SM[];   // [2][4][128][PITCH]
    uint32_t smb = smem_u32(SM);

    int tid = threadIdx.x;
    int warp = tid >> 5, lane = tid & 31;
    int wm = warp & 3, wn = warp >> 2;
    int g8 = lane >> 2, tg = lane & 3;

    const u16* WhE = Wh + (long)e * wES;
    const u16* WlE = Wl + (long)e * wES;

    // per-thread cp.async mapping: 2 16B chunks per array
    const u16* src[4][2];
    uint32_t doff[2];
    #pragma unroll
    for (int j = 0; j < 2; ++j) {
        int lin = j * 256 + tid;
        int row = lin >> 2, q = lin & 3;
        doff[j] = (uint32_t)(row * PITCH + q * 4) * 4;   // byte offset within array
        src[0][j] = Ah  + (long)(m0 + row) * K + q * 8;
        src[1][j] = Al  + (long)(m0 + row) * K + q * 8;
        src[2][j] = WhE + (long)(n0 + row) * K + q * 8;
        src[3][j] = WlE + (long)(n0 + row) * K + q * 8;
    }

    float acc[2][8][4] = {};
    int nch = K >> 5;

    // prologue: chunk 0 -> buf 0
    #pragma unroll
    for (int a = 0; a < 4; ++a)
        #pragma unroll
        for (int j = 0; j < 2; ++j)
            CP16(smb + a * (ARR_U32*4) + doff[j], src[a][j]);
    CPCOMMIT();

    for (int c = 0; c < nch; ++c) {
        CPWAIT0();
        __syncthreads();
        if (c + 1 < nch) {
            long koff = (long)(c + 1) * 32;
            uint32_t bb = smb + ((c + 1) & 1) * (BUF_U32*4);
            #pragma unroll
            for (int a = 0; a < 4; ++a)
                #pragma unroll
                for (int j = 0; j < 2; ++j)
                    CP16(bb + a * (ARR_U32*4) + doff[j], src[a][j] + koff);
            CPCOMMIT();
        }
        const uint32_t* B = SM + (c & 1) * BUF_U32;
        const uint32_t* AsH = B;
        const uint32_t* AsL = B + ARR_U32;
        const uint32_t* BsH = B + 2*ARR_U32;
        const uint32_t* BsL = B + 3*ARR_U32;
        #pragma unroll
        for (int kh = 0; kh < 2; ++kh) {
            int kb = kh * 8;
            uint32_t ah[2][4], al[2][4];
            #pragma unroll
            for (int mt = 0; mt < 2; ++mt) {
                int r = wm * 32 + mt * 16 + g8;
                ah[mt][0] = AsH[r*PITCH + kb+tg];       ah[mt][1] = AsH[(r+8)*PITCH + kb+tg];
                ah[mt][2] = AsH[r*PITCH + kb+tg+4];     ah[mt][3] = AsH[(r+8)*PITCH + kb+tg+4];
                al[mt][0] = AsL[r*PITCH + kb+tg];       al[mt][1] = AsL[(r+8)*PITCH + kb+tg];
                al[mt][2] = AsL[r*PITCH + kb+tg+4];     al[mt][3] = AsL[(r+8)*PITCH + kb+tg+4];
            }
            #pragma unroll
            for (int nt = 0; nt < 8; ++nt) {
                int n = wn * 64 + nt * 8 + g8;
                uint32_t bh[2] = { BsH[n*PITCH + kb+tg], BsH[n*PITCH + kb+tg+4] };
                uint32_t bl[2] = { BsL[n*PITCH + kb+tg], BsL[n*PITCH + kb+tg+4] };
                #pragma unroll
                for (int mt = 0; mt < 2; ++mt) {
                    mma16816(acc[mt][nt], ah[mt], bh);
                    mma16816(acc[mt][nt], ah[mt], bl);
                    mma16816(acc[mt][nt], al[mt], bh);
                }
            }
        }
        __syncthreads();
    }

    const float* bias = biasB ? (biasB + (long)e * bES) : (const float*)0;
    const float* ls = lsB ? (lsB + (long)e * lsES) : (const float*)0;
    #pragma unroll
    for (int mt = 0; mt < 2; ++mt) {
        int r0 = m0 + wm * 32 + mt * 16 + g8;
        int r1 = r0 + 8;
        bool ok0 = (r0 - base) < vrows;
        bool ok1 = (r1 - base) < vrows;
        #pragma unroll
        for (int nt = 0; nt < 8; ++nt) {
            int col = n0 + wn * 64 + nt * 8 + tg * 2;
            float* cc = acc[mt][nt];
            #pragma unroll
            for (int q = 0; q < 4; ++q) {
                int row = (q < 2) ? r0 : r1;
                bool ok = (q < 2) ? ok0 : ok1;
                if (!ok) continue;
                int cl = col + (q & 1);
                long idx = (long)row * N + cl;
                if (epi == 3) { C[idx] = cc[q]; continue; }
                float v = cc[q] + bias[cl];
                if (epi == 1) {
                    float gv = 0.5f * v * (1.f + erff(v * 0.70710678118654752f));
                    split1(gv, Chi[idx], Clo[idx]);
                } else if (epi == 2) {
                    C[idx] = C[idx] + ls[cl] * v;
                } else {
                    C[idx] = v;
                }
            }
        }
    }
}

// ---------------- reductions ----------------
__device__ __forceinline__ void blockReduce2(float& a, float& b, float* sh) {
    __syncthreads();
    int lane = threadIdx.x & 31, wid = threadIdx.x >> 5;
    #pragma unroll
    for (int o = 16; o; o >>= 1) { a += __shfl_xor_sync(~0u, a, o); b += __shfl_xor_sync(~0u, b, o); }
    if (lane == 0) { sh[wid] = a; sh[wid + 32] = b; }
    __syncthreads();
    int nw = blockDim.x >> 5;
    if (wid == 0) {
        a = (lane < nw) ? sh[lane] : 0.f;
        b = (lane < nw) ? sh[lane + 32] : 0.f;
        #pragma unroll
        for (int o = 16; o; o >>= 1) { a += __shfl_xor_sync(~0u, a, o); b += __shfl_xor_sync(~0u, b, o); }
        if (lane == 0) { sh[0] = a; sh[32] = b; }
    }
    __syncthreads();
    a = sh[0]; b = sh[32];
}
__device__ __forceinline__ float blockReduce1(float a, float* sh) {
    __syncthreads();
    int lane = threadIdx.x & 31, wid = threadIdx.x >> 5;
    #pragma unroll
    for (int o = 16; o; o >>= 1) a += __shfl_xor_sync(~0u, a, o);
    if (lane == 0) sh[wid] = a;
    __syncthreads();
    int nw = blockDim.x >> 5;
    if (wid == 0) {
        a = (lane < nw) ? sh[lane] : 0.f;
        #pragma unroll
        for (int o = 16; o; o >>= 1) a += __shfl_xor_sync(~0u, a, o);
        if (lane == 0) sh[0] = a;
    }
    __syncthreads();
    return sh[0];
}

// ---------------- gate kernels ----------------
__global__ void k_gate_mean(const float* __restrict__ img, float* __restrict__ gi) {
    int b = blockIdx.x;
    for (int h = threadIdx.x; h < HID; h += blockDim.x) {
        float s = 0.f;
        for (int l = 0; l < LV_; l++) s += img[((long)b*LV_ + l)*HID + h];
        gi[b*HID + h] = s * (1.f/LV_);
    }
}
__global__ void k_gate(const float* __restrict__ gi, const float* __restrict__ temb,
                       const float* __restrict__ eemb, const int* __restrict__ tids,
                       const int* __restrict__ eids, const float* __restrict__ glw,
                       const float* __restrict__ glb, const float* __restrict__ gwt,
                       const float* __restrict__ gbias, float* __restrict__ gates) {
    int b = blockIdx.x, tid = threadIdx.x;
    __shared__ float sh[64];
    __shared__ float logits[EXP];
    int ti = tids[b], ei = eids[b];
    float s = 0.f, ss = 0.f;
    for (int i = tid; i < GN; i += 256) {
        float v = (i < HID) ? gi[b*HID + i]
                : (i < HID + TDIM) ? temb[ti*TDIM + i - HID]
                : eemb[ei*TDIM + i - HID - TDIM];
        s += v; ss += v*v;
    }
    blockReduce2(s, ss, sh);
    float m  = s * (1.f/GN);
    float rs = rsqrtf(ss * (1.f/GN) - m*m + 1e-5f);
    for (int e = 0; e < EXP; e++) {
        float d = 0.f;
        for (int i = tid; i < GN; i += 256) {
            float v = (i < HID) ? gi[b*HID + i]
                    : (i < HID + TDIM) ? temb[ti*TDIM + i - HID]
                    : eemb[ei*TDIM + i - HID - TDIM];
            d += ((v - m)*rs*glw[i] + glb[i]) * gwt[(long)e*GN + i];
        }
        d = blockReduce1(d, sh);
        if (tid == 0) logits[e] = d + gbias[e];
    }
    __syncthreads();
    if (tid == 0) {
        float w[EXP]; float mx = -1e30f;
        for (int e = 0; e < EXP; e++) { float l = fminf(fmaxf(logits[e], -15.f), 15.f); w[e] = l; mx = fmaxf(mx, l); }
        float sum = 0.f;
        for (int e = 0; e < EXP; e++) { w[e] = expf(w[e] - mx); sum += w[e]; }
        for (int e = 0; e < EXP; e++) w[e] /= sum;
        int i0 = 0;
        for (int e = 1; e < EXP; e++) if (w[e] > w[i0]) i0 = e;
        int i1 = -1;
        for (int e = 0; e < EXP; e++) { if (e == i0) continue; if (i1 < 0 || w[e] > w[i1]) i1 = e; }
        float t = w[i0] + w[i1] + 1e-9f;
        for (int e = 0; e < EXP; e++) gates[b*EXP + e] = 0.f;
        gates[b*EXP + i0] = w[i0] / t;
        gates[b*EXP + i1] = w[i1] / t;
    }
}
// build compact slot tables (expert-major), segment bases, per-batch slot map
__global__ void k_slots(const float* __restrict__ gates, int* cnt, int* soff,
                        int* se, int* sb, float* sg,
                        int* xseg, int* kvseg, int* xvalid, int* kvvalid,
                        int* sxb, int* skvb, int* b2s) {
    if (threadIdx.x == 0) {
        int s = 0;
        for (int e = 0; e < EXP; e++) {
            soff[e] = s;
            int c = 0;
            for (int b = 0; b < BATCH; b++) {
                float g = gates[b*EXP + e];
                if (g != 0.f) { se[s] = e; sb[s] = b; sg[s] = g; s++; c++; }
            }
            cnt[e] = c;
        }
        xseg[0] = 0; kvseg[0] = 0;
        for (int e = 0; e < EXP; e++) {
            xvalid[e]  = cnt[e]*NQ_;
            kvvalid[e] = cnt[e]*KVR;
            xseg[e+1]  = xseg[e]  + ((cnt[e]*NQ_ + 127) & ~127);
            kvseg[e+1] = kvseg[e] + ((cnt[e]*KVR + 127) & ~127);
        }
        for (int i = 0; i < NSLOT; i++) {
            int e = se[i];
            sxb[i]  = xseg[e]  + (i - soff[e])*NQ_;
            skvb[i] = kvseg[e] + (i - soff[e])*KVR;
        }
        int fill[BATCH];
        for (int b = 0; b < BATCH; b++) fill[b] = 0;
        for (int i = 0; i < NSLOT; i++) {
            int b = sb[i];
            b2s[b*2 + fill[b]] = i;
            fill[b]++;
        }
    }
}

// ---------------- init x = full query block per slot ----------------
__global__ void k_initx(const float* __restrict__ query, float* __restrict__ gx,
                        const int* __restrict__ se, const int* __restrict__ sxb) {
    int r = blockIdx.x, s = blockIdx.y;
    int e = se[s];
    const float* srow = query + ((long)e*NQ_ + r)*HID;
    float* d = gx + (long)(sxb[s] + r)*HID;
    for (int i = threadIdx.x; i < HID; i += blockDim.x) d[i] = srow[i];
}

// ---------------- LayerNorm (x rows) -> bf16 hi/lo ----------------
__global__ void k_ln(const float* __restrict__ src,
                     const float* __restrict__ w, const float* __restrict__ bvec, long pES,
                     u16* __restrict__ dh, u16* __restrict__ dl,
                     const int* __restrict__ se, const int* __restrict__ sxb) {
    int r = blockIdx.x, s = blockIdx.y;
    int e = se[s];
    long row = (long)(sxb[s] + r)*HID;
    __shared__ float sh[64];
    float v[4]; float sm = 0.f, ss = 0.f;
    #pragma unroll
    for (int t = 0; t < 4; t++) { v[t] = src[row + threadIdx.x + t*256]; sm += v[t]; ss += v[t]*v[t]; }
    blockReduce2(sm, ss, sh);
    float m  = sm * (1.f/HID);
    float rs = rsqrtf(ss * (1.f/HID) - m*m + 1e-5f);
    const float* we = w + (long)e*pES;
    const float* be = bvec + (long)e*pES;
    #pragma unroll
    for (int t = 0; t < 4; t++) {
        int i = threadIdx.x + t*256;
        float rv = (v[t] - m)*rs*we[i] + be[i];
        split1(rv, dh[row + i], dl[row + i]);
    }
}

// ---------------- LayerNorm with kv0 gather (all stages) -> bf16 hi/lo ----------------
__global__ void k_ln_kv(const float* __restrict__ query, const float* __restrict__ img,
                        const float* __restrict__ pp,
                        const float* __restrict__ w, const float* __restrict__ bvec, long pES,
                        u16* __restrict__ dh, u16* __restrict__ dl,
                        const int* __restrict__ se, const int* __restrict__ sb,
                        const int* __restrict__ skvb) {
    int r = blockIdx.x, s = blockIdx.y;
    int e = se[s], b = sb[s];
    int rl, sq, qo, io;
    if (r < 320)      { rl = r;       sq = 64; qo = 0;   io = 0;   }
    else if (r < 624) { rl = r - 320; sq = 48; qo = 64;  io = 256; }
    else              { rl = r - 624; sq = 32; qo = 112; io = 512; }
    const float* row;
    if (rl < sq) row = query + ((long)e*NQ_ + qo + rl)*HID;
    else {
        int zi = io + rl - sq;
        if (zi < LV_) row = img + ((long)b*LV_ + zi)*HID;
        else          row = pp  + ((long)b*LP_ + zi - LV_)*HID;
    }
    long doff = (long)(skvb[s] + r)*HID;
    __shared__ float sh[64];
    float v[4]; float sm = 0.f, ss = 0.f;
    #pragma unroll
    for (int t = 0; t < 4; t++) { v[t] = row[threadIdx.x + t*256]; sm += v[t]; ss += v[t]*v[t]; }
    blockReduce2(sm, ss, sh);
    float m  = sm * (1.f/HID);
    float rs = rsqrtf(ss * (1.f/HID) - m*m + 1e-5f);
    const float* we = w + (long)e*pES;
    const float* be = bvec + (long)e*pES;
    #pragma unroll
    for (int t = 0; t < 4; t++) {
        int i = threadIdx.x + t*256;
        float rv = (v[t] - m)*rs*we[i] + be[i];
        split1(rv, dh[doff + i], dl[doff + i]);
    }
}

// ---------------- attention (all stages, 4-way ILP) -> bf16 hi/lo ----------------
__global__ void k_attn(const float* __restrict__ q, const float* __restrict__ kv,
                       u16* __restrict__ ath, u16* __restrict__ atl,
                       const int* __restrict__ sxb, const int* __restrict__ skvb) {
    int s = blockIdx.y, st = blockIdx.z;
    int sq    = (st == 0) ? 64 : (st == 1 ? 48 : 32);
    int qo    = (st == 0) ? 0  : (st == 1 ? 64 : 112);
    int kvo   = (st == 0) ? 0  : (st == 1 ? 320 : 624);
    int kvlen = sq + 256;
    int warp = threadIdx.x >> 5, lane = threadIdx.x & 31;
    int w = blockIdx.x * 4 + warp;
    if (w >= NHEADS * sq) return;
    int h = w / sq, qi = w % sq;
    __shared__ float sc[4][320];

    long qrow  = (long)sxb[s] + qo + qi;
    long kvrow = (long)skvb[s] + kvo;
    const float* qr = q + qrow*HID + h*HDIM;
    float q0 = qr[lane], q1 = qr[lane + 32];
    const float* kbase = kv + kvrow*2048 + h*HDIM;
    float mx = -1e30f;
    for (int j = 0; j < kvlen; j += 4) {
        const float* k0 = kbase + (long)j*2048;
        const float* k1 = k0 + 2048;
        const float* k2 = k1 + 2048;
        const float* k3 = k2 + 2048;
        float p0 = q0*k0[lane] + q1*k0[lane + 32];
        float p1 = q0*k1[lane] + q1*k1[lane + 32];
        float p2 = q0*k2[lane] + q1*k2[lane + 32];
        float p3 = q0*k3[lane] + q1*k3[lane + 32];
        #pragma unroll
        for (int o = 16; o; o >>= 1) {
            p0 += __shfl_xor_sync(~0u, p0, o);
            p1 += __shfl_xor_sync(~0u, p1, o);
            p2 += __shfl_xor_sync(~0u, p2, o);
            p3 += __shfl_xor_sync(~0u, p3, o);
        }
        p0 *= 0.125f; p1 *= 0.125f; p2 *= 0.125f; p3 *= 0.125f;
        if (lane == 0) {
            sc[warp][j]   = p0; sc[warp][j+1] = p1;
            sc[warp][j+2] = p2; sc[warp][j+3] = p3;
        }
        mx = fmaxf(mx, fmaxf(fmaxf(p0, p1), fmaxf(p2, p3)));
    }
    __syncwarp();
    float se_ = 0.f;
    for (int j = lane; j < kvlen; j += 32) {
        float ex = __expf(sc[warp][j] - mx);
        sc[warp][j] = ex;
        se_ += ex;
    }
    #pragma unroll
    for (int o = 16; o; o >>= 1) se_ += __shfl_xor_sync(~0u, se_, o);
    __syncwarp();
    float inv = 1.f / se_;
    const float* vbase = kv + kvrow*2048 + 1024 + h*HDIM;
    float a0 = 0.f, a1 = 0.f;
    #pragma unroll 4
    for (int j = 0; j < kvlen; j++) {
        float p = sc[warp][j];
        const float* vr = vbase + (long)j*2048;
        a0 += p*vr[lane]; a1 += p*vr[lane + 32];
    }
    long ooff = qrow*HID + h*HDIM;
    split1(a0 * inv, ath[ooff + lane],      atl[ooff + lane]);
    split1(a1 * inv, ath[ooff + lane + 32], atl[ooff + lane + 32]);
}

// ---------------- gate-scaled split of final x -> bf16 hi/lo ----------------
__global__ void k_gsplit(const float* __restrict__ gx,
                         u16* __restrict__ dh, u16* __restrict__ dl,
                         const int* __restrict__ sxb, const float* __restrict__ sg) {
    int r = blockIdx.x, s = blockIdx.y;
    float g = sg[s];
    long row = (long)(sxb[s] + r)*HID;
    for (int i = threadIdx.x; i < HID; i += blockDim.x)
        split1(g * gx[row + i], dh[row + i], dl[row + i]);
}

// ---------------- combine 2 slots per batch + gated bias + RMS + final scaling ----------------
__global__ void k_rms_combine(const float* __restrict__ O, const float* __restrict__ bo,
                              float* __restrict__ out, const float* __restrict__ fw,
                              const float* __restrict__ gain,
                              const int* __restrict__ b2s, const int* __restrict__ se,
                              const float* __restrict__ sg, const int* __restrict__ sxb) {
    int qrow = blockIdx.x, b = blockIdx.y;
    int s0 = b2s[b*2], s1 = b2s[b*2 + 1];
    int e0 = se[s0], e1 = se[s1];
    float g0 = sg[s0], g1 = sg[s1];
    long r0 = (long)(sxb[s0] + qrow)*OUTD;
    long r1 = (long)(sxb[s1] + qrow)*OUTD;
    const float* bo0 = bo + (long)e0*OUTD;
    const float* bo1 = bo + (long)e1*OUTD;
    float* orow = out + ((long)b*NQ_ + qrow)*OUTD;
    __shared__ float sh[64];
    float v[16]; float ss = 0.f;
    #pragma unroll
    for (int t = 0; t < 16; t++) {
        int o = threadIdx.x + t*256;
        float val = O[r0 + o] + O[r1 + o] + g0*bo0[o] + g1*bo1[o];
        v[t] = val; ss += val*val;
    }
    ss = blockReduce1(ss, sh);
    float sc = rsqrtf(ss * (1.f/OUTD) + 1e-6f);
    #pragma unroll
    for (int t = 0; t < 16; t++) {
        int o = threadIdx.x + t*256;
        orow[o] = v[t]*sc*fw[o]*gain[o];
    }
}

// ---------------- host orchestration ----------------
extern "C" void kernel_launch(void* const* d_in, const int* in_sizes, int n_in,
                              void* d_out, int out_size) {
    const float* image     = (const float*)d_in[0];
    const float* pp        = (const float*)d_in[1];
    const int*   tids      = (const int*)  d_in[2];
    const int*   eids      = (const int*)  d_in[3];
    const float* query     = (const float*)d_in[4];
    const float* ln1_w     = (const float*)d_in[5];
    const float* ln1_b     = (const float*)d_in[6];
    const float* ln1kv_w   = (const float*)d_in[7];
    const float* ln1kv_b   = (const float*)d_in[8];
    const float* attn_in_w = (const float*)d_in[9];
    const float* attn_in_b = (const float*)d_in[10];
    const float* attn_out_w= (const float*)d_in[11];
    const float* attn_out_b= (const float*)d_in[12];
    const float* ls1       = (const float*)d_in[13];
    const float* ls2       = (const float*)d_in[14];
    const float* ln2_w     = (const float*)d_in[15];
    const float* ln2_b     = (const float*)d_in[16];
    const float* fc_w      = (const float*)d_in[17];
    const float* fc_b      = (const float*)d_in[18];
    const float* proj_w    = (const float*)d_in[19];
    const float* proj_b    = (const float*)d_in[20];
    const float* outp_w    = (const float*)d_in[21];
    const float* outp_b    = (const float*)d_in[22];
    const float* temb      = (const float*)d_in[23];
    const float* eemb      = (const float*)d_in[24];
    const float* glw       = (const float*)d_in[25];
    const float* glb       = (const float*)d_in[26];
    const float* gwt       = (const float*)d_in[27];
    const float* gbias     = (const float*)d_in[28];
    const float* gain      = (const float*)d_in[29];
    const float* fw        = (const float*)d_in[30];
    float* out = (float*)d_out;

    float *px, *pq, *pkv, *po, *pg, *pgi, *psg;
    int *pcnt, *psoff, *pse, *psb, *pxseg, *pkvseg, *pxval, *pkvval, *psxb, *pskvb, *pb2s;
    cudaGetSymbolAddress((void**)&px,    g_x);
    cudaGetSymbolAddress((void**)&pq,    g_q);
    cudaGetSymbolAddress((void**)&pkv,   g_kv);
    cudaGetSymbolAddress((void**)&po,    g_o);
    cudaGetSymbolAddress((void**)&pg,    g_gates);
    cudaGetSymbolAddress((void**)&pgi,   g_gi);
    cudaGetSymbolAddress((void**)&pcnt,  g_cnt);
    cudaGetSymbolAddress((void**)&psoff, g_soff);
    cudaGetSymbolAddress((void**)&pse,   g_se);
    cudaGetSymbolAddress((void**)&psb,   g_sb);
    cudaGetSymbolAddress((void**)&psg,   g_sg);
    cudaGetSymbolAddress((void**)&pxseg, g_xseg);
    cudaGetSymbolAddress((void**)&pkvseg,g_kvseg);
    cudaGetSymbolAddress((void**)&pxval, g_xvalid);
    cudaGetSymbolAddress((void**)&pkvval,g_kvvalid);
    cudaGetSymbolAddress((void**)&psxb,  g_sxb);
    cudaGetSymbolAddress((void**)&pskvb, g_skvb);
    cudaGetSymbolAddress((void**)&pb2s,  g_b2s);

    u16 *xh, *xl, *kh, *kl, *ah, *al, *fh, *fl;
    cudaGetSymbolAddress((void**)&xh, g_xln_h); cudaGetSymbolAddress((void**)&xl, g_xln_l);
    cudaGetSymbolAddress((void**)&kh, g_kvn_h); cudaGetSymbolAddress((void**)&kl, g_kvn_l);
    cudaGetSymbolAddress((void**)&ah, g_att_h); cudaGetSymbolAddress((void**)&al, g_att_l);
    cudaGetSymbolAddress((void**)&fh, g_ffn_h); cudaGetSymbolAddress((void**)&fl, g_ffn_l);

    u16 *aiwh, *aiwl, *aowh, *aowl, *fcwh, *fcwl, *pjwh, *pjwl, *opwh, *opwl;
    cudaGetSymbolAddress((void**)&aiwh, g_aiw_h); cudaGetSymbolAddress((void**)&aiwl, g_aiw_l);
    cudaGetSymbolAddress((void**)&aowh, g_aow_h); cudaGetSymbolAddress((void**)&aowl, g_aow_l);
    cudaGetSymbolAddress((void**)&fcwh, g_fcw_h); cudaGetSymbolAddress((void**)&fcwl, g_fcw_l);
    cudaGetSymbolAddress((void**)&pjwh, g_pjw_h); cudaGetSymbolAddress((void**)&pjwl, g_pjw_l);
    cudaGetSymbolAddress((void**)&opwh, g_opw_h); cudaGetSymbolAddress((void**)&opwl, g_opw_l);

    cudaFuncSetAttribute(k_tgemm, cudaFuncAttributeMaxDynamicSharedMemorySize, TG_DSMEM);

    k_split_all<<<2048, 256>>>(
        (const float4*)attn_in_w,  (uint2*)aiwh, (uint2*)aiwl,
        (const float4*)attn_out_w, (uint2*)aowh, (uint2*)aowl,
        (const float4*)fc_w,       (uint2*)fcwh, (uint2*)fcwl,
        (const float4*)proj_w,     (uint2*)pjwh, (uint2*)pjwl,
        (const float4*)outp_w,     (uint2*)opwh, (uint2*)opwl);

    k_gate_mean<<<BATCH, 256>>>(image, pgi);
    k_gate<<<BATCH, 256>>>(pgi, temb, eemb, tids, eids, glw, glb, gwt, gbias, pg);
    k_slots<<<1, 32>>>(pg, pcnt, psoff, pse, psb, psg,
                       pxseg, pkvseg, pxval, pkvval, psxb, pskvb, pb2s);

    k_initx<<<dim3(NQ_, NSLOT), 256>>>(query, px, pse, psxb);

    const long HH = (long)HID*HID;
    const int XMB = 22;
    const int KVMB = 118;

    for (int l = 0; l < NLAYERS; l++) {
        k_ln_kv<<<dim3(KVR, NSLOT), 256>>>(query, image, pp,
            ln1kv_w + (long)l*HID, ln1kv_b + (long)l*HID, (long)NLAYERS*HID,
            kh, kl, pse, psb, pskvb);
        k_ln<<<dim3(NQ_, NSLOT), 256>>>(px,
            ln1_w + (long)l*HID, ln1_b + (long)l*HID, (long)NLAYERS*HID,
            xh, xl, pse, psxb);
        // Q projection (all stages)
        k_tgemm<<<dim3(8, XMB), 256, TG_DSMEM>>>(HID, HID,
            xh, xl, aiwh + (long)l*3*HH, aiwl + (long)l*3*HH, (long)NLAYERS*3*HH,
            attn_in_b + (long)l*3*HID, (long)NLAYERS*3*HID,
            pq, (u16*)0, (u16*)0, (const float*)0, 0, 0, pxseg, pxval);
        // fused K,V projection (all stages)
        k_tgemm<<<dim3(16, KVMB), 256, TG_DSMEM>>>(2048, HID,
            kh, kl, aiwh + (long)l*3*HH + HH, aiwl + (long)l*3*HH + HH, (long)NLAYERS*3*HH,
            attn_in_b + (long)l*3*HID + HID, (long)NLAYERS*3*HID,
            pkv, (u16*)0, (u16*)0, (const float*)0, 0, 0, pkvseg, pkvval);
        // attention (all stages)
        k_attn<<<dim3(256, NSLOT, 3), 128>>>(pq, pkv, ah, al, psxb, pskvb);
        // attn-out projection + residual
        k_tgemm<<<dim3(8, XMB), 256, TG_DSMEM>>>(HID, HID,
            ah, al, aowh + (long)l*HH, aowl + (long)l*HH, (long)NLAYERS*HH,
            attn_out_b + (long)l*HID, (long)NLAYERS*HID,
            px, (u16*)0, (u16*)0, ls1 + (long)l*HID, (long)NLAYERS*HID, 2, pxseg, pxval);
        // MLP
        k_ln<<<dim3(NQ_, NSLOT), 256>>>(px,
            ln2_w + (long)l*HID, ln2_b + (long)l*HID, (long)NLAYERS*HID,
            xh, xl, pse, psxb);
        k_tgemm<<<dim3(32, XMB), 256, TG_DSMEM>>>(4*HID, HID,
            xh, xl, fcwh + (long)l*4*HH, fcwl + (long)l*4*HH, (long)NLAYERS*4*HH,
            fc_b + (long)l*4*HID, (long)NLAYERS*4*HID,
            (float*)0, fh, fl, (const float*)0, 0, 1, pxseg, pxval);
        k_tgemm<<<dim3(8, XMB), 256, TG_DSMEM>>>(HID, 4*HID,
            fh, fl, pjwh + (long)l*4*HH, pjwl + (long)l*4*HH, (long)NLAYERS*4*HH,
            proj_b + (long)l*HID, (long)NLAYERS*HID,
            px, (u16*)0, (u16*)0, ls2 + (long)l*HID, (long)NLAYERS*HID, 2, pxseg, pxval);
    }

    // final projection: gate-scaled x -> per-slot O, then combine + RMS
    k_gsplit<<<dim3(NQ_, NSLOT), 256>>>(px, xh, xl, psxb, psg);
    k_tgemm<<<dim3(OUTD/128, XMB), 256, TG_DSMEM>>>(OUTD, HID,
        xh, xl, opwh, opwl, (long)OUTD*HID,
        (const float*)0, 0,
        po, (u16*)0, (u16*)0, (const float*)0, 0, 3, pxseg, pxval);
    k_rms_combine<<<dim3(NQ_, BATCH), 256>>>(po, outp_b, out, fw, gain, pb2s, pse, psg, psxb);
}

// round 9
// speedup vs baseline: 3.3322x; 1.0338x over previous
#include <cuda_runtime.h>
#include <cuda_bf16.h>
#include <math.h>
#include <stdint.h>

typedef unsigned short u16;

// ---------------- problem constants ----------------
#define EXP    4
#define BATCH  8
#define NQ_    144
#define NLAYERS 2
#define NHEADS 16
#define HDIM   64
#define HID    1024
#define OUTD   4096
#define TDIM   256
#define LV_    576
#define LP_    192
#define NSLOT  16
#define GN     (HID + 2*TDIM)   // 1536
#define KVR    912              // 320+304+288 kv rows per slot
#define XROWS  3072
#define KVROWS 16384

// ---------------- fp32 scratch ----------------
__device__ float g_x   [XROWS*HID];
__device__ float g_q   [XROWS*HID];
__device__ float g_kv  [KVROWS*2048];       // K | V
__device__ float g_o   [XROWS*OUTD];
__device__ float g_gates[BATCH*EXP];
__device__ float g_gi  [BATCH*HID];

// slot metadata
__device__ int   g_cnt[EXP], g_soff[EXP];
__device__ int   g_se[NSLOT], g_sb[NSLOT];
__device__ float g_sg[NSLOT];
__device__ int   g_xseg[EXP+1], g_kvseg[EXP+1];
__device__ int   g_xvalid[EXP], g_kvvalid[EXP];
__device__ int   g_sxb[NSLOT], g_skvb[NSLOT];
__device__ int   g_b2s[BATCH*2];

// ---------------- bf16 hi/lo activation scratch ----------------
__device__ u16 g_xln_h[XROWS*HID],  g_xln_l[XROWS*HID];
__device__ u16 g_kvn_h[KVROWS*HID], g_kvn_l[KVROWS*HID];
__device__ u16 g_att_h[XROWS*HID],  g_att_l[XROWS*HID];
__device__ u16 g_ffn_h[XROWS*4096], g_ffn_l[XROWS*4096];

// ---------------- bf16 hi/lo weight scratch ----------------
#define AIW_N (EXP*NLAYERS*3*HID*HID)
#define AOW_N (EXP*NLAYERS*HID*HID)
#define FCW_N (EXP*NLAYERS*4*HID*HID)
#define PJW_N (EXP*NLAYERS*HID*4*HID)
#define OPW_N (EXP*OUTD*HID)
__device__ u16 g_aiw_h[AIW_N], g_aiw_l[AIW_N];
__device__ u16 g_aow_h[AOW_N], g_aow_l[AOW_N];
__device__ u16 g_fcw_h[FCW_N], g_fcw_l[FCW_N];
__device__ u16 g_pjw_h[PJW_N], g_pjw_l[PJW_N];
__device__ u16 g_opw_h[OPW_N], g_opw_l[OPW_N];

// ================= helpers =================
__device__ __forceinline__ void mma16816(float* c, const uint32_t* a, const uint32_t* b) {
    asm volatile("mma.sync.aligned.m16n8k16.row.col.f32.bf16.bf16.f32 "
        "{%0,%1,%2,%3}, {%4,%5,%6,%7}, {%8,%9}, {%0,%1,%2,%3};"
        : "+f"(c[0]), "+f"(c[1]), "+f"(c[2]), "+f"(c[3])
        : "r"(a[0]), "r"(a[1]), "r"(a[2]), "r"(a[3]), "r"(b[0]), "r"(b[1]));
}
__device__ __forceinline__ uint32_t pack2(__nv_bfloat16 a, __nv_bfloat16 b) {
    return (uint32_t)__bfloat16_as_ushort(a) | ((uint32_t)__bfloat16_as_ushort(b) << 16);
}
__device__ __forceinline__ void split4(float4 v, uint2& h, uint2& l) {
    __nv_bfloat16 h0 = __float2bfloat16(v.x), h1 = __float2bfloat16(v.y);
    __nv_bfloat16 h2 = __float2bfloat16(v.z), h3 = __float2bfloat16(v.w);
    __nv_bfloat16 l0 = __float2bfloat16(v.x - __bfloat162float(h0));
    __nv_bfloat16 l1 = __float2bfloat16(v.y - __bfloat162float(h1));
    __nv_bfloat16 l2 = __float2bfloat16(v.z - __bfloat162float(h2));
    __nv_bfloat16 l3 = __float2bfloat16(v.w - __bfloat162float(h3));
    h = make_uint2(pack2(h0, h1), pack2(h2, h3));
    l = make_uint2(pack2(l0, l1), pack2(l2, l3));
}
__device__ __forceinline__ void split1(float v, u16& h, u16& l) {
    __nv_bfloat16 hh = __float2bfloat16(v);
    h = __bfloat16_as_ushort(hh);
    l = __bfloat16_as_ushort(__float2bfloat16(v - __bfloat162float(hh)));
}
__device__ __forceinline__ uint32_t smem_u32(const void* p) {
    uint32_t a;
    asm("{ .reg .u64 t; cvta.to.shared.u64 t, %1; cvt.u32.u64 %0, t; }" : "=r"(a) : "l"(p));
    return a;
}
#define CP16(dst, src) asm volatile("cp.async.cg.shared.global [%0], [%1], 16;" :: "r"(dst), "l"(src) : "memory")
#define CPCOMMIT() asm volatile("cp.async.commit_group;" ::: "memory")
#define CPWAIT0()  asm volatile("cp.async.wait_group 0;" ::: "memory")

// ---------------- merged weight pre-split (single launch) ----------------
__global__ void k_split_all(const float4* __restrict__ s0, uint2* __restrict__ h0, uint2* __restrict__ l0,
                            const float4* __restrict__ s1, uint2* __restrict__ h1, uint2* __restrict__ l1,
                            const float4* __restrict__ s2, uint2* __restrict__ h2, uint2* __restrict__ l2,
                            const float4* __restrict__ s3, uint2* __restrict__ h3, uint2* __restrict__ l3,
                            const float4* __restrict__ s4, uint2* __restrict__ h4, uint2* __restrict__ l4) {
    const long n0 = AIW_N/4, n1 = AOW_N/4, n2 = FCW_N/4, n3 = PJW_N/4, n4 = OPW_N/4;
    const long total = n0 + n1 + n2 + n3 + n4;
    long stride = (long)gridDim.x * blockDim.x;
    for (long i = (long)blockIdx.x * blockDim.x + threadIdx.x; i < total; i += stride) {
        const float4* s; uint2 *h, *l; long k = i;
        if (k < n0)              { s = s0; h = h0; l = l0; }
        else if ((k -= n0) < n1) { s = s1; h = h1; l = l1; }
        else if ((k -= n1) < n2) { s = s2; h = h2; l = l2; }
        else if ((k -= n2) < n3) { s = s3; h = h3; l = l3; }
        else                     { k -= n3; s = s4; h = h4; l = l4; }
        uint2 hh, ll;
        split4(s[k], hh, ll);
        h[k] = hh; l[k] = ll;
    }
}

#define PITCH 20
#define ARR_U32 (128*PITCH)
#define BUF_U32 (4*ARR_U32)
#define TG_DSMEM (2*BUF_U32*4)   // 81920 bytes

// ================= GEMM body (device fn): C(block m0,n0) = A @ W^T =================
__device__ __forceinline__ void tgemm_body(
    int N, int K, int m0, int n0, int base, int vrows,
    const u16* __restrict__ Ah, const u16* __restrict__ Al,
    const u16* __restrict__ WhE, const u16* __restrict__ WlE,
    const float* __restrict__ bias,
    float* __restrict__ C, u16* __restrict__ Chi, u16* __restrict__ Clo,
    const float* __restrict__ ls, int epi, uint32_t* SM)
{
    uint32_t smb = smem_u32(SM);
    int tid = threadIdx.x;
    int warp = tid >> 5, lane = tid & 31;
    int wm = warp & 3, wn = warp >> 2;
    int g8 = lane >> 2, tg = lane & 3;

    const u16* src[4][2];
    uint32_t doff[2];
    #pragma unroll
    for (int j = 0; j < 2; ++j) {
        int lin = j * 256 + tid;
        int row = lin >> 2, q = lin & 3;
        doff[j] = (uint32_t)(row * PITCH + q * 4) * 4;
        src[0][j] = Ah  + (long)(m0 + row) * K + q * 8;
        src[1][j] = Al  + (long)(m0 + row) * K + q * 8;
        src[2][j] = WhE + (long)(n0 + row) * K + q * 8;
        src[3][j] = WlE + (long)(n0 + row) * K + q * 8;
    }

    float acc[2][8][4] = {};
    int nch = K >> 5;

    #pragma unroll
    for (int a = 0; a < 4; ++a)
        #pragma unroll
        for (int j = 0; j < 2; ++j)
            CP16(smb + a * (ARR_U32*4) + doff[j], src[a][j]);
    CPCOMMIT();

    for (int c = 0; c < nch; ++c) {
        CPWAIT0();
        __syncthreads();
        if (c + 1 < nch) {
            long koff = (long)(c + 1) * 32;
            uint32_t bb = smb + ((c + 1) & 1) * (BUF_U32*4);
            #pragma unroll
            for (int a = 0; a < 4; ++a)
                #pragma unroll
                for (int j = 0; j < 2; ++j)
                    CP16(bb + a * (ARR_U32*4) + doff[j], src[a][j] + koff);
            CPCOMMIT();
        }
        const uint32_t* B = SM + (c & 1) * BUF_U32;
        const uint32_t* AsH = B;
        const uint32_t* AsL = B + ARR_U32;
        const uint32_t* BsH = B + 2*ARR_U32;
        const uint32_t* BsL = B + 3*ARR_U32;
        #pragma unroll
        for (int kh = 0; kh < 2; ++kh) {
            int kb = kh * 8;
            uint32_t ah[2][4], al[2][4];
            #pragma unroll
            for (int mt = 0; mt < 2; ++mt) {
                int r = wm * 32 + mt * 16 + g8;
                ah[mt][0] = AsH[r*PITCH + kb+tg];       ah[mt][1] = AsH[(r+8)*PITCH + kb+tg];
                ah[mt][2] = AsH[r*PITCH + kb+tg+4];     ah[mt][3] = AsH[(r+8)*PITCH + kb+tg+4];
                al[mt][0] = AsL[r*PITCH + kb+tg];       al[mt][1] = AsL[(r+8)*PITCH + kb+tg];
                al[mt][2] = AsL[r*PITCH + kb+tg+4];     al[mt][3] = AsL[(r+8)*PITCH + kb+tg+4];
            }
            #pragma unroll
            for (int nt = 0; nt < 8; ++nt) {
                int n = wn * 64 + nt * 8 + g8;
                uint32_t bh[2] = { BsH[n*PITCH + kb+tg], BsH[n*PITCH + kb+tg+4] };
                uint32_t bl[2] = { BsL[n*PITCH + kb+tg], BsL[n*PITCH + kb+tg+4] };
                #pragma unroll
                for (int mt = 0; mt < 2; ++mt) {
                    mma16816(acc[mt][nt], ah[mt], bh);
                    mma16816(acc[mt][nt], ah[mt], bl);
                    mma16816(acc[mt][nt], al[mt], bh);
                }
            }
        }
        __syncthreads();
    }

    #pragma unroll
    for (int mt = 0; mt < 2; ++mt) {
        int r0 = m0 + wm * 32 + mt * 16 + g8;
        int r1 = r0 + 8;
        bool ok0 = (r0 - base) < vrows;
        bool ok1 = (r1 - base) < vrows;
        #pragma unroll
        for (int nt = 0; nt < 8; ++nt) {
            int col = n0 + wn * 64 + nt * 8 + tg * 2;
            float* cc = acc[mt][nt];
            #pragma unroll
            for (int q = 0; q < 4; ++q) {
                int row = (q < 2) ? r0 : r1;
                bool ok = (q < 2) ? ok0 : ok1;
                if (!ok) continue;
                int cl = col + (q & 1);
                long idx = (long)row * N + cl;
                if (epi == 3) { C[idx] = cc[q]; continue; }
                float v = cc[q] + bias[cl];
                if (epi == 1) {
                    float gv = 0.5f * v * (1.f + erff(v * 0.70710678118654752f));
                    split1(gv, Chi[idx], Clo[idx]);
                } else if (epi == 2) {
                    C[idx] = C[idx] + ls[cl] * v;
                } else {
                    C[idx] = v;
                }
            }
        }
    }
}

__device__ __forceinline__ int resolve_expert(int m0, const int* segbase, int& base) {
    int e = -1; base = 0;
    #pragma unroll
    for (int i = 0; i < EXP; ++i)
        if (e < 0 && m0 >= segbase[i] && m0 < segbase[i+1]) { e = i; base = segbase[i]; }
    return e;
}

// ================= standard single-config GEMM =================
__global__ __launch_bounds__(256, 2) void k_tgemm(
    int N, int K,
    const u16* __restrict__ Ah, const u16* __restrict__ Al,
    const u16* __restrict__ Wh, const u16* __restrict__ Wl, long wES,
    const float* __restrict__ biasB, long bES,
    float* __restrict__ C, u16* __restrict__ Chi, u16* __restrict__ Clo,
    const float* __restrict__ lsB, long lsES,
    int epi, const int* __restrict__ segbase, const int* __restrict__ valid)
{
    int m0 = blockIdx.y * 128, n0 = blockIdx.x * 128;
    int base, e = resolve_expert(m0, segbase, base);
    if (e < 0) return;
    extern __shared__ uint32_t SM[];
    tgemm_body(N, K, m0, n0, base, valid[e],
               Ah, Al, Wh + (long)e*wES, Wl + (long)e*wES,
               biasB ? (biasB + (long)e*bES) : (const float*)0,
               C, Chi, Clo, lsB ? (lsB + (long)e*lsES) : (const float*)0, epi, SM);
}

// ================= dual GEMM: Q-proj (by < ymid) + KV-proj in one launch =================
__global__ __launch_bounds__(256, 2) void k_tgemm_qkv(
    int ymid,
    // Q: N=1024, A=xln, W=attn_in[0:1024), C=g_q
    const u16* __restrict__ QAh, const u16* __restrict__ QAl,
    const u16* __restrict__ QWh, const u16* __restrict__ QWl,
    const float* __restrict__ Qbias,
    float* __restrict__ QC,
    const int* __restrict__ qseg, const int* __restrict__ qval,
    // KV: N=2048, A=kvn, W=attn_in[1024:3072), C=g_kv
    const u16* __restrict__ KAh, const u16* __restrict__ KAl,
    const u16* __restrict__ KWh, const u16* __restrict__ KWl,
    const float* __restrict__ Kbias,
    float* __restrict__ KC,
    const int* __restrict__ kseg, const int* __restrict__ kval,
    long wES, long bES)
{
    extern __shared__ uint32_t SM[];
    if ((int)blockIdx.y < ymid) {
        if (blockIdx.x >= 8) return;   // Q has N=1024 -> 8 column blocks
        int m0 = blockIdx.y * 128, n0 = blockIdx.x * 128;
        int base, e = resolve_expert(m0, qseg, base);
        if (e < 0) return;
        tgemm_body(HID, HID, m0, n0, base, qval[e],
                   QAh, QAl, QWh + (long)e*wES, QWl + (long)e*wES,
                   Qbias, QC, (u16*)0, (u16*)0, (const float*)0, 0, SM);
    } else {
        int m0 = (blockIdx.y - ymid) * 128, n0 = blockIdx.x * 128;
        int base, e = resolve_expert(m0, kseg, base);
        if (e < 0) return;
        tgemm_body(2048, HID, m0, n0, base, kval[e],
                   KAh, KAl, KWh + (long)e*wES, KWl + (long)e*wES,
                   Kbias + (long)e*bES, KC, (u16*)0, (u16*)0, (const float*)0, 0, SM);
    }
}

// ---------------- reductions ----------------
__device__ __forceinline__ void blockReduce2(float& a, float& b, float* sh) {
    __syncthreads();
    int lane = threadIdx.x & 31, wid = threadIdx.x >> 5;
    #pragma unroll
    for (int o = 16; o; o >>= 1) { a += __shfl_xor_sync(~0u, a, o); b += __shfl_xor_sync(~0u, b, o); }
    if (lane == 0) { sh[wid] = a; sh[wid + 32] = b; }
    __syncthreads();
    int nw = blockDim.x >> 5;
    if (wid == 0) {
        a = (lane < nw) ? sh[lane] : 0.f;
        b = (lane < nw) ? sh[lane + 32] : 0.f;
        #pragma unroll
        for (int o = 16; o; o >>= 1) { a += __shfl_xor_sync(~0u, a, o); b += __shfl_xor_sync(~0u, b, o); }
        if (lane == 0) { sh[0] = a; sh[32] = b; }
    }
    __syncthreads();
    a = sh[0]; b = sh[32];
}
__device__ __forceinline__ float blockReduce1(float a, float* sh) {
    __syncthreads();
    int lane = threadIdx.x & 31, wid = threadIdx.x >> 5;
    #pragma unroll
    for (int o = 16; o; o >>= 1) a += __shfl_xor_sync(~0u, a, o);
    if (lane == 0) sh[wid] = a;
    __syncthreads();
    int nw = blockDim.x >> 5;
    if (wid == 0) {
        a = (lane < nw) ? sh[lane] : 0.f;
        #pragma unroll
        for (int o = 16; o; o >>= 1) a += __shfl_xor_sync(~0u, a, o);
        if (lane == 0) sh[0] = a;
    }
    __syncthreads();
    return sh[0];
}

// ---------------- gate kernels ----------------
__global__ void k_gate_mean(const float* __restrict__ img, float* __restrict__ gi) {
    int b = blockIdx.x;
    int h = blockIdx.y * 64 + (threadIdx.x & 63);
    int part = threadIdx.x >> 6;   // 4 parts
    __shared__ float sh[256];
    float s = 0.f;
    for (int l = part; l < LV_; l += 4)
        s += img[((long)b*LV_ + l)*HID + h];
    sh[threadIdx.x] = s;
    __syncthreads();
    if (part == 0) {
        float tot = sh[threadIdx.x] + sh[threadIdx.x + 64] + sh[threadIdx.x + 128] + sh[threadIdx.x + 192];
        gi[b*HID + h] = tot * (1.f/LV_);
    }
}
__global__ void k_gate(const float* __restrict__ gi, const float* __restrict__ temb,
                       const float* __restrict__ eemb, const int* __restrict__ tids,
                       const int* __restrict__ eids, const float* __restrict__ glw,
                       const float* __restrict__ glb, const float* __restrict__ gwt,
                       const float* __restrict__ gbias, float* __restrict__ gates) {
    int b = blockIdx.x, tid = threadIdx.x;
    __shared__ float sh[64];
    __shared__ float logits[EXP];
    int ti = tids[b], ei = eids[b];
    float s = 0.f, ss = 0.f;
    for (int i = tid; i < GN; i += 256) {
        float v = (i < HID) ? gi[b*HID + i]
                : (i < HID + TDIM) ? temb[ti*TDIM + i - HID]
                : eemb[ei*TDIM + i - HID - TDIM];
        s += v; ss += v*v;
    }
    blockReduce2(s, ss, sh);
    float m  = s * (1.f/GN);
    float rs = rsqrtf(ss * (1.f/GN) - m*m + 1e-5f);
    for (int e = 0; e < EXP; e++) {
        float d = 0.f;
        for (int i = tid; i < GN; i += 256) {
            float v = (i < HID) ? gi[b*HID + i]
                    : (i < HID + TDIM) ? temb[ti*TDIM + i - HID]
                    : eemb[ei*TDIM + i - HID - TDIM];
            d += ((v - m)*rs*glw[i] + glb[i]) * gwt[(long)e*GN + i];
        }
        d = blockReduce1(d, sh);
        if (tid == 0) logits[e] = d + gbias[e];
    }
    __syncthreads();
    if (tid == 0) {
        float w[EXP]; float mx = -1e30f;
        for (int e = 0; e < EXP; e++) { float l = fminf(fmaxf(logits[e], -15.f), 15.f); w[e] = l; mx = fmaxf(mx, l); }
        float sum = 0.f;
        for (int e = 0; e < EXP; e++) { w[e] = expf(w[e] - mx); sum += w[e]; }
        for (int e = 0; e < EXP; e++) w[e] /= sum;
        int i0 = 0;
        for (int e = 1; e < EXP; e++) if (w[e] > w[i0]) i0 = e;
        int i1 = -1;
        for (int e = 0; e < EXP; e++) { if (e == i0) continue; if (i1 < 0 || w[e] > w[i1]) i1 = e; }
        float t = w[i0] + w[i1] + 1e-9f;
        for (int e = 0; e < EXP; e++) gates[b*EXP + e] = 0.f;
        gates[b*EXP + i0] = w[i0] / t;
        gates[b*EXP + i1] = w[i1] / t;
    }
}
__global__ void k_slots(const float* __restrict__ gates, int* cnt, int* soff,
                        int* se, int* sb, float* sg,
                        int* xseg, int* kvseg, int* xvalid, int* kvvalid,
                        int* sxb, int* skvb, int* b2s) {
    if (threadIdx.x == 0) {
        int s = 0;
        for (int e = 0; e < EXP; e++) {
            soff[e] = s;
            int c = 0;
            for (int b = 0; b < BATCH; b++) {
                float g = gates[b*EXP + e];
                if (g != 0.f) { se[s] = e; sb[s] = b; sg[s] = g; s++; c++; }
            }
            cnt[e] = c;
        }
        xseg[0] = 0; kvseg[0] = 0;
        for (int e = 0; e < EXP; e++) {
            xvalid[e]  = cnt[e]*NQ_;
            kvvalid[e] = cnt[e]*KVR;
            xseg[e+1]  = xseg[e]  + ((cnt[e]*NQ_ + 127) & ~127);
            kvseg[e+1] = kvseg[e] + ((cnt[e]*KVR + 127) & ~127);
        }
        for (int i = 0; i < NSLOT; i++) {
            int e = se[i];
            sxb[i]  = xseg[e]  + (i - soff[e])*NQ_;
            skvb[i] = kvseg[e] + (i - soff[e])*KVR;
        }
        int fill[BATCH];
        for (int b = 0; b < BATCH; b++) fill[b] = 0;
        for (int i = 0; i < NSLOT; i++) {
            int b = sb[i];
            b2s[b*2 + fill[b]] = i;
            fill[b]++;
        }
    }
}

// ---------------- init x = full query block per slot ----------------
__global__ void k_initx(const float* __restrict__ query, float* __restrict__ gx,
                        const int* __restrict__ se, const int* __restrict__ sxb) {
    int r = blockIdx.x, s = blockIdx.y;
    int e = se[s];
    const float* srow = query + ((long)e*NQ_ + r)*HID;
    float* d = gx + (long)(sxb[s] + r)*HID;
    for (int i = threadIdx.x; i < HID; i += blockDim.x) d[i] = srow[i];
}

// ---------------- merged LN: x rows + kv0 rows in one launch -> bf16 hi/lo ----------------
__global__ void k_ln_all(const float* __restrict__ xsrc,
                         const float* __restrict__ query, const float* __restrict__ img,
                         const float* __restrict__ pp,
                         const float* __restrict__ xw, const float* __restrict__ xb,
                         const float* __restrict__ kw, const float* __restrict__ kb, long pES,
                         u16* __restrict__ xdh, u16* __restrict__ xdl,
                         u16* __restrict__ kdh, u16* __restrict__ kdl,
                         const int* __restrict__ se, const int* __restrict__ sb,
                         const int* __restrict__ sxb, const int* __restrict__ skvb) {
    int rr = blockIdx.x, s = blockIdx.y;
    int e = se[s];
    const float* row;
    const float *w, *bv;
    u16 *dh, *dl;
    long doff;
    if (rr < NQ_) {
        doff = (long)(sxb[s] + rr)*HID;
        row = xsrc + doff;
        w = xw; bv = xb; dh = xdh; dl = xdl;
    } else {
        int r = rr - NQ_;
        int b = sb[s];
        int rl, sq, qo, io;
        if (r < 320)      { rl = r;       sq = 64; qo = 0;   io = 0;   }
        else if (r < 624) { rl = r - 320; sq = 48; qo = 64;  io = 256; }
        else              { rl = r - 624; sq = 32; qo = 112; io = 512; }
        if (rl < sq) row = query + ((long)e*NQ_ + qo + rl)*HID;
        else {
            int zi = io + rl - sq;
            if (zi < LV_) row = img + ((long)b*LV_ + zi)*HID;
            else          row = pp  + ((long)b*LP_ + zi - LV_)*HID;
        }
        doff = (long)(skvb[s] + r)*HID;
        w = kw; bv = kb; dh = kdh; dl = kdl;
    }
    __shared__ float sh[64];
    float v[4]; float sm = 0.f, ss = 0.f;
    #pragma unroll
    for (int t = 0; t < 4; t++) { v[t] = row[threadIdx.x + t*256]; sm += v[t]; ss += v[t]*v[t]; }
    blockReduce2(sm, ss, sh);
    float m  = sm * (1.f/HID);
    float rs = rsqrtf(ss * (1.f/HID) - m*m + 1e-5f);
    const float* we = w + (long)e*pES;
    const float* be = bv + (long)e*pES;
    #pragma unroll
    for (int t = 0; t < 4; t++) {
        int i = threadIdx.x + t*256;
        float rv = (v[t] - m)*rs*we[i] + be[i];
        split1(rv, dh[doff + i], dl[doff + i]);
    }
}

// ---------------- LayerNorm (x rows only, for MLP LN) ----------------
__global__ void k_ln(const float* __restrict__ src,
                     const float* __restrict__ w, const float* __restrict__ bvec, long pES,
                     u16* __restrict__ dh, u16* __restrict__ dl,
                     const int* __restrict__ se, const int* __restrict__ sxb) {
    int r = blockIdx.x, s = blockIdx.y;
    int e = se[s];
    long row = (long)(sxb[s] + r)*HID;
    __shared__ float sh[64];
    float v[4]; float sm = 0.f, ss = 0.f;
    #pragma unroll
    for (int t = 0; t < 4; t++) { v[t] = src[row + threadIdx.x + t*256]; sm += v[t]; ss += v[t]*v[t]; }
    blockReduce2(sm, ss, sh);
    float m  = sm * (1.f/HID);
    float rs = rsqrtf(ss * (1.f/HID) - m*m + 1e-5f);
    const float* we = w + (long)e*pES;
    const float* be = bvec + (long)e*pES;
    #pragma unroll
    for (int t = 0; t < 4; t++) {
        int i = threadIdx.x + t*256;
        float rv = (v[t] - m)*rs*we[i] + be[i];
        split1(rv, dh[row + i], dl[row + i]);
    }
}

// ---------------- attention (all stages, 4-way ILP) -> bf16 hi/lo ----------------
__global__ void k_attn(const float* __restrict__ q, const float* __restrict__ kv,
                       u16* __restrict__ ath, u16* __restrict__ atl,
                       const int* __restrict__ sxb, const int* __restrict__ skvb) {
    int s = blockIdx.y, st = blockIdx.z;
    int sq    = (st == 0) ? 64 : (st == 1 ? 48 : 32);
    int qo    = (st == 0) ? 0  : (st == 1 ? 64 : 112);
    int kvo   = (st == 0) ? 0  : (st == 1 ? 320 : 624);
    int kvlen = sq + 256;
    int warp = threadIdx.x >> 5, lane = threadIdx.x & 31;
    int w = blockIdx.x * 4 + warp;
    if (w >= NHEADS * sq) return;
    int h = w / sq, qi = w % sq;
    __shared__ float sc[4][320];

    long qrow  = (long)sxb[s] + qo + qi;
    long kvrow = (long)skvb[s] + kvo;
    const float* qr = q + qrow*HID + h*HDIM;
    float q0 = qr[lane], q1 = qr[lane + 32];
    const float* kbase = kv + kvrow*2048 + h*HDIM;
    float mx = -1e30f;
    for (int j = 0; j < kvlen; j += 4) {
        const float* k0 = kbase + (long)j*2048;
        const float* k1 = k0 + 2048;
        const float* k2 = k1 + 2048;
        const float* k3 = k2 + 2048;
        float p0 = q0*k0[lane] + q1*k0[lane + 32];
        float p1 = q0*k1[lane] + q1*k1[lane + 32];
        float p2 = q0*k2[lane] + q1*k2[lane + 32];
        float p3 = q0*k3[lane] + q1*k3[lane + 32];
        #pragma unroll
        for (int o = 16; o; o >>= 1) {
            p0 += __shfl_xor_sync(~0u, p0, o);
            p1 += __shfl_xor_sync(~0u, p1, o);
            p2 += __shfl_xor_sync(~0u, p2, o);
            p3 += __shfl_xor_sync(~0u, p3, o);
        }
        p0 *= 0.125f; p1 *= 0.125f; p2 *= 0.125f; p3 *= 0.125f;
        if (lane == 0) {
            sc[warp][j]   = p0; sc[warp][j+1] = p1;
            sc[warp][j+2] = p2; sc[warp][j+3] = p3;
        }
        mx = fmaxf(mx, fmaxf(fmaxf(p0, p1), fmaxf(p2, p3)));
    }
    __syncwarp();
    float se_ = 0.f;
    for (int j = lane; j < kvlen; j += 32) {
        float ex = __expf(sc[warp][j] - mx);
        sc[warp][j] = ex;
        se_ += ex;
    }
    #pragma unroll
    for (int o = 16; o; o >>= 1) se_ += __shfl_xor_sync(~0u, se_, o);
    __syncwarp();
    float inv = 1.f / se_;
    const float* vbase = kv + kvrow*2048 + 1024 + h*HDIM;
    float a0 = 0.f, a1 = 0.f;
    #pragma unroll 4
    for (int j = 0; j < kvlen; j++) {
        float p = sc[warp][j];
        const float* vr = vbase + (long)j*2048;
        a0 += p*vr[lane]; a1 += p*vr[lane + 32];
    }
    long ooff = qrow*HID + h*HDIM;
    split1(a0 * inv, ath[ooff + lane],      atl[ooff + lane]);
    split1(a1 * inv, ath[ooff + lane + 32], atl[ooff + lane + 32]);
}

// ---------------- gate-scaled split of final x -> bf16 hi/lo ----------------
__global__ void k_gsplit(const float* __restrict__ gx,
                         u16* __restrict__ dh, u16* __restrict__ dl,
                         const int* __restrict__ sxb, const float* __restrict__ sg) {
    int r = blockIdx.x, s = blockIdx.y;
    float g = sg[s];
    long row = (long)(sxb[s] + r)*HID;
    for (int i = threadIdx.x; i < HID; i += blockDim.x)
        split1(g * gx[row + i], dh[row + i], dl[row + i]);
}

// ---------------- combine 2 slots per batch + gated bias + RMS + final scaling ----------------
__global__ void k_rms_combine(const float* __restrict__ O, const float* __restrict__ bo,
                              float* __restrict__ out, const float* __restrict__ fw,
                              const float* __restrict__ gain,
                              const int* __restrict__ b2s, const int* __restrict__ se,
                              const float* __restrict__ sg, const int* __restrict__ sxb) {
    int qrow = blockIdx.x, b = blockIdx.y;
    int s0 = b2s[b*2], s1 = b2s[b*2 + 1];
    int e0 = se[s0], e1 = se[s1];
    float g0 = sg[s0], g1 = sg[s1];
    long r0 = (long)(sxb[s0] + qrow)*OUTD;
    long r1 = (long)(sxb[s1] + qrow)*OUTD;
    const float* bo0 = bo + (long)e0*OUTD;
    const float* bo1 = bo + (long)e1*OUTD;
    float* orow = out + ((long)b*NQ_ + qrow)*OUTD;
    __shared__ float sh[64];
    float v[16]; float ss = 0.f;
    #pragma unroll
    for (int t = 0; t < 16; t++) {
        int o = threadIdx.x + t*256;
        float val = O[r0 + o] + O[r1 + o] + g0*bo0[o] + g1*bo1[o];
        v[t] = val; ss += val*val;
    }
    ss = blockReduce1(ss, sh);
    float sc = rsqrtf(ss * (1.f/OUTD) + 1e-6f);
    #pragma unroll
    for (int t = 0; t < 16; t++) {
        int o = threadIdx.x + t*256;
        orow[o] = v[t]*sc*fw[o]*gain[o];
    }
}

// ---------------- host orchestration ----------------
extern "C" void kernel_launch(void* const* d_in, const int* in_sizes, int n_in,
                              void* d_out, int out_size) {
    const float* image     = (const float*)d_in[0];
    const float* pp        = (const float*)d_in[1];
    const int*   tids      = (const int*)  d_in[2];
    const int*   eids      = (const int*)  d_in[3];
    const float* query     = (const float*)d_in[4];
    const float* ln1_w     = (const float*)d_in[5];
    const float* ln1_b     = (const float*)d_in[6];
    const float* ln1kv_w   = (const float*)d_in[7];
    const float* ln1kv_b   = (const float*)d_in[8];
    const float* attn_in_w = (const float*)d_in[9];
    const float* attn_in_b = (const float*)d_in[10];
    const float* attn_out_w= (const float*)d_in[11];
    const float* attn_out_b= (const float*)d_in[12];
    const float* ls1       = (const float*)d_in[13];
    const float* ls2       = (const float*)d_in[14];
    const float* ln2_w     = (const float*)d_in[15];
    const float* ln2_b     = (const float*)d_in[16];
    const float* fc_w      = (const float*)d_in[17];
    const float* fc_b      = (const float*)d_in[18];
    const float* proj_w    = (const float*)d_in[19];
    const float* proj_b    = (const float*)d_in[20];
    const float* outp_w    = (const float*)d_in[21];
    const float* outp_b    = (const float*)d_in[22];
    const float* temb      = (const float*)d_in[23];
    const float* eemb      = (const float*)d_in[24];
    const float* glw       = (const float*)d_in[25];
    const float* glb       = (const float*)d_in[26];
    const float* gwt       = (const float*)d_in[27];
    const float* gbias     = (const float*)d_in[28];
    const float* gain      = (const float*)d_in[29];
    const float* fw        = (const float*)d_in[30];
    float* out = (float*)d_out;

    float *px, *pq, *pkv, *po, *pg, *pgi, *psg;
    int *pcnt, *psoff, *pse, *psb, *pxseg, *pkvseg, *pxval, *pkvval, *psxb, *pskvb, *pb2s;
    cudaGetSymbolAddress((void**)&px,    g_x);
    cudaGetSymbolAddress((void**)&pq,    g_q);
    cudaGetSymbolAddress((void**)&pkv,   g_kv);
    cudaGetSymbolAddress((void**)&po,    g_o);
    cudaGetSymbolAddress((void**)&pg,    g_gates);
    cudaGetSymbolAddress((void**)&pgi,   g_gi);
    cudaGetSymbolAddress((void**)&pcnt,  g_cnt);
    cudaGetSymbolAddress((void**)&psoff, g_soff);
    cudaGetSymbolAddress((void**)&pse,   g_se);
    cudaGetSymbolAddress((void**)&psb,   g_sb);
    cudaGetSymbolAddress((void**)&psg,   g_sg);
    cudaGetSymbolAddress((void**)&pxseg, g_xseg);
    cudaGetSymbolAddress((void**)&pkvseg,g_kvseg);
    cudaGetSymbolAddress((void**)&pxval, g_xvalid);
    cudaGetSymbolAddress((void**)&pkvval,g_kvvalid);
    cudaGetSymbolAddress((void**)&psxb,  g_sxb);
    cudaGetSymbolAddress((void**)&pskvb, g_skvb);
    cudaGetSymbolAddress((void**)&pb2s,  g_b2s);

    u16 *xh, *xl, *kh, *kl, *ah, *al, *fh, *fl;
    cudaGetSymbolAddress((void**)&xh, g_xln_h); cudaGetSymbolAddress((void**)&xl, g_xln_l);
    cudaGetSymbolAddress((void**)&kh, g_kvn_h); cudaGetSymbolAddress((void**)&kl, g_kvn_l);
    cudaGetSymbolAddress((void**)&ah, g_att_h); cudaGetSymbolAddress((void**)&al, g_att_l);
    cudaGetSymbolAddress((void**)&fh, g_ffn_h); cudaGetSymbolAddress((void**)&fl, g_ffn_l);

    u16 *aiwh, *aiwl, *aowh, *aowl, *fcwh, *fcwl, *pjwh, *pjwl, *opwh, *opwl;
    cudaGetSymbolAddress((void**)&aiwh, g_aiw_h); cudaGetSymbolAddress((void**)&aiwl, g_aiw_l);
    cudaGetSymbolAddress((void**)&aowh, g_aow_h); cudaGetSymbolAddress((void**)&aowl, g_aow_l);
    cudaGetSymbolAddress((void**)&fcwh, g_fcw_h); cudaGetSymbolAddress((void**)&fcwl, g_fcw_l);
    cudaGetSymbolAddress((void**)&pjwh, g_pjw_h); cudaGetSymbolAddress((void**)&pjwl, g_pjw_l);
    cudaGetSymbolAddress((void**)&opwh, g_opw_h); cudaGetSymbolAddress((void**)&opwl, g_opw_l);

    cudaFuncSetAttribute(k_tgemm,     cudaFuncAttributeMaxDynamicSharedMemorySize, TG_DSMEM);
    cudaFuncSetAttribute(k_tgemm_qkv, cudaFuncAttributeMaxDynamicSharedMemorySize, TG_DSMEM);

    k_split_all<<<2048, 256>>>(
        (const float4*)attn_in_w,  (uint2*)aiwh, (uint2*)aiwl,
        (const float4*)attn_out_w, (uint2*)aowh, (uint2*)aowl,
        (const float4*)fc_w,       (uint2*)fcwh, (uint2*)fcwl,
        (const float4*)proj_w,     (uint2*)pjwh, (uint2*)pjwl,
        (const float4*)outp_w,     (uint2*)opwh, (uint2*)opwl);

    k_gate_mean<<<dim3(BATCH, 16), 256>>>(image, pgi);
    k_gate<<<BATCH, 256>>>(pgi, temb, eemb, tids, eids, glw, glb, gwt, gbias, pg);
    k_slots<<<1, 32>>>(pg, pcnt, psoff, pse, psb, psg,
                       pxseg, pkvseg, pxval, pkvval, psxb, pskvb, pb2s);

    k_initx<<<dim3(NQ_, NSLOT), 256>>>(query, px, pse, psxb);

    const long HH = (long)HID*HID;
    const int XMB = 22;
    const int KVMB = 118;

    for (int l = 0; l < NLAYERS; l++) {
        // merged LN (x + kv0) in one launch
        k_ln_all<<<dim3(NQ_ + KVR, NSLOT), 256>>>(px, query, image, pp,
            ln1_w + (long)l*HID, ln1_b + (long)l*HID,
            ln1kv_w + (long)l*HID, ln1kv_b + (long)l*HID, (long)NLAYERS*HID,
            xh, xl, kh, kl, pse, psb, psxb, pskvb);
        // merged Q + KV projection in one launch
        k_tgemm_qkv<<<dim3(16, XMB + KVMB), 256, TG_DSMEM>>>(XMB,
            xh, xl, aiwh + (long)l*3*HH, aiwl + (long)l*3*HH,
            attn_in_b + (long)l*3*HID, pq, pxseg, pxval,
            kh, kl, aiwh + (long)l*3*HH + HH, aiwl + (long)l*3*HH + HH,
            attn_in_b + (long)l*3*HID + HID, pkv, pkvseg, pkvval,
            (long)NLAYERS*3*HH, (long)NLAYERS*3*HID);
        // attention (all stages)
        k_attn<<<dim3(256, NSLOT, 3), 128>>>(pq, pkv, ah, al, psxb, pskvb);
        // attn-out projection + residual
        k_tgemm<<<dim3(8, XMB), 256, TG_DSMEM>>>(HID, HID,
            ah, al, aowh + (long)l*HH, aowl + (long)l*HH, (long)NLAYERS*HH,
            attn_out_b + (long)l*HID, (long)NLAYERS*HID,
            px, (u16*)0, (u16*)0, ls1 + (long)l*HID, (long)NLAYERS*HID, 2, pxseg, pxval);
        // MLP
        k_ln<<<dim3(NQ_, NSLOT), 256>>>(px,
            ln2_w + (long)l*HID, ln2_b + (long)l*HID, (long)NLAYERS*HID,
            xh, xl, pse, psxb);
        k_tgemm<<<dim3(32, XMB), 256, TG_DSMEM>>>(4*HID, HID,
            xh, xl, fcwh + (long)l*4*HH, fcwl + (long)l*4*HH, (long)NLAYERS*4*HH,
            fc_b + (long)l*4*HID, (long)NLAYERS*4*HID,
            (float*)0, fh, fl, (const float*)0, 0, 1, pxseg, pxval);
        k_tgemm<<<dim3(8, XMB), 256, TG_DSMEM>>>(HID, 4*HID,
            fh, fl, pjwh + (long)l*4*HH, pjwl + (long)l*4*HH, (long)NLAYERS*4*HH,
            proj_b + (long)l*HID, (long)NLAYERS*HID,
            px, (u16*)0, (u16*)0, ls2 + (long)l*HID, (long)NLAYERS*HID, 2, pxseg, pxval);
    }

    // final projection: gate-scaled x -> per-slot O, then combine + RMS
    k_gsplit<<<dim3(NQ_, NSLOT), 256>>>(px, xh, xl, psxb, psg);
    k_tgemm<<<dim3(OUTD/128, XMB), 256, TG_DSMEM>>>(OUTD, HID,
        xh, xl, opwh, opwl, (long)OUTD*HID,
        (const float*)0, 0,
        po, (u16*)0, (u16*)0, (const float*)0, 0, 3, pxseg, pxval);
    k_rms_combine<<<dim3(NQ_, BATCH), 256>>>(po, outp_b, out, fw, gain, pb2s, pse, psg, psxb);
}

// round 10
// speedup vs baseline: 4.1814x; 1.2548x over previous
#include <cuda_runtime.h>
#include <cuda_fp16.h>
#include <math.h>
#include <stdint.h>

typedef unsigned short u16;

// ---------------- problem constants ----------------
#define EXP    4
#define BATCH  8
#define NQ_    144
#define NLAYERS 2
#define NHEADS 16
#define HDIM   64
#define HID    1024
#define OUTD   4096
#define TDIM   256
#define LV_    576
#define LP_    192
#define NSLOT  16
#define GN     (HID + 2*TDIM)   // 1536
#define KVR    912              // 320+304+288 kv rows per slot
#define XROWS  3072
#define KVROWS 16384

// ---------------- fp32 scratch ----------------
__device__ float g_x   [XROWS*HID];
__device__ float g_q   [XROWS*HID];
__device__ float g_kv  [KVROWS*2048];       // K | V
__device__ float g_o   [XROWS*OUTD];
__device__ float g_gates[BATCH*EXP];
__device__ float g_gi  [BATCH*HID];

// slot metadata
__device__ int   g_cnt[EXP], g_soff[EXP];
__device__ int   g_se[NSLOT], g_sb[NSLOT];
__device__ float g_sg[NSLOT];
__device__ int   g_xseg[EXP+1], g_kvseg[EXP+1];
__device__ int   g_xvalid[EXP], g_kvvalid[EXP];
__device__ int   g_sxb[NSLOT], g_skvb[NSLOT];
__device__ int   g_b2s[BATCH*2];
__device__ float g_rowg[XROWS];

// ---------------- fp16 hi/lo activation scratch ----------------
__device__ u16 g_xln_h[XROWS*HID],  g_xln_l[XROWS*HID];
__device__ u16 g_kvn_h[KVROWS*HID], g_kvn_l[KVROWS*HID];
__device__ u16 g_att_h[XROWS*HID],  g_att_l[XROWS*HID];
__device__ u16 g_ffn_h[XROWS*4096], g_ffn_l[XROWS*4096];

// ---------------- fp16 weight scratch (single precision term) ----------------
#define AIW_N (EXP*NLAYERS*3*HID*HID)
#define AOW_N (EXP*NLAYERS*HID*HID)
#define FCW_N (EXP*NLAYERS*4*HID*HID)
#define PJW_N (EXP*NLAYERS*HID*4*HID)
#define OPW_N (EXP*OUTD*HID)
__device__ u16 g_aiw[AIW_N];
__device__ u16 g_aow[AOW_N];
__device__ u16 g_fcw[FCW_N];
__device__ u16 g_pjw[PJW_N];
__device__ u16 g_opw[OPW_N];

// ================= helpers =================
__device__ __forceinline__ void mma16816(float* c, const uint32_t* a, const uint32_t* b) {
    asm volatile("mma.sync.aligned.m16n8k16.row.col.f32.f16.f16.f32 "
        "{%0,%1,%2,%3}, {%4,%5,%6,%7}, {%8,%9}, {%0,%1,%2,%3};"
        : "+f"(c[0]), "+f"(c[1]), "+f"(c[2]), "+f"(c[3])
        : "r"(a[0]), "r"(a[1]), "r"(a[2]), "r"(a[3]), "r"(b[0]), "r"(b[1]));
}
__device__ __forceinline__ void fsplit1(float v, u16& h, u16& l) {
    __half hh = __float2half(v);
    h = __half_as_ushort(hh);
    l = __half_as_ushort(__float2half(v - __half2float(hh)));
}
__device__ __forceinline__ uint2 cvt4h(float4 v) {
    __half2 a = __floats2half2_rn(v.x, v.y);
    __half2 b = __floats2half2_rn(v.z, v.w);
    uint2 r;
    r.x = *reinterpret_cast<uint32_t*>(&a);
    r.y = *reinterpret_cast<uint32_t*>(&b);
    return r;
}
__device__ __forceinline__ uint32_t smem_u32(const void* p) {
    uint32_t a;
    asm("{ .reg .u64 t; cvta.to.shared.u64 t, %1; cvt.u32.u64 %0, t; }" : "=r"(a) : "l"(p));
    return a;
}
#define CP16(dst, src) asm volatile("cp.async.cg.shared.global [%0], [%1], 16;" :: "r"(dst), "l"(src) : "memory")
#define CPCOMMIT() asm volatile("cp.async.commit_group;" ::: "memory")
#define CPWAIT0()  asm volatile("cp.async.wait_group 0;" ::: "memory")

// ---------------- merged weight convert fp32 -> fp16 (single launch) ----------------
__global__ void k_cvt_all(const float4* __restrict__ s0, uint2* __restrict__ d0,
                          const float4* __restrict__ s1, uint2* __restrict__ d1,
                          const float4* __restrict__ s2, uint2* __restrict__ d2,
                          const float4* __restrict__ s3, uint2* __restrict__ d3,
                          const float4* __restrict__ s4, uint2* __restrict__ d4) {
    const long n0 = AIW_N/4, n1 = AOW_N/4, n2 = FCW_N/4, n3 = PJW_N/4, n4 = OPW_N/4;
    const long total = n0 + n1 + n2 + n3 + n4;
    long stride = (long)gridDim.x * blockDim.x;
    for (long i = (long)blockIdx.x * blockDim.x + threadIdx.x; i < total; i += stride) {
        const float4* s; uint2* d; long k = i;
        if (k < n0)              { s = s0; d = d0; }
        else if ((k -= n0) < n1) { s = s1; d = d1; }
        else if ((k -= n1) < n2) { s = s2; d = d2; }
        else if ((k -= n2) < n3) { s = s3; d = d3; }
        else                     { k -= n3; s = s4; d = d4; }
        d[k] = cvt4h(s[k]);
    }
}

#define PITCH 20
#define ARR_U32 (128*PITCH)        // 2560
#define BUF_U32 (3*ARR_U32)        // 7680
#define TG_DSMEM (2*BUF_U32*4)     // 61440 bytes

// ================= GEMM body: C(block m0,n0) = (Ah+Al) @ W^T  (2 MMA terms) =================
__device__ __forceinline__ void tgemm_body(
    int N, int K, int m0, int n0, int base, int vrows,
    const u16* __restrict__ Ah, const u16* __restrict__ Al,
    const u16* __restrict__ WE,
    const float* __restrict__ bias,
    float* __restrict__ C, u16* __restrict__ Chi, u16* __restrict__ Clo,
    const float* __restrict__ ls, const float* __restrict__ rowg,
    int epi, uint32_t* SM)
{
    uint32_t smb = smem_u32(SM);
    int tid = threadIdx.x;
    int warp = tid >> 5, lane = tid & 31;
    int wm = warp & 3, wn = warp >> 2;
    int g8 = lane >> 2, tg = lane & 3;

    const u16* src[3][2];
    uint32_t doff[2];
    #pragma unroll
    for (int j = 0; j < 2; ++j) {
        int lin = j * 256 + tid;
        int row = lin >> 2, q = lin & 3;
        doff[j] = (uint32_t)(row * PITCH + q * 4) * 4;
        src[0][j] = Ah + (long)(m0 + row) * K + q * 8;
        src[1][j] = Al + (long)(m0 + row) * K + q * 8;
        src[2][j] = WE + (long)(n0 + row) * K + q * 8;
    }

    float acc[2][8][4] = {};
    int nch = K >> 5;

    #pragma unroll
    for (int a = 0; a < 3; ++a)
        #pragma unroll
        for (int j = 0; j < 2; ++j)
            CP16(smb + a * (ARR_U32*4) + doff[j], src[a][j]);
    CPCOMMIT();

    for (int c = 0; c < nch; ++c) {
        CPWAIT0();
        __syncthreads();
        if (c + 1 < nch) {
            long koff = (long)(c + 1) * 32;
            uint32_t bb = smb + ((c + 1) & 1) * (BUF_U32*4);
            #pragma unroll
            for (int a = 0; a < 3; ++a)
                #pragma unroll
                for (int j = 0; j < 2; ++j)
                    CP16(bb + a * (ARR_U32*4) + doff[j], src[a][j] + koff);
            CPCOMMIT();
        }
        const uint32_t* B = SM + (c & 1) * BUF_U32;
        const uint32_t* AsH = B;
        const uint32_t* AsL = B + ARR_U32;
        const uint32_t* Bs  = B + 2*ARR_U32;
        #pragma unroll
        for (int kh = 0; kh < 2; ++kh) {
            int kb = kh * 8;
            uint32_t ah[2][4], al[2][4];
            #pragma unroll
            for (int mt = 0; mt < 2; ++mt) {
                int r = wm * 32 + mt * 16 + g8;
                ah[mt][0] = AsH[r*PITCH + kb+tg];       ah[mt][1] = AsH[(r+8)*PITCH + kb+tg];
                ah[mt][2] = AsH[r*PITCH + kb+tg+4];     ah[mt][3] = AsH[(r+8)*PITCH + kb+tg+4];
                al[mt][0] = AsL[r*PITCH + kb+tg];       al[mt][1] = AsL[(r+8)*PITCH + kb+tg];
                al[mt][2] = AsL[r*PITCH + kb+tg+4];     al[mt][3] = AsL[(r+8)*PITCH + kb+tg+4];
            }
            #pragma unroll
            for (int nt = 0; nt < 8; ++nt) {
                int n = wn * 64 + nt * 8 + g8;
                uint32_t b2[2] = { Bs[n*PITCH + kb+tg], Bs[n*PITCH + kb+tg+4] };
                #pragma unroll
                for (int mt = 0; mt < 2; ++mt) {
                    mma16816(acc[mt][nt], ah[mt], b2);
                    mma16816(acc[mt][nt], al[mt], b2);
                }
            }
        }
        __syncthreads();
    }

    #pragma unroll
    for (int mt = 0; mt < 2; ++mt) {
        int r0 = m0 + wm * 32 + mt * 16 + g8;
        int r1 = r0 + 8;
        bool ok0 = (r0 - base) < vrows;
        bool ok1 = (r1 - base) < vrows;
        #pragma unroll
        for (int nt = 0; nt < 8; ++nt) {
            int col = n0 + wn * 64 + nt * 8 + tg * 2;
            float* cc = acc[mt][nt];
            #pragma unroll
            for (int q = 0; q < 4; ++q) {
                int row = (q < 2) ? r0 : r1;
                bool ok = (q < 2) ? ok0 : ok1;
                if (!ok) continue;
                int cl = col + (q & 1);
                long idx = (long)row * N + cl;
                if (epi == 3) { C[idx] = cc[q]; continue; }
                float v = cc[q] + bias[cl];
                if (epi == 1) {
                    float gv = 0.5f * v * (1.f + erff(v * 0.70710678118654752f));
                    fsplit1(gv, Chi[idx], Clo[idx]);
                } else if (epi == 2) {
                    C[idx] = C[idx] + ls[cl] * v;
                } else if (epi == 4) {
                    float nv = C[idx] + ls[cl] * v;
                    C[idx] = nv;
                    fsplit1(rowg[row] * nv, Chi[idx], Clo[idx]);
                } else {
                    C[idx] = v;
                }
            }
        }
    }
}

__device__ __forceinline__ int resolve_expert(int m0, const int* segbase, int& base) {
    int e = -1; base = 0;
    #pragma unroll
    for (int i = 0; i < EXP; ++i)
        if (e < 0 && m0 >= segbase[i] && m0 < segbase[i+1]) { e = i; base = segbase[i]; }
    return e;
}

// ================= standard single-config GEMM =================
__global__ __launch_bounds__(256, 2) void k_tgemm(
    int N, int K,
    const u16* __restrict__ Ah, const u16* __restrict__ Al,
    const u16* __restrict__ W, long wES,
    const float* __restrict__ biasB, long bES,
    float* __restrict__ C, u16* __restrict__ Chi, u16* __restrict__ Clo,
    const float* __restrict__ lsB, long lsES,
    const float* __restrict__ rowg,
    int epi, const int* __restrict__ segbase, const int* __restrict__ valid)
{
    int m0 = blockIdx.y * 128, n0 = blockIdx.x * 128;
    int base, e = resolve_expert(m0, segbase, base);
    if (e < 0) return;
    extern __shared__ uint32_t SM[];
    tgemm_body(N, K, m0, n0, base, valid[e],
               Ah, Al, W + (long)e*wES,
               biasB ? (biasB + (long)e*bES) : (const float*)0,
               C, Chi, Clo, lsB ? (lsB + (long)e*lsES) : (const float*)0, rowg, epi, SM);
}

// ================= dual GEMM: Q-proj (by < ymid) + KV-proj in one launch =================
__global__ __launch_bounds__(256, 2) void k_tgemm_qkv(
    int ymid,
    const u16* __restrict__ QAh, const u16* __restrict__ QAl,
    const u16* __restrict__ QW, const float* __restrict__ Qbias,
    float* __restrict__ QC,
    const int* __restrict__ qseg, const int* __restrict__ qval,
    const u16* __restrict__ KAh, const u16* __restrict__ KAl,
    const u16* __restrict__ KW, const float* __restrict__ Kbias,
    float* __restrict__ KC,
    const int* __restrict__ kseg, const int* __restrict__ kval,
    long wES, long bES)
{
    extern __shared__ uint32_t SM[];
    if ((int)blockIdx.y < ymid) {
        if (blockIdx.x >= 8) return;
        int m0 = blockIdx.y * 128, n0 = blockIdx.x * 128;
        int base, e = resolve_expert(m0, qseg, base);
        if (e < 0) return;
        tgemm_body(HID, HID, m0, n0, base, qval[e],
                   QAh, QAl, QW + (long)e*wES,
                   Qbias, QC, (u16*)0, (u16*)0, (const float*)0, (const float*)0, 0, SM);
    } else {
        int m0 = (blockIdx.y - ymid) * 128, n0 = blockIdx.x * 128;
        int base, e = resolve_expert(m0, kseg, base);
        if (e < 0) return;
        tgemm_body(2048, HID, m0, n0, base, kval[e],
                   KAh, KAl, KW + (long)e*wES,
                   Kbias + (long)e*bES, KC, (u16*)0, (u16*)0, (const float*)0, (const float*)0, 0, SM);
    }
}

// ---------------- reductions ----------------
__device__ __forceinline__ void blockReduce2(float& a, float& b, float* sh) {
    __syncthreads();
    int lane = threadIdx.x & 31, wid = threadIdx.x >> 5;
    #pragma unroll
    for (int o = 16; o; o >>= 1) { a += __shfl_xor_sync(~0u, a, o); b += __shfl_xor_sync(~0u, b, o); }
    if (lane == 0) { sh[wid] = a; sh[wid + 32] = b; }
    __syncthreads();
    int nw = blockDim.x >> 5;
    if (wid == 0) {
        a = (lane < nw) ? sh[lane] : 0.f;
        b = (lane < nw) ? sh[lane + 32] : 0.f;
        #pragma unroll
        for (int o = 16; o; o >>= 1) { a += __shfl_xor_sync(~0u, a, o); b += __shfl_xor_sync(~0u, b, o); }
        if (lane == 0) { sh[0] = a; sh[32] = b; }
    }
    __syncthreads();
    a = sh[0]; b = sh[32];
}
__device__ __forceinline__ float blockReduce1(float a, float* sh) {
    __syncthreads();
    int lane = threadIdx.x & 31, wid = threadIdx.x >> 5;
    #pragma unroll
    for (int o = 16; o; o >>= 1) a += __shfl_xor_sync(~0u, a, o);
    if (lane == 0) sh[wid] = a;
    __syncthreads();
    int nw = blockDim.x >> 5;
    if (wid == 0) {
        a = (lane < nw) ? sh[lane] : 0.f;
        #pragma unroll
        for (int o = 16; o; o >>= 1) a += __shfl_xor_sync(~0u, a, o);
        if (lane == 0) sh[0] = a;
    }
    __syncthreads();
    return sh[0];
}

// ---------------- gate kernels ----------------
__global__ void k_gate_mean(const float* __restrict__ img, float* __restrict__ gi) {
    int b = blockIdx.x;
    int h = blockIdx.y * 64 + (threadIdx.x & 63);
    int part = threadIdx.x >> 6;
    __shared__ float sh[256];
    float s = 0.f;
    for (int l = part; l < LV_; l += 4)
        s += img[((long)b*LV_ + l)*HID + h];
    sh[threadIdx.x] = s;
    __syncthreads();
    if (part == 0) {
        float tot = sh[threadIdx.x] + sh[threadIdx.x + 64] + sh[threadIdx.x + 128] + sh[threadIdx.x + 192];
        gi[b*HID + h] = tot * (1.f/LV_);
    }
}
__global__ void k_gate(const float* __restrict__ gi, const float* __restrict__ temb,
                       const float* __restrict__ eemb, const int* __restrict__ tids,
                       const int* __restrict__ eids, const float* __restrict__ glw,
                       const float* __restrict__ glb, const float* __restrict__ gwt,
                       const float* __restrict__ gbias, float* __restrict__ gates) {
    int b = blockIdx.x, tid = threadIdx.x;
    __shared__ float sh[64];
    __shared__ float logits[EXP];
    int ti = tids[b], ei = eids[b];
    float s = 0.f, ss = 0.f;
    for (int i = tid; i < GN; i += 256) {
        float v = (i < HID) ? gi[b*HID + i]
                : (i < HID + TDIM) ? temb[ti*TDIM + i - HID]
                : eemb[ei*TDIM + i - HID - TDIM];
        s += v; ss += v*v;
    }
    blockReduce2(s, ss, sh);
    float m  = s * (1.f/GN);
    float rs = rsqrtf(ss * (1.f/GN) - m*m + 1e-5f);
    for (int e = 0; e < EXP; e++) {
        float d = 0.f;
        for (int i = tid; i < GN; i += 256) {
            float v = (i < HID) ? gi[b*HID + i]
                    : (i < HID + TDIM) ? temb[ti*TDIM + i - HID]
                    : eemb[ei*TDIM + i - HID - TDIM];
            d += ((v - m)*rs*glw[i] + glb[i]) * gwt[(long)e*GN + i];
        }
        d = blockReduce1(d, sh);
        if (tid == 0) logits[e] = d + gbias[e];
    }
    __syncthreads();
    if (tid == 0) {
        float w[EXP]; float mx = -1e30f;
        for (int e = 0; e < EXP; e++) { float l = fminf(fmaxf(logits[e], -15.f), 15.f); w[e] = l; mx = fmaxf(mx, l); }
        float sum = 0.f;
        for (int e = 0; e < EXP; e++) { w[e] = expf(w[e] - mx); sum += w[e]; }
        for (int e = 0; e < EXP; e++) w[e] /= sum;
        int i0 = 0;
        for (int e = 1; e < EXP; e++) if (w[e] > w[i0]) i0 = e;
        int i1 = -1;
        for (int e = 0; e < EXP; e++) { if (e == i0) continue; if (i1 < 0 || w[e] > w[i1]) i1 = e; }
        float t = w[i0] + w[i1] + 1e-9f;
        for (int e = 0; e < EXP; e++) gates[b*EXP + e] = 0.f;
        gates[b*EXP + i0] = w[i0] / t;
        gates[b*EXP + i1] = w[i1] / t;
    }
}
__global__ void k_slots(const float* __restrict__ gates, int* cnt, int* soff,
                        int* se, int* sb, float* sg,
                        int* xseg, int* kvseg, int* xvalid, int* kvvalid,
                        int* sxb, int* skvb, int* b2s, float* rowg) {
    if (threadIdx.x == 0) {
        int s = 0;
        for (int e = 0; e < EXP; e++) {
            soff[e] = s;
            int c = 0;
            for (int b = 0; b < BATCH; b++) {
                float g = gates[b*EXP + e];
                if (g != 0.f) { se[s] = e; sb[s] = b; sg[s] = g; s++; c++; }
            }
            cnt[e] = c;
        }
        xseg[0] = 0; kvseg[0] = 0;
        for (int e = 0; e < EXP; e++) {
            xvalid[e]  = cnt[e]*NQ_;
            kvvalid[e] = cnt[e]*KVR;
            xseg[e+1]  = xseg[e]  + ((cnt[e]*NQ_ + 127) & ~127);
            kvseg[e+1] = kvseg[e] + ((cnt[e]*KVR + 127) & ~127);
        }
        for (int i = 0; i < NSLOT; i++) {
            int e = se[i];
            sxb[i]  = xseg[e]  + (i - soff[e])*NQ_;
            skvb[i] = kvseg[e] + (i - soff[e])*KVR;
        }
        int fill[BATCH];
        for (int b = 0; b < BATCH; b++) fill[b] = 0;
        for (int i = 0; i < NSLOT; i++) {
            int b = sb[i];
            b2s[b*2 + fill[b]] = i;
            fill[b]++;
        }
    }
    __syncthreads();
    int tot = xseg[EXP];
    for (int r = threadIdx.x; r < tot; r += 32) {
        int e = 0, base = 0;
        for (int i = 0; i < EXP; i++)
            if (r >= xseg[i] && r < xseg[i+1]) { e = i; base = xseg[i]; }
        int local = r - base;
        rowg[r] = (local < cnt[e]*NQ_) ? sg[soff[e] + local/NQ_] : 0.f;
    }
}

// ---------------- init x = full query block per slot ----------------
__global__ void k_initx(const float* __restrict__ query, float* __restrict__ gx,
                        const int* __restrict__ se, const int* __restrict__ sxb) {
    int r = blockIdx.x, s = blockIdx.y;
    int e = se[s];
    const float* srow = query + ((long)e*NQ_ + r)*HID;
    float* d = gx + (long)(sxb[s] + r)*HID;
    for (int i = threadIdx.x; i < HID; i += blockDim.x) d[i] = srow[i];
}

// ---------------- merged LN: x rows + kv0 rows -> fp16 hi/lo ----------------
__global__ void k_ln_all(const float* __restrict__ xsrc,
                         const float* __restrict__ query, const float* __restrict__ img,
                         const float* __restrict__ pp,
                         const float* __restrict__ xw, const float* __restrict__ xb,
                         const float* __restrict__ kw, const float* __restrict__ kb, long pES,
                         u16* __restrict__ xdh, u16* __restrict__ xdl,
                         u16* __restrict__ kdh, u16* __restrict__ kdl,
                         const int* __restrict__ se, const int* __restrict__ sb,
                         const int* __restrict__ sxb, const int* __restrict__ skvb) {
    int rr = blockIdx.x, s = blockIdx.y;
    int e = se[s];
    const float* row;
    const float *w, *bv;
    u16 *dh, *dl;
    long doff;
    if (rr < NQ_) {
        doff = (long)(sxb[s] + rr)*HID;
        row = xsrc + doff;
        w = xw; bv = xb; dh = xdh; dl = xdl;
    } else {
        int r = rr - NQ_;
        int b = sb[s];
        int rl, sq, qo, io;
        if (r < 320)      { rl = r;       sq = 64; qo = 0;   io = 0;   }
        else if (r < 624) { rl = r - 320; sq = 48; qo = 64;  io = 256; }
        else              { rl = r - 624; sq = 32; qo = 112; io = 512; }
        if (rl < sq) row = query + ((long)e*NQ_ + qo + rl)*HID;
        else {
            int zi = io + rl - sq;
            if (zi < LV_) row = img + ((long)b*LV_ + zi)*HID;
            else          row = pp  + ((long)b*LP_ + zi - LV_)*HID;
        }
        doff = (long)(skvb[s] + r)*HID;
        w = kw; bv = kb; dh = kdh; dl = kdl;
    }
    __shared__ float sh[64];
    float v[4]; float sm = 0.f, ss = 0.f;
    #pragma unroll
    for (int t = 0; t < 4; t++) { v[t] = row[threadIdx.x + t*256]; sm += v[t]; ss += v[t]*v[t]; }
    blockReduce2(sm, ss, sh);
    float m  = sm * (1.f/HID);
    float rs = rsqrtf(ss * (1.f/HID) - m*m + 1e-5f);
    const float* we = w + (long)e*pES;
    const float* be = bv + (long)e*pES;
    #pragma unroll
    for (int t = 0; t < 4; t++) {
        int i = threadIdx.x + t*256;
        float rv = (v[t] - m)*rs*we[i] + be[i];
        fsplit1(rv, dh[doff + i], dl[doff + i]);
    }
}

// ---------------- LayerNorm (x rows only, MLP LN) ----------------
__global__ void k_ln(const float* __restrict__ src,
                     const float* __restrict__ w, const float* __restrict__ bvec, long pES,
                     u16* __restrict__ dh, u16* __restrict__ dl,
                     const int* __restrict__ se, const int* __restrict__ sxb) {
    int r = blockIdx.x, s = blockIdx.y;
    int e = se[s];
    long row = (long)(sxb[s] + r)*HID;
    __shared__ float sh[64];
    float v[4]; float sm = 0.f, ss = 0.f;
    #pragma unroll
    for (int t = 0; t < 4; t++) { v[t] = src[row + threadIdx.x + t*256]; sm += v[t]; ss += v[t]*v[t]; }
    blockReduce2(sm, ss, sh);
    float m  = sm * (1.f/HID);
    float rs = rsqrtf(ss * (1.f/HID) - m*m + 1e-5f);
    const float* we = w + (long)e*pES;
    const float* be = bvec + (long)e*pES;
    #pragma unroll
    for (int t = 0; t < 4; t++) {
        int i = threadIdx.x + t*256;
        float rv = (v[t] - m)*rs*we[i] + be[i];
        fsplit1(rv, dh[row + i], dl[row + i]);
    }
}

// ---------------- attention (all stages, 4-way ILP) -> fp16 hi/lo ----------------
__global__ void k_attn(const float* __restrict__ q, const float* __restrict__ kv,
                       u16* __restrict__ ath, u16* __restrict__ atl,
                       const int* __restrict__ sxb, const int* __restrict__ skvb) {
    int s = blockIdx.y, st = blockIdx.z;
    int sq    = (st == 0) ? 64 : (st == 1 ? 48 : 32);
    int qo    = (st == 0) ? 0  : (st == 1 ? 64 : 112);
    int kvo   = (st == 0) ? 0  : (st == 1 ? 320 : 624);
    int kvlen = sq + 256;
    int warp = threadIdx.x >> 5, lane = threadIdx.x & 31;
    int w = blockIdx.x * 4 + warp;
    if (w >= NHEADS * sq) return;
    int h = w / sq, qi = w % sq;
    __shared__ float sc[4][320];

    long qrow  = (long)sxb[s] + qo + qi;
    long kvrow = (long)skvb[s] + kvo;
    const float* qr = q + qrow*HID + h*HDIM;
    float q0 = qr[lane], q1 = qr[lane + 32];
    const float* kbase = kv + kvrow*2048 + h*HDIM;
    float mx = -1e30f;
    for (int j = 0; j < kvlen; j += 4) {
        const float* k0 = kbase + (long)j*2048;
        const float* k1 = k0 + 2048;
        const float* k2 = k1 + 2048;
        const float* k3 = k2 + 2048;
        float p0 = q0*k0[lane] + q1*k0[lane + 32];
        float p1 = q0*k1[lane] + q1*k1[lane + 32];
        float p2 = q0*k2[lane] + q1*k2[lane + 32];
        float p3 = q0*k3[lane] + q1*k3[lane + 32];
        #pragma unroll
        for (int o = 16; o; o >>= 1) {
            p0 += __shfl_xor_sync(~0u, p0, o);
            p1 += __shfl_xor_sync(~0u, p1, o);
            p2 += __shfl_xor_sync(~0u, p2, o);
            p3 += __shfl_xor_sync(~0u, p3, o);
        }
        p0 *= 0.125f; p1 *= 0.125f; p2 *= 0.125f; p3 *= 0.125f;
        if (lane == 0) {
            sc[warp][j]   = p0; sc[warp][j+1] = p1;
            sc[warp][j+2] = p2; sc[warp][j+3] = p3;
        }
        mx = fmaxf(mx, fmaxf(fmaxf(p0, p1), fmaxf(p2, p3)));
    }
    __syncwarp();
    float se_ = 0.f;
    for (int j = lane; j < kvlen; j += 32) {
        float ex = __expf(sc[warp][j] - mx);
        sc[warp][j] = ex;
        se_ += ex;
    }
    #pragma unroll
    for (int o = 16; o; o >>= 1) se_ += __shfl_xor_sync(~0u, se_, o);
    __syncwarp();
    float inv = 1.f / se_;
    const float* vbase = kv + kvrow*2048 + 1024 + h*HDIM;
    float a0 = 0.f, a1 = 0.f;
    #pragma unroll 4
    for (int j = 0; j < kvlen; j++) {
        float p = sc[warp][j];
        const float* vr = vbase + (long)j*2048;
        a0 += p*vr[lane]; a1 += p*vr[lane + 32];
    }
    long ooff = qrow*HID + h*HDIM;
    fsplit1(a0 * inv, ath[ooff + lane],      atl[ooff + lane]);
    fsplit1(a1 * inv, ath[ooff + lane + 32], atl[ooff + lane + 32]);
}

// ---------------- combine 2 slots per batch + gated bias + RMS + final scaling ----------------
__global__ void k_rms_combine(const float* __restrict__ O, const float* __restrict__ bo,
                              float* __restrict__ out, const float* __restrict__ fw,
                              const float* __restrict__ gain,
                              const int* __restrict__ b2s, const int* __restrict__ se,
                              const float* __restrict__ sg, const int* __restrict__ sxb) {
    int qrow = blockIdx.x, b = blockIdx.y;
    int s0 = b2s[b*2], s1 = b2s[b*2 + 1];
    int e0 = se[s0], e1 = se[s1];
    float g0 = sg[s0], g1 = sg[s1];
    long r0 = (long)(sxb[s0] + qrow)*OUTD;
    long r1 = (long)(sxb[s1] + qrow)*OUTD;
    const float* bo0 = bo + (long)e0*OUTD;
    const float* bo1 = bo + (long)e1*OUTD;
    float* orow = out + ((long)b*NQ_ + qrow)*OUTD;
    __shared__ float sh[64];
    float v[16]; float ss = 0.f;
    #pragma unroll
    for (int t = 0; t < 16; t++) {
        int o = threadIdx.x + t*256;
        float val = O[r0 + o] + O[r1 + o] + g0*bo0[o] + g1*bo1[o];
        v[t] = val; ss += val*val;
    }
    ss = blockReduce1(ss, sh);
    float sc = rsqrtf(ss * (1.f/OUTD) + 1e-6f);
    #pragma unroll
    for (int t = 0; t < 16; t++) {
        int o = threadIdx.x + t*256;
        orow[o] = v[t]*sc*fw[o]*gain[o];
    }
}

// ---------------- host orchestration ----------------
extern "C" void kernel_launch(void* const* d_in, const int* in_sizes, int n_in,
                              void* d_out, int out_size) {
    const float* image     = (const float*)d_in[0];
    const float* pp        = (const float*)d_in[1];
    const int*   tids      = (const int*)  d_in[2];
    const int*   eids      = (const int*)  d_in[3];
    const float* query     = (const float*)d_in[4];
    const float* ln1_w     = (const float*)d_in[5];
    const float* ln1_b     = (const float*)d_in[6];
    const float* ln1kv_w   = (const float*)d_in[7];
    const float* ln1kv_b   = (const float*)d_in[8];
    const float* attn_in_w = (const float*)d_in[9];
    const float* attn_in_b = (const float*)d_in[10];
    const float* attn_out_w= (const float*)d_in[11];
    const float* attn_out_b= (const float*)d_in[12];
    const float* ls1       = (const float*)d_in[13];
    const float* ls2       = (const float*)d_in[14];
    const float* ln2_w     = (const float*)d_in[15];
    const float* ln2_b     = (const float*)d_in[16];
    const float* fc_w      = (const float*)d_in[17];
    const float* fc_b      = (const float*)d_in[18];
    const float* proj_w    = (const float*)d_in[19];
    const float* proj_b    = (const float*)d_in[20];
    const float* outp_w    = (const float*)d_in[21];
    const float* outp_b    = (const float*)d_in[22];
    const float* temb      = (const float*)d_in[23];
    const float* eemb      = (const float*)d_in[24];
    const float* glw       = (const float*)d_in[25];
    const float* glb       = (const float*)d_in[26];
    const float* gwt       = (const float*)d_in[27];
    const float* gbias     = (const float*)d_in[28];
    const float* gain      = (const float*)d_in[29];
    const float* fw        = (const float*)d_in[30];
    float* out = (float*)d_out;

    float *px, *pq, *pkv, *po, *pg, *pgi, *psg, *prowg;
    int *pcnt, *psoff, *pse, *psb, *pxseg, *pkvseg, *pxval, *pkvval, *psxb, *pskvb, *pb2s;
    cudaGetSymbolAddress((void**)&px,    g_x);
    cudaGetSymbolAddress((void**)&pq,    g_q);
    cudaGetSymbolAddress((void**)&pkv,   g_kv);
    cudaGetSymbolAddress((void**)&po,    g_o);
    cudaGetSymbolAddress((void**)&pg,    g_gates);
    cudaGetSymbolAddress((void**)&pgi,   g_gi);
    cudaGetSymbolAddress((void**)&pcnt,  g_cnt);
    cudaGetSymbolAddress((void**)&psoff, g_soff);
    cudaGetSymbolAddress((void**)&pse,   g_se);
    cudaGetSymbolAddress((void**)&psb,   g_sb);
    cudaGetSymbolAddress((void**)&psg,   g_sg);
    cudaGetSymbolAddress((void**)&pxseg, g_xseg);
    cudaGetSymbolAddress((void**)&pkvseg,g_kvseg);
    cudaGetSymbolAddress((void**)&pxval, g_xvalid);
    cudaGetSymbolAddress((void**)&pkvval,g_kvvalid);
    cudaGetSymbolAddress((void**)&psxb,  g_sxb);
    cudaGetSymbolAddress((void**)&pskvb, g_skvb);
    cudaGetSymbolAddress((void**)&pb2s,  g_b2s);
    cudaGetSymbolAddress((void**)&prowg, g_rowg);

    u16 *xh, *xl, *kh, *kl, *ah, *al, *fh, *fl;
    cudaGetSymbolAddress((void**)&xh, g_xln_h); cudaGetSymbolAddress((void**)&xl, g_xln_l);
    cudaGetSymbolAddress((void**)&kh, g_kvn_h); cudaGetSymbolAddress((void**)&kl, g_kvn_l);
    cudaGetSymbolAddress((void**)&ah, g_att_h); cudaGetSymbolAddress((void**)&al, g_att_l);
    cudaGetSymbolAddress((void**)&fh, g_ffn_h); cudaGetSymbolAddress((void**)&fl, g_ffn_l);

    u16 *aiw, *aow, *fcw, *pjw, *opw;
    cudaGetSymbolAddress((void**)&aiw, g_aiw);
    cudaGetSymbolAddress((void**)&aow, g_aow);
    cudaGetSymbolAddress((void**)&fcw, g_fcw);
    cudaGetSymbolAddress((void**)&pjw, g_pjw);
    cudaGetSymbolAddress((void**)&opw, g_opw);

    cudaFuncSetAttribute(k_tgemm,     cudaFuncAttributeMaxDynamicSharedMemorySize, TG_DSMEM);
    cudaFuncSetAttribute(k_tgemm_qkv, cudaFuncAttributeMaxDynamicSharedMemorySize, TG_DSMEM);

    k_cvt_all<<<2048, 256>>>(
        (const float4*)attn_in_w,  (uint2*)aiw,
        (const float4*)attn_out_w, (uint2*)aow,
        (const float4*)fc_w,       (uint2*)fcw,
        (const float4*)proj_w,     (uint2*)pjw,
        (const float4*)outp_w,     (uint2*)opw);

    k_gate_mean<<<dim3(BATCH, 16), 256>>>(image, pgi);
    k_gate<<<BATCH, 256>>>(pgi, temb, eemb, tids, eids, glw, glb, gwt, gbias, pg);
    k_slots<<<1, 32>>>(pg, pcnt, psoff, pse, psb, psg,
                       pxseg, pkvseg, pxval, pkvval, psxb, pskvb, pb2s, prowg);

    k_initx<<<dim3(NQ_, NSLOT), 256>>>(query, px, pse, psxb);

    const long HH = (long)HID*HID;
    const int XMB = 22;
    const int KVMB = 118;

    for (int l = 0; l < NLAYERS; l++) {
        k_ln_all<<<dim3(NQ_ + KVR, NSLOT), 256>>>(px, query, image, pp,
            ln1_w + (long)l*HID, ln1_b + (long)l*HID,
            ln1kv_w + (long)l*HID, ln1kv_b + (long)l*HID, (long)NLAYERS*HID,
            xh, xl, kh, kl, pse, psb, psxb, pskvb);
        k_tgemm_qkv<<<dim3(16, XMB + KVMB), 256, TG_DSMEM>>>(XMB,
            xh, xl, aiw + (long)l*3*HH,
            attn_in_b + (long)l*3*HID, pq, pxseg, pxval,
            kh, kl, aiw + (long)l*3*HH + HH,
            attn_in_b + (long)l*3*HID + HID, pkv, pkvseg, pkvval,
            (long)NLAYERS*3*HH, (long)NLAYERS*3*HID);
        k_attn<<<dim3(256, NSLOT, 3), 128>>>(pq, pkv, ah, al, psxb, pskvb);
        k_tgemm<<<dim3(8, XMB), 256, TG_DSMEM>>>(HID, HID,
            ah, al, aow + (long)l*HH, (long)NLAYERS*HH,
            attn_out_b + (long)l*HID, (long)NLAYERS*HID,
            px, (u16*)0, (u16*)0, ls1 + (long)l*HID, (long)NLAYERS*HID,
            (const float*)0, 2, pxseg, pxval);
        k_ln<<<dim3(NQ_, NSLOT), 256>>>(px,
            ln2_w + (long)l*HID, ln2_b + (long)l*HID, (long)NLAYERS*HID,
            xh, xl, pse, psxb);
        k_tgemm<<<dim3(32, XMB), 256, TG_DSMEM>>>(4*HID, HID,
            xh, xl, fcw + (long)l*4*HH, (long)NLAYERS*4*HH,
            fc_b + (long)l*4*HID, (long)NLAYERS*4*HID,
            (float*)0, fh, fl, (const float*)0, 0,
            (const float*)0, 1, pxseg, pxval);
        // proj GEMM; last layer fuses gate-scaled fp16 split of final x (epi 4)
        k_tgemm<<<dim3(8, XMB), 256, TG_DSMEM>>>(HID, 4*HID,
            fh, fl, pjw + (long)l*4*HH, (long)NLAYERS*4*HH,
            proj_b + (long)l*HID, (long)NLAYERS*HID,
            px, xh, xl, ls2 + (long)l*HID, (long)NLAYERS*HID,
            prowg, (l == NLAYERS-1) ? 4 : 2, pxseg, pxval);
    }

    // out projection reads gate-scaled fp16 x (written by epi 4)
    k_tgemm<<<dim3(OUTD/128, XMB), 256, TG_DSMEM>>>(OUTD, HID,
        xh, xl, opw, (long)OUTD*HID,
        (const float*)0, 0,
        po, (u16*)0, (u16*)0, (const float*)0, 0,
        (const float*)0, 3, pxseg, pxval);
    k_rms_combine<<<dim3(NQ_, BATCH), 256>>>(po, outp_b, out, fw, gain, pb2s, pse, psg, psxb);
}

// round 11
// speedup vs baseline: 4.3965x; 1.0515x over previous
#include <cuda_runtime.h>
#include <cuda_fp16.h>
#include <math.h>
#include <stdint.h>

typedef unsigned short u16;

// ---------------- problem constants ----------------
#define EXP    4
#define BATCH  8
#define NQ_    144
#define NLAYERS 2
#define NHEADS 16
#define HDIM   64
#define HID    1024
#define OUTD   4096
#define TDIM   256
#define LV_    576
#define LP_    192
#define NSLOT  16
#define GN     (HID + 2*TDIM)   // 1536
#define KVR    912              // 320+304+288 kv rows per slot
#define XROWS  3072
#define KVROWS 16384

// ---------------- fp32 scratch ----------------
__device__ float g_x   [XROWS*HID];
__device__ float g_o   [XROWS*OUTD];
__device__ float g_gates[BATCH*EXP];
__device__ float g_gi  [BATCH*HID];

// fp16 Q / KV buffers (written by GEMM epi 5, read by attention)
__device__ u16 g_q16 [XROWS*HID];
__device__ u16 g_kv16[KVROWS*2048];   // K | V

// slot metadata
__device__ int   g_cnt[EXP], g_soff[EXP];
__device__ int   g_se[NSLOT], g_sb[NSLOT];
__device__ float g_sg[NSLOT];
__device__ int   g_xseg[EXP+1], g_kvseg[EXP+1];
__device__ int   g_xvalid[EXP], g_kvvalid[EXP];
__device__ int   g_sxb[NSLOT], g_skvb[NSLOT];
__device__ int   g_b2s[BATCH*2];
__device__ float g_rowg[XROWS];

// ---------------- fp16 hi/lo activation scratch ----------------
__device__ u16 g_xln_h[XROWS*HID],  g_xln_l[XROWS*HID];
__device__ u16 g_kvn_h[KVROWS*HID], g_kvn_l[KVROWS*HID];
__device__ u16 g_att_h[XROWS*HID],  g_att_l[XROWS*HID];
__device__ u16 g_ffn_h[XROWS*4096], g_ffn_l[XROWS*4096];

// ---------------- fp16 weight scratch ----------------
#define AIW_N (EXP*NLAYERS*3*HID*HID)
#define AOW_N (EXP*NLAYERS*HID*HID)
#define FCW_N (EXP*NLAYERS*4*HID*HID)
#define PJW_N (EXP*NLAYERS*HID*4*HID)
#define OPW_N (EXP*OUTD*HID)
__device__ u16 g_aiw[AIW_N];
__device__ u16 g_aow[AOW_N];
__device__ u16 g_fcw[FCW_N];
__device__ u16 g_pjw[PJW_N];
__device__ u16 g_opw[OPW_N];

// ================= helpers =================
__device__ __forceinline__ void mma16816(float* c, const uint32_t* a, const uint32_t* b) {
    asm volatile("mma.sync.aligned.m16n8k16.row.col.f32.f16.f16.f32 "
        "{%0,%1,%2,%3}, {%4,%5,%6,%7}, {%8,%9}, {%0,%1,%2,%3};"
        : "+f"(c[0]), "+f"(c[1]), "+f"(c[2]), "+f"(c[3])
        : "r"(a[0]), "r"(a[1]), "r"(a[2]), "r"(a[3]), "r"(b[0]), "r"(b[1]));
}
__device__ __forceinline__ void fsplit1(float v, u16& h, u16& l) {
    __half hh = __float2half(v);
    h = __half_as_ushort(hh);
    l = __half_as_ushort(__float2half(v - __half2float(hh)));
}
__device__ __forceinline__ uint2 cvt4h(float4 v) {
    __half2 a = __floats2half2_rn(v.x, v.y);
    __half2 b = __floats2half2_rn(v.z, v.w);
    uint2 r;
    r.x = *reinterpret_cast<uint32_t*>(&a);
    r.y = *reinterpret_cast<uint32_t*>(&b);
    return r;
}
__device__ __forceinline__ uint32_t smem_u32(const void* p) {
    uint32_t a;
    asm("{ .reg .u64 t; cvta.to.shared.u64 t, %1; cvt.u32.u64 %0, t; }" : "=r"(a) : "l"(p));
    return a;
}
#define CP16(dst, src) asm volatile("cp.async.cg.shared.global [%0], [%1], 16;" :: "r"(dst), "l"(src) : "memory")
#define CPCOMMIT() asm volatile("cp.async.commit_group;" ::: "memory")
#define CPWAIT0()  asm volatile("cp.async.wait_group 0;" ::: "memory")

// ---------------- merged weight convert fp32 -> fp16 (single launch) ----------------
__global__ void k_cvt_all(const float4* __restrict__ s0, uint2* __restrict__ d0,
                          const float4* __restrict__ s1, uint2* __restrict__ d1,
                          const float4* __restrict__ s2, uint2* __restrict__ d2,
                          const float4* __restrict__ s3, uint2* __restrict__ d3,
                          const float4* __restrict__ s4, uint2* __restrict__ d4) {
    const long n0 = AIW_N/4, n1 = AOW_N/4, n2 = FCW_N/4, n3 = PJW_N/4, n4 = OPW_N/4;
    const long total = n0 + n1 + n2 + n3 + n4;
    long stride = (long)gridDim.x * blockDim.x;
    for (long i = (long)blockIdx.x * blockDim.x + threadIdx.x; i < total; i += stride) {
        const float4* s; uint2* d; long k = i;
        if (k < n0)              { s = s0; d = d0; }
        else if ((k -= n0) < n1) { s = s1; d = d1; }
        else if ((k -= n1) < n2) { s = s2; d = d2; }
        else if ((k -= n2) < n3) { s = s3; d = d3; }
        else                     { k -= n3; s = s4; d = d4; }
        d[k] = cvt4h(s[k]);
    }
}

#define PITCH 20
#define ARR_U32 (128*PITCH)        // 2560
#define BUF_U32 (3*ARR_U32)        // 7680
#define TG_DSMEM (2*BUF_U32*4)     // 61440 bytes

// ================= GEMM body: C(block m0,n0) = (Ah+Al) @ W^T  (2 MMA terms) =================
// epi 0: fp32 acc+bias. 1: split(gelu)->hi/lo. 2: C+=ls*(acc+bias). 3: C=acc.
// epi 4: C+=ls*(..); Chi/Clo = fsplit(rowg*C). 5: Chi(fp16) = acc+bias.
__device__ __forceinline__ void tgemm_body(
    int N, int K, int m0, int n0, int base, int vrows,
    const u16* __restrict__ Ah, const u16* __restrict__ Al,
    const u16* __restrict__ WE,
    const float* __restrict__ bias,
    float* __restrict__ C, u16* __restrict__ Chi, u16* __restrict__ Clo,
    const float* __restrict__ ls, const float* __restrict__ rowg,
    int epi, uint32_t* SM)
{
    uint32_t smb = smem_u32(SM);
    int tid = threadIdx.x;
    int warp = tid >> 5, lane = tid & 31;
    int wm = warp & 3, wn = warp >> 2;
    int g8 = lane >> 2, tg = lane & 3;

    const u16* src[3][2];
    uint32_t doff[2];
    #pragma unroll
    for (int j = 0; j < 2; ++j) {
        int lin = j * 256 + tid;
        int row = lin >> 2, q = lin & 3;
        doff[j] = (uint32_t)(row * PITCH + q * 4) * 4;
        src[0][j] = Ah + (long)(m0 + row) * K + q * 8;
        src[1][j] = Al + (long)(m0 + row) * K + q * 8;
        src[2][j] = WE + (long)(n0 + row) * K + q * 8;
    }

    float acc[2][8][4] = {};
    int nch = K >> 5;

    #pragma unroll
    for (int a = 0; a < 3; ++a)
        #pragma unroll
        for (int j = 0; j < 2; ++j)
            CP16(smb + a * (ARR_U32*4) + doff[j], src[a][j]);
    CPCOMMIT();

    for (int c = 0; c < nch; ++c) {
        CPWAIT0();
        __syncthreads();
        if (c + 1 < nch) {
            long koff = (long)(c + 1) * 32;
            uint32_t bb = smb + ((c + 1) & 1) * (BUF_U32*4);
            #pragma unroll
            for (int a = 0; a < 3; ++a)
                #pragma unroll
                for (int j = 0; j < 2; ++j)
                    CP16(bb + a * (ARR_U32*4) + doff[j], src[a][j] + koff);
            CPCOMMIT();
        }
        const uint32_t* B = SM + (c & 1) * BUF_U32;
        const uint32_t* AsH = B;
        const uint32_t* AsL = B + ARR_U32;
        const uint32_t* Bs  = B + 2*ARR_U32;
        #pragma unroll
        for (int kh = 0; kh < 2; ++kh) {
            int kb = kh * 8;
            uint32_t ah[2][4], al[2][4];
            #pragma unroll
            for (int mt = 0; mt < 2; ++mt) {
                int r = wm * 32 + mt * 16 + g8;
                ah[mt][0] = AsH[r*PITCH + kb+tg];       ah[mt][1] = AsH[(r+8)*PITCH + kb+tg];
                ah[mt][2] = AsH[r*PITCH + kb+tg+4];     ah[mt][3] = AsH[(r+8)*PITCH + kb+tg+4];
                al[mt][0] = AsL[r*PITCH + kb+tg];       al[mt][1] = AsL[(r+8)*PITCH + kb+tg];
                al[mt][2] = AsL[r*PITCH + kb+tg+4];     al[mt][3] = AsL[(r+8)*PITCH + kb+tg+4];
            }
            #pragma unroll
            for (int nt = 0; nt < 8; ++nt) {
                int n = wn * 64 + nt * 8 + g8;
                uint32_t b2[2] = { Bs[n*PITCH + kb+tg], Bs[n*PITCH + kb+tg+4] };
                #pragma unroll
                for (int mt = 0; mt < 2; ++mt) {
                    mma16816(acc[mt][nt], ah[mt], b2);
                    mma16816(acc[mt][nt], al[mt], b2);
                }
            }
        }
        __syncthreads();
    }

    #pragma unroll
    for (int mt = 0; mt < 2; ++mt) {
        int r0 = m0 + wm * 32 + mt * 16 + g8;
        int r1 = r0 + 8;
        bool ok0 = (r0 - base) < vrows;
        bool ok1 = (r1 - base) < vrows;
        #pragma unroll
        for (int nt = 0; nt < 8; ++nt) {
            int col = n0 + wn * 64 + nt * 8 + tg * 2;
            float* cc = acc[mt][nt];
            #pragma unroll
            for (int q = 0; q < 4; ++q) {
                int row = (q < 2) ? r0 : r1;
                bool ok = (q < 2) ? ok0 : ok1;
                if (!ok) continue;
                int cl = col + (q & 1);
                long idx = (long)row * N + cl;
                if (epi == 3) { C[idx] = cc[q]; continue; }
                float v = cc[q] + bias[cl];
                if (epi == 1) {
                    float gv = 0.5f * v * (1.f + erff(v * 0.70710678118654752f));
                    fsplit1(gv, Chi[idx], Clo[idx]);
                } else if (epi == 2) {
                    C[idx] = C[idx] + ls[cl] * v;
                } else if (epi == 4) {
                    float nv = C[idx] + ls[cl] * v;
                    C[idx] = nv;
                    fsplit1(rowg[row] * nv, Chi[idx], Clo[idx]);
                } else if (epi == 5) {
                    Chi[idx] = __half_as_ushort(__float2half(v));
                } else {
                    C[idx] = v;
                }
            }
        }
    }
}

__device__ __forceinline__ int resolve_expert(int m0, const int* segbase, int& base) {
    int e = -1; base = 0;
    #pragma unroll
    for (int i = 0; i < EXP; ++i)
        if (e < 0 && m0 >= segbase[i] && m0 < segbase[i+1]) { e = i; base = segbase[i]; }
    return e;
}

// ================= standard single-config GEMM =================
__global__ __launch_bounds__(256, 2) void k_tgemm(
    int N, int K,
    const u16* __restrict__ Ah, const u16* __restrict__ Al,
    const u16* __restrict__ W, long wES,
    const float* __restrict__ biasB, long bES,
    float* __restrict__ C, u16* __restrict__ Chi, u16* __restrict__ Clo,
    const float* __restrict__ lsB, long lsES,
    const float* __restrict__ rowg,
    int epi, const int* __restrict__ segbase, const int* __restrict__ valid)
{
    int m0 = blockIdx.y * 128, n0 = blockIdx.x * 128;
    int base, e = resolve_expert(m0, segbase, base);
    if (e < 0) return;
    extern __shared__ uint32_t SM[];
    tgemm_body(N, K, m0, n0, base, valid[e],
               Ah, Al, W + (long)e*wES,
               biasB ? (biasB + (long)e*bES) : (const float*)0,
               C, Chi, Clo, lsB ? (lsB + (long)e*lsES) : (const float*)0, rowg, epi, SM);
}

// ================= dual GEMM: Q-proj + KV-proj, fp16 outputs (epi 5) =================
__global__ __launch_bounds__(256, 2) void k_tgemm_qkv(
    int ymid,
    const u16* __restrict__ QAh, const u16* __restrict__ QAl,
    const u16* __restrict__ QW, const float* __restrict__ Qbias,
    u16* __restrict__ QC16,
    const int* __restrict__ qseg, const int* __restrict__ qval,
    const u16* __restrict__ KAh, const u16* __restrict__ KAl,
    const u16* __restrict__ KW, const float* __restrict__ Kbias,
    u16* __restrict__ KC16,
    const int* __restrict__ kseg, const int* __restrict__ kval,
    long wES, long bES)
{
    extern __shared__ uint32_t SM[];
    if ((int)blockIdx.y < ymid) {
        if (blockIdx.x >= 8) return;
        int m0 = blockIdx.y * 128, n0 = blockIdx.x * 128;
        int base, e = resolve_expert(m0, qseg, base);
        if (e < 0) return;
        tgemm_body(HID, HID, m0, n0, base, qval[e],
                   QAh, QAl, QW + (long)e*wES,
                   Qbias, (float*)0, QC16, (u16*)0, (const float*)0, (const float*)0, 5, SM);
    } else {
        int m0 = (blockIdx.y - ymid) * 128, n0 = blockIdx.x * 128;
        int base, e = resolve_expert(m0, kseg, base);
        if (e < 0) return;
        tgemm_body(2048, HID, m0, n0, base, kval[e],
                   KAh, KAl, KW + (long)e*wES,
                   Kbias + (long)e*bES, (float*)0, KC16, (u16*)0, (const float*)0, (const float*)0, 5, SM);
    }
}

// ---------------- reductions ----------------
__device__ __forceinline__ void blockReduce2(float& a, float& b, float* sh) {
    __syncthreads();
    int lane = threadIdx.x & 31, wid = threadIdx.x >> 5;
    #pragma unroll
    for (int o = 16; o; o >>= 1) { a += __shfl_xor_sync(~0u, a, o); b += __shfl_xor_sync(~0u, b, o); }
    if (lane == 0) { sh[wid] = a; sh[wid + 32] = b; }
    __syncthreads();
    int nw = blockDim.x >> 5;
    if (wid == 0) {
        a = (lane < nw) ? sh[lane] : 0.f;
        b = (lane < nw) ? sh[lane + 32] : 0.f;
        #pragma unroll
        for (int o = 16; o; o >>= 1) { a += __shfl_xor_sync(~0u, a, o); b += __shfl_xor_sync(~0u, b, o); }
        if (lane == 0) { sh[0] = a; sh[32] = b; }
    }
    __syncthreads();
    a = sh[0]; b = sh[32];
}
__device__ __forceinline__ float blockReduce1(float a, float* sh) {
    __syncthreads();
    int lane = threadIdx.x & 31, wid = threadIdx.x >> 5;
    #pragma unroll
    for (int o = 16; o; o >>= 1) a += __shfl_xor_sync(~0u, a, o);
    if (lane == 0) sh[wid] = a;
    __syncthreads();
    int nw = blockDim.x >> 5;
    if (wid == 0) {
        a = (lane < nw) ? sh[lane] : 0.f;
        #pragma unroll
        for (int o = 16; o; o >>= 1) a += __shfl_xor_sync(~0u, a, o);
        if (lane == 0) sh[0] = a;
    }
    __syncthreads();
    return sh[0];
}

// ---------------- gate kernels ----------------
__global__ void k_gate_mean(const float* __restrict__ img, float* __restrict__ gi) {
    int b = blockIdx.x;
    int h = blockIdx.y * 64 + (threadIdx.x & 63);
    int part = threadIdx.x >> 6;
    __shared__ float sh[256];
    float s = 0.f;
    for (int l = part; l < LV_; l += 4)
        s += img[((long)b*LV_ + l)*HID + h];
    sh[threadIdx.x] = s;
    __syncthreads();
    if (part == 0) {
        float tot = sh[threadIdx.x] + sh[threadIdx.x + 64] + sh[threadIdx.x + 128] + sh[threadIdx.x + 192];
        gi[b*HID + h] = tot * (1.f/LV_);
    }
}
__global__ void k_gate(const float* __restrict__ gi, const float* __restrict__ temb,
                       const float* __restrict__ eemb, const int* __restrict__ tids,
                       const int* __restrict__ eids, const float* __restrict__ glw,
                       const float* __restrict__ glb, const float* __restrict__ gwt,
                       const float* __restrict__ gbias, float* __restrict__ gates) {
    int b = blockIdx.x, tid = threadIdx.x;
    __shared__ float sh[64];
    __shared__ float logits[EXP];
    int ti = tids[b], ei = eids[b];
    float s = 0.f, ss = 0.f;
    for (int i = tid; i < GN; i += 256) {
        float v = (i < HID) ? gi[b*HID + i]
                : (i < HID + TDIM) ? temb[ti*TDIM + i - HID]
                : eemb[ei*TDIM + i - HID - TDIM];
        s += v; ss += v*v;
    }
    blockReduce2(s, ss, sh);
    float m  = s * (1.f/GN);
    float rs = rsqrtf(ss * (1.f/GN) - m*m + 1e-5f);
    for (int e = 0; e < EXP; e++) {
        float d = 0.f;
        for (int i = tid; i < GN; i += 256) {
            float v = (i < HID) ? gi[b*HID + i]
                    : (i < HID + TDIM) ? temb[ti*TDIM + i - HID]
                    : eemb[ei*TDIM + i - HID - TDIM];
            d += ((v - m)*rs*glw[i] + glb[i]) * gwt[(long)e*GN + i];
        }
        d = blockReduce1(d, sh);
        if (tid == 0) logits[e] = d + gbias[e];
    }
    __syncthreads();
    if (tid == 0) {
        float w[EXP]; float mx = -1e30f;
        for (int e = 0; e < EXP; e++) { float l = fminf(fmaxf(logits[e], -15.f), 15.f); w[e] = l; mx = fmaxf(mx, l); }
        float sum = 0.f;
        for (int e = 0; e < EXP; e++) { w[e] = expf(w[e] - mx); sum += w[e]; }
        for (int e = 0; e < EXP; e++) w[e] /= sum;
        int i0 = 0;
        for (int e = 1; e < EXP; e++) if (w[e] > w[i0]) i0 = e;
        int i1 = -1;
        for (int e = 0; e < EXP; e++) { if (e == i0) continue; if (i1 < 0 || w[e] > w[i1]) i1 = e; }
        float t = w[i0] + w[i1] + 1e-9f;
        for (int e = 0; e < EXP; e++) gates[b*EXP + e] = 0.f;
        gates[b*EXP + i0] = w[i0] / t;
        gates[b*EXP + i1] = w[i1] / t;
    }
}
__global__ void k_slots(const float* __restrict__ gates, int* cnt, int* soff,
                        int* se, int* sb, float* sg,
                        int* xseg, int* kvseg, int* xvalid, int* kvvalid,
                        int* sxb, int* skvb, int* b2s, float* rowg) {
    if (threadIdx.x == 0) {
        int s = 0;
        for (int e = 0; e < EXP; e++) {
            soff[e] = s;
            int c = 0;
            for (int b = 0; b < BATCH; b++) {
                float g = gates[b*EXP + e];
                if (g != 0.f) { se[s] = e; sb[s] = b; sg[s] = g; s++; c++; }
            }
            cnt[e] = c;
        }
        xseg[0] = 0; kvseg[0] = 0;
        for (int e = 0; e < EXP; e++) {
            xvalid[e]  = cnt[e]*NQ_;
            kvvalid[e] = cnt[e]*KVR;
            xseg[e+1]  = xseg[e]  + ((cnt[e]*NQ_ + 127) & ~127);
            kvseg[e+1] = kvseg[e] + ((cnt[e]*KVR + 127) & ~127);
        }
        for (int i = 0; i < NSLOT; i++) {
            int e = se[i];
            sxb[i]  = xseg[e]  + (i - soff[e])*NQ_;
            skvb[i] = kvseg[e] + (i - soff[e])*KVR;
        }
        int fill[BATCH];
        for (int b = 0; b < BATCH; b++) fill[b] = 0;
        for (int i = 0; i < NSLOT; i++) {
            int b = sb[i];
            b2s[b*2 + fill[b]] = i;
            fill[b]++;
        }
    }
    __syncthreads();
    int tot = xseg[EXP];
    for (int r = threadIdx.x; r < tot; r += blockDim.x) {
        int e = 0, base = 0;
        for (int i = 0; i < EXP; i++)
            if (r >= xseg[i] && r < xseg[i+1]) { e = i; base = xseg[i]; }
        int local = r - base;
        rowg[r] = (local < cnt[e]*NQ_) ? sg[soff[e] + local/NQ_] : 0.f;
    }
}

// ---------------- init x = full query block per slot ----------------
__global__ void k_initx(const float* __restrict__ query, float* __restrict__ gx,
                        const int* __restrict__ se, const int* __restrict__ sxb) {
    int r = blockIdx.x, s = blockIdx.y;
    int e = se[s];
    const float* srow = query + ((long)e*NQ_ + r)*HID;
    float* d = gx + (long)(sxb[s] + r)*HID;
    for (int i = threadIdx.x; i < HID; i += blockDim.x) d[i] = srow[i];
}

// ---------------- merged LN: x rows + kv0 rows -> fp16 hi/lo ----------------
__global__ void k_ln_all(const float* __restrict__ xsrc,
                         const float* __restrict__ query, const float* __restrict__ img,
                         const float* __restrict__ pp,
                         const float* __restrict__ xw, const float* __restrict__ xb,
                         const float* __restrict__ kw, const float* __restrict__ kb, long pES,
                         u16* __restrict__ xdh, u16* __restrict__ xdl,
                         u16* __restrict__ kdh, u16* __restrict__ kdl,
                         const int* __restrict__ se, const int* __restrict__ sb,
                         const int* __restrict__ sxb, const int* __restrict__ skvb) {
    int rr = blockIdx.x, s = blockIdx.y;
    int e = se[s];
    const float* row;
    const float *w, *bv;
    u16 *dh, *dl;
    long doff;
    if (rr < NQ_) {
        doff = (long)(sxb[s] + rr)*HID;
        row = xsrc + doff;
        w = xw; bv = xb; dh = xdh; dl = xdl;
    } else {
        int r = rr - NQ_;
        int b = sb[s];
        int rl, sq, qo, io;
        if (r < 320)      { rl = r;       sq = 64; qo = 0;   io = 0;   }
        else if (r < 624) { rl = r - 320; sq = 48; qo = 64;  io = 256; }
        else              { rl = r - 624; sq = 32; qo = 112; io = 512; }
        if (rl < sq) row = query + ((long)e*NQ_ + qo + rl)*HID;
        else {
            int zi = io + rl - sq;
            if (zi < LV_) row = img + ((long)b*LV_ + zi)*HID;
            else          row = pp  + ((long)b*LP_ + zi - LV_)*HID;
        }
        doff = (long)(skvb[s] + r)*HID;
        w = kw; bv = kb; dh = kdh; dl = kdl;
    }
    __shared__ float sh[64];
    float v[4]; float sm = 0.f, ss = 0.f;
    #pragma unroll
    for (int t = 0; t < 4; t++) { v[t] = row[threadIdx.x + t*256]; sm += v[t]; ss += v[t]*v[t]; }
    blockReduce2(sm, ss, sh);
    float m  = sm * (1.f/HID);
    float rs = rsqrtf(ss * (1.f/HID) - m*m + 1e-5f);
    const float* we = w + (long)e*pES;
    const float* be = bv + (long)e*pES;
    #pragma unroll
    for (int t = 0; t < 4; t++) {
        int i = threadIdx.x + t*256;
        float rv = (v[t] - m)*rs*we[i] + be[i];
        fsplit1(rv, dh[doff + i], dl[doff + i]);
    }
}

// ---------------- LayerNorm (x rows only, MLP LN) ----------------
__global__ void k_ln(const float* __restrict__ src,
                     const float* __restrict__ w, const float* __restrict__ bvec, long pES,
                     u16* __restrict__ dh, u16* __restrict__ dl,
                     const int* __restrict__ se, const int* __restrict__ sxb) {
    int r = blockIdx.x, s = blockIdx.y;
    int e = se[s];
    long row = (long)(sxb[s] + r)*HID;
    __shared__ float sh[64];
    float v[4]; float sm = 0.f, ss = 0.f;
    #pragma unroll
    for (int t = 0; t < 4; t++) { v[t] = src[row + threadIdx.x + t*256]; sm += v[t]; ss += v[t]*v[t]; }
    blockReduce2(sm, ss, sh);
    float m  = sm * (1.f/HID);
    float rs = rsqrtf(ss * (1.f/HID) - m*m + 1e-5f);
    const float* we = w + (long)e*pES;
    const float* be = bvec + (long)e*pES;
    #pragma unroll
    for (int t = 0; t < 4; t++) {
        int i = threadIdx.x + t*256;
        float rv = (v[t] - m)*rs*we[i] + be[i];
        fsplit1(rv, dh[row + i], dl[row + i]);
    }
}

// ---------------- attention (fp16 Q/KV, 4-way ILP) -> fp16 hi/lo ----------------
__global__ void k_attn(const u16* __restrict__ q16, const u16* __restrict__ kv16,
                       u16* __restrict__ ath, u16* __restrict__ atl,
                       const int* __restrict__ sxb, const int* __restrict__ skvb) {
    int s = blockIdx.y, st = blockIdx.z;
    int sq    = (st == 0) ? 64 : (st == 1 ? 48 : 32);
    int qo    = (st == 0) ? 0  : (st == 1 ? 64 : 112);
    int kvo   = (st == 0) ? 0  : (st == 1 ? 320 : 624);
    int kvlen = sq + 256;
    int warp = threadIdx.x >> 5, lane = threadIdx.x & 31;
    int w = blockIdx.x * 4 + warp;
    if (w >= NHEADS * sq) return;
    int h = w / sq, qi = w % sq;
    __shared__ float sc[4][320];

    long qrow  = (long)sxb[s] + qo + qi;
    long kvrow = (long)skvb[s] + kvo;
    const __half2 qh = *(const __half2*)(q16 + qrow*HID + h*HDIM + lane*2);
    float q0 = __low2float(qh), q1 = __high2float(qh);
    const u16* kbase = kv16 + kvrow*2048 + h*HDIM + lane*2;
    float mx = -1e30f;
    for (int j = 0; j < kvlen; j += 4) {
        __half2 k0 = *(const __half2*)(kbase + (long)j*2048);
        __half2 k1 = *(const __half2*)(kbase + (long)(j+1)*2048);
        __half2 k2 = *(const __half2*)(kbase + (long)(j+2)*2048);
        __half2 k3 = *(const __half2*)(kbase + (long)(j+3)*2048);
        float p0 = q0*__low2float(k0) + q1*__high2float(k0);
        float p1 = q0*__low2float(k1) + q1*__high2float(k1);
        float p2 = q0*__low2float(k2) + q1*__high2float(k2);
        float p3 = q0*__low2float(k3) + q1*__high2float(k3);
        #pragma unroll
        for (int o = 16; o; o >>= 1) {
            p0 += __shfl_xor_sync(~0u, p0, o);
            p1 += __shfl_xor_sync(~0u, p1, o);
            p2 += __shfl_xor_sync(~0u, p2, o);
            p3 += __shfl_xor_sync(~0u, p3, o);
        }
        p0 *= 0.125f; p1 *= 0.125f; p2 *= 0.125f; p3 *= 0.125f;
        if (lane == 0) {
            sc[warp][j]   = p0; sc[warp][j+1] = p1;
            sc[warp][j+2] = p2; sc[warp][j+3] = p3;
        }
        mx = fmaxf(mx, fmaxf(fmaxf(p0, p1), fmaxf(p2, p3)));
    }
    __syncwarp();
    float se_ = 0.f;
    for (int j = lane; j < kvlen; j += 32) {
        float ex = __expf(sc[warp][j] - mx);
        sc[warp][j] = ex;
        se_ += ex;
    }
    #pragma unroll
    for (int o = 16; o; o >>= 1) se_ += __shfl_xor_sync(~0u, se_, o);
    __syncwarp();
    float inv = 1.f / se_;
    const u16* vbase = kv16 + kvrow*2048 + 1024 + h*HDIM + lane*2;
    float a0 = 0.f, a1 = 0.f;
    #pragma unroll 4
    for (int j = 0; j < kvlen; j++) {
        float p = sc[warp][j];
        __half2 vv = *(const __half2*)(vbase + (long)j*2048);
        a0 += p*__low2float(vv); a1 += p*__high2float(vv);
    }
    long ooff = qrow*HID + h*HDIM + lane*2;
    fsplit1(a0 * inv, ath[ooff],     atl[ooff]);
    fsplit1(a1 * inv, ath[ooff + 1], atl[ooff + 1]);
}

// ---------------- combine 2 slots per batch + gated bias + RMS + final scaling ----------------
__global__ void k_rms_combine(const float* __restrict__ O, const float* __restrict__ bo,
                              float* __restrict__ out, const float* __restrict__ fw,
                              const float* __restrict__ gain,
                              const int* __restrict__ b2s, const int* __restrict__ se,
                              const float* __restrict__ sg, const int* __restrict__ sxb) {
    int qrow = blockIdx.x, b = blockIdx.y;
    int s0 = b2s[b*2], s1 = b2s[b*2 + 1];
    int e0 = se[s0], e1 = se[s1];
    float g0 = sg[s0], g1 = sg[s1];
    long r0 = (long)(sxb[s0] + qrow)*OUTD;
    long r1 = (long)(sxb[s1] + qrow)*OUTD;
    const float* bo0 = bo + (long)e0*OUTD;
    const float* bo1 = bo + (long)e1*OUTD;
    float* orow = out + ((long)b*NQ_ + qrow)*OUTD;
    __shared__ float sh[64];
    float v[16]; float ss = 0.f;
    #pragma unroll
    for (int t = 0; t < 16; t++) {
        int o = threadIdx.x + t*256;
        float val = O[r0 + o] + O[r1 + o] + g0*bo0[o] + g1*bo1[o];
        v[t] = val; ss += val*val;
    }
    ss = blockReduce1(ss, sh);
    float sc = rsqrtf(ss * (1.f/OUTD) + 1e-6f);
    #pragma unroll
    for (int t = 0; t < 16; t++) {
        int o = threadIdx.x + t*256;
        orow[o] = v[t]*sc*fw[o]*gain[o];
    }
}

// ---------------- host orchestration ----------------
extern "C" void kernel_launch(void* const* d_in, const int* in_sizes, int n_in,
                              void* d_out, int out_size) {
    const float* image     = (const float*)d_in[0];
    const float* pp        = (const float*)d_in[1];
    const int*   tids      = (const int*)  d_in[2];
    const int*   eids      = (const int*)  d_in[3];
    const float* query     = (const float*)d_in[4];
    const float* ln1_w     = (const float*)d_in[5];
    const float* ln1_b     = (const float*)d_in[6];
    const float* ln1kv_w   = (const float*)d_in[7];
    const float* ln1kv_b   = (const float*)d_in[8];
    const float* attn_in_w = (const float*)d_in[9];
    const float* attn_in_b = (const float*)d_in[10];
    const float* attn_out_w= (const float*)d_in[11];
    const float* attn_out_b= (const float*)d_in[12];
    const float* ls1       = (const float*)d_in[13];
    const float* ls2       = (const float*)d_in[14];
    const float* ln2_w     = (const float*)d_in[15];
    const float* ln2_b     = (const float*)d_in[16];
    const float* fc_w      = (const float*)d_in[17];
    const float* fc_b      = (const float*)d_in[18];
    const float* proj_w    = (const float*)d_in[19];
    const float* proj_b    = (const float*)d_in[20];
    const float* outp_w    = (const float*)d_in[21];
    const float* outp_b    = (const float*)d_in[22];
    const float* temb      = (const float*)d_in[23];
    const float* eemb      = (const float*)d_in[24];
    const float* glw       = (const float*)d_in[25];
    const float* glb       = (const float*)d_in[26];
    const float* gwt       = (const float*)d_in[27];
    const float* gbias     = (const float*)d_in[28];
    const float* gain      = (const float*)d_in[29];
    const float* fw        = (const float*)d_in[30];
    float* out = (float*)d_out;

    float *px, *po, *pg, *pgi, *psg, *prowg;
    int *pcnt, *psoff, *pse, *psb, *pxseg, *pkvseg, *pxval, *pkvval, *psxb, *pskvb, *pb2s;
    cudaGetSymbolAddress((void**)&px,    g_x);
    cudaGetSymbolAddress((void**)&po,    g_o);
    cudaGetSymbolAddress((void**)&pg,    g_gates);
    cudaGetSymbolAddress((void**)&pgi,   g_gi);
    cudaGetSymbolAddress((void**)&pcnt,  g_cnt);
    cudaGetSymbolAddress((void**)&psoff, g_soff);
    cudaGetSymbolAddress((void**)&pse,   g_se);
    cudaGetSymbolAddress((void**)&psb,   g_sb);
    cudaGetSymbolAddress((void**)&psg,   g_sg);
    cudaGetSymbolAddress((void**)&pxseg, g_xseg);
    cudaGetSymbolAddress((void**)&pkvseg,g_kvseg);
    cudaGetSymbolAddress((void**)&pxval, g_xvalid);
    cudaGetSymbolAddress((void**)&pkvval,g_kvvalid);
    cudaGetSymbolAddress((void**)&psxb,  g_sxb);
    cudaGetSymbolAddress((void**)&pskvb, g_skvb);
    cudaGetSymbolAddress((void**)&pb2s,  g_b2s);
    cudaGetSymbolAddress((void**)&prowg, g_rowg);

    u16 *pq16, *pkv16;
    cudaGetSymbolAddress((void**)&pq16,  g_q16);
    cudaGetSymbolAddress((void**)&pkv16, g_kv16);

    u16 *xh, *xl, *kh, *kl, *ah, *al, *fh, *fl;
    cudaGetSymbolAddress((void**)&xh, g_xln_h); cudaGetSymbolAddress((void**)&xl, g_xln_l);
    cudaGetSymbolAddress((void**)&kh, g_kvn_h); cudaGetSymbolAddress((void**)&kl, g_kvn_l);
    cudaGetSymbolAddress((void**)&ah, g_att_h); cudaGetSymbolAddress((void**)&al, g_att_l);
    cudaGetSymbolAddress((void**)&fh, g_ffn_h); cudaGetSymbolAddress((void**)&fl, g_ffn_l);

    u16 *aiw, *aow, *fcw, *pjw, *opw;
    cudaGetSymbolAddress((void**)&aiw, g_aiw);
    cudaGetSymbolAddress((void**)&aow, g_aow);
    cudaGetSymbolAddress((void**)&fcw, g_fcw);
    cudaGetSymbolAddress((void**)&pjw, g_pjw);
    cudaGetSymbolAddress((void**)&opw, g_opw);

    cudaFuncSetAttribute(k_tgemm,     cudaFuncAttributeMaxDynamicSharedMemorySize, TG_DSMEM);
    cudaFuncSetAttribute(k_tgemm_qkv, cudaFuncAttributeMaxDynamicSharedMemorySize, TG_DSMEM);

    k_cvt_all<<<2048, 256>>>(
        (const float4*)attn_in_w,  (uint2*)aiw,
        (const float4*)attn_out_w, (uint2*)aow,
        (const float4*)fc_w,       (uint2*)fcw,
        (const float4*)proj_w,     (uint2*)pjw,
        (const float4*)outp_w,     (uint2*)opw);

    k_gate_mean<<<dim3(BATCH, 16), 256>>>(image, pgi);
    k_gate<<<BATCH, 256>>>(pgi, temb, eemb, tids, eids, glw, glb, gwt, gbias, pg);
    k_slots<<<1, 256>>>(pg, pcnt, psoff, pse, psb, psg,
                        pxseg, pkvseg, pxval, pkvval, psxb, pskvb, pb2s, prowg);

    k_initx<<<dim3(NQ_, NSLOT), 256>>>(query, px, pse, psxb);

    const long HH = (long)HID*HID;
    const int XMB = 22;
    const int KVMB = 118;

    for (int l = 0; l < NLAYERS; l++) {
        k_ln_all<<<dim3(NQ_ + KVR, NSLOT), 256>>>(px, query, image, pp,
            ln1_w + (long)l*HID, ln1_b + (long)l*HID,
            ln1kv_w + (long)l*HID, ln1kv_b + (long)l*HID, (long)NLAYERS*HID,
            xh, xl, kh, kl, pse, psb, psxb, pskvb);
        k_tgemm_qkv<<<dim3(16, XMB + KVMB), 256, TG_DSMEM>>>(XMB,
            xh, xl, aiw + (long)l*3*HH,
            attn_in_b + (long)l*3*HID, pq16, pxseg, pxval,
            kh, kl, aiw + (long)l*3*HH + HH,
            attn_in_b + (long)l*3*HID + HID, pkv16, pkvseg, pkvval,
            (long)NLAYERS*3*HH, (long)NLAYERS*3*HID);
        k_attn<<<dim3(256, NSLOT, 3), 128>>>(pq16, pkv16, ah, al, psxb, pskvb);
        k_tgemm<<<dim3(8, XMB), 256, TG_DSMEM>>>(HID, HID,
            ah, al, aow + (long)l*HH, (long)NLAYERS*HH,
            attn_out_b + (long)l*HID, (long)NLAYERS*HID,
            px, (u16*)0, (u16*)0, ls1 + (long)l*HID, (long)NLAYERS*HID,
            (const float*)0, 2, pxseg, pxval);
        k_ln<<<dim3(NQ_, NSLOT), 256>>>(px,
            ln2_w + (long)l*HID, ln2_b + (long)l*HID, (long)NLAYERS*HID,
            xh, xl, pse, psxb);
        k_tgemm<<<dim3(32, XMB), 256, TG_DSMEM>>>(4*HID, HID,
            xh, xl, fcw + (long)l*4*HH, (long)NLAYERS*4*HH,
            fc_b + (long)l*4*HID, (long)NLAYERS*4*HID,
            (float*)0, fh, fl, (const float*)0, 0,
            (const float*)0, 1, pxseg, pxval);
        // proj GEMM; last layer fuses gate-scaled fp16 split of final x (epi 4)
        k_tgemm<<<dim3(8, XMB), 256, TG_DSMEM>>>(HID, 4*HID,
            fh, fl, pjw + (long)l*4*HH, (long)NLAYERS*4*HH,
            proj_b + (long)l*HID, (long)NLAYERS*HID,
            px, xh, xl, ls2 + (long)l*HID, (long)NLAYERS*HID,
            prowg, (l == NLAYERS-1) ? 4 : 2, pxseg, pxval);
    }

    // out projection reads gate-scaled fp16 x (written by epi 4)
    k_tgemm<<<dim3(OUTD/128, XMB), 256, TG_DSMEM>>>(OUTD, HID,
        xh, xl, opw, (long)OUTD*HID,
        (const float*)0, 0,
        po, (u16*)0, (u16*)0, (const float*)0, 0,
        (const float*)0, 3, pxseg, pxval);
    k_rms_combine<<<dim3(NQ_, BATCH), 256>>>(po, outp_b, out, fw, gain, pb2s, pse, psg, psxb);
}

// round 12
// speedup vs baseline: 5.5082x; 1.2529x over previous
#include <cuda_runtime.h>
#include <cuda_fp16.h>
#include <math.h>
#include <stdint.h>

typedef unsigned short u16;

// ---------------- problem constants ----------------
#define EXP    4
#define BATCH  8
#define NQ_    144
#define NLAYERS 2
#define NHEADS 16
#define HDIM   64
#define HID    1024
#define OUTD   4096
#define TDIM   256
#define LV_    576
#define LP_    192
#define NSLOT  16
#define GN     (HID + 2*TDIM)   // 1536
#define KVR    912
#define XROWS  3072
#define KVROWS 16384

// ---------------- fp32 scratch ----------------
__device__ float g_x   [XROWS*HID];
__device__ float g_o   [XROWS*OUTD];
__device__ float g_gates[BATCH*EXP];
__device__ float g_gi  [BATCH*HID];

// fp16 Q / KV buffers
__device__ u16 g_q16 [XROWS*HID];
__device__ u16 g_kv16[KVROWS*2048];   // K | V

// slot metadata
__device__ int   g_cnt[EXP], g_soff[EXP];
__device__ int   g_se[NSLOT], g_sb[NSLOT];
__device__ float g_sg[NSLOT];
__device__ int   g_xseg[EXP+1], g_kvseg[EXP+1];
__device__ int   g_xvalid[EXP], g_kvvalid[EXP];
__device__ int   g_sxb[NSLOT], g_skvb[NSLOT];
__device__ int   g_b2s[BATCH*2];
__device__ float g_rowg[XROWS];

// ---------------- fp16 hi/lo activation scratch ----------------
__device__ u16 g_xln_h[XROWS*HID],  g_xln_l[XROWS*HID];
__device__ u16 g_kvn_h[KVROWS*HID], g_kvn_l[KVROWS*HID];
__device__ u16 g_att_h[XROWS*HID],  g_att_l[XROWS*HID];
__device__ u16 g_ffn_h[XROWS*4096], g_ffn_l[XROWS*4096];

// ---------------- fp16 weight scratch ----------------
#define AIW_N (EXP*NLAYERS*3*HID*HID)
#define AOW_N (EXP*NLAYERS*HID*HID)
#define FCW_N (EXP*NLAYERS*4*HID*HID)
#define PJW_N (EXP*NLAYERS*HID*4*HID)
#define OPW_N (EXP*OUTD*HID)
__device__ u16 g_aiw[AIW_N];
__device__ u16 g_aow[AOW_N];
__device__ u16 g_fcw[FCW_N];
__device__ u16 g_pjw[PJW_N];
__device__ u16 g_opw[OPW_N];

// ================= helpers =================
__device__ __forceinline__ void mma16816(float* c, const uint32_t* a, const uint32_t* b) {
    asm volatile("mma.sync.aligned.m16n8k16.row.col.f32.f16.f16.f32 "
        "{%0,%1,%2,%3}, {%4,%5,%6,%7}, {%8,%9}, {%0,%1,%2,%3};"
        : "+f"(c[0]), "+f"(c[1]), "+f"(c[2]), "+f"(c[3])
        : "r"(a[0]), "r"(a[1]), "r"(a[2]), "r"(a[3]), "r"(b[0]), "r"(b[1]));
}
__device__ __forceinline__ void fsplit1(float v, u16& h, u16& l) {
    __half hh = __float2half(v);
    h = __half_as_ushort(hh);
    l = __half_as_ushort(__float2half(v - __half2float(hh)));
}
__device__ __forceinline__ uint2 cvt4h(float4 v) {
    __half2 a = __floats2half2_rn(v.x, v.y);
    __half2 b = __floats2half2_rn(v.z, v.w);
    uint2 r;
    r.x = *reinterpret_cast<uint32_t*>(&a);
    r.y = *reinterpret_cast<uint32_t*>(&b);
    return r;
}
__device__ __forceinline__ uint32_t smem_u32(const void* p) {
    uint32_t a;
    asm("{ .reg .u64 t; cvta.to.shared.u64 t, %1; cvt.u32.u64 %0, t; }" : "=r"(a) : "l"(p));
    return a;
}
#define CP16(dst, src) asm volatile("cp.async.cg.shared.global [%0], [%1], 16;" :: "r"(dst), "l"(src) : "memory")
#define CPCOMMIT() asm volatile("cp.async.commit_group;" ::: "memory")
#define CPWAIT0()  asm volatile("cp.async.wait_group 0;" ::: "memory")

// ---------------- merged weight convert fp32 -> fp16 ----------------
__global__ void k_cvt_all(const float4* __restrict__ s0, uint2* __restrict__ d0,
                          const float4* __restrict__ s1, uint2* __restrict__ d1,
                          const float4* __restrict__ s2, uint2* __restrict__ d2,
                          const float4* __restrict__ s3, uint2* __restrict__ d3,
                          const float4* __restrict__ s4, uint2* __restrict__ d4) {
    const long n0 = AIW_N/4, n1 = AOW_N/4, n2 = FCW_N/4, n3 = PJW_N/4, n4 = OPW_N/4;
    const long total = n0 + n1 + n2 + n3 + n4;
    long stride = (long)gridDim.x * blockDim.x;
    for (long i = (long)blockIdx.x * blockDim.x + threadIdx.x; i < total; i += stride) {
        const float4* s; uint2* d; long k = i;
        if (k < n0)              { s = s0; d = d0; }
        else if ((k -= n0) < n1) { s = s1; d = d1; }
        else if ((k -= n1) < n2) { s = s2; d = d2; }
        else if ((k -= n2) < n3) { s = s3; d = d3; }
        else                     { k -= n3; s = s4; d = d4; }
        d[k] = cvt4h(s[k]);
    }
}

#define PITCH 20
#define ARR_U32 (128*PITCH)                 // 2560 u32 per array
#define DSMEM_T(T) (2*((T)+1)*ARR_U32*4)    // bytes: 2 stages x (T+1) arrays

// ================= GEMM body template: C = (sum of T activation terms) @ W^T =================
// epi 0: fp32 acc+bias. 1: split(gelu)->hi/lo. 2: C+=ls*(acc+bias). 3: C=acc.
// epi 4: C+=ls*(..); Chi/Clo = fsplit(rowg*C). 5: Chi(fp16) = acc+bias.
template<int T>
__device__ __forceinline__ void tgemm_body(
    int N, int K, int m0, int n0, int base, int vrows,
    const u16* __restrict__ Ah, const u16* __restrict__ Al,
    const u16* __restrict__ WE,
    const float* __restrict__ bias,
    float* __restrict__ C, u16* __restrict__ Chi, u16* __restrict__ Clo,
    const float* __restrict__ ls, const float* __restrict__ rowg,
    int epi, uint32_t* SM)
{
    const int NARR = T + 1;
    const int BUFU = NARR * ARR_U32;
    uint32_t smb = smem_u32(SM);
    int tid = threadIdx.x;
    int warp = tid >> 5, lane = tid & 31;
    int wm = warp & 3, wn = warp >> 2;
    int g8 = lane >> 2, tg = lane & 3;

    const u16* src[NARR][2];
    uint32_t doff[2];
    #pragma unroll
    for (int j = 0; j < 2; ++j) {
        int lin = j * 256 + tid;
        int row = lin >> 2, q = lin & 3;
        doff[j] = (uint32_t)(row * PITCH + q * 4) * 4;
        src[0][j] = Ah + (long)(m0 + row) * K + q * 8;
        if (T == 2) src[1][j] = Al + (long)(m0 + row) * K + q * 8;
        src[NARR-1][j] = WE + (long)(n0 + row) * K + q * 8;
    }

    float acc[2][8][4] = {};
    int nch = K >> 5;

    #pragma unroll
    for (int a = 0; a < NARR; ++a)
        #pragma unroll
        for (int j = 0; j < 2; ++j)
            CP16(smb + a * (ARR_U32*4) + doff[j], src[a][j]);
    CPCOMMIT();

    for (int c = 0; c < nch; ++c) {
        CPWAIT0();
        __syncthreads();
        if (c + 1 < nch) {
            long koff = (long)(c + 1) * 32;
            uint32_t bb = smb + ((c + 1) & 1) * (BUFU*4);
            #pragma unroll
            for (int a = 0; a < NARR; ++a)
                #pragma unroll
                for (int j = 0; j < 2; ++j)
                    CP16(bb + a * (ARR_U32*4) + doff[j], src[a][j] + koff);
            CPCOMMIT();
        }
        const uint32_t* B = SM + (c & 1) * BUFU;
        const uint32_t* AsH = B;
        const uint32_t* AsL = B + ARR_U32;            // valid when T==2
        const uint32_t* Bs  = B + (NARR-1)*ARR_U32;
        #pragma unroll
        for (int kh = 0; kh < 2; ++kh) {
            int kb = kh * 8;
            uint32_t ah[2][4], al[2][4];
            #pragma unroll
            for (int mt = 0; mt < 2; ++mt) {
                int r = wm * 32 + mt * 16 + g8;
                ah[mt][0] = AsH[r*PITCH + kb+tg];     ah[mt][1] = AsH[(r+8)*PITCH + kb+tg];
                ah[mt][2] = AsH[r*PITCH + kb+tg+4];   ah[mt][3] = AsH[(r+8)*PITCH + kb+tg+4];
                if (T == 2) {
                    al[mt][0] = AsL[r*PITCH + kb+tg];     al[mt][1] = AsL[(r+8)*PITCH + kb+tg];
                    al[mt][2] = AsL[r*PITCH + kb+tg+4];   al[mt][3] = AsL[(r+8)*PITCH + kb+tg+4];
                }
            }
            #pragma unroll
            for (int nt = 0; nt < 8; ++nt) {
                int n = wn * 64 + nt * 8 + g8;
                uint32_t b2[2] = { Bs[n*PITCH + kb+tg], Bs[n*PITCH + kb+tg+4] };
                #pragma unroll
                for (int mt = 0; mt < 2; ++mt) {
                    mma16816(acc[mt][nt], ah[mt], b2);
                    if (T == 2) mma16816(acc[mt][nt], al[mt], b2);
                }
            }
        }
        __syncthreads();
    }

    #pragma unroll
    for (int mt = 0; mt < 2; ++mt) {
        int r0 = m0 + wm * 32 + mt * 16 + g8;
        int r1 = r0 + 8;
        bool ok0 = (r0 - base) < vrows;
        bool ok1 = (r1 - base) < vrows;
        #pragma unroll
        for (int nt = 0; nt < 8; ++nt) {
            int col = n0 + wn * 64 + nt * 8 + tg * 2;
            float* cc = acc[mt][nt];
            #pragma unroll
            for (int q = 0; q < 4; ++q) {
                int row = (q < 2) ? r0 : r1;
                bool ok = (q < 2) ? ok0 : ok1;
                if (!ok) continue;
                int cl = col + (q & 1);
                long idx = (long)row * N + cl;
                if (epi == 3) { C[idx] = cc[q]; continue; }
                float v = cc[q] + bias[cl];
                if (epi == 1) {
                    float gv = 0.5f * v * (1.f + erff(v * 0.70710678118654752f));
                    fsplit1(gv, Chi[idx], Clo[idx]);
                } else if (epi == 2) {
                    C[idx] = C[idx] + ls[cl] * v;
                } else if (epi == 4) {
                    float nv = C[idx] + ls[cl] * v;
                    C[idx] = nv;
                    fsplit1(rowg[row] * nv, Chi[idx], Clo[idx]);
                } else if (epi == 5) {
                    Chi[idx] = __half_as_ushort(__float2half(v));
                } else {
                    C[idx] = v;
                }
            }
        }
    }
}

__device__ __forceinline__ int resolve_expert(int m0, const int* segbase, int& base) {
    int e = -1; base = 0;
    #pragma unroll
    for (int i = 0; i < EXP; ++i)
        if (e < 0 && m0 >= segbase[i] && m0 < segbase[i+1]) { e = i; base = segbase[i]; }
    return e;
}

// ================= single-config GEMM, T activation terms =================
template<int T>
__global__ __launch_bounds__(256, 2) void k_tgemm(
    int N, int K,
    const u16* __restrict__ Ah, const u16* __restrict__ Al,
    const u16* __restrict__ W, long wES,
    const float* __restrict__ biasB, long bES,
    float* __restrict__ C, u16* __restrict__ Chi, u16* __restrict__ Clo,
    const float* __restrict__ lsB, long lsES,
    const float* __restrict__ rowg,
    int epi, const int* __restrict__ segbase, const int* __restrict__ valid)
{
    int m0 = blockIdx.y * 128, n0 = blockIdx.x * 128;
    int base, e = resolve_expert(m0, segbase, base);
    if (e < 0) return;
    extern __shared__ uint32_t SM[];
    tgemm_body<T>(N, K, m0, n0, base, valid[e],
                  Ah, Al, W + (long)e*wES,
                  biasB ? (biasB + (long)e*bES) : (const float*)0,
                  C, Chi, Clo, lsB ? (lsB + (long)e*lsES) : (const float*)0, rowg, epi, SM);
}

// ================= dual GEMM: Q-proj + KV-proj, fp16 outputs, 1-term =================
__global__ __launch_bounds__(256, 2) void k_tgemm_qkv(
    int ymid,
    const u16* __restrict__ QAh,
    const u16* __restrict__ QW, const float* __restrict__ Qbias,
    u16* __restrict__ QC16,
    const int* __restrict__ qseg, const int* __restrict__ qval,
    const u16* __restrict__ KAh,
    const u16* __restrict__ KW, const float* __restrict__ Kbias,
    u16* __restrict__ KC16,
    const int* __restrict__ kseg, const int* __restrict__ kval,
    long wES, long bES)
{
    extern __shared__ uint32_t SM[];
    if ((int)blockIdx.y < ymid) {
        if (blockIdx.x >= 8) return;
        int m0 = blockIdx.y * 128, n0 = blockIdx.x * 128;
        int base, e = resolve_expert(m0, qseg, base);
        if (e < 0) return;
        tgemm_body<1>(HID, HID, m0, n0, base, qval[e],
                      QAh, (const u16*)0, QW + (long)e*wES,
                      Qbias, (float*)0, QC16, (u16*)0, (const float*)0, (const float*)0, 5, SM);
    } else {
        int m0 = (blockIdx.y - ymid) * 128, n0 = blockIdx.x * 128;
        int base, e = resolve_expert(m0, kseg, base);
        if (e < 0) return;
        tgemm_body<1>(2048, HID, m0, n0, base, kval[e],
                      KAh, (const u16*)0, KW + (long)e*wES,
                      Kbias + (long)e*bES, (float*)0, KC16, (u16*)0, (const float*)0, (const float*)0, 5, SM);
    }
}

// ---------------- reductions ----------------
__device__ __forceinline__ void blockReduce2(float& a, float& b, float* sh) {
    __syncthreads();
    int lane = threadIdx.x & 31, wid = threadIdx.x >> 5;
    #pragma unroll
    for (int o = 16; o; o >>= 1) { a += __shfl_xor_sync(~0u, a, o); b += __shfl_xor_sync(~0u, b, o); }
    if (lane == 0) { sh[wid] = a; sh[wid + 32] = b; }
    __syncthreads();
    int nw = blockDim.x >> 5;
    if (wid == 0) {
        a = (lane < nw) ? sh[lane] : 0.f;
        b = (lane < nw) ? sh[lane + 32] : 0.f;
        #pragma unroll
        for (int o = 16; o; o >>= 1) { a += __shfl_xor_sync(~0u, a, o); b += __shfl_xor_sync(~0u, b, o); }
        if (lane == 0) { sh[0] = a; sh[32] = b; }
    }
    __syncthreads();
    a = sh[0]; b = sh[32];
}
__device__ __forceinline__ float blockReduce1(float a, float* sh) {
    __syncthreads();
    int lane = threadIdx.x & 31, wid = threadIdx.x >> 5;
    #pragma unroll
    for (int o = 16; o; o >>= 1) a += __shfl_xor_sync(~0u, a, o);
    if (lane == 0) sh[wid] = a;
    __syncthreads();
    int nw = blockDim.x >> 5;
    if (wid == 0) {
        a = (lane < nw) ? sh[lane] : 0.f;
        #pragma unroll
        for (int o = 16; o; o >>= 1) a += __shfl_xor_sync(~0u, a, o);
        if (lane == 0) sh[0] = a;
    }
    __syncthreads();
    return sh[0];
}

// ---------------- gate kernels ----------------
__global__ void k_gate_mean(const float* __restrict__ img, float* __restrict__ gi) {
    int b = blockIdx.x;
    int h = blockIdx.y * 64 + (threadIdx.x & 63);
    int part = threadIdx.x >> 6;
    __shared__ float sh[256];
    float s = 0.f;
    for (int l = part; l < LV_; l += 4)
        s += img[((long)b*LV_ + l)*HID + h];
    sh[threadIdx.x] = s;
    __syncthreads();
    if (part == 0) {
        float tot = sh[threadIdx.x] + sh[threadIdx.x + 64] + sh[threadIdx.x + 128] + sh[threadIdx.x + 192];
        gi[b*HID + h] = tot * (1.f/LV_);
    }
}
__global__ void k_gate(const float* __restrict__ gi, const float* __restrict__ temb,
                       const float* __restrict__ eemb, const int* __restrict__ tids,
                       const int* __restrict__ eids, const float* __restrict__ glw,
                       const float* __restrict__ glb, const float* __restrict__ gwt,
                       const float* __restrict__ gbias, float* __restrict__ gates) {
    int b = blockIdx.x, tid = threadIdx.x;
    __shared__ float sh[64];
    __shared__ float logits[EXP];
    int ti = tids[b], ei = eids[b];
    float s = 0.f, ss = 0.f;
    for (int i = tid; i < GN; i += 256) {
        float v = (i < HID) ? gi[b*HID + i]
                : (i < HID + TDIM) ? temb[ti*TDIM + i - HID]
                : eemb[ei*TDIM + i - HID - TDIM];
        s += v; ss += v*v;
    }
    blockReduce2(s, ss, sh);
    float m  = s * (1.f/GN);
    float rs = rsqrtf(ss * (1.f/GN) - m*m + 1e-5f);
    for (int e = 0; e < EXP; e++) {
        float d = 0.f;
        for (int i = tid; i < GN; i += 256) {
            float v = (i < HID) ? gi[b*HID + i]
                    : (i < HID + TDIM) ? temb[ti*TDIM + i - HID]
                    : eemb[ei*TDIM + i - HID - TDIM];
            d += ((v - m)*rs*glw[i] + glb[i]) * gwt[(long)e*GN + i];
        }
        d = blockReduce1(d, sh);
        if (tid == 0) logits[e] = d + gbias[e];
    }
    __syncthreads();
    if (tid == 0) {
        float w[EXP]; float mx = -1e30f;
        for (int e = 0; e < EXP; e++) { float l = fminf(fmaxf(logits[e], -15.f), 15.f); w[e] = l; mx = fmaxf(mx, l); }
        float sum = 0.f;
        for (int e = 0; e < EXP; e++) { w[e] = expf(w[e] - mx); sum += w[e]; }
        for (int e = 0; e < EXP; e++) w[e] /= sum;
        int i0 = 0;
        for (int e = 1; e < EXP; e++) if (w[e] > w[i0]) i0 = e;
        int i1 = -1;
        for (int e = 0; e < EXP; e++) { if (e == i0) continue; if (i1 < 0 || w[e] > w[i1]) i1 = e; }
        float t = w[i0] + w[i1] + 1e-9f;
        for (int e = 0; e < EXP; e++) gates[b*EXP + e] = 0.f;
        gates[b*EXP + i0] = w[i0] / t;
        gates[b*EXP + i1] = w[i1] / t;
    }
}
__global__ void k_slots(const float* __restrict__ gates, int* cnt, int* soff,
                        int* se, int* sb, float* sg,
                        int* xseg, int* kvseg, int* xvalid, int* kvvalid,
                        int* sxb, int* skvb, int* b2s, float* rowg) {
    if (threadIdx.x == 0) {
        int s = 0;
        for (int e = 0; e < EXP; e++) {
            soff[e] = s;
            int c = 0;
            for (int b = 0; b < BATCH; b++) {
                float g = gates[b*EXP + e];
                if (g != 0.f) { se[s] = e; sb[s] = b; sg[s] = g; s++; c++; }
            }
            cnt[e] = c;
        }
        xseg[0] = 0; kvseg[0] = 0;
        for (int e = 0; e < EXP; e++) {
            xvalid[e]  = cnt[e]*NQ_;
            kvvalid[e] = cnt[e]*KVR;
            xseg[e+1]  = xseg[e]  + ((cnt[e]*NQ_ + 127) & ~127);
            kvseg[e+1] = kvseg[e] + ((cnt[e]*KVR + 127) & ~127);
        }
        for (int i = 0; i < NSLOT; i++) {
            int e = se[i];
            sxb[i]  = xseg[e]  + (i - soff[e])*NQ_;
            skvb[i] = kvseg[e] + (i - soff[e])*KVR;
        }
        int fill[BATCH];
        for (int b = 0; b < BATCH; b++) fill[b] = 0;
        for (int i = 0; i < NSLOT; i++) {
            int b = sb[i];
            b2s[b*2 + fill[b]] = i;
            fill[b]++;
        }
    }
    __syncthreads();
    int tot = xseg[EXP];
    for (int r = threadIdx.x; r < tot; r += blockDim.x) {
        int e = 0, base = 0;
        for (int i = 0; i < EXP; i++)
            if (r >= xseg[i] && r < xseg[i+1]) { e = i; base = xseg[i]; }
        int local = r - base;
        rowg[r] = (local < cnt[e]*NQ_) ? sg[soff[e] + local/NQ_] : 0.f;
    }
}

// ---------------- init x = full query block per slot ----------------
__global__ void k_initx(const float* __restrict__ query, float* __restrict__ gx,
                        const int* __restrict__ se, const int* __restrict__ sxb) {
    int r = blockIdx.x, s = blockIdx.y;
    int e = se[s];
    const float* srow = query + ((long)e*NQ_ + r)*HID;
    float* d = gx + (long)(sxb[s] + r)*HID;
    for (int i = threadIdx.x; i < HID; i += blockDim.x) d[i] = srow[i];
}

// ---------------- merged LN: x rows + kv0 rows -> fp16 hi/lo ----------------
__global__ void k_ln_all(const float* __restrict__ xsrc,
                         const float* __restrict__ query, const float* __restrict__ img,
                         const float* __restrict__ pp,
                         const float* __restrict__ xw, const float* __restrict__ xb,
                         const float* __restrict__ kw, const float* __restrict__ kb, long pES,
                         u16* __restrict__ xdh, u16* __restrict__ xdl,
                         u16* __restrict__ kdh, u16* __restrict__ kdl,
                         const int* __restrict__ se, const int* __restrict__ sb,
                         const int* __restrict__ sxb, const int* __restrict__ skvb) {
    int rr = blockIdx.x, s = blockIdx.y;
    int e = se[s];
    const float* row;
    const float *w, *bv;
    u16 *dh, *dl;
    long doff;
    if (rr < NQ_) {
        doff = (long)(sxb[s] + rr)*HID;
        row = xsrc + doff;
        w = xw; bv = xb; dh = xdh; dl = xdl;
    } else {
        int r = rr - NQ_;
        int b = sb[s];
        int rl, sq, qo, io;
        if (r < 320)      { rl = r;       sq = 64; qo = 0;   io = 0;   }
        else if (r < 624) { rl = r - 320; sq = 48; qo = 64;  io = 256; }
        else              { rl = r - 624; sq = 32; qo = 112; io = 512; }
        if (rl < sq) row = query + ((long)e*NQ_ + qo + rl)*HID;
        else {
            int zi = io + rl - sq;
            if (zi < LV_) row = img + ((long)b*LV_ + zi)*HID;
            else          row = pp  + ((long)b*LP_ + zi - LV_)*HID;
        }
        doff = (long)(skvb[s] + r)*HID;
        w = kw; bv = kb; dh = kdh; dl = kdl;
    }
    __shared__ float sh[64];
    float v[4]; float sm = 0.f, ss = 0.f;
    #pragma unroll
    for (int t = 0; t < 4; t++) { v[t] = row[threadIdx.x + t*256]; sm += v[t]; ss += v[t]*v[t]; }
    blockReduce2(sm, ss, sh);
    float m  = sm * (1.f/HID);
    float rs = rsqrtf(ss * (1.f/HID) - m*m + 1e-5f);
    const float* we = w + (long)e*pES;
    const float* be = bv + (long)e*pES;
    #pragma unroll
    for (int t = 0; t < 4; t++) {
        int i = threadIdx.x + t*256;
        float rv = (v[t] - m)*rs*we[i] + be[i];
        fsplit1(rv, dh[doff + i], dl[doff + i]);
    }
}

// ---------------- LayerNorm (x rows only, MLP LN) ----------------
__global__ void k_ln(const float* __restrict__ src,
                     const float* __restrict__ w, const float* __restrict__ bvec, long pES,
                     u16* __restrict__ dh, u16* __restrict__ dl,
                     const int* __restrict__ se, const int* __restrict__ sxb) {
    int r = blockIdx.x, s = blockIdx.y;
    int e = se[s];
    long row = (long)(sxb[s] + r)*HID;
    __shared__ float sh[64];
    float v[4]; float sm = 0.f, ss = 0.f;
    #pragma unroll
    for (int t = 0; t < 4; t++) { v[t] = src[row + threadIdx.x + t*256]; sm += v[t]; ss += v[t]*v[t]; }
    blockReduce2(sm, ss, sh);
    float m  = sm * (1.f/HID);
    float rs = rsqrtf(ss * (1.f/HID) - m*m + 1e-5f);
    const float* we = w + (long)e*pES;
    const float* be = bvec + (long)e*pES;
    #pragma unroll
    for (int t = 0; t < 4; t++) {
        int i = threadIdx.x + t*256;
        float rv = (v[t] - m)*rs*we[i] + be[i];
        fsplit1(rv, dh[row + i], dl[row + i]);
    }
}

// ---------------- attention (fp16 Q/KV, 4-way ILP) -> fp16 hi/lo ----------------
__global__ void k_attn(const u16* __restrict__ q16, const u16* __restrict__ kv16,
                       u16* __restrict__ ath, u16* __restrict__ atl,
                       const int* __restrict__ sxb, const int* __restrict__ skvb) {
    int s = blockIdx.y, st = blockIdx.z;
    int sq    = (st == 0) ? 64 : (st == 1 ? 48 : 32);
    int qo    = (st == 0) ? 0  : (st == 1 ? 64 : 112);
    int kvo   = (st == 0) ? 0  : (st == 1 ? 320 : 624);
    int kvlen = sq + 256;
    int warp = threadIdx.x >> 5, lane = threadIdx.x & 31;
    int w = blockIdx.x * 4 + warp;
    if (w >= NHEADS * sq) return;
    int h = w / sq, qi = w % sq;
    __shared__ float sc[4][320];

    long qrow  = (long)sxb[s] + qo + qi;
    long kvrow = (long)skvb[s] + kvo;
    const __half2 qh = *(const __half2*)(q16 + qrow*HID + h*HDIM + lane*2);
    float q0 = __low2float(qh), q1 = __high2float(qh);
    const u16* kbase = kv16 + kvrow*2048 + h*HDIM + lane*2;
    float mx = -1e30f;
    for (int j = 0; j < kvlen; j += 4) {
        __half2 k0 = *(const __half2*)(kbase + (long)j*2048);
        __half2 k1 = *(const __half2*)(kbase + (long)(j+1)*2048);
        __half2 k2 = *(const __half2*)(kbase + (long)(j+2)*2048);
        __half2 k3 = *(const __half2*)(kbase + (long)(j+3)*2048);
        float p0 = q0*__low2float(k0) + q1*__high2float(k0);
        float p1 = q0*__low2float(k1) + q1*__high2float(k1);
        float p2 = q0*__low2float(k2) + q1*__high2float(k2);
        float p3 = q0*__low2float(k3) + q1*__high2float(k3);
        #pragma unroll
        for (int o = 16; o; o >>= 1) {
            p0 += __shfl_xor_sync(~0u, p0, o);
            p1 += __shfl_xor_sync(~0u, p1, o);
            p2 += __shfl_xor_sync(~0u, p2, o);
            p3 += __shfl_xor_sync(~0u, p3, o);
        }
        p0 *= 0.125f; p1 *= 0.125f; p2 *= 0.125f; p3 *= 0.125f;
        if (lane == 0) {
            sc[warp][j]   = p0; sc[warp][j+1] = p1;
            sc[warp][j+2] = p2; sc[warp][j+3] = p3;
        }
        mx = fmaxf(mx, fmaxf(fmaxf(p0, p1), fmaxf(p2, p3)));
    }
    __syncwarp();
    float se_ = 0.f;
    for (int j = lane; j < kvlen; j += 32) {
        float ex = __expf(sc[warp][j] - mx);
        sc[warp][j] = ex;
        se_ += ex;
    }
    #pragma unroll
    for (int o = 16; o; o >>= 1) se_ += __shfl_xor_sync(~0u, se_, o);
    __syncwarp();
    float inv = 1.f / se_;
    const u16* vbase = kv16 + kvrow*2048 + 1024 + h*HDIM + lane*2;
    float a0 = 0.f, a1 = 0.f;
    #pragma unroll 4
    for (int j = 0; j < kvlen; j++) {
        float p = sc[warp][j];
        __half2 vv = *(const __half2*)(vbase + (long)j*2048);
        a0 += p*__low2float(vv); a1 += p*__high2float(vv);
    }
    long ooff = qrow*HID + h*HDIM + lane*2;
    fsplit1(a0 * inv, ath[ooff],     atl[ooff]);
    fsplit1(a1 * inv, ath[ooff + 1], atl[ooff + 1]);
}

// ---------------- combine 2 slots per batch + gated bias + RMS + final scaling ----------------
__global__ void k_rms_combine(const float* __restrict__ O, const float* __restrict__ bo,
                              float* __restrict__ out, const float* __restrict__ fw,
                              const float* __restrict__ gain,
                              const int* __restrict__ b2s, const int* __restrict__ se,
                              const float* __restrict__ sg, const int* __restrict__ sxb) {
    int qrow = blockIdx.x, b = blockIdx.y;
    int s0 = b2s[b*2], s1 = b2s[b*2 + 1];
    int e0 = se[s0], e1 = se[s1];
    float g0 = sg[s0], g1 = sg[s1];
    long r0 = (long)(sxb[s0] + qrow)*OUTD;
    long r1 = (long)(sxb[s1] + qrow)*OUTD;
    const float* bo0 = bo + (long)e0*OUTD;
    const float* bo1 = bo + (long)e1*OUTD;
    float* orow = out + ((long)b*NQ_ + qrow)*OUTD;
    __shared__ float sh[64];
    float v[16]; float ss = 0.f;
    #pragma unroll
    for (int t = 0; t < 16; t++) {
        int o = threadIdx.x + t*256;
        float val = O[r0 + o] + O[r1 + o] + g0*bo0[o] + g1*bo1[o];
        v[t] = val; ss += val*val;
    }
    ss = blockReduce1(ss, sh);
    float sc = rsqrtf(ss * (1.f/OUTD) + 1e-6f);
    #pragma unroll
    for (int t = 0; t < 16; t++) {
        int o = threadIdx.x + t*256;
        orow[o] = v[t]*sc*fw[o]*gain[o];
    }
}

// ---------------- host orchestration ----------------
extern "C" void kernel_launch(void* const* d_in, const int* in_sizes, int n_in,
                              void* d_out, int out_size) {
    const float* image     = (const float*)d_in[0];
    const float* pp        = (const float*)d_in[1];
    const int*   tids      = (const int*)  d_in[2];
    const int*   eids      = (const int*)  d_in[3];
    const float* query     = (const float*)d_in[4];
    const float* ln1_w     = (const float*)d_in[5];
    const float* ln1_b     = (const float*)d_in[6];
    const float* ln1kv_w   = (const float*)d_in[7];
    const float* ln1kv_b   = (const float*)d_in[8];
    const float* attn_in_w = (const float*)d_in[9];
    const float* attn_in_b = (const float*)d_in[10];
    const float* attn_out_w= (const float*)d_in[11];
    const float* attn_out_b= (const float*)d_in[12];
    const float* ls1       = (const float*)d_in[13];
    const float* ls2       = (const float*)d_in[14];
    const float* ln2_w     = (const float*)d_in[15];
    const float* ln2_b     = (const float*)d_in[16];
    const float* fc_w      = (const float*)d_in[17];
    const float* fc_b      = (const float*)d_in[18];
    const float* proj_w    = (const float*)d_in[19];
    const float* proj_b    = (const float*)d_in[20];
    const float* outp_w    = (const float*)d_in[21];
    const float* outp_b    = (const float*)d_in[22];
    const float* temb      = (const float*)d_in[23];
    const float* eemb      = (const float*)d_in[24];
    const float* glw       = (const float*)d_in[25];
    const float* glb       = (const float*)d_in[26];
    const float* gwt       = (const float*)d_in[27];
    const float* gbias     = (const float*)d_in[28];
    const float* gain      = (const float*)d_in[29];
    const float* fw        = (const float*)d_in[30];
    float* out = (float*)d_out;

    float *px, *po, *pg, *pgi, *psg, *prowg;
    int *pcnt, *psoff, *pse, *psb, *pxseg, *pkvseg, *pxval, *pkvval, *psxb, *pskvb, *pb2s;
    cudaGetSymbolAddress((void**)&px,    g_x);
    cudaGetSymbolAddress((void**)&po,    g_o);
    cudaGetSymbolAddress((void**)&pg,    g_gates);
    cudaGetSymbolAddress((void**)&pgi,   g_gi);
    cudaGetSymbolAddress((void**)&pcnt,  g_cnt);
    cudaGetSymbolAddress((void**)&psoff, g_soff);
    cudaGetSymbolAddress((void**)&pse,   g_se);
    cudaGetSymbolAddress((void**)&psb,   g_sb);
    cudaGetSymbolAddress((void**)&psg,   g_sg);
    cudaGetSymbolAddress((void**)&pxseg, g_xseg);
    cudaGetSymbolAddress((void**)&pkvseg,g_kvseg);
    cudaGetSymbolAddress((void**)&pxval, g_xvalid);
    cudaGetSymbolAddress((void**)&pkvval,g_kvvalid);
    cudaGetSymbolAddress((void**)&psxb,  g_sxb);
    cudaGetSymbolAddress((void**)&pskvb, g_skvb);
    cudaGetSymbolAddress((void**)&pb2s,  g_b2s);
    cudaGetSymbolAddress((void**)&prowg, g_rowg);

    u16 *pq16, *pkv16;
    cudaGetSymbolAddress((void**)&pq16,  g_q16);
    cudaGetSymbolAddress((void**)&pkv16, g_kv16);

    u16 *xh, *xl, *kh, *kl, *ah, *al, *fh, *fl;
    cudaGetSymbolAddress((void**)&xh, g_xln_h); cudaGetSymbolAddress((void**)&xl, g_xln_l);
    cudaGetSymbolAddress((void**)&kh, g_kvn_h); cudaGetSymbolAddress((void**)&kl, g_kvn_l);
    cudaGetSymbolAddress((void**)&ah, g_att_h); cudaGetSymbolAddress((void**)&al, g_att_l);
    cudaGetSymbolAddress((void**)&fh, g_ffn_h); cudaGetSymbolAddress((void**)&fl, g_ffn_l);

    u16 *aiw, *aow, *fcw, *pjw, *opw;
    cudaGetSymbolAddress((void**)&aiw, g_aiw);
    cudaGetSymbolAddress((void**)&aow, g_aow);
    cudaGetSymbolAddress((void**)&fcw, g_fcw);
    cudaGetSymbolAddress((void**)&pjw, g_pjw);
    cudaGetSymbolAddress((void**)&opw, g_opw);

    cudaFuncSetAttribute(k_tgemm<1>,  cudaFuncAttributeMaxDynamicSharedMemorySize, DSMEM_T(1));
    cudaFuncSetAttribute(k_tgemm<2>,  cudaFuncAttributeMaxDynamicSharedMemorySize, DSMEM_T(2));
    cudaFuncSetAttribute(k_tgemm_qkv, cudaFuncAttributeMaxDynamicSharedMemorySize, DSMEM_T(1));

    k_cvt_all<<<2048, 256>>>(
        (const float4*)attn_in_w,  (uint2*)aiw,
        (const float4*)attn_out_w, (uint2*)aow,
        (const float4*)fc_w,       (uint2*)fcw,
        (const float4*)proj_w,     (uint2*)pjw,
        (const float4*)outp_w,     (uint2*)opw);

    k_gate_mean<<<dim3(BATCH, 16), 256>>>(image, pgi);
    k_gate<<<BATCH, 256>>>(pgi, temb, eemb, tids, eids, glw, glb, gwt, gbias, pg);
    k_slots<<<1, 256>>>(pg, pcnt, psoff, pse, psb, psg,
                        pxseg, pkvseg, pxval, pkvval, psxb, pskvb, pb2s, prowg);

    k_initx<<<dim3(NQ_, NSLOT), 256>>>(query, px, pse, psxb);

    const long HH = (long)HID*HID;
    const int XMB = 22;
    const int KVMB = 118;

    for (int l = 0; l < NLAYERS; l++) {
        k_ln_all<<<dim3(NQ_ + KVR, NSLOT), 256>>>(px, query, image, pp,
            ln1_w + (long)l*HID, ln1_b + (long)l*HID,
            ln1kv_w + (long)l*HID, ln1kv_b + (long)l*HID, (long)NLAYERS*HID,
            xh, xl, kh, kl, pse, psb, psxb, pskvb);
        // Q + KV projections, 1-term activations (score path, damped)
        k_tgemm_qkv<<<dim3(16, XMB + KVMB), 256, DSMEM_T(1)>>>(XMB,
            xh, aiw + (long)l*3*HH,
            attn_in_b + (long)l*3*HID, pq16, pxseg, pxval,
            kh, aiw + (long)l*3*HH + HH,
            attn_in_b + (long)l*3*HID + HID, pkv16, pkvseg, pkvval,
            (long)NLAYERS*3*HH, (long)NLAYERS*3*HID);
        k_attn<<<dim3(256, NSLOT, 3), 128>>>(pq16, pkv16, ah, al, psxb, pskvb);
        // attn-out projection + residual (ls1-damped): 1-term
        k_tgemm<1><<<dim3(8, XMB), 256, DSMEM_T(1)>>>(HID, HID,
            ah, al, aow + (long)l*HH, (long)NLAYERS*HH,
            attn_out_b + (long)l*HID, (long)NLAYERS*HID,
            px, (u16*)0, (u16*)0, ls1 + (long)l*HID, (long)NLAYERS*HID,
            (const float*)0, 2, pxseg, pxval);
        k_ln<<<dim3(NQ_, NSLOT), 256>>>(px,
            ln2_w + (long)l*HID, ln2_b + (long)l*HID, (long)NLAYERS*HID,
            xh, xl, pse, psxb);
        // FC (ls2-damped downstream): 1-term
        k_tgemm<1><<<dim3(32, XMB), 256, DSMEM_T(1)>>>(4*HID, HID,
            xh, xl, fcw + (long)l*4*HH, (long)NLAYERS*4*HH,
            fc_b + (long)l*4*HID, (long)NLAYERS*4*HID,
            (float*)0, fh, fl, (const float*)0, 0,
            (const float*)0, 1, pxseg, pxval);
        // proj (ls2-damped): 1-term; last layer fuses gate-scaled fp16 split (epi 4)
        k_tgemm<1><<<dim3(8, XMB), 256, DSMEM_T(1)>>>(HID, 4*HID,
            fh, fl, pjw + (long)l*4*HH, (long)NLAYERS*4*HH,
            proj_b + (long)l*HID, (long)NLAYERS*HID,
            px, xh, xl, ls2 + (long)l*HID, (long)NLAYERS*HID,
            prowg, (l == NLAYERS-1) ? 4 : 2, pxseg, pxval);
    }

    // out projection: undamped direct path — keep 2-term activations
    k_tgemm<2><<<dim3(OUTD/128, XMB), 256, DSMEM_T(2)>>>(OUTD, HID,
        xh, xl, opw, (long)OUTD*HID,
        (const float*)0, 0,
        po, (u16*)0, (u16*)0, (const float*)0, 0,
        (const float*)0, 3, pxseg, pxval);
    k_rms_combine<<<dim3(NQ_, BATCH), 256>>>(po, outp_b, out, fw, gain, pb2s, pse, psg, psxb);
}

// round 15
// speedup vs baseline: 5.9579x; 1.0816x over previous
#include <cuda_runtime.h>
#include <cuda_fp16.h>
#include <math.h>
#include <stdint.h>

typedef unsigned short u16;

// ---------------- problem constants ----------------
#define EXP    4
#define BATCH  8
#define NQ_    144
#define NLAYERS 2
#define NHEADS 16
#define HDIM   64
#define HID    1024
#define OUTD   4096
#define TDIM   256
#define LV_    576
#define LP_    192
#define NSLOT  16
#define GN     (HID + 2*TDIM)   // 1536
#define KVR    912
#define XROWS  3072
#define KVROWS 16384

// ---------------- fp32 scratch ----------------
__device__ float g_x   [XROWS*HID];
__device__ float g_o   [XROWS*OUTD];
__device__ float g_gates[BATCH*EXP];
__device__ float g_gi  [BATCH*HID];

// fp16 Q / KV buffers
__device__ u16 g_q16 [XROWS*HID];
__device__ u16 g_kv16[KVROWS*2048];   // K | V

// slot metadata
__device__ int   g_cnt[EXP], g_soff[EXP];
__device__ int   g_se[NSLOT], g_sb[NSLOT];
__device__ float g_sg[NSLOT];
__device__ int   g_xseg[EXP+1], g_kvseg[EXP+1];
__device__ int   g_xvalid[EXP], g_kvvalid[EXP];
__device__ int   g_sxb[NSLOT], g_skvb[NSLOT];
__device__ int   g_b2s[BATCH*2];
__device__ float g_rowg[XROWS];

// ---------------- fp16 hi/lo activation scratch ----------------
__device__ u16 g_xln_h[XROWS*HID],  g_xln_l[XROWS*HID];
__device__ u16 g_kvn_h[KVROWS*HID], g_kvn_l[KVROWS*HID];
__device__ u16 g_att_h[XROWS*HID],  g_att_l[XROWS*HID];
__device__ u16 g_ffn_h[XROWS*4096], g_ffn_l[XROWS*4096];

// ---------------- fp16 weight scratch ----------------
#define AIW_N (EXP*NLAYERS*3*HID*HID)
#define AOW_N (EXP*NLAYERS*HID*HID)
#define FCW_N (EXP*NLAYERS*4*HID*HID)
#define PJW_N (EXP*NLAYERS*HID*4*HID)
#define OPW_N (EXP*OUTD*HID)
__device__ u16 g_aiw[AIW_N];
__device__ u16 g_aow[AOW_N];
__device__ u16 g_fcw[FCW_N];
__device__ u16 g_pjw[PJW_N];
__device__ u16 g_opw[OPW_N];

// ================= helpers =================
__device__ __forceinline__ void mma16816(float* c, const uint32_t* a, const uint32_t* b) {
    asm volatile("mma.sync.aligned.m16n8k16.row.col.f32.f16.f16.f32 "
        "{%0,%1,%2,%3}, {%4,%5,%6,%7}, {%8,%9}, {%0,%1,%2,%3};"
        : "+f"(c[0]), "+f"(c[1]), "+f"(c[2]), "+f"(c[3])
        : "r"(a[0]), "r"(a[1]), "r"(a[2]), "r"(a[3]), "r"(b[0]), "r"(b[1]));
}
__device__ __forceinline__ void fsplit1(float v, u16& h, u16& l) {
    __half hh = __float2half(v);
    h = __half_as_ushort(hh);
    l = __half_as_ushort(__float2half(v - __half2float(hh)));
}
__device__ __forceinline__ uint2 cvt4h(float4 v) {
    __half2 a = __floats2half2_rn(v.x, v.y);
    __half2 b = __floats2half2_rn(v.z, v.w);
    uint2 r;
    r.x = *reinterpret_cast<uint32_t*>(&a);
    r.y = *reinterpret_cast<uint32_t*>(&b);
    return r;
}
__device__ __forceinline__ uint32_t smem_u32(const void* p) {
    uint32_t a;
    asm("{ .reg .u64 t; cvta.to.shared.u64 t, %1; cvt.u32.u64 %0, t; }" : "=r"(a) : "l"(p));
    return a;
}
#define CP16(dst, src) asm volatile("cp.async.cg.shared.global [%0], [%1], 16;" :: "r"(dst), "l"(src) : "memory")
#define CPCOMMIT() asm volatile("cp.async.commit_group;" ::: "memory")
#define CPWAIT0()  asm volatile("cp.async.wait_group 0;" ::: "memory")

// ---------------- merged weight convert fp32 -> fp16 ----------------
__global__ void k_cvt_all(const float4* __restrict__ s0, uint2* __restrict__ d0,
                          const float4* __restrict__ s1, uint2* __restrict__ d1,
                          const float4* __restrict__ s2, uint2* __restrict__ d2,
                          const float4* __restrict__ s3, uint2* __restrict__ d3,
                          const float4* __restrict__ s4, uint2* __restrict__ d4) {
    const long n0 = AIW_N/4, n1 = AOW_N/4, n2 = FCW_N/4, n3 = PJW_N/4, n4 = OPW_N/4;
    const long total = n0 + n1 + n2 + n3 + n4;
    long stride = (long)gridDim.x * blockDim.x;
    for (long i = (long)blockIdx.x * blockDim.x + threadIdx.x; i < total; i += stride) {
        const float4* s; uint2* d; long k = i;
        if (k < n0)              { s = s0; d = d0; }
        else if ((k -= n0) < n1) { s = s1; d = d1; }
        else if ((k -= n1) < n2) { s = s2; d = d2; }
        else if ((k -= n2) < n3) { s = s3; d = d3; }
        else                     { k -= n3; s = s4; d = d4; }
        d[k] = cvt4h(s[k]);
    }
}

// smem bytes for T activation terms + 1 weight array, chunk CH, 2 stages
#define PITCH_OF(CH)  ((CH)/2 + 4)
#define ARRU_OF(CH)   (128*PITCH_OF(CH))
#define DSMEM(T, CH)  (2*((T)+1)*ARRU_OF(CH)*4)

// ================= GEMM body template: C = (sum of T activation terms) @ W^T =================
// epi 0: fp32 acc+bias. 1: split(gelu)->hi/lo. 2: C+=ls*(acc+bias). 3: C=acc.
// epi 4: C+=ls*(..); Chi/Clo = fsplit(rowg*C). 5: Chi(fp16) = acc+bias.
template<int T, int CH>
__device__ __forceinline__ void tgemm_body(
    int N, int K, int m0, int n0, int base, int vrows,
    const u16* __restrict__ Ah, const u16* __restrict__ Al,
    const u16* __restrict__ WE,
    const float* __restrict__ bias,
    float* __restrict__ C, u16* __restrict__ Chi, u16* __restrict__ Clo,
    const float* __restrict__ ls, const float* __restrict__ rowg,
    int epi, uint32_t* SM)
{
    const int NARR = T + 1;
    const int PIT  = PITCH_OF(CH);
    const int ARRU = ARRU_OF(CH);
    const int BUFU = NARR * ARRU;
    const int QS   = CH / 8;        // 16B units per row
    const int NLD  = QS / 2;        // per-thread 16B loads per array
    uint32_t smb = smem_u32(SM);
    int tid = threadIdx.x;
    int warp = tid >> 5, lane = tid & 31;
    int wm = warp & 3, wn = warp >> 2;
    int g8 = lane >> 2, tg = lane & 3;

    const u16* src[NARR][NLD];
    uint32_t doff[NLD];
    #pragma unroll
    for (int j = 0; j < NLD; ++j) {
        int lin = j * 256 + tid;
        int row = lin / QS, q = lin % QS;
        doff[j] = (uint32_t)(row * PIT + q * 4) * 4;
        src[0][j] = Ah + (long)(m0 + row) * K + q * 8;
        if (T == 2) src[1][j] = Al + (long)(m0 + row) * K + q * 8;
        src[NARR-1][j] = WE + (long)(n0 + row) * K + q * 8;
    }

    float acc[2][8][4] = {};
    int nch = K / CH;

    #pragma unroll
    for (int a = 0; a < NARR; ++a)
        #pragma unroll
        for (int j = 0; j < NLD; ++j)
            CP16(smb + a * (ARRU*4) + doff[j], src[a][j]);
    CPCOMMIT();

    for (int c = 0; c < nch; ++c) {
        CPWAIT0();
        __syncthreads();
        if (c + 1 < nch) {
            long koff = (long)(c + 1) * CH;
            uint32_t bb = smb + ((c + 1) & 1) * (BUFU*4);
            #pragma unroll
            for (int a = 0; a < NARR; ++a)
                #pragma unroll
                for (int j = 0; j < NLD; ++j)
                    CP16(bb + a * (ARRU*4) + doff[j], src[a][j] + koff);
            CPCOMMIT();
        }
        const uint32_t* B = SM + (c & 1) * BUFU;
        const uint32_t* AsH = B;
        const uint32_t* AsL = B + ARRU;            // valid when T==2
        const uint32_t* Bs  = B + (NARR-1)*ARRU;
        #pragma unroll
        for (int kh = 0; kh < CH/16; ++kh) {
            int kb = kh * 8;
            uint32_t ah[2][4], al[2][4];
            #pragma unroll
            for (int mt = 0; mt < 2; ++mt) {
                int r = wm * 32 + mt * 16 + g8;
                ah[mt][0] = AsH[r*PIT + kb+tg];     ah[mt][1] = AsH[(r+8)*PIT + kb+tg];
                ah[mt][2] = AsH[r*PIT + kb+tg+4];   ah[mt][3] = AsH[(r+8)*PIT + kb+tg+4];
                if (T == 2) {
                    al[mt][0] = AsL[r*PIT + kb+tg];     al[mt][1] = AsL[(r+8)*PIT + kb+tg];
                    al[mt][2] = AsL[r*PIT + kb+tg+4];   al[mt][3] = AsL[(r+8)*PIT + kb+tg+4];
                }
            }
            #pragma unroll
            for (int nt = 0; nt < 8; ++nt) {
                int n = wn * 64 + nt * 8 + g8;
                uint32_t b2[2] = { Bs[n*PIT + kb+tg], Bs[n*PIT + kb+tg+4] };
                #pragma unroll
                for (int mt = 0; mt < 2; ++mt) {
                    mma16816(acc[mt][nt], ah[mt], b2);
                    if (T == 2) mma16816(acc[mt][nt], al[mt], b2);
                }
            }
        }
        __syncthreads();
    }

    #pragma unroll
    for (int mt = 0; mt < 2; ++mt) {
        int r0 = m0 + wm * 32 + mt * 16 + g8;
        int r1 = r0 + 8;
        bool ok0 = (r0 - base) < vrows;
        bool ok1 = (r1 - base) < vrows;
        #pragma unroll
        for (int nt = 0; nt < 8; ++nt) {
            int col = n0 + wn * 64 + nt * 8 + tg * 2;
            float* cc = acc[mt][nt];
            #pragma unroll
            for (int q = 0; q < 4; ++q) {
                int row = (q < 2) ? r0 : r1;
                bool ok = (q < 2) ? ok0 : ok1;
                if (!ok) continue;
                int cl = col + (q & 1);
                long idx = (long)row * N + cl;
                if (epi == 3) { C[idx] = cc[q]; continue; }
                float v = cc[q] + bias[cl];
                if (epi == 1) {
                    float gv = 0.5f * v * (1.f + erff(v * 0.70710678118654752f));
                    fsplit1(gv, Chi[idx], Clo[idx]);
                } else if (epi == 2) {
                    C[idx] = C[idx] + ls[cl] * v;
                } else if (epi == 4) {
                    float nv = C[idx] + ls[cl] * v;
                    C[idx] = nv;
                    fsplit1(rowg[row] * nv, Chi[idx], Clo[idx]);
                } else if (epi == 5) {
                    Chi[idx] = __half_as_ushort(__float2half(v));
                } else {
                    C[idx] = v;
                }
            }
        }
    }
}

__device__ __forceinline__ int resolve_expert(int m0, const int* segbase, int& base) {
    int e = -1; base = 0;
    #pragma unroll
    for (int i = 0; i < EXP; ++i)
        if (e < 0 && m0 >= segbase[i] && m0 < segbase[i+1]) { e = i; base = segbase[i]; }
    return e;
}

// ================= single-config GEMM =================
template<int T, int CH>
__global__ __launch_bounds__(256, 2) void k_tgemm(
    int N, int K,
    const u16* __restrict__ Ah, const u16* __restrict__ Al,
    const u16* __restrict__ W, long wES,
    const float* __restrict__ biasB, long bES,
    float* __restrict__ C, u16* __restrict__ Chi, u16* __restrict__ Clo,
    const float* __restrict__ lsB, long lsES,
    const float* __restrict__ rowg,
    int epi, const int* __restrict__ segbase, const int* __restrict__ valid)
{
    int m0 = blockIdx.y * 128, n0 = blockIdx.x * 128;
    int base, e = resolve_expert(m0, segbase, base);
    if (e < 0) return;
    extern __shared__ uint32_t SM[];
    tgemm_body<T, CH>(N, K, m0, n0, base, valid[e],
                      Ah, Al, W + (long)e*wES,
                      biasB ? (biasB + (long)e*bES) : (const float*)0,
                      C, Chi, Clo, lsB ? (lsB + (long)e*lsES) : (const float*)0, rowg, epi, SM);
}

// ================= dual GEMM: Q-proj + KV-proj, fp16 outputs, 1-term, chunk 64 =================
__global__ __launch_bounds__(256, 2) void k_tgemm_qkv(
    int ymid,
    const u16* __restrict__ QAh,
    const u16* __restrict__ QW, const float* __restrict__ Qbias,
    u16* __restrict__ QC16,
    const int* __restrict__ qseg, const int* __restrict__ qval,
    const u16* __restrict__ KAh,
    const u16* __restrict__ KW, const float* __restrict__ Kbias,
    u16* __restrict__ KC16,
    const int* __restrict__ kseg, const int* __restrict__ kval,
    long wES, long bES)
{
    extern __shared__ uint32_t SM[];
    if ((int)blockIdx.y < ymid) {
        if (blockIdx.x >= 8) return;
        int m0 = blockIdx.y * 128, n0 = blockIdx.x * 128;
        int base, e = resolve_expert(m0, qseg, base);
        if (e < 0) return;
        tgemm_body<1, 64>(HID, HID, m0, n0, base, qval[e],
                          QAh, (const u16*)0, QW + (long)e*wES,
                          Qbias, (float*)0, QC16, (u16*)0, (const float*)0, (const float*)0, 5, SM);
    } else {
        int m0 = (blockIdx.y - ymid) * 128, n0 = blockIdx.x * 128;
        int base, e = resolve_expert(m0, kseg, base);
        if (e < 0) return;
        tgemm_body<1, 64>(2048, HID, m0, n0, base, kval[e],
                          KAh, (const u16*)0, KW + (long)e*wES,
                          Kbias + (long)e*bES, (float*)0, KC16, (u16*)0, (const float*)0, (const float*)0, 5, SM);
    }
}

// ---------------- reductions ----------------
__device__ __forceinline__ void blockReduce2(float& a, float& b, float* sh) {
    __syncthreads();
    int lane = threadIdx.x & 31, wid = threadIdx.x >> 5;
    #pragma unroll
    for (int o = 16; o; o >>= 1) { a += __shfl_xor_sync(~0u, a, o); b += __shfl_xor_sync(~0u, b, o); }
    if (lane == 0) { sh[wid] = a; sh[wid + 32] = b; }
    __syncthreads();
    int nw = blockDim.x >> 5;
    if (wid == 0) {
        a = (lane < nw) ? sh[lane] : 0.f;
        b = (lane < nw) ? sh[lane + 32] : 0.f;
        #pragma unroll
        for (int o = 16; o; o >>= 1) { a += __shfl_xor_sync(~0u, a, o); b += __shfl_xor_sync(~0u, b, o); }
        if (lane == 0) { sh[0] = a; sh[32] = b; }
    }
    __syncthreads();
    a = sh[0]; b = sh[32];
}
__device__ __forceinline__ float blockReduce1(float a, float* sh) {
    __syncthreads();
    int lane = threadIdx.x & 31, wid = threadIdx.x >> 5;
    #pragma unroll
    for (int o = 16; o; o >>= 1) a += __shfl_xor_sync(~0u, a, o);
    if (lane == 0) sh[wid] = a;
    __syncthreads();
    int nw = blockDim.x >> 5;
    if (wid == 0) {
        a = (lane < nw) ? sh[lane] : 0.f;
        #pragma unroll
        for (int o = 16; o; o >>= 1) a += __shfl_xor_sync(~0u, a, o);
        if (lane == 0) sh[0] = a;
    }
    __syncthreads();
    return sh[0];
}

// ---------------- gate kernels ----------------
__global__ void k_gate_mean(const float* __restrict__ img, float* __restrict__ gi) {
    int b = blockIdx.x;
    int h = blockIdx.y * 64 + (threadIdx.x & 63);
    int part = threadIdx.x >> 6;
    __shared__ float sh[256];
    float s = 0.f;
    for (int l = part; l < LV_; l += 4)
        s += img[((long)b*LV_ + l)*HID + h];
    sh[threadIdx.x] = s;
    __syncthreads();
    if (part == 0) {
        float tot = sh[threadIdx.x] + sh[threadIdx.x + 64] + sh[threadIdx.x + 128] + sh[threadIdx.x + 192];
        gi[b*HID + h] = tot * (1.f/LV_);
    }
}
__global__ void k_gate(const float* __restrict__ gi, const float* __restrict__ temb,
                       const float* __restrict__ eemb, const int* __restrict__ tids,
                       const int* __restrict__ eids, const float* __restrict__ glw,
                       const float* __restrict__ glb, const float* __restrict__ gwt,
                       const float* __restrict__ gbias, float* __restrict__ gates) {
    int b = blockIdx.x, tid = threadIdx.x;
    __shared__ float sh[64];
    __shared__ float logits[EXP];
    int ti = tids[b], ei = eids[b];
    float s = 0.f, ss = 0.f;
    for (int i = tid; i < GN; i += 256) {
        float v = (i < HID) ? gi[b*HID + i]
                : (i < HID + TDIM) ? temb[ti*TDIM + i - HID]
                : eemb[ei*TDIM + i - HID - TDIM];
        s += v; ss += v*v;
    }
    blockReduce2(s, ss, sh);
    float m  = s * (1.f/GN);
    float rs = rsqrtf(ss * (1.f/GN) - m*m + 1e-5f);
    for (int e = 0; e < EXP; e++) {
        float d = 0.f;
        for (int i = tid; i < GN; i += 256) {
            float v = (i < HID) ? gi[b*HID + i]
                    : (i < HID + TDIM) ? temb[ti*TDIM + i - HID]
                    : eemb[ei*TDIM + i - HID - TDIM];
            d += ((v - m)*rs*glw[i] + glb[i]) * gwt[(long)e*GN + i];
        }
        d = blockReduce1(d, sh);
        if (tid == 0) logits[e] = d + gbias[e];
    }
    __syncthreads();
    if (tid == 0) {
        float w[EXP]; float mx = -1e30f;
        for (int e = 0; e < EXP; e++) { float l = fminf(fmaxf(logits[e], -15.f), 15.f); w[e] = l; mx = fmaxf(mx, l); }
        float sum = 0.f;
        for (int e = 0; e < EXP; e++) { w[e] = expf(w[e] - mx); sum += w[e]; }
        for (int e = 0; e < EXP; e++) w[e] /= sum;
        int i0 = 0;
        for (int e = 1; e < EXP; e++) if (w[e] > w[i0]) i0 = e;
        int i1 = -1;
        for (int e = 0; e < EXP; e++) { if (e == i0) continue; if (i1 < 0 || w[e] > w[i1]) i1 = e; }
        float t = w[i0] + w[i1] + 1e-9f;
        for (int e = 0; e < EXP; e++) gates[b*EXP + e] = 0.f;
        gates[b*EXP + i0] = w[i0] / t;
        gates[b*EXP + i1] = w[i1] / t;
    }
}
__global__ void k_slots(const float* __restrict__ gates, int* cnt, int* soff,
                        int* se, int* sb, float* sg,
                        int* xseg, int* kvseg, int* xvalid, int* kvvalid,
                        int* sxb, int* skvb, int* b2s, float* rowg) {
    if (threadIdx.x == 0) {
        int s = 0;
        for (int e = 0; e < EXP; e++) {
            soff[e] = s;
            int c = 0;
            for (int b = 0; b < BATCH; b++) {
                float g = gates[b*EXP + e];
                if (g != 0.f) { se[s] = e; sb[s] = b; sg[s] = g; s++; c++; }
            }
            cnt[e] = c;
        }
        xseg[0] = 0; kvseg[0] = 0;
        for (int e = 0; e < EXP; e++) {
            xvalid[e]  = cnt[e]*NQ_;
            kvvalid[e] = cnt[e]*KVR;
            xseg[e+1]  = xseg[e]  + ((cnt[e]*NQ_ + 127) & ~127);
            kvseg[e+1] = kvseg[e] + ((cnt[e]*KVR + 127) & ~127);
        }
        for (int i = 0; i < NSLOT; i++) {
            int e = se[i];
            sxb[i]  = xseg[e]  + (i - soff[e])*NQ_;
            skvb[i] = kvseg[e] + (i - soff[e])*KVR;
        }
        int fill[BATCH];
        for (int b = 0; b < BATCH; b++) fill[b] = 0;
        for (int i = 0; i < NSLOT; i++) {
            int b = sb[i];
            b2s[b*2 + fill[b]] = i;
            fill[b]++;
        }
    }
    __syncthreads();
    int tot = xseg[EXP];
    for (int r = threadIdx.x; r < tot; r += blockDim.x) {
        int e = 0, base = 0;
        for (int i = 0; i < EXP; i++)
            if (r >= xseg[i] && r < xseg[i+1]) { e = i; base = xseg[i]; }
        int local = r - base;
        rowg[r] = (local < cnt[e]*NQ_) ? sg[soff[e] + local/NQ_] : 0.f;
    }
}

// ---------------- init x = full query block per slot ----------------
__global__ void k_initx(const float* __restrict__ query, float* __restrict__ gx,
                        const int* __restrict__ se, const int* __restrict__ sxb) {
    int r = blockIdx.x, s = blockIdx.y;
    int e = se[s];
    const float* srow = query + ((long)e*NQ_ + r)*HID;
    float* d = gx + (long)(sxb[s] + r)*HID;
    for (int i = threadIdx.x; i < HID; i += blockDim.x) d[i] = srow[i];
}

// ---------------- merged LN: x rows + kv0 rows -> fp16 hi/lo ----------------
__global__ void k_ln_all(const float* __restrict__ xsrc,
                         const float* __restrict__ query, const float* __restrict__ img,
                         const float* __restrict__ pp,
                         const float* __restrict__ xw, const float* __restrict__ xb,
                         const float* __restrict__ kw, const float* __restrict__ kb, long pES,
                         u16* __restrict__ xdh, u16* __restrict__ xdl,
                         u16* __restrict__ kdh, u16* __restrict__ kdl,
                         const int* __restrict__ se, const int* __restrict__ sb,
                         const int* __restrict__ sxb, const int* __restrict__ skvb) {
    int rr = blockIdx.x, s = blockIdx.y;
    int e = se[s];
    const float* row;
    const float *w, *bv;
    u16 *dh, *dl;
    long doff;
    if (rr < NQ_) {
        doff = (long)(sxb[s] + rr)*HID;
        row = xsrc + doff;
        w = xw; bv = xb; dh = xdh; dl = xdl;
    } else {
        int r = rr - NQ_;
        int b = sb[s];
        int rl, sq, qo, io;
        if (r < 320)      { rl = r;       sq = 64; qo = 0;   io = 0;   }
        else if (r < 624) { rl = r - 320; sq = 48; qo = 64;  io = 256; }
        else              { rl = r - 624; sq = 32; qo = 112; io = 512; }
        if (rl < sq) row = query + ((long)e*NQ_ + qo + rl)*HID;
        else {
            int zi = io + rl - sq;
            if (zi < LV_) row = img + ((long)b*LV_ + zi)*HID;
            else          row = pp  + ((long)b*LP_ + zi - LV_)*HID;
        }
        doff = (long)(skvb[s] + r)*HID;
        w = kw; bv = kb; dh = kdh; dl = kdl;
    }
    __shared__ float sh[64];
    float v[4]; float sm = 0.f, ss = 0.f;
    #pragma unroll
    for (int t = 0; t < 4; t++) { v[t] = row[threadIdx.x + t*256]; sm += v[t]; ss += v[t]*v[t]; }
    blockReduce2(sm, ss, sh);
    float m  = sm * (1.f/HID);
    float rs = rsqrtf(ss * (1.f/HID) - m*m + 1e-5f);
    const float* we = w + (long)e*pES;
    const float* be = bv + (long)e*pES;
    #pragma unroll
    for (int t = 0; t < 4; t++) {
        int i = threadIdx.x + t*256;
        float rv = (v[t] - m)*rs*we[i] + be[i];
        fsplit1(rv, dh[doff + i], dl[doff + i]);
    }
}

// ---------------- LayerNorm (x rows only, MLP LN) ----------------
__global__ void k_ln(const float* __restrict__ src,
                     const float* __restrict__ w, const float* __restrict__ bvec, long pES,
                     u16* __restrict__ dh, u16* __restrict__ dl,
                     const int* __restrict__ se, const int* __restrict__ sxb) {
    int r = blockIdx.x, s = blockIdx.y;
    int e = se[s];
    long row = (long)(sxb[s] + r)*HID;
    __shared__ float sh[64];
    float v[4]; float sm = 0.f, ss = 0.f;
    #pragma unroll
    for (int t = 0; t < 4; t++) { v[t] = src[row + threadIdx.x + t*256]; sm += v[t]; ss += v[t]*v[t]; }
    blockReduce2(sm, ss, sh);
    float m  = sm * (1.f/HID);
    float rs = rsqrtf(ss * (1.f/HID) - m*m + 1e-5f);
    const float* we = w + (long)e*pES;
    const float* be = bvec + (long)e*pES;
    #pragma unroll
    for (int t = 0; t < 4; t++) {
        int i = threadIdx.x + t*256;
        float rv = (v[t] - m)*rs*we[i] + be[i];
        fsplit1(rv, dh[row + i], dl[row + i]);
    }
}

// ---------------- attention (fp16 Q/KV, 4-way ILP) -> fp16 hi/lo ----------------
__global__ void k_attn(const u16* __restrict__ q16, const u16* __restrict__ kv16,
                       u16* __restrict__ ath, u16* __restrict__ atl,
                       const int* __restrict__ sxb, const int* __restrict__ skvb) {
    int s = blockIdx.y, st = blockIdx.z;
    int sq    = (st == 0) ? 64 : (st == 1 ? 48 : 32);
    int qo    = (st == 0) ? 0  : (st == 1 ? 64 : 112);
    int kvo   = (st == 0) ? 0  : (st == 1 ? 320 : 624);
    int kvlen = sq + 256;
    int warp = threadIdx.x >> 5, lane = threadIdx.x & 31;
    int w = blockIdx.x * 4 + warp;
    if (w >= NHEADS * sq) return;
    int h = w / sq, qi = w % sq;
    __shared__ float sc[4][320];

    long qrow  = (long)sxb[s] + qo + qi;
    long kvrow = (long)skvb[s] + kvo;
    const __half2 qh = *(const __half2*)(q16 + qrow*HID + h*HDIM + lane*2);
    float q0 = __low2float(qh), q1 = __high2float(qh);
    const u16* kbase = kv16 + kvrow*2048 + h*HDIM + lane*2;
    float mx = -1e30f;
    for (int j = 0; j < kvlen; j += 4) {
        __half2 k0 = *(const __half2*)(kbase + (long)j*2048);
        __half2 k1 = *(const __half2*)(kbase + (long)(j+1)*2048);
        __half2 k2 = *(const __half2*)(kbase + (long)(j+2)*2048);
        __half2 k3 = *(const __half2*)(kbase + (long)(j+3)*2048);
        float p0 = q0*__low2float(k0) + q1*__high2float(k0);
        float p1 = q0*__low2float(k1) + q1*__high2float(k1);
        float p2 = q0*__low2float(k2) + q1*__high2float(k2);
        float p3 = q0*__low2float(k3) + q1*__high2float(k3);
        #pragma unroll
        for (int o = 16; o; o >>= 1) {
            p0 += __shfl_xor_sync(~0u, p0, o);
            p1 += __shfl_xor_sync(~0u, p1, o);
            p2 += __shfl_xor_sync(~0u, p2, o);
            p3 += __shfl_xor_sync(~0u, p3, o);
        }
        p0 *= 0.125f; p1 *= 0.125f; p2 *= 0.125f; p3 *= 0.125f;
        if (lane == 0) {
            sc[warp][j]   = p0; sc[warp][j+1] = p1;
            sc[warp][j+2] = p2; sc[warp][j+3] = p3;
        }
        mx = fmaxf(mx, fmaxf(fmaxf(p0, p1), fmaxf(p2, p3)));
    }
    __syncwarp();
    float se_ = 0.f;
    for (int j = lane; j < kvlen; j += 32) {
        float ex = __expf(sc[warp][j] - mx);
        sc[warp][j] = ex;
        se_ += ex;
    }
    #pragma unroll
    for (int o = 16; o; o >>= 1) se_ += __shfl_xor_sync(~0u, se_, o);
    __syncwarp();
    float inv = 1.f / se_;
    const u16* vbase = kv16 + kvrow*2048 + 1024 + h*HDIM + lane*2;
    float a0 = 0.f, a1 = 0.f;
    #pragma unroll 4
    for (int j = 0; j < kvlen; j++) {
        float p = sc[warp][j];
        __half2 vv = *(const __half2*)(vbase + (long)j*2048);
        a0 += p*__low2float(vv); a1 += p*__high2float(vv);
    }
    long ooff = qrow*HID + h*HDIM + lane*2;
    fsplit1(a0 * inv, ath[ooff],     atl[ooff]);
    fsplit1(a1 * inv, ath[ooff + 1], atl[ooff + 1]);
}

// ---------------- combine 2 slots per batch + gated bias + RMS + final scaling ----------------
__global__ void k_rms_combine(const float* __restrict__ O, const float* __restrict__ bo,
                              float* __restrict__ out, const float* __restrict__ fw,
                              const float* __restrict__ gain,
                              const int* __restrict__ b2s, const int* __restrict__ se,
                              const float* __restrict__ sg, const int* __restrict__ sxb) {
    int qrow = blockIdx.x, b = blockIdx.y;
    int s0 = b2s[b*2], s1 = b2s[b*2 + 1];
    int e0 = se[s0], e1 = se[s1];
    float g0 = sg[s0], g1 = sg[s1];
    long r0 = (long)(sxb[s0] + qrow)*OUTD;
    long r1 = (long)(sxb[s1] + qrow)*OUTD;
    const float* bo0 = bo + (long)e0*OUTD;
    const float* bo1 = bo + (long)e1*OUTD;
    float* orow = out + ((long)b*NQ_ + qrow)*OUTD;
    __shared__ float sh[64];
    float v[16]; float ss = 0.f;
    #pragma unroll
    for (int t = 0; t < 16; t++) {
        int o = threadIdx.x + t*256;
        float val = O[r0 + o] + O[r1 + o] + g0*bo0[o] + g1*bo1[o];
        v[t] = val; ss += val*val;
    }
    ss = blockReduce1(ss, sh);
    float sc = rsqrtf(ss * (1.f/OUTD) + 1e-6f);
    #pragma unroll
    for (int t = 0; t < 16; t++) {
        int o = threadIdx.x + t*256;
        orow[o] = v[t]*sc*fw[o]*gain[o];
    }
}

// ---------------- host orchestration ----------------
extern "C" void kernel_launch(void* const* d_in, const int* in_sizes, int n_in,
                              void* d_out, int out_size) {
    const float* image     = (const float*)d_in[0];
    const float* pp        = (const float*)d_in[1];
    const int*   tids      = (const int*)  d_in[2];
    const int*   eids      = (const int*)  d_in[3];
    const float* query     = (const float*)d_in[4];
    const float* ln1_w     = (const float*)d_in[5];
    const float* ln1_b     = (const float*)d_in[6];
    const float* ln1kv_w   = (const float*)d_in[7];
    const float* ln1kv_b   = (const float*)d_in[8];
    const float* attn_in_w = (const float*)d_in[9];
    const float* attn_in_b = (const float*)d_in[10];
    const float* attn_out_w= (const float*)d_in[11];
    const float* attn_out_b= (const float*)d_in[12];
    const float* ls1       = (const float*)d_in[13];
    const float* ls2       = (const float*)d_in[14];
    const float* ln2_w     = (const float*)d_in[15];
    const float* ln2_b     = (const float*)d_in[16];
    const float* fc_w      = (const float*)d_in[17];
    const float* fc_b      = (const float*)d_in[18];
    const float* proj_w    = (const float*)d_in[19];
    const float* proj_b    = (const float*)d_in[20];
    const float* outp_w    = (const float*)d_in[21];
    const float* outp_b    = (const float*)d_in[22];
    const float* temb      = (const float*)d_in[23];
    const float* eemb      = (const float*)d_in[24];
    const float* glw       = (const float*)d_in[25];
    const float* glb       = (const float*)d_in[26];
    const float* gwt       = (const float*)d_in[27];
    const float* gbias     = (const float*)d_in[28];
    const float* gain      = (const float*)d_in[29];
    const float* fw        = (const float*)d_in[30];
    float* out = (float*)d_out;

    float *px, *po, *pg, *pgi, *prowg;
    int *pcnt, *psoff, *pse, *psb, *pxseg, *pkvseg, *pxval, *pkvval, *psxb, *pskvb, *pb2s;
    float *psg;
    cudaGetSymbolAddress((void**)&px,    g_x);
    cudaGetSymbolAddress((void**)&po,    g_o);
    cudaGetSymbolAddress((void**)&pg,    g_gates);
    cudaGetSymbolAddress((void**)&pgi,   g_gi);
    cudaGetSymbolAddress((void**)&pcnt,  g_cnt);
    cudaGetSymbolAddress((void**)&psoff, g_soff);
    cudaGetSymbolAddress((void**)&pse,   g_se);
    cudaGetSymbolAddress((void**)&psb,   g_sb);
    cudaGetSymbolAddress((void**)&psg,   g_sg);
    cudaGetSymbolAddress((void**)&pxseg, g_xseg);
    cudaGetSymbolAddress((void**)&pkvseg,g_kvseg);
    cudaGetSymbolAddress((void**)&pxval, g_xvalid);
    cudaGetSymbolAddress((void**)&pkvval,g_kvvalid);
    cudaGetSymbolAddress((void**)&psxb,  g_sxb);
    cudaGetSymbolAddress((void**)&pskvb, g_skvb);
    cudaGetSymbolAddress((void**)&pb2s,  g_b2s);
    cudaGetSymbolAddress((void**)&prowg, g_rowg);

    u16 *pq16, *pkv16;
    cudaGetSymbolAddress((void**)&pq16,  g_q16);
    cudaGetSymbolAddress((void**)&pkv16, g_kv16);

    u16 *xh, *xl, *kh, *kl, *ah, *al, *fh, *fl;
    cudaGetSymbolAddress((void**)&xh, g_xln_h); cudaGetSymbolAddress((void**)&xl, g_xln_l);
    cudaGetSymbolAddress((void**)&kh, g_kvn_h); cudaGetSymbolAddress((void**)&kl, g_kvn_l);
    cudaGetSymbolAddress((void**)&ah, g_att_h); cudaGetSymbolAddress((void**)&al, g_att_l);
    cudaGetSymbolAddress((void**)&fh, g_ffn_h); cudaGetSymbolAddress((void**)&fl, g_ffn_l);

    u16 *aiw, *aow, *fcw, *pjw, *opw;
    cudaGetSymbolAddress((void**)&aiw, g_aiw);
    cudaGetSymbolAddress((void**)&aow, g_aow);
    cudaGetSymbolAddress((void**)&fcw, g_fcw);
    cudaGetSymbolAddress((void**)&pjw, g_pjw);
    cudaGetSymbolAddress((void**)&opw, g_opw);

    cudaFuncSetAttribute((const void*)k_tgemm<1,64>, cudaFuncAttributeMaxDynamicSharedMemorySize, DSMEM(1,64));
    cudaFuncSetAttribute((const void*)k_tgemm<2,32>, cudaFuncAttributeMaxDynamicSharedMemorySize, DSMEM(2,32));
    cudaFuncSetAttribute((const void*)k_tgemm_qkv,   cudaFuncAttributeMaxDynamicSharedMemorySize, DSMEM(1,64));

    k_cvt_all<<<2048, 256>>>(
        (const float4*)attn_in_w,  (uint2*)aiw,
        (const float4*)attn_out_w, (uint2*)aow,
        (const float4*)fc_w,       (uint2*)fcw,
        (const float4*)proj_w,     (uint2*)pjw,
        (const float4*)outp_w,     (uint2*)opw);

    k_gate_mean<<<dim3(BATCH, 16), 256>>>(image, pgi);
    k_gate<<<BATCH, 256>>>(pgi, temb, eemb, tids, eids, glw, glb, gwt, gbias, pg);
    k_slots<<<1, 256>>>(pg, pcnt, psoff, pse, psb, psg,
                        pxseg, pkvseg, pxval, pkvval, psxb, pskvb, pb2s, prowg);

    k_initx<<<dim3(NQ_, NSLOT), 256>>>(query, px, pse, psxb);

    const long HH = (long)HID*HID;
    const int XMB = 22;
    const int KVMB = 118;

    for (int l = 0; l < NLAYERS; l++) {
        k_ln_all<<<dim3(NQ_ + KVR, NSLOT), 256>>>(px, query, image, pp,
            ln1_w + (long)l*HID, ln1_b + (long)l*HID,
            ln1kv_w + (long)l*HID, ln1kv_b + (long)l*HID, (long)NLAYERS*HID,
            xh, xl, kh, kl, pse, psb, psxb, pskvb);
        // Q + KV projections, 1-term activations, chunk 64
        k_tgemm_qkv<<<dim3(16, XMB + KVMB), 256, DSMEM(1,64)>>>(XMB,
            xh, aiw + (long)l*3*HH,
            attn_in_b + (long)l*3*HID, pq16, pxseg, pxval,
            kh, aiw + (long)l*3*HH + HH,
            attn_in_b + (long)l*3*HID + HID, pkv16, pkvseg, pkvval,
            (long)NLAYERS*3*HH, (long)NLAYERS*3*HID);
        k_attn<<<dim3(256, NSLOT, 3), 128>>>(pq16, pkv16, ah, al, psxb, pskvb);
        // attn-out projection + residual (ls1-damped): 1-term, chunk 64
        k_tgemm<1,64><<<dim3(8, XMB), 256, DSMEM(1,64)>>>(HID, HID,
            ah, al, aow + (long)l*HH, (long)NLAYERS*HH,
            attn_out_b + (long)l*HID, (long)NLAYERS*HID,
            px, (u16*)0, (u16*)0, ls1 + (long)l*HID, (long)NLAYERS*HID,
            (const float*)0, 2, pxseg, pxval);
        k_ln<<<dim3(NQ_, NSLOT), 256>>>(px,
            ln2_w + (long)l*HID, ln2_b + (long)l*HID, (long)NLAYERS*HID,
            xh, xl, pse, psxb);
        // FC: 1-term, chunk 64
        k_tgemm<1,64><<<dim3(32, XMB), 256, DSMEM(1,64)>>>(4*HID, HID,
            xh, xl, fcw + (long)l*4*HH, (long)NLAYERS*4*HH,
            fc_b + (long)l*4*HID, (long)NLAYERS*4*HID,
            (float*)0, fh, fl, (const float*)0, 0,
            (const float*)0, 1, pxseg, pxval);
        // proj: 1-term, chunk 64; last layer fuses gate-scaled fp16 split (epi 4)
        k_tgemm<1,64><<<dim3(8, XMB), 256, DSMEM(1,64)>>>(HID, 4*HID,
            fh, fl, pjw + (long)l*4*HH, (long)NLAYERS*4*HH,
            proj_b + (long)l*HID, (long)NLAYERS*HID,
            px, xh, xl, ls2 + (long)l*HID, (long)NLAYERS*HID,
            prowg, (l == NLAYERS-1) ? 4 : 2, pxseg, pxval);
    }

    // out projection: undamped direct path — 2-term activations, chunk 32
    k_tgemm<2,32><<<dim3(OUTD/128, XMB), 256, DSMEM(2,32)>>>(OUTD, HID,
        xh, xl, opw, (long)OUTD*HID,
        (const float*)0, 0,
        po, (u16*)0, (u16*)0, (const float*)0, 0,
        (const float*)0, 3, pxseg, pxval);
    k_rms_combine<<<dim3(NQ_, BATCH), 256>>>(po, outp_b, out, fw, gain, pb2s, pse, psg, psxb);
}

// round 16
// speedup vs baseline: 6.1559x; 1.0332x over previous
#include <cuda_runtime.h>
#include <cuda_fp16.h>
#include <math.h>
#include <stdint.h>

typedef unsigned short u16;

// ---------------- problem constants ----------------
#define EXP    4
#define BATCH  8
#define NQ_    144
#define NLAYERS 2
#define NHEADS 16
#define HDIM   64
#define HID    1024
#define OUTD   4096
#define TDIM   256
#define LV_    576
#define LP_    192
#define NSLOT  16
#define GN     (HID + 2*TDIM)   // 1536
#define KVR    912
#define XROWS  3072
#define KVROWS 16384

// ---------------- fp32 scratch ----------------
__device__ float g_x   [XROWS*HID];
__device__ float g_o   [XROWS*OUTD];
__device__ float g_gates[BATCH*EXP];
__device__ float g_gi  [BATCH*HID];

// fp16 Q / KV buffers
__device__ u16 g_q16 [XROWS*HID];
__device__ u16 g_kv16[KVROWS*2048];   // K | V

// slot metadata
__device__ int   g_cnt[EXP], g_soff[EXP];
__device__ int   g_se[NSLOT], g_sb[NSLOT];
__device__ float g_sg[NSLOT];
__device__ int   g_xseg[EXP+1], g_kvseg[EXP+1];
__device__ int   g_xvalid[EXP], g_kvvalid[EXP];
__device__ int   g_sxb[NSLOT], g_skvb[NSLOT];
__device__ int   g_b2s[BATCH*2];
__device__ float g_rowg[XROWS];

// ---------------- fp16 hi/lo activation scratch ----------------
__device__ u16 g_xln_h[XROWS*HID],  g_xln_l[XROWS*HID];
__device__ u16 g_kvn_h[KVROWS*HID], g_kvn_l[KVROWS*HID];
__device__ u16 g_att_h[XROWS*HID],  g_att_l[XROWS*HID];
__device__ u16 g_ffn_h[XROWS*4096], g_ffn_l[XROWS*4096];

// ---------------- fp16 weight scratch ----------------
#define AIW_N (EXP*NLAYERS*3*HID*HID)
#define AOW_N (EXP*NLAYERS*HID*HID)
#define FCW_N (EXP*NLAYERS*4*HID*HID)
#define PJW_N (EXP*NLAYERS*HID*4*HID)
#define OPW_N (EXP*OUTD*HID)
__device__ u16 g_aiw[AIW_N];
__device__ u16 g_aow[AOW_N];
__device__ u16 g_fcw[FCW_N];
__device__ u16 g_pjw[PJW_N];
__device__ u16 g_opw[OPW_N];

// ================= helpers =================
__device__ __forceinline__ void mma16816(float* c, const uint32_t* a, const uint32_t* b) {
    asm volatile("mma.sync.aligned.m16n8k16.row.col.f32.f16.f16.f32 "
        "{%0,%1,%2,%3}, {%4,%5,%6,%7}, {%8,%9}, {%0,%1,%2,%3};"
        : "+f"(c[0]), "+f"(c[1]), "+f"(c[2]), "+f"(c[3])
        : "r"(a[0]), "r"(a[1]), "r"(a[2]), "r"(a[3]), "r"(b[0]), "r"(b[1]));
}
__device__ __forceinline__ void ldmA(uint32_t* r, uint32_t addr) {
    asm volatile("ldmatrix.sync.aligned.m8n8.x4.shared.b16 {%0,%1,%2,%3}, [%4];"
        : "=r"(r[0]), "=r"(r[1]), "=r"(r[2]), "=r"(r[3]) : "r"(addr));
}
__device__ __forceinline__ void ldmB(uint32_t* r, uint32_t addr) {
    asm volatile("ldmatrix.sync.aligned.m8n8.x2.shared.b16 {%0,%1}, [%2];"
        : "=r"(r[0]), "=r"(r[1]) : "r"(addr));
}
__device__ __forceinline__ void fsplit1(float v, u16& h, u16& l) {
    __half hh = __float2half(v);
    h = __half_as_ushort(hh);
    l = __half_as_ushort(__float2half(v - __half2float(hh)));
}
__device__ __forceinline__ uint2 cvt4h(float4 v) {
    __half2 a = __floats2half2_rn(v.x, v.y);
    __half2 b = __floats2half2_rn(v.z, v.w);
    uint2 r;
    r.x = *reinterpret_cast<uint32_t*>(&a);
    r.y = *reinterpret_cast<uint32_t*>(&b);
    return r;
}
__device__ __forceinline__ uint32_t smem_u32(const void* p) {
    uint32_t a;
    asm("{ .reg .u64 t; cvta.to.shared.u64 t, %1; cvt.u32.u64 %0, t; }" : "=r"(a) : "l"(p));
    return a;
}
#define CP16(dst, src) asm volatile("cp.async.cg.shared.global [%0], [%1], 16;" :: "r"(dst), "l"(src) : "memory")
#define CPCOMMIT() asm volatile("cp.async.commit_group;" ::: "memory")
#define CPWAIT0()  asm volatile("cp.async.wait_group 0;" ::: "memory")

// ---------------- merged weight convert fp32 -> fp16 ----------------
__global__ void k_cvt_all(const float4* __restrict__ s0, uint2* __restrict__ d0,
                          const float4* __restrict__ s1, uint2* __restrict__ d1,
                          const float4* __restrict__ s2, uint2* __restrict__ d2,
                          const float4* __restrict__ s3, uint2* __restrict__ d3,
                          const float4* __restrict__ s4, uint2* __restrict__ d4) {
    const long n0 = AIW_N/4, n1 = AOW_N/4, n2 = FCW_N/4, n3 = PJW_N/4, n4 = OPW_N/4;
    const long total = n0 + n1 + n2 + n3 + n4;
    long stride = (long)gridDim.x * blockDim.x;
    for (long i = (long)blockIdx.x * blockDim.x + threadIdx.x; i < total; i += stride) {
        const float4* s; uint2* d; long k = i;
        if (k < n0)              { s = s0; d = d0; }
        else if ((k -= n0) < n1) { s = s1; d = d1; }
        else if ((k -= n1) < n2) { s = s2; d = d2; }
        else if ((k -= n2) < n3) { s = s3; d = d3; }
        else                     { k -= n3; s = s4; d = d4; }
        d[k] = cvt4h(s[k]);
    }
}

// smem bytes for T activation terms + 1 weight array, chunk CH, 2 stages
#define PITCH_OF(CH)  ((CH)/2 + 4)
#define ARRU_OF(CH)   (128*PITCH_OF(CH))
#define DSMEM(T, CH)  (2*((T)+1)*ARRU_OF(CH)*4)

// ================= GEMM body template: C = (sum of T activation terms) @ W^T =================
// epi 0: fp32 acc+bias. 1: split(gelu)->hi/lo. 2: C+=ls*(acc+bias). 3: C=acc.
// epi 4: C+=ls*(..); Chi/Clo = fsplit(rowg*C). 5: Chi(fp16) = acc+bias.
template<int T, int CH>
__device__ __forceinline__ void tgemm_body(
    int N, int K, int m0, int n0, int base, int vrows,
    const u16* __restrict__ Ah, const u16* __restrict__ Al,
    const u16* __restrict__ WE,
    const float* __restrict__ bias,
    float* __restrict__ C, u16* __restrict__ Chi, u16* __restrict__ Clo,
    const float* __restrict__ ls, const float* __restrict__ rowg,
    int epi, uint32_t* SM)
{
    const int NARR = T + 1;
    const int PIT  = PITCH_OF(CH);
    const int ARRU = ARRU_OF(CH);
    const int BUFU = NARR * ARRU;
    const int QS   = CH / 8;        // 16B units per row
    const int NLD  = QS / 2;        // per-thread 16B loads per array
    uint32_t smb = smem_u32(SM);
    int tid = threadIdx.x;
    int warp = tid >> 5, lane = tid & 31;
    int wm = warp & 3, wn = warp >> 2;
    int g8 = lane >> 2, tg = lane & 3;

    const u16* src[NARR][NLD];
    uint32_t doff[NLD];
    #pragma unroll
    for (int j = 0; j < NLD; ++j) {
        int lin = j * 256 + tid;
        int row = lin / QS, q = lin % QS;
        doff[j] = (uint32_t)(row * PIT + q * 4) * 4;
        src[0][j] = Ah + (long)(m0 + row) * K + q * 8;
        if (T == 2) src[1][j] = Al + (long)(m0 + row) * K + q * 8;
        src[NARR-1][j] = WE + (long)(n0 + row) * K + q * 8;
    }

    // ldmatrix per-lane relative byte offsets within one array
    uint32_t relA[2];
    #pragma unroll
    for (int mt = 0; mt < 2; ++mt) {
        int R = wm * 32 + mt * 16;
        relA[mt] = (uint32_t)((R + (lane & 15)) * PIT + (lane >> 4) * 4) * 4;
    }
    uint32_t relB[8];
    #pragma unroll
    for (int nt = 0; nt < 8; ++nt) {
        int N0 = wn * 64 + nt * 8;
        relB[nt] = (uint32_t)((N0 + (lane & 7)) * PIT + ((lane >> 3) & 1) * 4) * 4;
    }

    float acc[2][8][4] = {};
    int nch = K / CH;

    #pragma unroll
    for (int a = 0; a < NARR; ++a)
        #pragma unroll
        for (int j = 0; j < NLD; ++j)
            CP16(smb + a * (ARRU*4) + doff[j], src[a][j]);
    CPCOMMIT();

    for (int c = 0; c < nch; ++c) {
        CPWAIT0();
        __syncthreads();
        if (c + 1 < nch) {
            long koff = (long)(c + 1) * CH;
            uint32_t bb = smb + ((c + 1) & 1) * (BUFU*4);
            #pragma unroll
            for (int a = 0; a < NARR; ++a)
                #pragma unroll
                for (int j = 0; j < NLD; ++j)
                    CP16(bb + a * (ARRU*4) + doff[j], src[a][j] + koff);
            CPCOMMIT();
        }
        uint32_t bufb = smb + (c & 1) * (BUFU*4);
        uint32_t aBase = bufb;                      // AsH
        uint32_t lBase = bufb + ARRU*4;             // AsL (T==2)
        uint32_t bBase = bufb + (NARR-1)*(ARRU*4);  // Bs
        #pragma unroll
        for (int kh = 0; kh < CH/16; ++kh) {
            uint32_t ko = (uint32_t)kh * 32;        // kh*8 u32 = 32 bytes
            uint32_t ah[2][4], al[2][4];
            #pragma unroll
            for (int mt = 0; mt < 2; ++mt) {
                ldmA(ah[mt], aBase + relA[mt] + ko);
                if (T == 2) ldmA(al[mt], lBase + relA[mt] + ko);
            }
            #pragma unroll
            for (int nt = 0; nt < 8; ++nt) {
                uint32_t b2[2];
                ldmB(b2, bBase + relB[nt] + ko);
                #pragma unroll
                for (int mt = 0; mt < 2; ++mt) {
                    mma16816(acc[mt][nt], ah[mt], b2);
                    if (T == 2) mma16816(acc[mt][nt], al[mt], b2);
                }
            }
        }
        __syncthreads();
    }

    #pragma unroll
    for (int mt = 0; mt < 2; ++mt) {
        int r0 = m0 + wm * 32 + mt * 16 + g8;
        int r1 = r0 + 8;
        bool ok0 = (r0 - base) < vrows;
        bool ok1 = (r1 - base) < vrows;
        #pragma unroll
        for (int nt = 0; nt < 8; ++nt) {
            int col = n0 + wn * 64 + nt * 8 + tg * 2;
            float* cc = acc[mt][nt];
            #pragma unroll
            for (int q = 0; q < 4; ++q) {
                int row = (q < 2) ? r0 : r1;
                bool ok = (q < 2) ? ok0 : ok1;
                if (!ok) continue;
                int cl = col + (q & 1);
                long idx = (long)row * N + cl;
                if (epi == 3) { C[idx] = cc[q]; continue; }
                float v = cc[q] + bias[cl];
                if (epi == 1) {
                    float gv = 0.5f * v * (1.f + erff(v * 0.70710678118654752f));
                    fsplit1(gv, Chi[idx], Clo[idx]);
                } else if (epi == 2) {
                    C[idx] = C[idx] + ls[cl] * v;
                } else if (epi == 4) {
                    float nv = C[idx] + ls[cl] * v;
                    C[idx] = nv;
                    fsplit1(rowg[row] * nv, Chi[idx], Clo[idx]);
                } else if (epi == 5) {
                    Chi[idx] = __half_as_ushort(__float2half(v));
                } else {
                    C[idx] = v;
                }
            }
        }
    }
}

__device__ __forceinline__ int resolve_expert(int m0, const int* segbase, int& base) {
    int e = -1; base = 0;
    #pragma unroll
    for (int i = 0; i < EXP; ++i)
        if (e < 0 && m0 >= segbase[i] && m0 < segbase[i+1]) { e = i; base = segbase[i]; }
    return e;
}

// ================= single-config GEMM =================
template<int T, int CH>
__global__ __launch_bounds__(256, 2) void k_tgemm(
    int N, int K,
    const u16* __restrict__ Ah, const u16* __restrict__ Al,
    const u16* __restrict__ W, long wES,
    const float* __restrict__ biasB, long bES,
    float* __restrict__ C, u16* __restrict__ Chi, u16* __restrict__ Clo,
    const float* __restrict__ lsB, long lsES,
    const float* __restrict__ rowg,
    int epi, const int* __restrict__ segbase, const int* __restrict__ valid)
{
    int m0 = blockIdx.y * 128, n0 = blockIdx.x * 128;
    int base, e = resolve_expert(m0, segbase, base);
    if (e < 0) return;
    extern __shared__ uint32_t SM[];
    tgemm_body<T, CH>(N, K, m0, n0, base, valid[e],
                      Ah, Al, W + (long)e*wES,
                      biasB ? (biasB + (long)e*bES) : (const float*)0,
                      C, Chi, Clo, lsB ? (lsB + (long)e*lsES) : (const float*)0, rowg, epi, SM);
}

// ================= dual GEMM: Q-proj + KV-proj, fp16 outputs, 1-term, chunk 64 =================
__global__ __launch_bounds__(256, 2) void k_tgemm_qkv(
    int ymid,
    const u16* __restrict__ QAh,
    const u16* __restrict__ QW, const float* __restrict__ Qbias,
    u16* __restrict__ QC16,
    const int* __restrict__ qseg, const int* __restrict__ qval,
    const u16* __restrict__ KAh,
    const u16* __restrict__ KW, const float* __restrict__ Kbias,
    u16* __restrict__ KC16,
    const int* __restrict__ kseg, const int* __restrict__ kval,
    long wES, long bES)
{
    extern __shared__ uint32_t SM[];
    if ((int)blockIdx.y < ymid) {
        if (blockIdx.x >= 8) return;
        int m0 = blockIdx.y * 128, n0 = blockIdx.x * 128;
        int base, e = resolve_expert(m0, qseg, base);
        if (e < 0) return;
        tgemm_body<1, 64>(HID, HID, m0, n0, base, qval[e],
                          QAh, (const u16*)0, QW + (long)e*wES,
                          Qbias, (float*)0, QC16, (u16*)0, (const float*)0, (const float*)0, 5, SM);
    } else {
        int m0 = (blockIdx.y - ymid) * 128, n0 = blockIdx.x * 128;
        int base, e = resolve_expert(m0, kseg, base);
        if (e < 0) return;
        tgemm_body<1, 64>(2048, HID, m0, n0, base, kval[e],
                          KAh, (const u16*)0, KW + (long)e*wES,
                          Kbias + (long)e*bES, (float*)0, KC16, (u16*)0, (const float*)0, (const float*)0, 5, SM);
    }
}

// ---------------- reductions ----------------
__device__ __forceinline__ void blockReduce2(float& a, float& b, float* sh) {
    __syncthreads();
    int lane = threadIdx.x & 31, wid = threadIdx.x >> 5;
    #pragma unroll
    for (int o = 16; o; o >>= 1) { a += __shfl_xor_sync(~0u, a, o); b += __shfl_xor_sync(~0u, b, o); }
    if (lane == 0) { sh[wid] = a; sh[wid + 32] = b; }
    __syncthreads();
    int nw = blockDim.x >> 5;
    if (wid == 0) {
        a = (lane < nw) ? sh[lane] : 0.f;
        b = (lane < nw) ? sh[lane + 32] : 0.f;
        #pragma unroll
        for (int o = 16; o; o >>= 1) { a += __shfl_xor_sync(~0u, a, o); b += __shfl_xor_sync(~0u, b, o); }
        if (lane == 0) { sh[0] = a; sh[32] = b; }
    }
    __syncthreads();
    a = sh[0]; b = sh[32];
}
__device__ __forceinline__ float blockReduce1(float a, float* sh) {
    __syncthreads();
    int lane = threadIdx.x & 31, wid = threadIdx.x >> 5;
    #pragma unroll
    for (int o = 16; o; o >>= 1) a += __shfl_xor_sync(~0u, a, o);
    if (lane == 0) sh[wid] = a;
    __syncthreads();
    int nw = blockDim.x >> 5;
    if (wid == 0) {
        a = (lane < nw) ? sh[lane] : 0.f;
        #pragma unroll
        for (int o = 16; o; o >>= 1) a += __shfl_xor_sync(~0u, a, o);
        if (lane == 0) sh[0] = a;
    }
    __syncthreads();
    return sh[0];
}

// ---------------- gate kernels ----------------
__global__ void k_gate_mean(const float* __restrict__ img, float* __restrict__ gi) {
    int b = blockIdx.x;
    int h = blockIdx.y * 64 + (threadIdx.x & 63);
    int part = threadIdx.x >> 6;
    __shared__ float sh[256];
    float s = 0.f;
    for (int l = part; l < LV_; l += 4)
        s += img[((long)b*LV_ + l)*HID + h];
    sh[threadIdx.x] = s;
    __syncthreads();
    if (part == 0) {
        float tot = sh[threadIdx.x] + sh[threadIdx.x + 64] + sh[threadIdx.x + 128] + sh[threadIdx.x + 192];
        gi[b*HID + h] = tot * (1.f/LV_);
    }
}
__global__ void k_gate(const float* __restrict__ gi, const float* __restrict__ temb,
                       const float* __restrict__ eemb, const int* __restrict__ tids,
                       const int* __restrict__ eids, const float* __restrict__ glw,
                       const float* __restrict__ glb, const float* __restrict__ gwt,
                       const float* __restrict__ gbias, float* __restrict__ gates) {
    int b = blockIdx.x, tid = threadIdx.x;
    __shared__ float sh[64];
    __shared__ float logits[EXP];
    int ti = tids[b], ei = eids[b];
    float s = 0.f, ss = 0.f;
    for (int i = tid; i < GN; i += 256) {
        float v = (i < HID) ? gi[b*HID + i]
                : (i < HID + TDIM) ? temb[ti*TDIM + i - HID]
                : eemb[ei*TDIM + i - HID - TDIM];
        s += v; ss += v*v;
    }
    blockReduce2(s, ss, sh);
    float m  = s * (1.f/GN);
    float rs = rsqrtf(ss * (1.f/GN) - m*m + 1e-5f);
    for (int e = 0; e < EXP; e++) {
        float d = 0.f;
        for (int i = tid; i < GN; i += 256) {
            float v = (i < HID) ? gi[b*HID + i]
                    : (i < HID + TDIM) ? temb[ti*TDIM + i - HID]
                    : eemb[ei*TDIM + i - HID - TDIM];
            d += ((v - m)*rs*glw[i] + glb[i]) * gwt[(long)e*GN + i];
        }
        d = blockReduce1(d, sh);
        if (tid == 0) logits[e] = d + gbias[e];
    }
    __syncthreads();
    if (tid == 0) {
        float w[EXP]; float mx = -1e30f;
        for (int e = 0; e < EXP; e++) { float l = fminf(fmaxf(logits[e], -15.f), 15.f); w[e] = l; mx = fmaxf(mx, l); }
        float sum = 0.f;
        for (int e = 0; e < EXP; e++) { w[e] = expf(w[e] - mx); sum += w[e]; }
        for (int e = 0; e < EXP; e++) w[e] /= sum;
        int i0 = 0;
        for (int e = 1; e < EXP; e++) if (w[e] > w[i0]) i0 = e;
        int i1 = -1;
        for (int e = 0; e < EXP; e++) { if (e == i0) continue; if (i1 < 0 || w[e] > w[i1]) i1 = e; }
        float t = w[i0] + w[i1] + 1e-9f;
        for (int e = 0; e < EXP; e++) gates[b*EXP + e] = 0.f;
        gates[b*EXP + i0] = w[i0] / t;
        gates[b*EXP + i1] = w[i1] / t;
    }
}
__global__ void k_slots(const float* __restrict__ gates, int* cnt, int* soff,
                        int* se, int* sb, float* sg,
                        int* xseg, int* kvseg, int* xvalid, int* kvvalid,
                        int* sxb, int* skvb, int* b2s, float* rowg) {
    if (threadIdx.x == 0) {
        int s = 0;
        for (int e = 0; e < EXP; e++) {
            soff[e] = s;
            int c = 0;
            for (int b = 0; b < BATCH; b++) {
                float g = gates[b*EXP + e];
                if (g != 0.f) { se[s] = e; sb[s] = b; sg[s] = g; s++; c++; }
            }
            cnt[e] = c;
        }
        xseg[0] = 0; kvseg[0] = 0;
        for (int e = 0; e < EXP; e++) {
            xvalid[e]  = cnt[e]*NQ_;
            kvvalid[e] = cnt[e]*KVR;
            xseg[e+1]  = xseg[e]  + ((cnt[e]*NQ_ + 127) & ~127);
            kvseg[e+1] = kvseg[e] + ((cnt[e]*KVR + 127) & ~127);
        }
        for (int i = 0; i < NSLOT; i++) {
            int e = se[i];
            sxb[i]  = xseg[e]  + (i - soff[e])*NQ_;
            skvb[i] = kvseg[e] + (i - soff[e])*KVR;
        }
        int fill[BATCH];
        for (int b = 0; b < BATCH; b++) fill[b] = 0;
        for (int i = 0; i < NSLOT; i++) {
            int b = sb[i];
            b2s[b*2 + fill[b]] = i;
            fill[b]++;
        }
    }
    __syncthreads();
    int tot = xseg[EXP];
    for (int r = threadIdx.x; r < tot; r += blockDim.x) {
        int e = 0, base = 0;
        for (int i = 0; i < EXP; i++)
            if (r >= xseg[i] && r < xseg[i+1]) { e = i; base = xseg[i]; }
        int local = r - base;
        rowg[r] = (local < cnt[e]*NQ_) ? sg[soff[e] + local/NQ_] : 0.f;
    }
}

// ---------------- init x = full query block per slot ----------------
__global__ void k_initx(const float* __restrict__ query, float* __restrict__ gx,
                        const int* __restrict__ se, const int* __restrict__ sxb) {
    int r = blockIdx.x, s = blockIdx.y;
    int e = se[s];
    const float* srow = query + ((long)e*NQ_ + r)*HID;
    float* d = gx + (long)(sxb[s] + r)*HID;
    for (int i = threadIdx.x; i < HID; i += blockDim.x) d[i] = srow[i];
}

// ---------------- merged LN: x rows + kv0 rows -> fp16 hi/lo ----------------
__global__ void k_ln_all(const float* __restrict__ xsrc,
                         const float* __restrict__ query, const float* __restrict__ img,
                         const float* __restrict__ pp,
                         const float* __restrict__ xw, const float* __restrict__ xb,
                         const float* __restrict__ kw, const float* __restrict__ kb, long pES,
                         u16* __restrict__ xdh, u16* __restrict__ xdl,
                         u16* __restrict__ kdh, u16* __restrict__ kdl,
                         const int* __restrict__ se, const int* __restrict__ sb,
                         const int* __restrict__ sxb, const int* __restrict__ skvb) {
    int rr = blockIdx.x, s = blockIdx.y;
    int e = se[s];
    const float* row;
    const float *w, *bv;
    u16 *dh, *dl;
    long doff;
    if (rr < NQ_) {
        doff = (long)(sxb[s] + rr)*HID;
        row = xsrc + doff;
        w = xw; bv = xb; dh = xdh; dl = xdl;
    } else {
        int r = rr - NQ_;
        int b = sb[s];
        int rl, sq, qo, io;
        if (r < 320)      { rl = r;       sq = 64; qo = 0;   io = 0;   }
        else if (r < 624) { rl = r - 320; sq = 48; qo = 64;  io = 256; }
        else              { rl = r - 624; sq = 32; qo = 112; io = 512; }
        if (rl < sq) row = query + ((long)e*NQ_ + qo + rl)*HID;
        else {
            int zi = io + rl - sq;
            if (zi < LV_) row = img + ((long)b*LV_ + zi)*HID;
            else          row = pp  + ((long)b*LP_ + zi - LV_)*HID;
        }
        doff = (long)(skvb[s] + r)*HID;
        w = kw; bv = kb; dh = kdh; dl = kdl;
    }
    __shared__ float sh[64];
    float v[4]; float sm = 0.f, ss = 0.f;
    #pragma unroll
    for (int t = 0; t < 4; t++) { v[t] = row[threadIdx.x + t*256]; sm += v[t]; ss += v[t]*v[t]; }
    blockReduce2(sm, ss, sh);
    float m  = sm * (1.f/HID);
    float rs = rsqrtf(ss * (1.f/HID) - m*m + 1e-5f);
    const float* we = w + (long)e*pES;
    const float* be = bv + (long)e*pES;
    #pragma unroll
    for (int t = 0; t < 4; t++) {
        int i = threadIdx.x + t*256;
        float rv = (v[t] - m)*rs*we[i] + be[i];
        fsplit1(rv, dh[doff + i], dl[doff + i]);
    }
}

// ---------------- LayerNorm (x rows only, MLP LN) ----------------
__global__ void k_ln(const float* __restrict__ src,
                     const float* __restrict__ w, const float* __restrict__ bvec, long pES,
                     u16* __restrict__ dh, u16* __restrict__ dl,
                     const int* __restrict__ se, const int* __restrict__ sxb) {
    int r = blockIdx.x, s = blockIdx.y;
    int e = se[s];
    long row = (long)(sxb[s] + r)*HID;
    __shared__ float sh[64];
    float v[4]; float sm = 0.f, ss = 0.f;
    #pragma unroll
    for (int t = 0; t < 4; t++) { v[t] = src[row + threadIdx.x + t*256]; sm += v[t]; ss += v[t]*v[t]; }
    blockReduce2(sm, ss, sh);
    float m  = sm * (1.f/HID);
    float rs = rsqrtf(ss * (1.f/HID) - m*m + 1e-5f);
    const float* we = w + (long)e*pES;
    const float* be = bvec + (long)e*pES;
    #pragma unroll
    for (int t = 0; t < 4; t++) {
        int i = threadIdx.x + t*256;
        float rv = (v[t] - m)*rs*we[i] + be[i];
        fsplit1(rv, dh[row + i], dl[row + i]);
    }
}

// ---------------- attention (fp16 Q/KV, 4-way ILP) -> fp16 hi/lo ----------------
__global__ void k_attn(const u16* __restrict__ q16, const u16* __restrict__ kv16,
                       u16* __restrict__ ath, u16* __restrict__ atl,
                       const int* __restrict__ sxb, const int* __restrict__ skvb) {
    int s = blockIdx.y, st = blockIdx.z;
    int sq    = (st == 0) ? 64 : (st == 1 ? 48 : 32);
    int qo    = (st == 0) ? 0  : (st == 1 ? 64 : 112);
    int kvo   = (st == 0) ? 0  : (st == 1 ? 320 : 624);
    int kvlen = sq + 256;
    int warp = threadIdx.x >> 5, lane = threadIdx.x & 31;
    int w = blockIdx.x * 4 + warp;
    if (w >= NHEADS * sq) return;
    int h = w / sq, qi = w % sq;
    __shared__ float sc[4][320];

    long qrow  = (long)sxb[s] + qo + qi;
    long kvrow = (long)skvb[s] + kvo;
    const __half2 qh = *(const __half2*)(q16 + qrow*HID + h*HDIM + lane*2);
    float q0 = __low2float(qh), q1 = __high2float(qh);
    const u16* kbase = kv16 + kvrow*2048 + h*HDIM + lane*2;
    float mx = -1e30f;
    for (int j = 0; j < kvlen; j += 4) {
        __half2 k0 = *(const __half2*)(kbase + (long)j*2048);
        __half2 k1 = *(const __half2*)(kbase + (long)(j+1)*2048);
        __half2 k2 = *(const __half2*)(kbase + (long)(j+2)*2048);
        __half2 k3 = *(const __half2*)(kbase + (long)(j+3)*2048);
        float p0 = q0*__low2float(k0) + q1*__high2float(k0);
        float p1 = q0*__low2float(k1) + q1*__high2float(k1);
        float p2 = q0*__low2float(k2) + q1*__high2float(k2);
        float p3 = q0*__low2float(k3) + q1*__high2float(k3);
        #pragma unroll
        for (int o = 16; o; o >>= 1) {
            p0 += __shfl_xor_sync(~0u, p0, o);
            p1 += __shfl_xor_sync(~0u, p1, o);
            p2 += __shfl_xor_sync(~0u, p2, o);
            p3 += __shfl_xor_sync(~0u, p3, o);
        }
        p0 *= 0.125f; p1 *= 0.125f; p2 *= 0.125f; p3 *= 0.125f;
        if (lane == 0) {
            sc[warp][j]   = p0; sc[warp][j+1] = p1;
            sc[warp][j+2] = p2; sc[warp][j+3] = p3;
        }
        mx = fmaxf(mx, fmaxf(fmaxf(p0, p1), fmaxf(p2, p3)));
    }
    __syncwarp();
    float se_ = 0.f;
    for (int j = lane; j < kvlen; j += 32) {
        float ex = __expf(sc[warp][j] - mx);
        sc[warp][j] = ex;
        se_ += ex;
    }
    #pragma unroll
    for (int o = 16; o; o >>= 1) se_ += __shfl_xor_sync(~0u, se_, o);
    __syncwarp();
    float inv = 1.f / se_;
    const u16* vbase = kv16 + kvrow*2048 + 1024 + h*HDIM + lane*2;
    float a0 = 0.f, a1 = 0.f;
    #pragma unroll 4
    for (int j = 0; j < kvlen; j++) {
        float p = sc[warp][j];
        __half2 vv = *(const __half2*)(vbase + (long)j*2048);
        a0 += p*__low2float(vv); a1 += p*__high2float(vv);
    }
    long ooff = qrow*HID + h*HDIM + lane*2;
    fsplit1(a0 * inv, ath[ooff],     atl[ooff]);
    fsplit1(a1 * inv, ath[ooff + 1], atl[ooff + 1]);
}

// ---------------- combine 2 slots per batch + gated bias + RMS + final scaling ----------------
__global__ void k_rms_combine(const float* __restrict__ O, const float* __restrict__ bo,
                              float* __restrict__ out, const float* __restrict__ fw,
                              const float* __restrict__ gain,
                              const int* __restrict__ b2s, const int* __restrict__ se,
                              const float* __restrict__ sg, const int* __restrict__ sxb) {
    int qrow = blockIdx.x, b = blockIdx.y;
    int s0 = b2s[b*2], s1 = b2s[b*2 + 1];
    int e0 = se[s0], e1 = se[s1];
    float g0 = sg[s0], g1 = sg[s1];
    long r0 = (long)(sxb[s0] + qrow)*OUTD;
    long r1 = (long)(sxb[s1] + qrow)*OUTD;
    const float* bo0 = bo + (long)e0*OUTD;
    const float* bo1 = bo + (long)e1*OUTD;
    float* orow = out + ((long)b*NQ_ + qrow)*OUTD;
    __shared__ float sh[64];
    float v[16]; float ss = 0.f;
    #pragma unroll
    for (int t = 0; t < 16; t++) {
        int o = threadIdx.x + t*256;
        float val = O[r0 + o] + O[r1 + o] + g0*bo0[o] + g1*bo1[o];
        v[t] = val; ss += val*val;
    }
    ss = blockReduce1(ss, sh);
    float sc = rsqrtf(ss * (1.f/OUTD) + 1e-6f);
    #pragma unroll
    for (int t = 0; t < 16; t++) {
        int o = threadIdx.x + t*256;
        orow[o] = v[t]*sc*fw[o]*gain[o];
    }
}

// ---------------- host orchestration ----------------
extern "C" void kernel_launch(void* const* d_in, const int* in_sizes, int n_in,
                              void* d_out, int out_size) {
    const float* image     = (const float*)d_in[0];
    const float* pp        = (const float*)d_in[1];
    const int*   tids      = (const int*)  d_in[2];
    const int*   eids      = (const int*)  d_in[3];
    const float* query     = (const float*)d_in[4];
    const float* ln1_w     = (const float*)d_in[5];
    const float* ln1_b     = (const float*)d_in[6];
    const float* ln1kv_w   = (const float*)d_in[7];
    const float* ln1kv_b   = (const float*)d_in[8];
    const float* attn_in_w = (const float*)d_in[9];
    const float* attn_in_b = (const float*)d_in[10];
    const float* attn_out_w= (const float*)d_in[11];
    const float* attn_out_b= (const float*)d_in[12];
    const float* ls1       = (const float*)d_in[13];
    const float* ls2       = (const float*)d_in[14];
    const float* ln2_w     = (const float*)d_in[15];
    const float* ln2_b     = (const float*)d_in[16];
    const float* fc_w      = (const float*)d_in[17];
    const float* fc_b      = (const float*)d_in[18];
    const float* proj_w    = (const float*)d_in[19];
    const float* proj_b    = (const float*)d_in[20];
    const float* outp_w    = (const float*)d_in[21];
    const float* outp_b    = (const float*)d_in[22];
    const float* temb      = (const float*)d_in[23];
    const float* eemb      = (const float*)d_in[24];
    const float* glw       = (const float*)d_in[25];
    const float* glb       = (const float*)d_in[26];
    const float* gwt       = (const float*)d_in[27];
    const float* gbias     = (const float*)d_in[28];
    const float* gain      = (const float*)d_in[29];
    const float* fw        = (const float*)d_in[30];
    float* out = (float*)d_out;

    float *px, *po, *pg, *pgi, *prowg;
    int *pcnt, *psoff, *pse, *psb, *pxseg, *pkvseg, *pxval, *pkvval, *psxb, *pskvb, *pb2s;
    float *psg;
    cudaGetSymbolAddress((void**)&px,    g_x);
    cudaGetSymbolAddress((void**)&po,    g_o);
    cudaGetSymbolAddress((void**)&pg,    g_gates);
    cudaGetSymbolAddress((void**)&pgi,   g_gi);
    cudaGetSymbolAddress((void**)&pcnt,  g_cnt);
    cudaGetSymbolAddress((void**)&psoff, g_soff);
    cudaGetSymbolAddress((void**)&pse,   g_se);
    cudaGetSymbolAddress((void**)&psb,   g_sb);
    cudaGetSymbolAddress((void**)&psg,   g_sg);
    cudaGetSymbolAddress((void**)&pxseg, g_xseg);
    cudaGetSymbolAddress((void**)&pkvseg,g_kvseg);
    cudaGetSymbolAddress((void**)&pxval, g_xvalid);
    cudaGetSymbolAddress((void**)&pkvval,g_kvvalid);
    cudaGetSymbolAddress((void**)&psxb,  g_sxb);
    cudaGetSymbolAddress((void**)&pskvb, g_skvb);
    cudaGetSymbolAddress((void**)&pb2s,  g_b2s);
    cudaGetSymbolAddress((void**)&prowg, g_rowg);

    u16 *pq16, *pkv16;
    cudaGetSymbolAddress((void**)&pq16,  g_q16);
    cudaGetSymbolAddress((void**)&pkv16, g_kv16);

    u16 *xh, *xl, *kh, *kl, *ah, *al, *fh, *fl;
    cudaGetSymbolAddress((void**)&xh, g_xln_h); cudaGetSymbolAddress((void**)&xl, g_xln_l);
    cudaGetSymbolAddress((void**)&kh, g_kvn_h); cudaGetSymbolAddress((void**)&kl, g_kvn_l);
    cudaGetSymbolAddress((void**)&ah, g_att_h); cudaGetSymbolAddress((void**)&al, g_att_l);
    cudaGetSymbolAddress((void**)&fh, g_ffn_h); cudaGetSymbolAddress((void**)&fl, g_ffn_l);

    u16 *aiw, *aow, *fcw, *pjw, *opw;
    cudaGetSymbolAddress((void**)&aiw, g_aiw);
    cudaGetSymbolAddress((void**)&aow, g_aow);
    cudaGetSymbolAddress((void**)&fcw, g_fcw);
    cudaGetSymbolAddress((void**)&pjw, g_pjw);
    cudaGetSymbolAddress((void**)&opw, g_opw);

    cudaFuncSetAttribute((const void*)k_tgemm<1,64>, cudaFuncAttributeMaxDynamicSharedMemorySize, DSMEM(1,64));
    cudaFuncSetAttribute((const void*)k_tgemm<2,32>, cudaFuncAttributeMaxDynamicSharedMemorySize, DSMEM(2,32));
    cudaFuncSetAttribute((const void*)k_tgemm_qkv,   cudaFuncAttributeMaxDynamicSharedMemorySize, DSMEM(1,64));

    k_cvt_all<<<2048, 256>>>(
        (const float4*)attn_in_w,  (uint2*)aiw,
        (const float4*)attn_out_w, (uint2*)aow,
        (const float4*)fc_w,       (uint2*)fcw,
        (const float4*)proj_w,     (uint2*)pjw,
        (const float4*)outp_w,     (uint2*)opw);

    k_gate_mean<<<dim3(BATCH, 16), 256>>>(image, pgi);
    k_gate<<<BATCH, 256>>>(pgi, temb, eemb, tids, eids, glw, glb, gwt, gbias, pg);
    k_slots<<<1, 256>>>(pg, pcnt, psoff, pse, psb, psg,
                        pxseg, pkvseg, pxval, pkvval, psxb, pskvb, pb2s, prowg);

    k_initx<<<dim3(NQ_, NSLOT), 256>>>(query, px, pse, psxb);

    const long HH = (long)HID*HID;
    const int XMB = 22;
    const int KVMB = 118;

    for (int l = 0; l < NLAYERS; l++) {
        k_ln_all<<<dim3(NQ_ + KVR, NSLOT), 256>>>(px, query, image, pp,
            ln1_w + (long)l*HID, ln1_b + (long)l*HID,
            ln1kv_w + (long)l*HID, ln1kv_b + (long)l*HID, (long)NLAYERS*HID,
            xh, xl, kh, kl, pse, psb, psxb, pskvb);
        // Q + KV projections, 1-term activations, chunk 64
        k_tgemm_qkv<<<dim3(16, XMB + KVMB), 256, DSMEM(1,64)>>>(XMB,
            xh, aiw + (long)l*3*HH,
            attn_in_b + (long)l*3*HID, pq16, pxseg, pxval,
            kh, aiw + (long)l*3*HH + HH,
            attn_in_b + (long)l*3*HID + HID, pkv16, pkvseg, pkvval,
            (long)NLAYERS*3*HH, (long)NLAYERS*3*HID);
        k_attn<<<dim3(256, NSLOT, 3), 128>>>(pq16, pkv16, ah, al, psxb, pskvb);
        // attn-out projection + residual (ls1-damped): 1-term, chunk 64
        k_tgemm<1,64><<<dim3(8, XMB), 256, DSMEM(1,64)>>>(HID, HID,
            ah, al, aow + (long)l*HH, (long)NLAYERS*HH,
            attn_out_b + (long)l*HID, (long)NLAYERS*HID,
            px, (u16*)0, (u16*)0, ls1 + (long)l*HID, (long)NLAYERS*HID,
            (const float*)0, 2, pxseg, pxval);
        k_ln<<<dim3(NQ_, NSLOT), 256>>>(px,
            ln2_w + (long)l*HID, ln2_b + (long)l*HID, (long)NLAYERS*HID,
            xh, xl, pse, psxb);
        // FC: 1-term, chunk 64
        k_tgemm<1,64><<<dim3(32, XMB), 256, DSMEM(1,64)>>>(4*HID, HID,
            xh, xl, fcw + (long)l*4*HH, (long)NLAYERS*4*HH,
            fc_b + (long)l*4*HID, (long)NLAYERS*4*HID,
            (float*)0, fh, fl, (const float*)0, 0,
            (const float*)0, 1, pxseg, pxval);
        // proj: 1-term, chunk 64; last layer fuses gate-scaled fp16 split (epi 4)
        k_tgemm<1,64><<<dim3(8, XMB), 256, DSMEM(1,64)>>>(HID, 4*HID,
            fh, fl, pjw + (long)l*4*HH, (long)NLAYERS*4*HH,
            proj_b + (long)l*HID, (long)NLAYERS*HID,
            px, xh, xl, ls2 + (long)l*HID, (long)NLAYERS*HID,
            prowg, (l == NLAYERS-1) ? 4 : 2, pxseg, pxval);
    }

    // out projection: undamped direct path — 2-term activations, chunk 32
    k_tgemm<2,32><<<dim3(OUTD/128, XMB), 256, DSMEM(2,32)>>>(OUTD, HID,
        xh, xl, opw, (long)OUTD*HID,
        (const float*)0, 0,
        po, (u16*)0, (u16*)0, (const float*)0, 0,
        (const float*)0, 3, pxseg, pxval);
    k_rms_combine<<<dim3(NQ_, BATCH), 256>>>(po, outp_b, out, fw, gain, pb2s, pse, psg, psxb);
}